// round 1
// baseline (speedup 1.0000x reference)
#include <cuda_runtime.h>
#include <math.h>

// ---------------- problem constants ----------------
namespace {
constexpr int B = 2, S = 2048, D = 1024, E = 16, HD = 64, CAP = 1280, TOPK = 8;
constexpr float EPS = 1e-6f;
constexpr float THETA = 10000.0f;
constexpr int EB = E * B;    // 32
constexpr int NTOK = B * S;  // 4096
}

// ---------------- scratch (device globals; no allocation allowed) ----------------
__device__ float g_route[NTOK * E];        // route[b][s][e]
__device__ int   g_seq[EB * CAP];          // selected token seq index (sorted ascending)
__device__ float g_w[EB * CAP];            // routing weight of selected token
__device__ float g_q[EB * CAP * HD];
__device__ float g_k[EB * CAP * HD];
__device__ float g_v[EB * CAP * HD];
__device__ float g_ctx[EB * CAP * HD];
__device__ float g_comb[NTOK * D];         // scatter-add target

// ================= stage 1: gating (logits -> softmax -> top-8 mask -> mg) =================
__global__ void gate_kernel(const float* __restrict__ x,
                            const float* __restrict__ wg,
                            const float* __restrict__ bg) {
    int token = blockIdx.x;                      // 0..NTOK-1
    const float* xr = x + (size_t)token * D;
    float acc[E];
#pragma unroll
    for (int e = 0; e < E; e++) acc[e] = 0.f;
    for (int d = threadIdx.x; d < D; d += 256) {
        float xv = xr[d];
        const float* w = wg + (size_t)d * E;
#pragma unroll
        for (int e = 0; e < E; e++) acc[e] += xv * w[e];
    }
#pragma unroll
    for (int off = 16; off > 0; off >>= 1) {
#pragma unroll
        for (int e = 0; e < E; e++)
            acc[e] += __shfl_xor_sync(0xffffffffu, acc[e], off);
    }
    __shared__ float red[8][E];
    int warp = threadIdx.x >> 5, lane = threadIdx.x & 31;
    if (lane == 0) {
#pragma unroll
        for (int e = 0; e < E; e++) red[warp][e] = acc[e];
    }
    __syncthreads();
    if (threadIdx.x == 0) {
        float g[E];
        float mx = -3.402823466e38f;
#pragma unroll
        for (int e = 0; e < E; e++) {
            float s = bg[e];
            for (int w = 0; w < 8; w++) s += red[w][e];
            g[e] = s;
            mx = fmaxf(mx, s);
        }
        float den = 0.f;
#pragma unroll
        for (int e = 0; e < E; e++) { g[e] = expf(g[e] - mx); den += g[e]; }
        float inv = 1.f / den;
#pragma unroll
        for (int e = 0; e < E; e++) g[e] *= inv;
        // top-8 mask, ties -> lower index wins (matches jax.lax.top_k)
#pragma unroll
        for (int e = 0; e < E; e++) {
            int r = 0;
#pragma unroll
            for (int j = 0; j < E; j++)
                r += (g[j] > g[e]) || (g[j] == g[e] && j < e);
            g_route[(size_t)token * E + e] = (r < TOPK) ? g[e] : 0.f;
        }
    }
}

// ================= stage 2: route = mg / (sum_b mg + EPS) * capacity(=2) =================
__global__ void route_kernel() {
    int idx = blockIdx.x * blockDim.x + threadIdx.x;
    if (idx >= S * E) return;
    int s = idx / E, e = idx % E;
    float m0 = g_route[(size_t)s * E + e];
    float m1 = g_route[(size_t)(S + s) * E + e];
    float den = m0 + m1 + EPS;
    g_route[(size_t)s * E + e]       = m0 / den * 2.0f;
    g_route[(size_t)(S + s) * E + e] = m1 / den * 2.0f;
}

// ================= stage 3: top-CAP token selection per (e,b), jax tie semantics =========
__global__ void select_kernel() {
    int eb = blockIdx.x;          // e*B + b
    int e = eb >> 1, b = eb & 1;
    __shared__ float sv[S];
    __shared__ unsigned char sm[S];
    for (int s = threadIdx.x; s < S; s += 256)
        sv[s] = g_route[(size_t)(b * S + s) * E + e];
    __syncthreads();
    for (int i = threadIdx.x; i < S; i += 256) {
        float vi = sv[i];
        int cnt = 0;
        for (int j = 0; j < S; j++) {
            float vj = sv[j];
            cnt += (vj > vi) || (vj == vi && j < i);
        }
        sm[i] = (cnt < CAP) ? 1 : 0;
    }
    __syncthreads();
    if (threadIdx.x == 0) {
        int p = 0;
        for (int s = 0; s < S; s++) {
            if (sm[s]) {
                g_seq[eb * CAP + p] = s;
                g_w[eb * CAP + p] = sv[s];
                p++;
            }
        }
    }
}

// ================= stage 4a: Q/K/V projection GEMM (gathered rows) =================
// grid (CAP/64=20, 3, EB=32), 256 threads, 64x64 tile, BK=16, 4x4 per thread
__global__ void proj_kernel(const float* __restrict__ x,
                            const float* __restrict__ Wq,
                            const float* __restrict__ Wkv) {
    int mt = blockIdx.x, nt = blockIdx.y, eb = blockIdx.z;
    int e = eb >> 1, b = eb & 1;
    __shared__ float As[16][68];  // [k][m]
    __shared__ float Bs[16][68];  // [k][n]
    int tid = threadIdx.x;
    int tx = tid & 15, ty = tid >> 4;
    int m0 = mt * 64;
    int lrow = tid >> 2, lk = (tid & 3) << 2;
    int seqv = g_seq[eb * CAP + m0 + lrow];
    const float* arow = x + (size_t)(b * S + seqv) * D;
    int bk = tid >> 4, bn = (tid & 15) << 2;
    const float* Bbase;
    int bstride;
    if (nt == 0) { Bbase = Wq + (size_t)e * D * HD; bstride = HD; }
    else         { Bbase = Wkv + (size_t)e * D * (2 * HD) + (nt == 2 ? HD : 0); bstride = 2 * HD; }
    float acc[4][4];
#pragma unroll
    for (int i = 0; i < 4; i++)
#pragma unroll
        for (int j = 0; j < 4; j++) acc[i][j] = 0.f;

    for (int k0 = 0; k0 < D; k0 += 16) {
        float4 a4 = *(const float4*)(arow + k0 + lk);
        As[lk + 0][lrow] = a4.x;
        As[lk + 1][lrow] = a4.y;
        As[lk + 2][lrow] = a4.z;
        As[lk + 3][lrow] = a4.w;
        float4 b4 = *(const float4*)(Bbase + (size_t)(k0 + bk) * bstride + bn);
        *(float4*)&Bs[bk][bn] = b4;
        __syncthreads();
#pragma unroll
        for (int kk = 0; kk < 16; kk++) {
            float a[4], bb[4];
#pragma unroll
            for (int i = 0; i < 4; i++) a[i] = As[kk][ty * 4 + i];
#pragma unroll
            for (int j = 0; j < 4; j++) bb[j] = Bs[kk][tx * 4 + j];
#pragma unroll
            for (int i = 0; i < 4; i++)
#pragma unroll
                for (int j = 0; j < 4; j++) acc[i][j] += a[i] * bb[j];
        }
        __syncthreads();
    }
    float* outb = (nt == 0) ? g_q : (nt == 1 ? g_k : g_v);
#pragma unroll
    for (int i = 0; i < 4; i++) {
        int row = m0 + ty * 4 + i;
        float* orow = outb + ((size_t)eb * CAP + row) * HD;
#pragma unroll
        for (int j = 0; j < 4; j++) orow[tx * 4 + j] = acc[i][j];
    }
}

// ================= stage 4b: RoPE on q and k =================
__global__ void rope_kernel() {
    int idx = blockIdx.x * blockDim.x + threadIdx.x;
    if (idx >= EB * CAP * 32) return;
    int h = idx & 31;
    int t = idx >> 5;                 // 0..EB*CAP-1
    int pos = g_seq[t];
    float invf = powf(THETA, -(float)(2 * h) / (float)HD);
    float ang = (float)pos * invf;
    float c = cosf(ang), s = sinf(ang);
    float* q = g_q + (size_t)t * HD;
    float* k = g_k + (size_t)t * HD;
    float q1 = q[h], q2 = q[h + 32];
    q[h]      = q1 * c - q2 * s;
    q[h + 32] = q2 * c + q1 * s;
    float k1 = k[h], k2 = k[h + 32];
    k[h]      = k1 * c - k2 * s;
    k[h + 32] = k2 * c + k1 * s;
}

// ================= stage 5: causal flash attention =================
// grid (CAP/64=20, EB=32), 256 threads, BM=BN=64, dynamic smem
namespace { constexpr int SD = 65; }
__global__ void attn_kernel() {
    extern __shared__ float smem[];
    float* Qs = smem;
    float* Ks = Qs + 64 * SD;
    float* Vs = Ks + 64 * SD;
    float* Ps = Vs + 64 * SD;
    int mt = blockIdx.x, eb = blockIdx.y;
    int m0 = mt * 64;
    const float* qb = g_q + (size_t)eb * CAP * HD;
    const float* kb = g_k + (size_t)eb * CAP * HD;
    const float* vb = g_v + (size_t)eb * CAP * HD;
    int tid = threadIdx.x;
    int tx = tid & 15, ty = tid >> 4;

    for (int i = tid; i < 64 * 16; i += 256) {
        int row = i >> 4, c4 = (i & 15) << 2;
        float4 v4 = *(const float4*)(qb + (size_t)(m0 + row) * HD + c4);
        Qs[row * SD + c4 + 0] = v4.x;
        Qs[row * SD + c4 + 1] = v4.y;
        Qs[row * SD + c4 + 2] = v4.z;
        Qs[row * SD + c4 + 3] = v4.w;
    }
    float mrow[4], lsum[4], o[4][4];
#pragma unroll
    for (int i = 0; i < 4; i++) {
        mrow[i] = -3.402823466e38f;
        lsum[i] = 0.f;
#pragma unroll
        for (int j = 0; j < 4; j++) o[i][j] = 0.f;
    }

    for (int nt = 0; nt <= mt; nt++) {
        int n0 = nt * 64;
        for (int i = tid; i < 64 * 16; i += 256) {
            int row = i >> 4, c4 = (i & 15) << 2;
            float4 k4 = *(const float4*)(kb + (size_t)(n0 + row) * HD + c4);
            Ks[row * SD + c4 + 0] = k4.x;
            Ks[row * SD + c4 + 1] = k4.y;
            Ks[row * SD + c4 + 2] = k4.z;
            Ks[row * SD + c4 + 3] = k4.w;
            float4 v4 = *(const float4*)(vb + (size_t)(n0 + row) * HD + c4);
            Vs[row * SD + c4 + 0] = v4.x;
            Vs[row * SD + c4 + 1] = v4.y;
            Vs[row * SD + c4 + 2] = v4.z;
            Vs[row * SD + c4 + 3] = v4.w;
        }
        __syncthreads();
        float s[4][4];
#pragma unroll
        for (int i = 0; i < 4; i++)
#pragma unroll
            for (int j = 0; j < 4; j++) s[i][j] = 0.f;
        for (int kk = 0; kk < 64; kk++) {
            float a[4], bb[4];
#pragma unroll
            for (int i = 0; i < 4; i++) a[i] = Qs[(ty * 4 + i) * SD + kk];
#pragma unroll
            for (int j = 0; j < 4; j++) bb[j] = Ks[(tx * 4 + j) * SD + kk];
#pragma unroll
            for (int i = 0; i < 4; i++)
#pragma unroll
                for (int j = 0; j < 4; j++) s[i][j] += a[i] * bb[j];
        }
        bool diag = (nt == mt);
#pragma unroll
        for (int i = 0; i < 4; i++) {
#pragma unroll
            for (int j = 0; j < 4; j++) {
                float val = s[i][j] * 0.125f;
                if (diag && (n0 + tx * 4 + j) > (m0 + ty * 4 + i))
                    val = -3.402823466e38f;
                s[i][j] = val;
            }
        }
        float nm[4], corr[4];
#pragma unroll
        for (int i = 0; i < 4; i++) {
            float m = fmaxf(fmaxf(s[i][0], s[i][1]), fmaxf(s[i][2], s[i][3]));
#pragma unroll
            for (int off = 8; off > 0; off >>= 1)
                m = fmaxf(m, __shfl_xor_sync(0xffffffffu, m, off));
            nm[i] = fmaxf(mrow[i], m);
            corr[i] = expf(mrow[i] - nm[i]);
        }
#pragma unroll
        for (int i = 0; i < 4; i++) {
            float rs = 0.f;
#pragma unroll
            for (int j = 0; j < 4; j++) {
                float p = expf(s[i][j] - nm[i]);
                s[i][j] = p;
                rs += p;
            }
#pragma unroll
            for (int off = 8; off > 0; off >>= 1)
                rs += __shfl_xor_sync(0xffffffffu, rs, off);
            lsum[i] = lsum[i] * corr[i] + rs;
            mrow[i] = nm[i];
#pragma unroll
            for (int j = 0; j < 4; j++) o[i][j] *= corr[i];
        }
#pragma unroll
        for (int i = 0; i < 4; i++)
#pragma unroll
            for (int j = 0; j < 4; j++)
                Ps[(ty * 4 + i) * SD + tx * 4 + j] = s[i][j];
        __syncthreads();
        for (int n = 0; n < 64; n++) {
            float p[4], vv[4];
#pragma unroll
            for (int i = 0; i < 4; i++) p[i] = Ps[(ty * 4 + i) * SD + n];
#pragma unroll
            for (int j = 0; j < 4; j++) vv[j] = Vs[n * SD + tx * 4 + j];
#pragma unroll
            for (int i = 0; i < 4; i++)
#pragma unroll
                for (int j = 0; j < 4; j++) o[i][j] += p[i] * vv[j];
        }
        __syncthreads();
    }
#pragma unroll
    for (int i = 0; i < 4; i++) {
        float invl = 1.f / lsum[i];
        int row = m0 + ty * 4 + i;
        float* orow = g_ctx + ((size_t)eb * CAP + row) * HD;
#pragma unroll
        for (int j = 0; j < 4; j++) orow[tx * 4 + j] = o[i][j] * invl;
    }
}

// ================= zero combined =================
__global__ void zero_kernel() {
    int i = blockIdx.x * blockDim.x + threadIdx.x;
    float4* p = (float4*)g_comb;
    if (i < NTOK * D / 4) p[i] = make_float4(0.f, 0.f, 0.f, 0.f);
}

// ================= stage 6a: out = (ctx @ Wff + bff) * w, scatter-add =================
// grid (CAP/64=20, D/64=16, EB=32), 256 threads
__global__ void outproj_kernel(const float* __restrict__ Wff,
                               const float* __restrict__ bff) {
    int mt = blockIdx.x, nt = blockIdx.y, eb = blockIdx.z;
    int e = eb >> 1, b = eb & 1;
    __shared__ float As[64][68];  // ctx [m][k]
    __shared__ float Bs[64][68];  // Wff [k][n]
    int tid = threadIdx.x, tx = tid & 15, ty = tid >> 4;
    int m0 = mt * 64, n0 = nt * 64;
#pragma unroll
    for (int it = 0; it < 4; it++) {
        int li = tid + it * 256;
        int row = li >> 4, c4 = (li & 15) << 2;
        float4 a4 = *(const float4*)(g_ctx + ((size_t)eb * CAP + m0 + row) * HD + c4);
        *(float4*)&As[row][c4] = a4;
        float4 b4 = *(const float4*)(Wff + ((size_t)e * HD + row) * D + n0 + c4);
        *(float4*)&Bs[row][c4] = b4;
    }
    __syncthreads();
    float acc[4][4];
#pragma unroll
    for (int i = 0; i < 4; i++)
#pragma unroll
        for (int j = 0; j < 4; j++) acc[i][j] = 0.f;
    for (int kk = 0; kk < 64; kk++) {
        float a[4], bb[4];
#pragma unroll
        for (int i = 0; i < 4; i++) a[i] = As[ty * 4 + i][kk];
#pragma unroll
        for (int j = 0; j < 4; j++) bb[j] = Bs[kk][tx * 4 + j];
#pragma unroll
        for (int i = 0; i < 4; i++)
#pragma unroll
            for (int j = 0; j < 4; j++) acc[i][j] += a[i] * bb[j];
    }
#pragma unroll
    for (int i = 0; i < 4; i++) {
        int row = m0 + ty * 4 + i;
        float wv = g_w[eb * CAP + row];
        int seqv = g_seq[eb * CAP + row];
        float* crow = g_comb + (size_t)(b * S + seqv) * D + n0;
#pragma unroll
        for (int j = 0; j < 4; j++) {
            float val = (acc[i][j] + bff[n0 + tx * 4 + j]) * wv;
            atomicAdd(&crow[tx * 4 + j], val);
        }
    }
}

// ================= stage 6b: residual + LayerNorm =================
__global__ void ln_kernel(const float* __restrict__ x,
                          const float* __restrict__ gamma,
                          const float* __restrict__ beta,
                          float* __restrict__ out) {
    int token = blockIdx.x;
    const float* xr = x + (size_t)token * D;
    const float* cr = g_comb + (size_t)token * D;
    int tid = threadIdx.x;
    float h[4];
    float s = 0.f;
#pragma unroll
    for (int t = 0; t < 4; t++) {
        int d = tid + t * 256;
        h[t] = xr[d] + cr[d];
        s += h[t];
    }
    __shared__ float red[8];
#pragma unroll
    for (int off = 16; off > 0; off >>= 1) s += __shfl_xor_sync(0xffffffffu, s, off);
    int warp = tid >> 5, lane = tid & 31;
    if (lane == 0) red[warp] = s;
    __syncthreads();
    float total = 0.f;
#pragma unroll
    for (int w = 0; w < 8; w++) total += red[w];
    __syncthreads();
    float mu = total * (1.0f / D);
    float ss = 0.f;
#pragma unroll
    for (int t = 0; t < 4; t++) {
        float dlt = h[t] - mu;
        ss += dlt * dlt;
    }
#pragma unroll
    for (int off = 16; off > 0; off >>= 1) ss += __shfl_xor_sync(0xffffffffu, ss, off);
    if (lane == 0) red[warp] = ss;
    __syncthreads();
    float vtot = 0.f;
#pragma unroll
    for (int w = 0; w < 8; w++) vtot += red[w];
    float var = vtot * (1.0f / D);
    float inv = rsqrtf(var + 1e-5f);
#pragma unroll
    for (int t = 0; t < 4; t++) {
        int d = tid + t * 256;
        out[(size_t)token * D + d] = (h[t] - mu) * inv * gamma[d] + beta[d];
    }
}

// ================= launch =================
extern "C" void kernel_launch(void* const* d_in, const int* in_sizes, int n_in,
                              void* d_out, int out_size) {
    const float* x     = (const float*)d_in[0];
    const float* wg    = (const float*)d_in[1];
    const float* bg    = (const float*)d_in[2];
    const float* Wq    = (const float*)d_in[3];
    const float* Wkv   = (const float*)d_in[4];
    const float* Wff   = (const float*)d_in[5];
    const float* bff   = (const float*)d_in[6];
    const float* gamma = (const float*)d_in[7];
    const float* beta  = (const float*)d_in[8];
    float* out = (float*)d_out;

    (void)in_sizes; (void)n_in; (void)out_size;

    gate_kernel<<<NTOK, 256>>>(x, wg, bg);
    route_kernel<<<(S * E + 255) / 256, 256>>>();
    select_kernel<<<EB, 256>>>();
    proj_kernel<<<dim3(CAP / 64, 3, EB), 256>>>(x, Wq, Wkv);
    rope_kernel<<<(EB * CAP * 32 + 255) / 256, 256>>>();

    int attn_smem = 4 * 64 * SD * (int)sizeof(float);
    cudaFuncSetAttribute(attn_kernel, cudaFuncAttributeMaxDynamicSharedMemorySize, attn_smem);
    attn_kernel<<<dim3(CAP / 64, EB), 256, attn_smem>>>();

    zero_kernel<<<(NTOK * D / 4 + 255) / 256, 256>>>();
    outproj_kernel<<<dim3(CAP / 64, D / 64, EB), 256>>>(Wff, bff);
    ln_kernel<<<NTOK, 256>>>(x, gamma, beta, out);
}

// round 2
// speedup vs baseline: 1.1813x; 1.1813x over previous
#include <cuda_runtime.h>
#include <math.h>

// ---------------- problem constants ----------------
namespace {
constexpr int B = 2, S = 2048, D = 1024, E = 16, HD = 64, CAP = 1280, TOPK = 8;
constexpr float EPS = 1e-6f;
constexpr float THETA = 10000.0f;
constexpr int EB = E * B;    // 32
constexpr int NTOK = B * S;  // 4096
}

// ---------------- scratch (device globals; no allocation allowed) ----------------
__device__ float g_route[NTOK * E];        // route[b][s][e]
__device__ int   g_seq[EB * CAP];          // selected token seq index (sorted ascending)
__device__ float g_w[EB * CAP];            // routing weight of selected token
__device__ int   g_inv[E * NTOK];          // inverse map: pos in selected list or -1
__device__ float g_q[EB * CAP * HD];
__device__ float g_k[EB * CAP * HD];
__device__ float g_v[EB * CAP * HD];
__device__ float g_ctx[EB * CAP * HD];
__device__ float g_out[(size_t)EB * CAP * D];  // per-expert weighted outputs (168MB)

// ================= stage 1: gating (logits -> softmax -> top-8 mask -> mg) =================
__global__ void gate_kernel(const float* __restrict__ x,
                            const float* __restrict__ wg,
                            const float* __restrict__ bg) {
    int token = blockIdx.x;                      // 0..NTOK-1
    const float* xr = x + (size_t)token * D;
    float acc[E];
#pragma unroll
    for (int e = 0; e < E; e++) acc[e] = 0.f;
    for (int d = threadIdx.x; d < D; d += 256) {
        float xv = xr[d];
        const float* w = wg + (size_t)d * E;
#pragma unroll
        for (int e = 0; e < E; e++) acc[e] += xv * w[e];
    }
#pragma unroll
    for (int off = 16; off > 0; off >>= 1) {
#pragma unroll
        for (int e = 0; e < E; e++)
            acc[e] += __shfl_xor_sync(0xffffffffu, acc[e], off);
    }
    __shared__ float red[8][E];
    int warp = threadIdx.x >> 5, lane = threadIdx.x & 31;
    if (lane == 0) {
#pragma unroll
        for (int e = 0; e < E; e++) red[warp][e] = acc[e];
    }
    __syncthreads();
    if (threadIdx.x == 0) {
        float g[E];
        float mx = -3.402823466e38f;
#pragma unroll
        for (int e = 0; e < E; e++) {
            float s = bg[e];
            for (int w = 0; w < 8; w++) s += red[w][e];
            g[e] = s;
            mx = fmaxf(mx, s);
        }
        float den = 0.f;
#pragma unroll
        for (int e = 0; e < E; e++) { g[e] = expf(g[e] - mx); den += g[e]; }
        float inv = 1.f / den;
#pragma unroll
        for (int e = 0; e < E; e++) g[e] *= inv;
        // top-8 mask, ties -> lower index wins (matches jax.lax.top_k)
#pragma unroll
        for (int e = 0; e < E; e++) {
            int r = 0;
#pragma unroll
            for (int j = 0; j < E; j++)
                r += (g[j] > g[e]) || (g[j] == g[e] && j < e);
            g_route[(size_t)token * E + e] = (r < TOPK) ? g[e] : 0.f;
        }
    }
}

// ================= stage 2: route = mg / (sum_b mg + EPS) * capacity(=2) =================
__global__ void route_kernel() {
    int idx = blockIdx.x * blockDim.x + threadIdx.x;
    if (idx >= S * E) return;
    int s = idx / E, e = idx % E;
    float m0 = g_route[(size_t)s * E + e];
    float m1 = g_route[(size_t)(S + s) * E + e];
    float den = m0 + m1 + EPS;
    g_route[(size_t)s * E + e]       = m0 / den * 2.0f;
    g_route[(size_t)(S + s) * E + e] = m1 / den * 2.0f;
}

// ================= stage 3: top-CAP token selection per (e,b), jax tie semantics =========
__global__ void select_kernel() {
    int eb = blockIdx.x;          // e*B + b
    int e = eb >> 1, b = eb & 1;
    __shared__ float sv[S];
    __shared__ unsigned char sm[S];
    __shared__ int cnt[256];
    for (int s = threadIdx.x; s < S; s += 256)
        sv[s] = g_route[(size_t)(b * S + s) * E + e];
    __syncthreads();
    for (int i = threadIdx.x; i < S; i += 256) {
        float vi = sv[i];
        int c = 0;
        for (int j = 0; j < S; j++) {
            float vj = sv[j];
            c += (vj > vi) || (vj == vi && j < i);
        }
        sm[i] = (c < CAP) ? 1 : 0;
    }
    __syncthreads();
    // parallel compaction: each thread owns 8 consecutive indices
    int t = threadIdx.x;
    int local = 0;
#pragma unroll
    for (int k = 0; k < 8; k++) local += sm[t * 8 + k];
    cnt[t] = local;
    __syncthreads();
    if (t == 0) {
        int run = 0;
        for (int i = 0; i < 256; i++) { int c = cnt[i]; cnt[i] = run; run += c; }
    }
    __syncthreads();
    int pos = cnt[t];
#pragma unroll
    for (int k = 0; k < 8; k++) {
        int s = t * 8 + k;
        if (sm[s]) {
            g_seq[eb * CAP + pos] = s;
            g_w[eb * CAP + pos] = sv[s];
            g_inv[e * NTOK + b * S + s] = pos;
            pos++;
        } else {
            g_inv[e * NTOK + b * S + s] = -1;
        }
    }
}

// ================= stage 4a: fused Q/K/V projection GEMM (gathered rows) =================
// grid (CAP/64=20, EB=32), 256 threads; tile M=64, N=192 (q|k|v), BK=16; 8x6 per thread
__global__ void proj_kernel(const float* __restrict__ x,
                            const float* __restrict__ Wq,
                            const float* __restrict__ Wkv) {
    int mt = blockIdx.x, eb = blockIdx.y;
    int e = eb >> 1, b = eb & 1;
    __shared__ float As[16][65];   // [k][m]
    __shared__ float Bs[16][200];  // [k][n=192 padded]
    int tid = threadIdx.x;
    int tx = tid & 31;             // n: 6 cols each
    int ty = tid >> 5;             // m: 8 rows each
    int m0 = mt * 64;

    int lrow = tid >> 2, lk = (tid & 3) << 2;
    int seqv = g_seq[eb * CAP + m0 + lrow];
    const float* arow = x + (size_t)(b * S + seqv) * D;

    const float* wq = Wq + (size_t)e * D * HD;
    const float* wkv = Wkv + (size_t)e * D * (2 * HD);

    float acc[8][6];
#pragma unroll
    for (int i = 0; i < 8; i++)
#pragma unroll
        for (int j = 0; j < 6; j++) acc[i][j] = 0.f;

    for (int k0 = 0; k0 < D; k0 += 16) {
        // A tile: 64 rows x 16 k
        float4 a4 = *(const float4*)(arow + k0 + lk);
        As[lk + 0][lrow] = a4.x;
        As[lk + 1][lrow] = a4.y;
        As[lk + 2][lrow] = a4.z;
        As[lk + 3][lrow] = a4.w;
        // B tile: 16 k x 192 n  (48 float4 per row, 768 total, 3 per thread)
#pragma unroll
        for (int it = 0; it < 3; it++) {
            int f = tid + it * 256;
            int kk = f / 48, c4 = f % 48;
            float4 b4;
            if (c4 < 16)
                b4 = *(const float4*)(wq + (size_t)(k0 + kk) * HD + c4 * 4);
            else
                b4 = *(const float4*)(wkv + (size_t)(k0 + kk) * (2 * HD) + (c4 - 16) * 4);
            *(float4*)&Bs[kk][c4 * 4] = b4;
        }
        __syncthreads();
#pragma unroll
        for (int kk = 0; kk < 16; kk++) {
            float a[8], bb[6];
#pragma unroll
            for (int i = 0; i < 8; i++) a[i] = As[kk][ty * 8 + i];
            float2 b0 = *(const float2*)&Bs[kk][tx * 6 + 0];
            float2 b1 = *(const float2*)&Bs[kk][tx * 6 + 2];
            float2 b2 = *(const float2*)&Bs[kk][tx * 6 + 4];
            bb[0] = b0.x; bb[1] = b0.y; bb[2] = b1.x; bb[3] = b1.y; bb[4] = b2.x; bb[5] = b2.y;
#pragma unroll
            for (int i = 0; i < 8; i++)
#pragma unroll
                for (int j = 0; j < 6; j++) acc[i][j] += a[i] * bb[j];
        }
        __syncthreads();
    }
    // epilogue: cols 0-63 -> q, 64-127 -> k, 128-191 -> v
#pragma unroll
    for (int i = 0; i < 8; i++) {
        int row = m0 + ty * 8 + i;
        size_t rbase = (size_t)eb * CAP + row;
#pragma unroll
        for (int j = 0; j < 6; j++) {
            int col = tx * 6 + j;
            float v = acc[i][j];
            if (col < 64)       g_q[rbase * HD + col] = v;
            else if (col < 128) g_k[rbase * HD + (col - 64)] = v;
            else                g_v[rbase * HD + (col - 128)] = v;
        }
    }
}

// ================= stage 4b: RoPE on q and k =================
__global__ void rope_kernel() {
    int idx = blockIdx.x * blockDim.x + threadIdx.x;
    if (idx >= EB * CAP * 32) return;
    int h = idx & 31;
    int t = idx >> 5;                 // 0..EB*CAP-1
    int pos = g_seq[t];
    float invf = powf(THETA, -(float)(2 * h) / (float)HD);
    float ang = (float)pos * invf;
    float c = cosf(ang), s = sinf(ang);
    float* q = g_q + (size_t)t * HD;
    float* k = g_k + (size_t)t * HD;
    float q1 = q[h], q2 = q[h + 32];
    q[h]      = q1 * c - q2 * s;
    q[h + 32] = q2 * c + q1 * s;
    float k1 = k[h], k2 = k[h + 32];
    k[h]      = k1 * c - k2 * s;
    k[h + 32] = k2 * c + k1 * s;
}

// ================= stage 5: causal flash attention =================
// grid (CAP/128=10, EB=32), 256 threads, BM=128, BN=64, 8x4 per thread
__global__ void attn_kernel() {
    extern __shared__ float smem[];
    float* Qs = smem;                 // [128][68]
    float* Ks = Qs + 128 * 68;        // [64][65]
    float* Vs = Ks + 64 * 65;         // [64][68]
    float* Ps = Vs + 64 * 68;         // [128][68]
    int mt = blockIdx.x, eb = blockIdx.y;
    int m0 = mt * 128;
    const float* qb = g_q + (size_t)eb * CAP * HD;
    const float* kb = g_k + (size_t)eb * CAP * HD;
    const float* vb = g_v + (size_t)eb * CAP * HD;
    int tid = threadIdx.x;
    int tx = tid & 15;                // n: 4 cols
    int ty = tid >> 4;                // m: 8 rows

    // load Q tile 128x64
#pragma unroll
    for (int it = 0; it < 8; it++) {
        int idx = tid + it * 256;
        int row = idx >> 4, c4 = (idx & 15) << 2;
        float4 v4 = *(const float4*)(qb + (size_t)(m0 + row) * HD + c4);
        *(float4*)&Qs[row * 68 + c4] = v4;
    }

    float mrow[8], lsum[8], o[8][4];
#pragma unroll
    for (int i = 0; i < 8; i++) {
        mrow[i] = -3.402823466e38f;
        lsum[i] = 0.f;
#pragma unroll
        for (int j = 0; j < 4; j++) o[i][j] = 0.f;
    }

    int ntiles = 2 * mt + 2;
    for (int nt = 0; nt < ntiles; nt++) {
        int n0 = nt * 64;
        // load K (transposed-read layout [n][k], stride 65) and V ([n][k] stride 68)
#pragma unroll
        for (int it = 0; it < 4; it++) {
            int idx = tid + it * 256;
            int row = idx >> 4, c4 = (idx & 15) << 2;
            float4 k4 = *(const float4*)(kb + (size_t)(n0 + row) * HD + c4);
            Ks[row * 65 + c4 + 0] = k4.x;
            Ks[row * 65 + c4 + 1] = k4.y;
            Ks[row * 65 + c4 + 2] = k4.z;
            Ks[row * 65 + c4 + 3] = k4.w;
            float4 v4 = *(const float4*)(vb + (size_t)(n0 + row) * HD + c4);
            *(float4*)&Vs[row * 68 + c4] = v4;
        }
        __syncthreads();
        // S = Q K^T
        float s[8][4];
#pragma unroll
        for (int i = 0; i < 8; i++)
#pragma unroll
            for (int j = 0; j < 4; j++) s[i][j] = 0.f;
#pragma unroll 4
        for (int kk = 0; kk < 64; kk++) {
            float a[8], bb[4];
#pragma unroll
            for (int i = 0; i < 8; i++) a[i] = Qs[(ty * 8 + i) * 68 + kk];
#pragma unroll
            for (int j = 0; j < 4; j++) bb[j] = Ks[(tx * 4 + j) * 65 + kk];
#pragma unroll
            for (int i = 0; i < 8; i++)
#pragma unroll
                for (int j = 0; j < 4; j++) s[i][j] += a[i] * bb[j];
        }
        bool maskTile = (nt >= 2 * mt);
#pragma unroll
        for (int i = 0; i < 8; i++) {
            int rowg = m0 + ty * 8 + i;
#pragma unroll
            for (int j = 0; j < 4; j++) {
                float val = s[i][j] * 0.125f;
                if (maskTile && (n0 + tx * 4 + j) > rowg)
                    val = -3.402823466e38f;
                s[i][j] = val;
            }
        }
        // online softmax (row reduction over 16-lane tx group)
#pragma unroll
        for (int i = 0; i < 8; i++) {
            float m = fmaxf(fmaxf(s[i][0], s[i][1]), fmaxf(s[i][2], s[i][3]));
#pragma unroll
            for (int off = 8; off > 0; off >>= 1)
                m = fmaxf(m, __shfl_xor_sync(0xffffffffu, m, off));
            float nm = fmaxf(mrow[i], m);
            float corr = __expf(mrow[i] - nm);
            float rs = 0.f;
#pragma unroll
            for (int j = 0; j < 4; j++) {
                float p = __expf(s[i][j] - nm);
                s[i][j] = p;
                rs += p;
            }
#pragma unroll
            for (int off = 8; off > 0; off >>= 1)
                rs += __shfl_xor_sync(0xffffffffu, rs, off);
            lsum[i] = lsum[i] * corr + rs;
            mrow[i] = nm;
#pragma unroll
            for (int j = 0; j < 4; j++) o[i][j] *= corr;
        }
        // write P to smem
#pragma unroll
        for (int i = 0; i < 8; i++)
            *(float4*)&Ps[(ty * 8 + i) * 68 + tx * 4] =
                make_float4(s[i][0], s[i][1], s[i][2], s[i][3]);
        __syncthreads();
        // O += P V
#pragma unroll 4
        for (int n = 0; n < 64; n++) {
            float4 v4 = *(const float4*)&Vs[n * 68 + tx * 4];
#pragma unroll
            for (int i = 0; i < 8; i++) {
                float p = Ps[(ty * 8 + i) * 68 + n];
                o[i][0] += p * v4.x;
                o[i][1] += p * v4.y;
                o[i][2] += p * v4.z;
                o[i][3] += p * v4.w;
            }
        }
        __syncthreads();
    }
#pragma unroll
    for (int i = 0; i < 8; i++) {
        float invl = 1.f / lsum[i];
        int row = m0 + ty * 8 + i;
        float* orow = g_ctx + ((size_t)eb * CAP + row) * HD;
        *(float4*)(orow + tx * 4) = make_float4(o[i][0] * invl, o[i][1] * invl,
                                                o[i][2] * invl, o[i][3] * invl);
    }
}

// ================= stage 6a: out = (ctx @ Wff + bff) * w -> dense g_out =================
// grid (CAP/128=10, D/64=16, EB=32), 256 threads, 8x4 per thread, K=64
__global__ void outproj_kernel(const float* __restrict__ Wff,
                               const float* __restrict__ bff) {
    int mt = blockIdx.x, nt = blockIdx.y, eb = blockIdx.z;
    int e = eb >> 1;
    __shared__ float As[128][65];  // ctx [m][k]
    __shared__ float Bs[64][68];   // Wff [k][n]
    int tid = threadIdx.x, tx = tid & 15, ty = tid >> 4;
    int m0 = mt * 128, n0 = nt * 64;
#pragma unroll
    for (int it = 0; it < 8; it++) {
        int idx = tid + it * 256;
        int row = idx >> 4, c4 = (idx & 15) << 2;
        float4 a4 = *(const float4*)(g_ctx + ((size_t)eb * CAP + m0 + row) * HD + c4);
        As[row][c4 + 0] = a4.x;
        As[row][c4 + 1] = a4.y;
        As[row][c4 + 2] = a4.z;
        As[row][c4 + 3] = a4.w;
    }
#pragma unroll
    for (int it = 0; it < 4; it++) {
        int idx = tid + it * 256;
        int row = idx >> 4, c4 = (idx & 15) << 2;
        float4 b4 = *(const float4*)(Wff + ((size_t)e * HD + row) * D + n0 + c4);
        *(float4*)&Bs[row][c4] = b4;
    }
    __syncthreads();
    float acc[8][4];
#pragma unroll
    for (int i = 0; i < 8; i++)
#pragma unroll
        for (int j = 0; j < 4; j++) acc[i][j] = 0.f;
#pragma unroll 4
    for (int kk = 0; kk < 64; kk++) {
        float a[8];
#pragma unroll
        for (int i = 0; i < 8; i++) a[i] = As[ty * 8 + i][kk];
        float4 b4 = *(const float4*)&Bs[kk][tx * 4];
#pragma unroll
        for (int i = 0; i < 8; i++) {
            acc[i][0] += a[i] * b4.x;
            acc[i][1] += a[i] * b4.y;
            acc[i][2] += a[i] * b4.z;
            acc[i][3] += a[i] * b4.w;
        }
    }
    float4 bf = *(const float4*)(bff + n0 + tx * 4);
#pragma unroll
    for (int i = 0; i < 8; i++) {
        int row = m0 + ty * 8 + i;
        float wv = g_w[eb * CAP + row];
        float4 r;
        r.x = (acc[i][0] + bf.x) * wv;
        r.y = (acc[i][1] + bf.y) * wv;
        r.z = (acc[i][2] + bf.z) * wv;
        r.w = (acc[i][3] + bf.w) * wv;
        *(float4*)(g_out + ((size_t)eb * CAP + row) * D + n0 + tx * 4) = r;
    }
}

// ================= stage 6b: gather-combine + residual + LayerNorm =================
__global__ void ln_kernel(const float* __restrict__ x,
                          const float* __restrict__ gamma,
                          const float* __restrict__ beta,
                          float* __restrict__ out) {
    int token = blockIdx.x;
    int b = token >> 11;  // S = 2048
    int tid = threadIdx.x;
    __shared__ int sh_base[E];
    __shared__ float red[8];
    if (tid < E) {
        int p = g_inv[tid * NTOK + token];
        sh_base[tid] = (p < 0) ? -1 : ((tid * B + b) * CAP + p);
    }
    __syncthreads();
    // each thread owns 4 consecutive d (one float4)
    float4 c = make_float4(0.f, 0.f, 0.f, 0.f);
#pragma unroll
    for (int e = 0; e < E; e++) {
        int base = sh_base[e];
        if (base >= 0) {
            float4 t4 = *(const float4*)(g_out + (size_t)base * D + tid * 4);
            c.x += t4.x; c.y += t4.y; c.z += t4.z; c.w += t4.w;
        }
    }
    float4 x4 = *(const float4*)(x + (size_t)token * D + tid * 4);
    float h[4] = {x4.x + c.x, x4.y + c.y, x4.z + c.z, x4.w + c.w};
    float s = h[0] + h[1] + h[2] + h[3];
#pragma unroll
    for (int off = 16; off > 0; off >>= 1) s += __shfl_xor_sync(0xffffffffu, s, off);
    int warp = tid >> 5, lane = tid & 31;
    if (lane == 0) red[warp] = s;
    __syncthreads();
    float total = 0.f;
#pragma unroll
    for (int w = 0; w < 8; w++) total += red[w];
    __syncthreads();
    float mu = total * (1.0f / D);
    float ss = 0.f;
#pragma unroll
    for (int t = 0; t < 4; t++) {
        float dlt = h[t] - mu;
        ss += dlt * dlt;
    }
#pragma unroll
    for (int off = 16; off > 0; off >>= 1) ss += __shfl_xor_sync(0xffffffffu, ss, off);
    if (lane == 0) red[warp] = ss;
    __syncthreads();
    float vtot = 0.f;
#pragma unroll
    for (int w = 0; w < 8; w++) vtot += red[w];
    float var = vtot * (1.0f / D);
    float inv = rsqrtf(var + 1e-5f);
    float4 g4 = *(const float4*)(gamma + tid * 4);
    float4 be4 = *(const float4*)(beta + tid * 4);
    float4 o4;
    o4.x = (h[0] - mu) * inv * g4.x + be4.x;
    o4.y = (h[1] - mu) * inv * g4.y + be4.y;
    o4.z = (h[2] - mu) * inv * g4.z + be4.z;
    o4.w = (h[3] - mu) * inv * g4.w + be4.w;
    *(float4*)(out + (size_t)token * D + tid * 4) = o4;
}

// ================= launch =================
extern "C" void kernel_launch(void* const* d_in, const int* in_sizes, int n_in,
                              void* d_out, int out_size) {
    const float* x     = (const float*)d_in[0];
    const float* wg    = (const float*)d_in[1];
    const float* bg    = (const float*)d_in[2];
    const float* Wq    = (const float*)d_in[3];
    const float* Wkv   = (const float*)d_in[4];
    const float* Wff   = (const float*)d_in[5];
    const float* bff   = (const float*)d_in[6];
    const float* gamma = (const float*)d_in[7];
    const float* beta  = (const float*)d_in[8];
    float* out = (float*)d_out;

    (void)in_sizes; (void)n_in; (void)out_size;

    gate_kernel<<<NTOK, 256>>>(x, wg, bg);
    route_kernel<<<(S * E + 255) / 256, 256>>>();
    select_kernel<<<EB, 256>>>();
    proj_kernel<<<dim3(CAP / 64, EB), 256>>>(x, Wq, Wkv);
    rope_kernel<<<(EB * CAP * 32 + 255) / 256, 256>>>();

    int attn_smem = (128 * 68 + 64 * 65 + 64 * 68 + 128 * 68) * (int)sizeof(float);
    cudaFuncSetAttribute(attn_kernel, cudaFuncAttributeMaxDynamicSharedMemorySize, attn_smem);
    attn_kernel<<<dim3(CAP / 128, EB), 256, attn_smem>>>();

    outproj_kernel<<<dim3(CAP / 128, D / 64, EB), 256>>>(Wff, bff);
    ln_kernel<<<NTOK, 256>>>(x, gamma, beta, out);
}

// round 3
// speedup vs baseline: 1.4759x; 1.2493x over previous
#include <cuda_runtime.h>
#include <math.h>
#include <stdint.h>

// ---------------- problem constants ----------------
namespace {
constexpr int B = 2, S = 2048, D = 1024, E = 16, HD = 64, CAP = 1280, TOPK = 8;
constexpr float EPS = 1e-6f;
constexpr float THETA = 10000.0f;
constexpr int EB = E * B;    // 32
constexpr int NTOK = B * S;  // 4096
}

// ---------------- scratch (device globals; no allocation allowed) ----------------
__device__ float g_route[NTOK * E];        // route[b][s][e]
__device__ int   g_seq[EB * CAP];          // selected token seq index (sorted ascending)
__device__ float g_w[EB * CAP];            // routing weight of selected token
__device__ int   g_inv[E * NTOK];          // inverse map: pos in selected list or -1
__device__ float g_q[EB * CAP * HD];
__device__ float g_k[EB * CAP * HD];
__device__ float g_v[EB * CAP * HD];
__device__ float g_ctx[EB * CAP * HD];
__device__ float g_out[(size_t)EB * CAP * D];  // per-expert weighted outputs (168MB)

// ---------------- tf32 helpers ----------------
__device__ __forceinline__ uint32_t f2tf32(float f) {
    uint32_t r;
    asm("cvt.rna.tf32.f32 %0, %1;" : "=r"(r) : "f"(f));
    return r;
}
__device__ __forceinline__ void mma_tf32(float& c0, float& c1, float& c2, float& c3,
                                         uint32_t a0, uint32_t a1, uint32_t a2, uint32_t a3,
                                         uint32_t b0, uint32_t b1) {
    asm volatile(
        "mma.sync.aligned.m16n8k8.row.col.f32.tf32.tf32.f32 "
        "{%0,%1,%2,%3}, {%4,%5,%6,%7}, {%8,%9}, {%0,%1,%2,%3};\n"
        : "+f"(c0), "+f"(c1), "+f"(c2), "+f"(c3)
        : "r"(a0), "r"(a1), "r"(a2), "r"(a3), "r"(b0), "r"(b1));
}

// ================= stage 1: gating (logits -> softmax -> top-8 mask -> mg) =================
__global__ void gate_kernel(const float* __restrict__ x,
                            const float* __restrict__ wg,
                            const float* __restrict__ bg) {
    int token = blockIdx.x;                      // 0..NTOK-1
    const float* xr = x + (size_t)token * D;
    float acc[E];
#pragma unroll
    for (int e = 0; e < E; e++) acc[e] = 0.f;
    for (int d = threadIdx.x; d < D; d += 256) {
        float xv = xr[d];
        const float* w = wg + (size_t)d * E;
#pragma unroll
        for (int e = 0; e < E; e++) acc[e] += xv * w[e];
    }
#pragma unroll
    for (int off = 16; off > 0; off >>= 1) {
#pragma unroll
        for (int e = 0; e < E; e++)
            acc[e] += __shfl_xor_sync(0xffffffffu, acc[e], off);
    }
    __shared__ float red[8][E];
    int warp = threadIdx.x >> 5, lane = threadIdx.x & 31;
    if (lane == 0) {
#pragma unroll
        for (int e = 0; e < E; e++) red[warp][e] = acc[e];
    }
    __syncthreads();
    if (threadIdx.x == 0) {
        float g[E];
        float mx = -3.402823466e38f;
#pragma unroll
        for (int e = 0; e < E; e++) {
            float s = bg[e];
            for (int w = 0; w < 8; w++) s += red[w][e];
            g[e] = s;
            mx = fmaxf(mx, s);
        }
        float den = 0.f;
#pragma unroll
        for (int e = 0; e < E; e++) { g[e] = expf(g[e] - mx); den += g[e]; }
        float inv = 1.f / den;
#pragma unroll
        for (int e = 0; e < E; e++) g[e] *= inv;
        // top-8 mask, ties -> lower index wins (matches jax.lax.top_k)
#pragma unroll
        for (int e = 0; e < E; e++) {
            int r = 0;
#pragma unroll
            for (int j = 0; j < E; j++)
                r += (g[j] > g[e]) || (g[j] == g[e] && j < e);
            g_route[(size_t)token * E + e] = (r < TOPK) ? g[e] : 0.f;
        }
    }
}

// ================= stage 2: route = mg / (sum_b mg + EPS) * capacity(=2) =================
__global__ void route_kernel() {
    int idx = blockIdx.x * blockDim.x + threadIdx.x;
    if (idx >= S * E) return;
    int s = idx / E, e = idx % E;
    float m0 = g_route[(size_t)s * E + e];
    float m1 = g_route[(size_t)(S + s) * E + e];
    float den = m0 + m1 + EPS;
    g_route[(size_t)s * E + e]       = m0 / den * 2.0f;
    g_route[(size_t)(S + s) * E + e] = m1 / den * 2.0f;
}

// ================= stage 3: top-CAP token selection per (e,b), jax tie semantics =========
__global__ void select_kernel() {
    int eb = blockIdx.x;          // e*B + b
    int e = eb >> 1, b = eb & 1;
    __shared__ float sv[S];
    __shared__ unsigned char sm[S];
    __shared__ int cnt[256];
    for (int s = threadIdx.x; s < S; s += 256)
        sv[s] = g_route[(size_t)(b * S + s) * E + e];
    __syncthreads();
    for (int i = threadIdx.x; i < S; i += 256) {
        float vi = sv[i];
        int c = 0;
        for (int j = 0; j < S; j++) {
            float vj = sv[j];
            c += (vj > vi) || (vj == vi && j < i);
        }
        sm[i] = (c < CAP) ? 1 : 0;
    }
    __syncthreads();
    // parallel compaction: each thread owns 8 consecutive indices
    int t = threadIdx.x;
    int local = 0;
#pragma unroll
    for (int k = 0; k < 8; k++) local += sm[t * 8 + k];
    cnt[t] = local;
    __syncthreads();
    if (t == 0) {
        int run = 0;
        for (int i = 0; i < 256; i++) { int c = cnt[i]; cnt[i] = run; run += c; }
    }
    __syncthreads();
    int pos = cnt[t];
#pragma unroll
    for (int k = 0; k < 8; k++) {
        int s = t * 8 + k;
        if (sm[s]) {
            g_seq[eb * CAP + pos] = s;
            g_w[eb * CAP + pos] = sv[s];
            g_inv[e * NTOK + b * S + s] = pos;
            pos++;
        } else {
            g_inv[e * NTOK + b * S + s] = -1;
        }
    }
}

// ================= stage 4a: fused Q/K/V projection, TF32 tensor cores =================
// grid (CAP/64=20, EB=32), 256 threads (8 warps: 2M x 4N), block tile 64x192, BK=16
// warp tile 32x48 = (2 m16) x (6 n8), K inner 2 x k8
__global__ void __launch_bounds__(256) proj_kernel(const float* __restrict__ x,
                                                   const float* __restrict__ Wq,
                                                   const float* __restrict__ Wkv) {
    constexpr int AST = 20;    // A smem row stride (words): conflict-free for frag loads
    constexpr int BST = 200;   // B smem row stride
    __shared__ uint32_t As[64 * AST];   // [m][k] tf32
    __shared__ uint32_t Bs[16 * BST];   // [k][n] tf32
    int mt = blockIdx.x, eb = blockIdx.y;
    int e = eb >> 1, b = eb & 1;
    int tid = threadIdx.x;
    int lane = tid & 31, w = tid >> 5;
    int wm = (w & 1) * 32;       // warp m offset in tile
    int wn = (w >> 1) * 48;      // warp n offset
    int m0 = mt * 64;

    // A staging coords: each thread loads x[row][k0 + 4*(t&3) .. +3]
    int ar = tid >> 2, ak = (tid & 3) << 2;
    int seqv = g_seq[eb * CAP + m0 + ar];
    const float* arow = x + (size_t)(b * S + seqv) * D;
    const float* wq  = Wq  + (size_t)e * D * HD;
    const float* wkv = Wkv + (size_t)e * D * (2 * HD);

    float acc[2][6][4];
#pragma unroll
    for (int i = 0; i < 2; i++)
#pragma unroll
        for (int j = 0; j < 6; j++)
#pragma unroll
            for (int r = 0; r < 4; r++) acc[i][j][r] = 0.f;

    // B staging coords: 768 float4 per stage, 3 per thread
    int bk[3], bj[3];
#pragma unroll
    for (int it = 0; it < 3; it++) {
        int f = tid + it * 256;
        bk[it] = f / 48;
        bj[it] = f % 48;
    }

    float4 pa;
    float4 pb[3];
    // prologue: load stage 0
    pa = *(const float4*)(arow + ak);
#pragma unroll
    for (int it = 0; it < 3; it++) {
        int j = bj[it];
        pb[it] = (j < 16)
            ? *(const float4*)(wq  + (size_t)bk[it] * HD        + j * 4)
            : *(const float4*)(wkv + (size_t)bk[it] * (2 * HD)  + (j - 16) * 4);
    }
    // store stage 0
    {
        uint32_t* ad = &As[ar * AST + ak];
        ad[0] = f2tf32(pa.x); ad[1] = f2tf32(pa.y); ad[2] = f2tf32(pa.z); ad[3] = f2tf32(pa.w);
#pragma unroll
        for (int it = 0; it < 3; it++) {
            uint32_t* bd = &Bs[bk[it] * BST + bj[it] * 4];
            bd[0] = f2tf32(pb[it].x); bd[1] = f2tf32(pb[it].y);
            bd[2] = f2tf32(pb[it].z); bd[3] = f2tf32(pb[it].w);
        }
    }
    __syncthreads();

    for (int k0 = 16; k0 <= D; k0 += 16) {
        // prefetch next stage to regs
        if (k0 < D) {
            pa = *(const float4*)(arow + k0 + ak);
#pragma unroll
            for (int it = 0; it < 3; it++) {
                int j = bj[it];
                pb[it] = (j < 16)
                    ? *(const float4*)(wq  + (size_t)(k0 + bk[it]) * HD       + j * 4)
                    : *(const float4*)(wkv + (size_t)(k0 + bk[it]) * (2 * HD) + (j - 16) * 4);
            }
        }
        // compute current stage: 2 k8 sub-steps
#pragma unroll
        for (int kb = 0; kb < 16; kb += 8) {
            uint32_t a[2][4], bb[6][2];
            int r0 = wm + (lane >> 2);
            int c0 = kb + (lane & 3);
#pragma unroll
            for (int mb = 0; mb < 2; mb++) {
                const uint32_t* ap = &As[(r0 + mb * 16) * AST + c0];
                a[mb][0] = ap[0];
                a[mb][1] = ap[8 * AST];
                a[mb][2] = ap[4];
                a[mb][3] = ap[8 * AST + 4];
            }
            int kr = kb + (lane & 3);
            int nc = wn + (lane >> 2);
#pragma unroll
            for (int nb = 0; nb < 6; nb++) {
                const uint32_t* bp = &Bs[kr * BST + nc + nb * 8];
                bb[nb][0] = bp[0];
                bb[nb][1] = bp[4 * BST];
            }
#pragma unroll
            for (int mb = 0; mb < 2; mb++)
#pragma unroll
                for (int nb = 0; nb < 6; nb++)
                    mma_tf32(acc[mb][nb][0], acc[mb][nb][1], acc[mb][nb][2], acc[mb][nb][3],
                             a[mb][0], a[mb][1], a[mb][2], a[mb][3],
                             bb[nb][0], bb[nb][1]);
        }
        __syncthreads();
        if (k0 < D) {
            uint32_t* ad = &As[ar * AST + ak];
            ad[0] = f2tf32(pa.x); ad[1] = f2tf32(pa.y); ad[2] = f2tf32(pa.z); ad[3] = f2tf32(pa.w);
#pragma unroll
            for (int it = 0; it < 3; it++) {
                uint32_t* bd = &Bs[bk[it] * BST + bj[it] * 4];
                bd[0] = f2tf32(pb[it].x); bd[1] = f2tf32(pb[it].y);
                bd[2] = f2tf32(pb[it].z); bd[3] = f2tf32(pb[it].w);
            }
            __syncthreads();
        }
    }

    // epilogue: cols 0-63 -> q, 64-127 -> k, 128-191 -> v
#pragma unroll
    for (int nb = 0; nb < 6; nb++) {
        int colg = wn + nb * 8 + 2 * (lane & 3);
        float* dst;
        int col;
        if (colg < 64)       { dst = g_q; col = colg; }
        else if (colg < 128) { dst = g_k; col = colg - 64; }
        else                 { dst = g_v; col = colg - 128; }
#pragma unroll
        for (int mb = 0; mb < 2; mb++) {
            int rowg = m0 + wm + mb * 16 + (lane >> 2);
            size_t base0 = ((size_t)eb * CAP + rowg) * HD + col;
            size_t base1 = ((size_t)eb * CAP + rowg + 8) * HD + col;
            *(float2*)(dst + base0) = make_float2(acc[mb][nb][0], acc[mb][nb][1]);
            *(float2*)(dst + base1) = make_float2(acc[mb][nb][2], acc[mb][nb][3]);
        }
    }
}

// ================= stage 4b: RoPE on q and k =================
__global__ void rope_kernel() {
    int idx = blockIdx.x * blockDim.x + threadIdx.x;
    if (idx >= EB * CAP * 32) return;
    int h = idx & 31;
    int t = idx >> 5;                 // 0..EB*CAP-1
    int pos = g_seq[t];
    float invf = powf(THETA, -(float)(2 * h) / (float)HD);
    float ang = (float)pos * invf;
    float c = cosf(ang), s = sinf(ang);
    float* q = g_q + (size_t)t * HD;
    float* k = g_k + (size_t)t * HD;
    float q1 = q[h], q2 = q[h + 32];
    q[h]      = q1 * c - q2 * s;
    q[h + 32] = q2 * c + q1 * s;
    float k1 = k[h], k2 = k[h + 32];
    k[h]      = k1 * c - k2 * s;
    k[h + 32] = k2 * c + k1 * s;
}

// ================= stage 5: causal flash attention =================
// grid (CAP/128=10, EB=32), 256 threads, BM=128, BN=64, 8x4 per thread
__global__ void attn_kernel() {
    extern __shared__ float smem[];
    float* Qs = smem;                 // [128][68]
    float* Ks = Qs + 128 * 68;        // [64][65]
    float* Vs = Ks + 64 * 65;         // [64][68]
    float* Ps = Vs + 64 * 68;         // [128][68]
    int mt = blockIdx.x, eb = blockIdx.y;
    int m0 = mt * 128;
    const float* qb = g_q + (size_t)eb * CAP * HD;
    const float* kb = g_k + (size_t)eb * CAP * HD;
    const float* vb = g_v + (size_t)eb * CAP * HD;
    int tid = threadIdx.x;
    int tx = tid & 15;                // n: 4 cols
    int ty = tid >> 4;                // m: 8 rows

    // load Q tile 128x64
#pragma unroll
    for (int it = 0; it < 8; it++) {
        int idx = tid + it * 256;
        int row = idx >> 4, c4 = (idx & 15) << 2;
        float4 v4 = *(const float4*)(qb + (size_t)(m0 + row) * HD + c4);
        *(float4*)&Qs[row * 68 + c4] = v4;
    }

    float mrow[8], lsum[8], o[8][4];
#pragma unroll
    for (int i = 0; i < 8; i++) {
        mrow[i] = -3.402823466e38f;
        lsum[i] = 0.f;
#pragma unroll
        for (int j = 0; j < 4; j++) o[i][j] = 0.f;
    }

    int ntiles = 2 * mt + 2;
    for (int nt = 0; nt < ntiles; nt++) {
        int n0 = nt * 64;
        // load K (transposed-read layout [n][k], stride 65) and V ([n][k] stride 68)
#pragma unroll
        for (int it = 0; it < 4; it++) {
            int idx = tid + it * 256;
            int row = idx >> 4, c4 = (idx & 15) << 2;
            float4 k4 = *(const float4*)(kb + (size_t)(n0 + row) * HD + c4);
            Ks[row * 65 + c4 + 0] = k4.x;
            Ks[row * 65 + c4 + 1] = k4.y;
            Ks[row * 65 + c4 + 2] = k4.z;
            Ks[row * 65 + c4 + 3] = k4.w;
            float4 v4 = *(const float4*)(vb + (size_t)(n0 + row) * HD + c4);
            *(float4*)&Vs[row * 68 + c4] = v4;
        }
        __syncthreads();
        // S = Q K^T
        float s[8][4];
#pragma unroll
        for (int i = 0; i < 8; i++)
#pragma unroll
            for (int j = 0; j < 4; j++) s[i][j] = 0.f;
#pragma unroll 4
        for (int kk = 0; kk < 64; kk++) {
            float a[8], bb[4];
#pragma unroll
            for (int i = 0; i < 8; i++) a[i] = Qs[(ty * 8 + i) * 68 + kk];
#pragma unroll
            for (int j = 0; j < 4; j++) bb[j] = Ks[(tx * 4 + j) * 65 + kk];
#pragma unroll
            for (int i = 0; i < 8; i++)
#pragma unroll
                for (int j = 0; j < 4; j++) s[i][j] += a[i] * bb[j];
        }
        bool maskTile = (nt >= 2 * mt);
#pragma unroll
        for (int i = 0; i < 8; i++) {
            int rowg = m0 + ty * 8 + i;
#pragma unroll
            for (int j = 0; j < 4; j++) {
                float val = s[i][j] * 0.125f;
                if (maskTile && (n0 + tx * 4 + j) > rowg)
                    val = -3.402823466e38f;
                s[i][j] = val;
            }
        }
        // online softmax (row reduction over 16-lane tx group)
#pragma unroll
        for (int i = 0; i < 8; i++) {
            float m = fmaxf(fmaxf(s[i][0], s[i][1]), fmaxf(s[i][2], s[i][3]));
#pragma unroll
            for (int off = 8; off > 0; off >>= 1)
                m = fmaxf(m, __shfl_xor_sync(0xffffffffu, m, off));
            float nm = fmaxf(mrow[i], m);
            float corr = __expf(mrow[i] - nm);
            float rs = 0.f;
#pragma unroll
            for (int j = 0; j < 4; j++) {
                float p = __expf(s[i][j] - nm);
                s[i][j] = p;
                rs += p;
            }
#pragma unroll
            for (int off = 8; off > 0; off >>= 1)
                rs += __shfl_xor_sync(0xffffffffu, rs, off);
            lsum[i] = lsum[i] * corr + rs;
            mrow[i] = nm;
#pragma unroll
            for (int j = 0; j < 4; j++) o[i][j] *= corr;
        }
        // write P to smem
#pragma unroll
        for (int i = 0; i < 8; i++)
            *(float4*)&Ps[(ty * 8 + i) * 68 + tx * 4] =
                make_float4(s[i][0], s[i][1], s[i][2], s[i][3]);
        __syncthreads();
        // O += P V
#pragma unroll 4
        for (int n = 0; n < 64; n++) {
            float4 v4 = *(const float4*)&Vs[n * 68 + tx * 4];
#pragma unroll
            for (int i = 0; i < 8; i++) {
                float p = Ps[(ty * 8 + i) * 68 + n];
                o[i][0] += p * v4.x;
                o[i][1] += p * v4.y;
                o[i][2] += p * v4.z;
                o[i][3] += p * v4.w;
            }
        }
        __syncthreads();
    }
#pragma unroll
    for (int i = 0; i < 8; i++) {
        float invl = 1.f / lsum[i];
        int row = m0 + ty * 8 + i;
        float* orow = g_ctx + ((size_t)eb * CAP + row) * HD;
        *(float4*)(orow + tx * 4) = make_float4(o[i][0] * invl, o[i][1] * invl,
                                                o[i][2] * invl, o[i][3] * invl);
    }
}

// ================= stage 6a: out = (ctx @ Wff + bff) * w -> dense g_out =================
// grid (CAP/128=10, D/64=16, EB=32), 256 threads, 8x4 per thread, K=64
__global__ void outproj_kernel(const float* __restrict__ Wff,
                               const float* __restrict__ bff) {
    int mt = blockIdx.x, nt = blockIdx.y, eb = blockIdx.z;
    int e = eb >> 1;
    __shared__ float As[128][65];  // ctx [m][k]
    __shared__ float Bs[64][68];   // Wff [k][n]
    int tid = threadIdx.x, tx = tid & 15, ty = tid >> 4;
    int m0 = mt * 128, n0 = nt * 64;
#pragma unroll
    for (int it = 0; it < 8; it++) {
        int idx = tid + it * 256;
        int row = idx >> 4, c4 = (idx & 15) << 2;
        float4 a4 = *(const float4*)(g_ctx + ((size_t)eb * CAP + m0 + row) * HD + c4);
        As[row][c4 + 0] = a4.x;
        As[row][c4 + 1] = a4.y;
        As[row][c4 + 2] = a4.z;
        As[row][c4 + 3] = a4.w;
    }
#pragma unroll
    for (int it = 0; it < 4; it++) {
        int idx = tid + it * 256;
        int row = idx >> 4, c4 = (idx & 15) << 2;
        float4 b4 = *(const float4*)(Wff + ((size_t)e * HD + row) * D + n0 + c4);
        *(float4*)&Bs[row][c4] = b4;
    }
    __syncthreads();
    float acc[8][4];
#pragma unroll
    for (int i = 0; i < 8; i++)
#pragma unroll
        for (int j = 0; j < 4; j++) acc[i][j] = 0.f;
#pragma unroll 4
    for (int kk = 0; kk < 64; kk++) {
        float a[8];
#pragma unroll
        for (int i = 0; i < 8; i++) a[i] = As[ty * 8 + i][kk];
        float4 b4 = *(const float4*)&Bs[kk][tx * 4];
#pragma unroll
        for (int i = 0; i < 8; i++) {
            acc[i][0] += a[i] * b4.x;
            acc[i][1] += a[i] * b4.y;
            acc[i][2] += a[i] * b4.z;
            acc[i][3] += a[i] * b4.w;
        }
    }
    float4 bf = *(const float4*)(bff + n0 + tx * 4);
#pragma unroll
    for (int i = 0; i < 8; i++) {
        int row = m0 + ty * 8 + i;
        float wv = g_w[eb * CAP + row];
        float4 r;
        r.x = (acc[i][0] + bf.x) * wv;
        r.y = (acc[i][1] + bf.y) * wv;
        r.z = (acc[i][2] + bf.z) * wv;
        r.w = (acc[i][3] + bf.w) * wv;
        *(float4*)(g_out + ((size_t)eb * CAP + row) * D + n0 + tx * 4) = r;
    }
}

// ================= stage 6b: gather-combine + residual + LayerNorm =================
__global__ void ln_kernel(const float* __restrict__ x,
                          const float* __restrict__ gamma,
                          const float* __restrict__ beta,
                          float* __restrict__ out) {
    int token = blockIdx.x;
    int b = token >> 11;  // S = 2048
    int tid = threadIdx.x;
    __shared__ int sh_base[E];
    __shared__ float red[8];
    if (tid < E) {
        int p = g_inv[tid * NTOK + token];
        sh_base[tid] = (p < 0) ? -1 : ((tid * B + b) * CAP + p);
    }
    __syncthreads();
    // each thread owns 4 consecutive d (one float4)
    float4 c = make_float4(0.f, 0.f, 0.f, 0.f);
#pragma unroll
    for (int e = 0; e < E; e++) {
        int base = sh_base[e];
        if (base >= 0) {
            float4 t4 = *(const float4*)(g_out + (size_t)base * D + tid * 4);
            c.x += t4.x; c.y += t4.y; c.z += t4.z; c.w += t4.w;
        }
    }
    float4 x4 = *(const float4*)(x + (size_t)token * D + tid * 4);
    float h[4] = {x4.x + c.x, x4.y + c.y, x4.z + c.z, x4.w + c.w};
    float s = h[0] + h[1] + h[2] + h[3];
#pragma unroll
    for (int off = 16; off > 0; off >>= 1) s += __shfl_xor_sync(0xffffffffu, s, off);
    int warp = tid >> 5, lane = tid & 31;
    if (lane == 0) red[warp] = s;
    __syncthreads();
    float total = 0.f;
#pragma unroll
    for (int w = 0; w < 8; w++) total += red[w];
    __syncthreads();
    float mu = total * (1.0f / D);
    float ss = 0.f;
#pragma unroll
    for (int t = 0; t < 4; t++) {
        float dlt = h[t] - mu;
        ss += dlt * dlt;
    }
#pragma unroll
    for (int off = 16; off > 0; off >>= 1) ss += __shfl_xor_sync(0xffffffffu, ss, off);
    if (lane == 0) red[warp] = ss;
    __syncthreads();
    float vtot = 0.f;
#pragma unroll
    for (int w = 0; w < 8; w++) vtot += red[w];
    float var = vtot * (1.0f / D);
    float inv = rsqrtf(var + 1e-5f);
    float4 g4 = *(const float4*)(gamma + tid * 4);
    float4 be4 = *(const float4*)(beta + tid * 4);
    float4 o4;
    o4.x = (h[0] - mu) * inv * g4.x + be4.x;
    o4.y = (h[1] - mu) * inv * g4.y + be4.y;
    o4.z = (h[2] - mu) * inv * g4.z + be4.z;
    o4.w = (h[3] - mu) * inv * g4.w + be4.w;
    *(float4*)(out + (size_t)token * D + tid * 4) = o4;
}

// ================= launch =================
extern "C" void kernel_launch(void* const* d_in, const int* in_sizes, int n_in,
                              void* d_out, int out_size) {
    const float* x     = (const float*)d_in[0];
    const float* wg    = (const float*)d_in[1];
    const float* bg    = (const float*)d_in[2];
    const float* Wq    = (const float*)d_in[3];
    const float* Wkv   = (const float*)d_in[4];
    const float* Wff   = (const float*)d_in[5];
    const float* bff   = (const float*)d_in[6];
    const float* gamma = (const float*)d_in[7];
    const float* beta  = (const float*)d_in[8];
    float* out = (float*)d_out;

    (void)in_sizes; (void)n_in; (void)out_size;

    gate_kernel<<<NTOK, 256>>>(x, wg, bg);
    route_kernel<<<(S * E + 255) / 256, 256>>>();
    select_kernel<<<EB, 256>>>();
    proj_kernel<<<dim3(CAP / 64, EB), 256>>>(x, Wq, Wkv);
    rope_kernel<<<(EB * CAP * 32 + 255) / 256, 256>>>();

    int attn_smem = (128 * 68 + 64 * 65 + 64 * 68 + 128 * 68) * (int)sizeof(float);
    cudaFuncSetAttribute(attn_kernel, cudaFuncAttributeMaxDynamicSharedMemorySize, attn_smem);
    attn_kernel<<<dim3(CAP / 128, EB), 256, attn_smem>>>();

    outproj_kernel<<<dim3(CAP / 128, D / 64, EB), 256>>>(Wff, bff);
    ln_kernel<<<NTOK, 256>>>(x, gamma, beta, out);
}

// round 4
// speedup vs baseline: 1.9420x; 1.3158x over previous
#include <cuda_runtime.h>
#include <math.h>
#include <stdint.h>

// ---------------- problem constants ----------------
namespace {
constexpr int B = 2, S = 2048, D = 1024, E = 16, HD = 64, CAP = 1280, TOPK = 8;
constexpr float EPS = 1e-6f;
constexpr float THETA = 10000.0f;
constexpr int EB = E * B;    // 32
constexpr int NTOK = B * S;  // 4096
}

// ---------------- scratch (device globals; no allocation allowed) ----------------
__device__ float g_route[NTOK * E];        // route[b][s][e]
__device__ int   g_seq[EB * CAP];          // selected token seq index (sorted ascending)
__device__ float g_w[EB * CAP];            // routing weight of selected token
__device__ int   g_inv[E * NTOK];          // inverse map: pos in selected list or -1
__device__ float g_q[EB * CAP * HD];
__device__ float g_k[EB * CAP * HD];
__device__ float g_v[EB * CAP * HD];
__device__ float g_ctx[EB * CAP * HD];
__device__ float g_out[(size_t)EB * CAP * D];  // per-expert weighted outputs (168MB)

// ---------------- tf32 helpers ----------------
__device__ __forceinline__ uint32_t f2tf32(float f) {
    uint32_t r;
    asm("cvt.rna.tf32.f32 %0, %1;" : "=r"(r) : "f"(f));
    return r;
}
__device__ __forceinline__ void mma_tf32(float& c0, float& c1, float& c2, float& c3,
                                         uint32_t a0, uint32_t a1, uint32_t a2, uint32_t a3,
                                         uint32_t b0, uint32_t b1) {
    asm volatile(
        "mma.sync.aligned.m16n8k8.row.col.f32.tf32.tf32.f32 "
        "{%0,%1,%2,%3}, {%4,%5,%6,%7}, {%8,%9}, {%0,%1,%2,%3};\n"
        : "+f"(c0), "+f"(c1), "+f"(c2), "+f"(c3)
        : "r"(a0), "r"(a1), "r"(a2), "r"(a3), "r"(b0), "r"(b1));
}

// ================= stage 1: gating (logits -> softmax -> top-8 mask -> mg) =================
__global__ void gate_kernel(const float* __restrict__ x,
                            const float* __restrict__ wg,
                            const float* __restrict__ bg) {
    int token = blockIdx.x;                      // 0..NTOK-1
    const float* xr = x + (size_t)token * D;
    float acc[E];
#pragma unroll
    for (int e = 0; e < E; e++) acc[e] = 0.f;
    for (int d = threadIdx.x; d < D; d += 256) {
        float xv = xr[d];
        const float* w = wg + (size_t)d * E;
#pragma unroll
        for (int e = 0; e < E; e++) acc[e] += xv * w[e];
    }
#pragma unroll
    for (int off = 16; off > 0; off >>= 1) {
#pragma unroll
        for (int e = 0; e < E; e++)
            acc[e] += __shfl_xor_sync(0xffffffffu, acc[e], off);
    }
    __shared__ float red[8][E];
    int warp = threadIdx.x >> 5, lane = threadIdx.x & 31;
    if (lane == 0) {
#pragma unroll
        for (int e = 0; e < E; e++) red[warp][e] = acc[e];
    }
    __syncthreads();
    if (threadIdx.x == 0) {
        float g[E];
        float mx = -3.402823466e38f;
#pragma unroll
        for (int e = 0; e < E; e++) {
            float s = bg[e];
            for (int w = 0; w < 8; w++) s += red[w][e];
            g[e] = s;
            mx = fmaxf(mx, s);
        }
        float den = 0.f;
#pragma unroll
        for (int e = 0; e < E; e++) { g[e] = expf(g[e] - mx); den += g[e]; }
        float inv = 1.f / den;
#pragma unroll
        for (int e = 0; e < E; e++) g[e] *= inv;
        // top-8 mask, ties -> lower index wins (matches jax.lax.top_k)
#pragma unroll
        for (int e = 0; e < E; e++) {
            int r = 0;
#pragma unroll
            for (int j = 0; j < E; j++)
                r += (g[j] > g[e]) || (g[j] == g[e] && j < e);
            g_route[(size_t)token * E + e] = (r < TOPK) ? g[e] : 0.f;
        }
    }
}

// ================= stage 2: route = mg / (sum_b mg + EPS) * capacity(=2) =================
__global__ void route_kernel() {
    int idx = blockIdx.x * blockDim.x + threadIdx.x;
    if (idx >= S * E) return;
    int s = idx / E, e = idx % E;
    float m0 = g_route[(size_t)s * E + e];
    float m1 = g_route[(size_t)(S + s) * E + e];
    float den = m0 + m1 + EPS;
    g_route[(size_t)s * E + e]       = m0 / den * 2.0f;
    g_route[(size_t)(S + s) * E + e] = m1 / den * 2.0f;
}

// ================= stage 3: top-CAP token selection per (e,b), jax tie semantics =========
__global__ void select_kernel() {
    int eb = blockIdx.x;          // e*B + b
    int e = eb >> 1, b = eb & 1;
    __shared__ float sv[S];
    __shared__ unsigned char sm[S];
    __shared__ int cnt[256];
    for (int s = threadIdx.x; s < S; s += 256)
        sv[s] = g_route[(size_t)(b * S + s) * E + e];
    __syncthreads();
    for (int i = threadIdx.x; i < S; i += 256) {
        float vi = sv[i];
        int c = 0;
        for (int j = 0; j < S; j++) {
            float vj = sv[j];
            c += (vj > vi) || (vj == vi && j < i);
        }
        sm[i] = (c < CAP) ? 1 : 0;
    }
    __syncthreads();
    // parallel compaction: each thread owns 8 consecutive indices
    int t = threadIdx.x;
    int local = 0;
#pragma unroll
    for (int k = 0; k < 8; k++) local += sm[t * 8 + k];
    cnt[t] = local;
    __syncthreads();
    if (t == 0) {
        int run = 0;
        for (int i = 0; i < 256; i++) { int c = cnt[i]; cnt[i] = run; run += c; }
    }
    __syncthreads();
    int pos = cnt[t];
#pragma unroll
    for (int k = 0; k < 8; k++) {
        int s = t * 8 + k;
        if (sm[s]) {
            g_seq[eb * CAP + pos] = s;
            g_w[eb * CAP + pos] = sv[s];
            g_inv[e * NTOK + b * S + s] = pos;
            pos++;
        } else {
            g_inv[e * NTOK + b * S + s] = -1;
        }
    }
}

// ================= stage 4a: fused Q/K/V projection, TF32 tensor cores =================
// grid (CAP/64=20, EB=32), 256 threads (8 warps: 2M x 4N), block tile 64x192, BK=16
__global__ void __launch_bounds__(256) proj_kernel(const float* __restrict__ x,
                                                   const float* __restrict__ Wq,
                                                   const float* __restrict__ Wkv) {
    constexpr int AST = 20;    // A smem row stride (words)
    constexpr int BST = 200;   // B smem row stride
    __shared__ uint32_t As[64 * AST];   // [m][k] tf32
    __shared__ uint32_t Bs[16 * BST];   // [k][n] tf32
    int mt = blockIdx.x, eb = blockIdx.y;
    int e = eb >> 1, b = eb & 1;
    int tid = threadIdx.x;
    int lane = tid & 31, w = tid >> 5;
    int wm = (w & 1) * 32;       // warp m offset in tile
    int wn = (w >> 1) * 48;      // warp n offset
    int m0 = mt * 64;

    int ar = tid >> 2, ak = (tid & 3) << 2;
    int seqv = g_seq[eb * CAP + m0 + ar];
    const float* arow = x + (size_t)(b * S + seqv) * D;
    const float* wq  = Wq  + (size_t)e * D * HD;
    const float* wkv = Wkv + (size_t)e * D * (2 * HD);

    float acc[2][6][4];
#pragma unroll
    for (int i = 0; i < 2; i++)
#pragma unroll
        for (int j = 0; j < 6; j++)
#pragma unroll
            for (int r = 0; r < 4; r++) acc[i][j][r] = 0.f;

    int bk[3], bj[3];
#pragma unroll
    for (int it = 0; it < 3; it++) {
        int f = tid + it * 256;
        bk[it] = f / 48;
        bj[it] = f % 48;
    }

    float4 pa;
    float4 pb[3];
    pa = *(const float4*)(arow + ak);
#pragma unroll
    for (int it = 0; it < 3; it++) {
        int j = bj[it];
        pb[it] = (j < 16)
            ? *(const float4*)(wq  + (size_t)bk[it] * HD        + j * 4)
            : *(const float4*)(wkv + (size_t)bk[it] * (2 * HD)  + (j - 16) * 4);
    }
    {
        uint32_t* ad = &As[ar * AST + ak];
        ad[0] = f2tf32(pa.x); ad[1] = f2tf32(pa.y); ad[2] = f2tf32(pa.z); ad[3] = f2tf32(pa.w);
#pragma unroll
        for (int it = 0; it < 3; it++) {
            uint32_t* bd = &Bs[bk[it] * BST + bj[it] * 4];
            bd[0] = f2tf32(pb[it].x); bd[1] = f2tf32(pb[it].y);
            bd[2] = f2tf32(pb[it].z); bd[3] = f2tf32(pb[it].w);
        }
    }
    __syncthreads();

    for (int k0 = 16; k0 <= D; k0 += 16) {
        if (k0 < D) {
            pa = *(const float4*)(arow + k0 + ak);
#pragma unroll
            for (int it = 0; it < 3; it++) {
                int j = bj[it];
                pb[it] = (j < 16)
                    ? *(const float4*)(wq  + (size_t)(k0 + bk[it]) * HD       + j * 4)
                    : *(const float4*)(wkv + (size_t)(k0 + bk[it]) * (2 * HD) + (j - 16) * 4);
            }
        }
#pragma unroll
        for (int kb2 = 0; kb2 < 16; kb2 += 8) {
            uint32_t a[2][4], bb[6][2];
            int r0 = wm + (lane >> 2);
            int c0 = kb2 + (lane & 3);
#pragma unroll
            for (int mb = 0; mb < 2; mb++) {
                const uint32_t* ap = &As[(r0 + mb * 16) * AST + c0];
                a[mb][0] = ap[0];
                a[mb][1] = ap[8 * AST];
                a[mb][2] = ap[4];
                a[mb][3] = ap[8 * AST + 4];
            }
            int kr = kb2 + (lane & 3);
            int nc = wn + (lane >> 2);
#pragma unroll
            for (int nb = 0; nb < 6; nb++) {
                const uint32_t* bp = &Bs[kr * BST + nc + nb * 8];
                bb[nb][0] = bp[0];
                bb[nb][1] = bp[4 * BST];
            }
#pragma unroll
            for (int mb = 0; mb < 2; mb++)
#pragma unroll
                for (int nb = 0; nb < 6; nb++)
                    mma_tf32(acc[mb][nb][0], acc[mb][nb][1], acc[mb][nb][2], acc[mb][nb][3],
                             a[mb][0], a[mb][1], a[mb][2], a[mb][3],
                             bb[nb][0], bb[nb][1]);
        }
        __syncthreads();
        if (k0 < D) {
            uint32_t* ad = &As[ar * AST + ak];
            ad[0] = f2tf32(pa.x); ad[1] = f2tf32(pa.y); ad[2] = f2tf32(pa.z); ad[3] = f2tf32(pa.w);
#pragma unroll
            for (int it = 0; it < 3; it++) {
                uint32_t* bd = &Bs[bk[it] * BST + bj[it] * 4];
                bd[0] = f2tf32(pb[it].x); bd[1] = f2tf32(pb[it].y);
                bd[2] = f2tf32(pb[it].z); bd[3] = f2tf32(pb[it].w);
            }
            __syncthreads();
        }
    }

#pragma unroll
    for (int nb = 0; nb < 6; nb++) {
        int colg = wn + nb * 8 + 2 * (lane & 3);
        float* dst;
        int col;
        if (colg < 64)       { dst = g_q; col = colg; }
        else if (colg < 128) { dst = g_k; col = colg - 64; }
        else                 { dst = g_v; col = colg - 128; }
#pragma unroll
        for (int mb = 0; mb < 2; mb++) {
            int rowg = m0 + wm + mb * 16 + (lane >> 2);
            size_t base0 = ((size_t)eb * CAP + rowg) * HD + col;
            size_t base1 = ((size_t)eb * CAP + rowg + 8) * HD + col;
            *(float2*)(dst + base0) = make_float2(acc[mb][nb][0], acc[mb][nb][1]);
            *(float2*)(dst + base1) = make_float2(acc[mb][nb][2], acc[mb][nb][3]);
        }
    }
}

// ================= stage 4b: RoPE on q and k =================
__global__ void rope_kernel() {
    int idx = blockIdx.x * blockDim.x + threadIdx.x;
    if (idx >= EB * CAP * 32) return;
    int h = idx & 31;
    int t = idx >> 5;                 // 0..EB*CAP-1
    int pos = g_seq[t];
    float invf = powf(THETA, -(float)(2 * h) / (float)HD);
    float ang = (float)pos * invf;
    float c = cosf(ang), s = sinf(ang);
    float* q = g_q + (size_t)t * HD;
    float* k = g_k + (size_t)t * HD;
    float q1 = q[h], q2 = q[h + 32];
    q[h]      = q1 * c - q2 * s;
    q[h + 32] = q2 * c + q1 * s;
    float k1 = k[h], k2 = k[h + 32];
    k[h]      = k1 * c - k2 * s;
    k[h + 32] = k2 * c + k1 * s;
}

// ================= stage 5: causal flash attention, TF32 tensor cores =================
// grid (CAP/128=10, EB=32), 256 threads = 8 warps; warp w owns rows [16w,16w+16)
// BM=128, BN=64; smem stride 72 words (conflict-free for all fragment patterns)
__global__ void __launch_bounds__(256, 2) attn_kernel() {
    constexpr int ST = 72;
    extern __shared__ uint32_t dsm[];
    uint32_t* Qs = dsm;                 // 128*ST
    uint32_t* Ks = Qs + 128 * ST;       // 64*ST
    uint32_t* Vs = Ks + 64 * ST;        // 64*ST
    uint32_t* Ps = Vs + 64 * ST;        // 128*ST
    int mt = blockIdx.x, eb = blockIdx.y;
    int m0 = mt * 128;
    const float* qptr = g_q + (size_t)eb * CAP * HD;
    const float* kptr = g_k + (size_t)eb * CAP * HD;
    const float* vptr = g_v + (size_t)eb * CAP * HD;
    int tid = threadIdx.x;
    int lane = tid & 31, w = tid >> 5;
    int lr = lane >> 2, lc = lane & 3;
    int wrow = 16 * w;

    // load Q tile 128x64 -> tf32 smem
#pragma unroll
    for (int it = 0; it < 8; it++) {
        int idx = tid + it * 256;
        int row = idx >> 4, c4 = (idx & 15) << 2;
        float4 v4 = *(const float4*)(qptr + (size_t)(m0 + row) * HD + c4);
        uint32_t* d = &Qs[row * ST + c4];
        d[0] = f2tf32(v4.x); d[1] = f2tf32(v4.y); d[2] = f2tf32(v4.z); d[3] = f2tf32(v4.w);
    }

    float o[8][4];
#pragma unroll
    for (int t8 = 0; t8 < 8; t8++)
#pragma unroll
        for (int r = 0; r < 4; r++) o[t8][r] = 0.f;
    float mrow0 = -3.402823466e38f, mrow1 = -3.402823466e38f;
    float lsum0 = 0.f, lsum1 = 0.f;

    int ntiles = 2 * mt + 2;
    for (int nt = 0; nt < ntiles; nt++) {
        int n0 = nt * 64;
        __syncthreads();   // previous tile's Ks/Vs reads complete (and Q visible on first iter)
#pragma unroll
        for (int it = 0; it < 4; it++) {
            int idx = tid + it * 256;
            int row = idx >> 4, c4 = (idx & 15) << 2;
            float4 k4 = *(const float4*)(kptr + (size_t)(n0 + row) * HD + c4);
            uint32_t* kd = &Ks[row * ST + c4];
            kd[0] = f2tf32(k4.x); kd[1] = f2tf32(k4.y); kd[2] = f2tf32(k4.z); kd[3] = f2tf32(k4.w);
            float4 v4 = *(const float4*)(vptr + (size_t)(n0 + row) * HD + c4);
            uint32_t* vd = &Vs[row * ST + c4];
            vd[0] = f2tf32(v4.x); vd[1] = f2tf32(v4.y); vd[2] = f2tf32(v4.z); vd[3] = f2tf32(v4.w);
        }
        __syncthreads();

        // S = Q K^T  (per warp: 1 m16 x 8 n8 x 8 k8)
        float sacc[8][4];
#pragma unroll
        for (int t8 = 0; t8 < 8; t8++)
#pragma unroll
            for (int r = 0; r < 4; r++) sacc[t8][r] = 0.f;
#pragma unroll
        for (int kk = 0; kk < 8; kk++) {
            const uint32_t* ap = &Qs[(wrow + lr) * ST + kk * 8 + lc];
            uint32_t a0 = ap[0], a1 = ap[8 * ST], a2 = ap[4], a3 = ap[8 * ST + 4];
#pragma unroll
            for (int t8 = 0; t8 < 8; t8++) {
                const uint32_t* bp = &Ks[(t8 * 8 + lr) * ST + kk * 8 + lc];
                mma_tf32(sacc[t8][0], sacc[t8][1], sacc[t8][2], sacc[t8][3],
                         a0, a1, a2, a3, bp[0], bp[4]);
            }
        }

        // scale + causal mask
        bool maskT = (nt >= 2 * mt);
#pragma unroll
        for (int t8 = 0; t8 < 8; t8++) {
            int cbase = n0 + t8 * 8 + 2 * lc;
#pragma unroll
            for (int r = 0; r < 4; r++) {
                float v = sacc[t8][r] * 0.125f;
                if (maskT) {
                    int row = m0 + wrow + lr + ((r >= 2) ? 8 : 0);
                    int col = cbase + (r & 1);
                    if (col > row) v = -3.402823466e38f;
                }
                sacc[t8][r] = v;
            }
        }

        // online softmax (rows r and r+8, reduction over quad lanes)
        float mx0 = -3.402823466e38f, mx1 = -3.402823466e38f;
#pragma unroll
        for (int t8 = 0; t8 < 8; t8++) {
            mx0 = fmaxf(mx0, fmaxf(sacc[t8][0], sacc[t8][1]));
            mx1 = fmaxf(mx1, fmaxf(sacc[t8][2], sacc[t8][3]));
        }
        mx0 = fmaxf(mx0, __shfl_xor_sync(0xffffffffu, mx0, 1));
        mx0 = fmaxf(mx0, __shfl_xor_sync(0xffffffffu, mx0, 2));
        mx1 = fmaxf(mx1, __shfl_xor_sync(0xffffffffu, mx1, 1));
        mx1 = fmaxf(mx1, __shfl_xor_sync(0xffffffffu, mx1, 2));
        float nm0 = fmaxf(mrow0, mx0), nm1 = fmaxf(mrow1, mx1);
        float corr0 = __expf(mrow0 - nm0), corr1 = __expf(mrow1 - nm1);
        float rs0 = 0.f, rs1 = 0.f;
#pragma unroll
        for (int t8 = 0; t8 < 8; t8++) {
            float p0 = __expf(sacc[t8][0] - nm0);
            float p1 = __expf(sacc[t8][1] - nm0);
            float p2 = __expf(sacc[t8][2] - nm1);
            float p3 = __expf(sacc[t8][3] - nm1);
            rs0 += p0 + p1; rs1 += p2 + p3;
            int b0 = (wrow + lr) * ST + t8 * 8 + 2 * lc;
            Ps[b0]     = f2tf32(p0);
            Ps[b0 + 1] = f2tf32(p1);
            int b1 = (wrow + lr + 8) * ST + t8 * 8 + 2 * lc;
            Ps[b1]     = f2tf32(p2);
            Ps[b1 + 1] = f2tf32(p3);
        }
        rs0 += __shfl_xor_sync(0xffffffffu, rs0, 1);
        rs0 += __shfl_xor_sync(0xffffffffu, rs0, 2);
        rs1 += __shfl_xor_sync(0xffffffffu, rs1, 1);
        rs1 += __shfl_xor_sync(0xffffffffu, rs1, 2);
        lsum0 = lsum0 * corr0 + rs0;
        lsum1 = lsum1 * corr1 + rs1;
        mrow0 = nm0; mrow1 = nm1;
#pragma unroll
        for (int t8 = 0; t8 < 8; t8++) {
            o[t8][0] *= corr0; o[t8][1] *= corr0;
            o[t8][2] *= corr1; o[t8][3] *= corr1;
        }
        __syncwarp();   // P rows of this warp visible to its own lanes

        // O += P V  (8 k8 steps over BN, 8 n8 tiles over HD)
#pragma unroll
        for (int kk = 0; kk < 8; kk++) {
            const uint32_t* ap = &Ps[(wrow + lr) * ST + kk * 8 + lc];
            uint32_t a0 = ap[0], a1 = ap[8 * ST], a2 = ap[4], a3 = ap[8 * ST + 4];
#pragma unroll
            for (int t8 = 0; t8 < 8; t8++) {
                uint32_t b0 = Vs[(kk * 8 + lc) * ST + t8 * 8 + lr];
                uint32_t b1 = Vs[(kk * 8 + lc + 4) * ST + t8 * 8 + lr];
                mma_tf32(o[t8][0], o[t8][1], o[t8][2], o[t8][3],
                         a0, a1, a2, a3, b0, b1);
            }
        }
    }

    float invl0 = 1.f / lsum0, invl1 = 1.f / lsum1;
    int row0 = m0 + wrow + lr, row1 = row0 + 8;
#pragma unroll
    for (int t8 = 0; t8 < 8; t8++) {
        int col = t8 * 8 + 2 * lc;
        *(float2*)(g_ctx + ((size_t)eb * CAP + row0) * HD + col) =
            make_float2(o[t8][0] * invl0, o[t8][1] * invl0);
        *(float2*)(g_ctx + ((size_t)eb * CAP + row1) * HD + col) =
            make_float2(o[t8][2] * invl1, o[t8][3] * invl1);
    }
}

// ================= stage 6a: out = (ctx @ Wff + bff) * w -> dense g_out (TF32) =========
// grid (CAP/128=10, D/128=8, EB=32), 256 threads = 8 warps (4M x 2N), warp tile 32x64
__global__ void __launch_bounds__(256) outproj_kernel(const float* __restrict__ Wff,
                                                      const float* __restrict__ bff) {
    constexpr int AST = 72, BST = 136;
    extern __shared__ uint32_t dsm[];
    uint32_t* As = dsm;              // ctx [m=128][k=64]
    uint32_t* Bs = As + 128 * AST;   // Wff [k=64][n=128]
    int mt = blockIdx.x, nt = blockIdx.y, eb = blockIdx.z;
    int e = eb >> 1;
    int tid = threadIdx.x;
    int lane = tid & 31, w = tid >> 5;
    int lr = lane >> 2, lc = lane & 3;
    int wm = (w & 3) * 32, wn = (w >> 2) * 64;
    int m0 = mt * 128, n0 = nt * 128;

    // load ctx 128x64
#pragma unroll
    for (int it = 0; it < 8; it++) {
        int idx = tid + it * 256;
        int row = idx >> 4, c4 = (idx & 15) << 2;
        float4 a4 = *(const float4*)(g_ctx + ((size_t)eb * CAP + m0 + row) * HD + c4);
        uint32_t* d = &As[row * AST + c4];
        d[0] = f2tf32(a4.x); d[1] = f2tf32(a4.y); d[2] = f2tf32(a4.z); d[3] = f2tf32(a4.w);
    }
    // load Wff 64x128
#pragma unroll
    for (int it = 0; it < 8; it++) {
        int idx = tid + it * 256;
        int row = idx >> 5, c4 = (idx & 31) << 2;
        float4 b4 = *(const float4*)(Wff + ((size_t)e * HD + row) * D + n0 + c4);
        uint32_t* d = &Bs[row * BST + c4];
        d[0] = f2tf32(b4.x); d[1] = f2tf32(b4.y); d[2] = f2tf32(b4.z); d[3] = f2tf32(b4.w);
    }
    __syncthreads();

    float acc[2][8][4];
#pragma unroll
    for (int mi = 0; mi < 2; mi++)
#pragma unroll
        for (int t8 = 0; t8 < 8; t8++)
#pragma unroll
            for (int r = 0; r < 4; r++) acc[mi][t8][r] = 0.f;

#pragma unroll
    for (int kk = 0; kk < 8; kk++) {
        uint32_t a[2][4];
#pragma unroll
        for (int mi = 0; mi < 2; mi++) {
            const uint32_t* ap = &As[(wm + mi * 16 + lr) * AST + kk * 8 + lc];
            a[mi][0] = ap[0]; a[mi][1] = ap[8 * AST];
            a[mi][2] = ap[4]; a[mi][3] = ap[8 * AST + 4];
        }
#pragma unroll
        for (int t8 = 0; t8 < 8; t8++) {
            uint32_t b0 = Bs[(kk * 8 + lc) * BST + wn + t8 * 8 + lr];
            uint32_t b1 = Bs[(kk * 8 + lc + 4) * BST + wn + t8 * 8 + lr];
#pragma unroll
            for (int mi = 0; mi < 2; mi++)
                mma_tf32(acc[mi][t8][0], acc[mi][t8][1], acc[mi][t8][2], acc[mi][t8][3],
                         a[mi][0], a[mi][1], a[mi][2], a[mi][3], b0, b1);
        }
    }

#pragma unroll
    for (int mi = 0; mi < 2; mi++) {
        int row0 = m0 + wm + mi * 16 + lr;
        int row1 = row0 + 8;
        float wv0 = g_w[eb * CAP + row0];
        float wv1 = g_w[eb * CAP + row1];
#pragma unroll
        for (int t8 = 0; t8 < 8; t8++) {
            int col = n0 + wn + t8 * 8 + 2 * lc;
            float2 bf = *(const float2*)(bff + col);
            *(float2*)(g_out + ((size_t)eb * CAP + row0) * D + col) =
                make_float2((acc[mi][t8][0] + bf.x) * wv0, (acc[mi][t8][1] + bf.y) * wv0);
            *(float2*)(g_out + ((size_t)eb * CAP + row1) * D + col) =
                make_float2((acc[mi][t8][2] + bf.x) * wv1, (acc[mi][t8][3] + bf.y) * wv1);
        }
    }
}

// ================= stage 6b: gather-combine + residual + LayerNorm =================
__global__ void ln_kernel(const float* __restrict__ x,
                          const float* __restrict__ gamma,
                          const float* __restrict__ beta,
                          float* __restrict__ out) {
    int token = blockIdx.x;
    int b = token >> 11;  // S = 2048
    int tid = threadIdx.x;
    __shared__ int sh_base[E];
    __shared__ float red[8];
    if (tid < E) {
        int p = g_inv[tid * NTOK + token];
        sh_base[tid] = (p < 0) ? -1 : ((tid * B + b) * CAP + p);
    }
    __syncthreads();
    float4 c = make_float4(0.f, 0.f, 0.f, 0.f);
#pragma unroll
    for (int e = 0; e < E; e++) {
        int base = sh_base[e];
        if (base >= 0) {
            float4 t4 = *(const float4*)(g_out + (size_t)base * D + tid * 4);
            c.x += t4.x; c.y += t4.y; c.z += t4.z; c.w += t4.w;
        }
    }
    float4 x4 = *(const float4*)(x + (size_t)token * D + tid * 4);
    float h[4] = {x4.x + c.x, x4.y + c.y, x4.z + c.z, x4.w + c.w};
    float s = h[0] + h[1] + h[2] + h[3];
#pragma unroll
    for (int off = 16; off > 0; off >>= 1) s += __shfl_xor_sync(0xffffffffu, s, off);
    int warp = tid >> 5, lane = tid & 31;
    if (lane == 0) red[warp] = s;
    __syncthreads();
    float total = 0.f;
#pragma unroll
    for (int w = 0; w < 8; w++) total += red[w];
    __syncthreads();
    float mu = total * (1.0f / D);
    float ss = 0.f;
#pragma unroll
    for (int t = 0; t < 4; t++) {
        float dlt = h[t] - mu;
        ss += dlt * dlt;
    }
#pragma unroll
    for (int off = 16; off > 0; off >>= 1) ss += __shfl_xor_sync(0xffffffffu, ss, off);
    if (lane == 0) red[warp] = ss;
    __syncthreads();
    float vtot = 0.f;
#pragma unroll
    for (int w = 0; w < 8; w++) vtot += red[w];
    float var = vtot * (1.0f / D);
    float inv = rsqrtf(var + 1e-5f);
    float4 g4 = *(const float4*)(gamma + tid * 4);
    float4 be4 = *(const float4*)(beta + tid * 4);
    float4 o4;
    o4.x = (h[0] - mu) * inv * g4.x + be4.x;
    o4.y = (h[1] - mu) * inv * g4.y + be4.y;
    o4.z = (h[2] - mu) * inv * g4.z + be4.z;
    o4.w = (h[3] - mu) * inv * g4.w + be4.w;
    *(float4*)(out + (size_t)token * D + tid * 4) = o4;
}

// ================= launch =================
extern "C" void kernel_launch(void* const* d_in, const int* in_sizes, int n_in,
                              void* d_out, int out_size) {
    const float* x     = (const float*)d_in[0];
    const float* wg    = (const float*)d_in[1];
    const float* bg    = (const float*)d_in[2];
    const float* Wq    = (const float*)d_in[3];
    const float* Wkv   = (const float*)d_in[4];
    const float* Wff   = (const float*)d_in[5];
    const float* bff   = (const float*)d_in[6];
    const float* gamma = (const float*)d_in[7];
    const float* beta  = (const float*)d_in[8];
    float* out = (float*)d_out;

    (void)in_sizes; (void)n_in; (void)out_size;

    gate_kernel<<<NTOK, 256>>>(x, wg, bg);
    route_kernel<<<(S * E + 255) / 256, 256>>>();
    select_kernel<<<EB, 256>>>();
    proj_kernel<<<dim3(CAP / 64, EB), 256>>>(x, Wq, Wkv);
    rope_kernel<<<(EB * CAP * 32 + 255) / 256, 256>>>();

    int attn_smem = 384 * 72 * (int)sizeof(uint32_t);   // 110,592 B
    cudaFuncSetAttribute(attn_kernel, cudaFuncAttributeMaxDynamicSharedMemorySize, attn_smem);
    attn_kernel<<<dim3(CAP / 128, EB), 256, attn_smem>>>();

    int op_smem = (128 * 72 + 64 * 136) * (int)sizeof(uint32_t);  // 71,680 B
    cudaFuncSetAttribute(outproj_kernel, cudaFuncAttributeMaxDynamicSharedMemorySize, op_smem);
    outproj_kernel<<<dim3(CAP / 128, D / 128, EB), 256, op_smem>>>(Wff, bff);

    ln_kernel<<<NTOK, 256>>>(x, gamma, beta, out);
}

// round 5
// speedup vs baseline: 2.1007x; 1.0817x over previous
#include <cuda_runtime.h>
#include <math.h>
#include <stdint.h>

// ---------------- problem constants ----------------
namespace {
constexpr int B = 2, S = 2048, D = 1024, E = 16, HD = 64, CAP = 1280, TOPK = 8;
constexpr float EPS = 1e-6f;
constexpr int EB = E * B;    // 32
constexpr int NTOK = B * S;  // 4096
}

// ---------------- scratch (device globals; no allocation allowed) ----------------
__device__ float g_route[NTOK * E];        // route[b][s][e]
__device__ int   g_seq[EB * CAP];          // selected token seq index (sorted ascending)
__device__ float g_w[EB * CAP];            // routing weight of selected token
__device__ int   g_inv[E * NTOK];          // inverse map: pos in selected list or -1
__device__ float g_q[EB * CAP * HD];
__device__ float g_k[EB * CAP * HD];
__device__ float g_v[EB * CAP * HD];
__device__ float g_ctx[EB * CAP * HD];
__device__ float g_out[(size_t)EB * CAP * D];  // per-expert weighted outputs (168MB)

// ---------------- helpers ----------------
__device__ __forceinline__ void mma_tf32(float& c0, float& c1, float& c2, float& c3,
                                         uint32_t a0, uint32_t a1, uint32_t a2, uint32_t a3,
                                         uint32_t b0, uint32_t b1) {
    asm volatile(
        "mma.sync.aligned.m16n8k8.row.col.f32.tf32.tf32.f32 "
        "{%0,%1,%2,%3}, {%4,%5,%6,%7}, {%8,%9}, {%0,%1,%2,%3};\n"
        : "+f"(c0), "+f"(c1), "+f"(c2), "+f"(c3)
        : "r"(a0), "r"(a1), "r"(a2), "r"(a3), "r"(b0), "r"(b1));
}
__device__ __forceinline__ void cp_async16(uint32_t saddr, const void* g) {
    asm volatile("cp.async.ca.shared.global [%0], [%1], 16;" :: "r"(saddr), "l"(g));
}
__device__ __forceinline__ void cp_commit() { asm volatile("cp.async.commit_group;"); }
__device__ __forceinline__ void cp_wait1()  { asm volatile("cp.async.wait_group 1;"); }

// ================= stage 1: gating =================
__global__ void gate_kernel(const float* __restrict__ x,
                            const float* __restrict__ wg,
                            const float* __restrict__ bg) {
    int token = blockIdx.x;
    const float* xr = x + (size_t)token * D;
    float acc[E];
#pragma unroll
    for (int e = 0; e < E; e++) acc[e] = 0.f;
    for (int d = threadIdx.x; d < D; d += 256) {
        float xv = xr[d];
        const float* w = wg + (size_t)d * E;
#pragma unroll
        for (int e = 0; e < E; e++) acc[e] += xv * w[e];
    }
#pragma unroll
    for (int off = 16; off > 0; off >>= 1) {
#pragma unroll
        for (int e = 0; e < E; e++)
            acc[e] += __shfl_xor_sync(0xffffffffu, acc[e], off);
    }
    __shared__ float red[8][E];
    int warp = threadIdx.x >> 5, lane = threadIdx.x & 31;
    if (lane == 0) {
#pragma unroll
        for (int e = 0; e < E; e++) red[warp][e] = acc[e];
    }
    __syncthreads();
    if (threadIdx.x == 0) {
        float g[E];
        float mx = -3.402823466e38f;
#pragma unroll
        for (int e = 0; e < E; e++) {
            float s = bg[e];
            for (int w = 0; w < 8; w++) s += red[w][e];
            g[e] = s;
            mx = fmaxf(mx, s);
        }
        float den = 0.f;
#pragma unroll
        for (int e = 0; e < E; e++) { g[e] = expf(g[e] - mx); den += g[e]; }
        float inv = 1.f / den;
#pragma unroll
        for (int e = 0; e < E; e++) g[e] *= inv;
#pragma unroll
        for (int e = 0; e < E; e++) {
            int r = 0;
#pragma unroll
            for (int j = 0; j < E; j++)
                r += (g[j] > g[e]) || (g[j] == g[e] && j < e);
            g_route[(size_t)token * E + e] = (r < TOPK) ? g[e] : 0.f;
        }
    }
}

// ================= stage 2: route normalize =================
__global__ void route_kernel() {
    int idx = blockIdx.x * blockDim.x + threadIdx.x;
    if (idx >= S * E) return;
    int s = idx / E, e = idx % E;
    float m0 = g_route[(size_t)s * E + e];
    float m1 = g_route[(size_t)(S + s) * E + e];
    float den = m0 + m1 + EPS;
    g_route[(size_t)s * E + e]       = m0 / den * 2.0f;
    g_route[(size_t)(S + s) * E + e] = m1 / den * 2.0f;
}

// ================= stage 3: top-CAP token selection =================
__global__ void select_kernel() {
    int eb = blockIdx.x;
    int e = eb >> 1, b = eb & 1;
    __shared__ float sv[S];
    __shared__ unsigned char sm[S];
    __shared__ int cnt[256];
    for (int s = threadIdx.x; s < S; s += 256)
        sv[s] = g_route[(size_t)(b * S + s) * E + e];
    __syncthreads();
    for (int i = threadIdx.x; i < S; i += 256) {
        float vi = sv[i];
        int c = 0;
        for (int j = 0; j < S; j++) {
            float vj = sv[j];
            c += (vj > vi) || (vj == vi && j < i);
        }
        sm[i] = (c < CAP) ? 1 : 0;
    }
    __syncthreads();
    int t = threadIdx.x;
    int local = 0;
#pragma unroll
    for (int k = 0; k < 8; k++) local += sm[t * 8 + k];
    cnt[t] = local;
    __syncthreads();
    if (t == 0) {
        int run = 0;
        for (int i = 0; i < 256; i++) { int c = cnt[i]; cnt[i] = run; run += c; }
    }
    __syncthreads();
    int pos = cnt[t];
#pragma unroll
    for (int k = 0; k < 8; k++) {
        int s = t * 8 + k;
        if (sm[s]) {
            g_seq[eb * CAP + pos] = s;
            g_w[eb * CAP + pos] = sv[s];
            g_inv[e * NTOK + b * S + s] = pos;
            pos++;
        } else {
            g_inv[e * NTOK + b * S + s] = -1;
        }
    }
}

// ================= stage 4a: fused Q/K/V projection, TF32 + cp.async 3-stage =========
// grid (CAP/64=20, EB=32), 256 threads (8 warps: 2M x 4N), block tile 64x192, BK=16
__global__ void __launch_bounds__(256) proj_kernel(const float* __restrict__ x,
                                                   const float* __restrict__ Wq,
                                                   const float* __restrict__ Wkv) {
    constexpr int AST = 20, BST = 200;
    constexpr int AW = 64 * AST;   // words per A stage
    constexpr int BW = 16 * BST;   // words per B stage
    extern __shared__ uint32_t dsm[];
    uint32_t* As = dsm;            // 3 stages of [m][k]
    uint32_t* Bs = dsm + 3 * AW;   // 3 stages of [k][n]
    int mt = blockIdx.x, eb = blockIdx.y;
    int e = eb >> 1, b = eb & 1;
    int tid = threadIdx.x;
    int lane = tid & 31, w = tid >> 5;
    int lr = lane >> 2, lc = lane & 3;
    int wm = (w & 1) * 32;
    int wn = (w >> 1) * 48;
    int m0 = mt * 64;

    int ar = tid >> 2, ak = (tid & 3) << 2;
    int seqv = g_seq[eb * CAP + m0 + ar];
    const float* arow = x + (size_t)(b * S + seqv) * D + ak;
    const float* wq  = Wq  + (size_t)e * D * HD;
    const float* wkv = Wkv + (size_t)e * D * (2 * HD);

    const float* bptr[3];
    int bstep[3];
    uint32_t bsoff[3];
#pragma unroll
    for (int it = 0; it < 3; it++) {
        int f = tid + it * 256;
        int bk = f / 48, bj = f % 48;
        if (bj < 16) { bptr[it] = wq  + (size_t)bk * HD       + bj * 4;        bstep[it] = HD; }
        else         { bptr[it] = wkv + (size_t)bk * (2 * HD) + (bj - 16) * 4; bstep[it] = 2 * HD; }
        bsoff[it] = bk * BST + bj * 4;
    }
    uint32_t asoff = ar * AST + ak;

    float acc[2][6][4];
#pragma unroll
    for (int i = 0; i < 2; i++)
#pragma unroll
        for (int j = 0; j < 6; j++)
#pragma unroll
            for (int r = 0; r < 4; r++) acc[i][j][r] = 0.f;

    // prologue: stages 0,1
#pragma unroll
    for (int p = 0; p < 2; p++) {
        int s = p;
        cp_async16((uint32_t)__cvta_generic_to_shared(As + s * AW + asoff), arow + p * 16);
#pragma unroll
        for (int it = 0; it < 3; it++)
            cp_async16((uint32_t)__cvta_generic_to_shared(Bs + s * BW + bsoff[it]),
                       bptr[it] + (size_t)(p * 16) * bstep[it]);
        cp_commit();
    }

    for (int kt = 0; kt < 64; kt++) {
        cp_wait1();
        __syncthreads();
        int nxt = kt + 2;
        if (nxt < 64) {
            int s = nxt - (nxt / 3) * 3;
            int k0 = nxt * 16;
            cp_async16((uint32_t)__cvta_generic_to_shared(As + s * AW + asoff), arow + k0);
#pragma unroll
            for (int it = 0; it < 3; it++)
                cp_async16((uint32_t)__cvta_generic_to_shared(Bs + s * BW + bsoff[it]),
                           bptr[it] + (size_t)k0 * bstep[it]);
        }
        cp_commit();
        int cs = kt - (kt / 3) * 3;
        const uint32_t* Acur = As + cs * AW;
        const uint32_t* Bcur = Bs + cs * BW;
#pragma unroll
        for (int kb2 = 0; kb2 < 16; kb2 += 8) {
            uint32_t a[2][4], bb[6][2];
#pragma unroll
            for (int mb = 0; mb < 2; mb++) {
                const uint32_t* ap = &Acur[(wm + mb * 16 + lr) * AST + kb2 + lc];
                a[mb][0] = ap[0];
                a[mb][1] = ap[8 * AST];
                a[mb][2] = ap[4];
                a[mb][3] = ap[8 * AST + 4];
            }
#pragma unroll
            for (int nb = 0; nb < 6; nb++) {
                const uint32_t* bp = &Bcur[(kb2 + lc) * BST + wn + lr + nb * 8];
                bb[nb][0] = bp[0];
                bb[nb][1] = bp[4 * BST];
            }
#pragma unroll
            for (int mb = 0; mb < 2; mb++)
#pragma unroll
                for (int nb = 0; nb < 6; nb++)
                    mma_tf32(acc[mb][nb][0], acc[mb][nb][1], acc[mb][nb][2], acc[mb][nb][3],
                             a[mb][0], a[mb][1], a[mb][2], a[mb][3],
                             bb[nb][0], bb[nb][1]);
        }
    }

    // epilogue: cols 0-63 -> q, 64-127 -> k, 128-191 -> v
#pragma unroll
    for (int nb = 0; nb < 6; nb++) {
        int colg = wn + nb * 8 + 2 * lc;
        float* dst;
        int col;
        if (colg < 64)       { dst = g_q; col = colg; }
        else if (colg < 128) { dst = g_k; col = colg - 64; }
        else                 { dst = g_v; col = colg - 128; }
#pragma unroll
        for (int mb = 0; mb < 2; mb++) {
            int rowg = m0 + wm + mb * 16 + lr;
            size_t base0 = ((size_t)eb * CAP + rowg) * HD + col;
            size_t base1 = ((size_t)eb * CAP + rowg + 8) * HD + col;
            *(float2*)(dst + base0) = make_float2(acc[mb][nb][0], acc[mb][nb][1]);
            *(float2*)(dst + base1) = make_float2(acc[mb][nb][2], acc[mb][nb][3]);
        }
    }
}

// ================= stage 4b: RoPE on q and k =================
__global__ void rope_kernel() {
    int idx = blockIdx.x * blockDim.x + threadIdx.x;
    if (idx >= EB * CAP * 32) return;
    int h = idx & 31;
    int t = idx >> 5;
    int pos = g_seq[t];
    // theta^(-2h/64) = 2^(-h * log2(theta)/32)
    float invf = exp2f(-(float)h * 0.4152410118609203f);
    float ang = (float)pos * invf;
    float c, s;
    sincosf(ang, &s, &c);
    float* q = g_q + (size_t)t * HD;
    float* k = g_k + (size_t)t * HD;
    float q1 = q[h], q2 = q[h + 32];
    q[h]      = q1 * c - q2 * s;
    q[h + 32] = q2 * c + q1 * s;
    float k1 = k[h], k2 = k[h + 32];
    k[h]      = k1 * c - k2 * s;
    k[h + 32] = k2 * c + k1 * s;
}

// ================= stage 5: causal flash attention, TF32 =================
// grid (CAP/128=10, EB=32), 256 threads = 8 warps; warp w owns rows [16w,16w+16)
__global__ void __launch_bounds__(256, 2) attn_kernel() {
    constexpr int ST = 72;
    extern __shared__ uint32_t dsm[];
    uint32_t* Qs = dsm;                 // 128*ST
    uint32_t* Ks = Qs + 128 * ST;       // 64*ST
    uint32_t* Vs = Ks + 64 * ST;        // 64*ST
    uint32_t* Ps = Vs + 64 * ST;        // 128*ST
    int mt = blockIdx.x, eb = blockIdx.y;
    int m0 = mt * 128;
    const float* qptr = g_q + (size_t)eb * CAP * HD;
    const float* kptr = g_k + (size_t)eb * CAP * HD;
    const float* vptr = g_v + (size_t)eb * CAP * HD;
    int tid = threadIdx.x;
    int lane = tid & 31, w = tid >> 5;
    int lr = lane >> 2, lc = lane & 3;
    int wrow = 16 * w;

#pragma unroll
    for (int it = 0; it < 8; it++) {
        int idx = tid + it * 256;
        int row = idx >> 4, c4 = (idx & 15) << 2;
        float4 v4 = *(const float4*)(qptr + (size_t)(m0 + row) * HD + c4);
        uint32_t* d = &Qs[row * ST + c4];
        d[0] = __float_as_uint(v4.x); d[1] = __float_as_uint(v4.y);
        d[2] = __float_as_uint(v4.z); d[3] = __float_as_uint(v4.w);
    }

    float o[8][4];
#pragma unroll
    for (int t8 = 0; t8 < 8; t8++)
#pragma unroll
        for (int r = 0; r < 4; r++) o[t8][r] = 0.f;
    float mrow0 = -3.402823466e38f, mrow1 = -3.402823466e38f;
    float lsum0 = 0.f, lsum1 = 0.f;

    int ntiles = 2 * mt + 2;
    for (int nt = 0; nt < ntiles; nt++) {
        int n0 = nt * 64;
        __syncthreads();
#pragma unroll
        for (int it = 0; it < 4; it++) {
            int idx = tid + it * 256;
            int row = idx >> 4, c4 = (idx & 15) << 2;
            float4 k4 = *(const float4*)(kptr + (size_t)(n0 + row) * HD + c4);
            uint32_t* kd = &Ks[row * ST + c4];
            kd[0] = __float_as_uint(k4.x); kd[1] = __float_as_uint(k4.y);
            kd[2] = __float_as_uint(k4.z); kd[3] = __float_as_uint(k4.w);
            float4 v4 = *(const float4*)(vptr + (size_t)(n0 + row) * HD + c4);
            uint32_t* vd = &Vs[row * ST + c4];
            vd[0] = __float_as_uint(v4.x); vd[1] = __float_as_uint(v4.y);
            vd[2] = __float_as_uint(v4.z); vd[3] = __float_as_uint(v4.w);
        }
        __syncthreads();

        float sacc[8][4];
#pragma unroll
        for (int t8 = 0; t8 < 8; t8++)
#pragma unroll
            for (int r = 0; r < 4; r++) sacc[t8][r] = 0.f;
#pragma unroll
        for (int kk = 0; kk < 8; kk++) {
            const uint32_t* ap = &Qs[(wrow + lr) * ST + kk * 8 + lc];
            uint32_t a0 = ap[0], a1 = ap[8 * ST], a2 = ap[4], a3 = ap[8 * ST + 4];
#pragma unroll
            for (int t8 = 0; t8 < 8; t8++) {
                const uint32_t* bp = &Ks[(t8 * 8 + lr) * ST + kk * 8 + lc];
                mma_tf32(sacc[t8][0], sacc[t8][1], sacc[t8][2], sacc[t8][3],
                         a0, a1, a2, a3, bp[0], bp[4]);
            }
        }

        bool maskT = (nt >= 2 * mt);
#pragma unroll
        for (int t8 = 0; t8 < 8; t8++) {
            int cbase = n0 + t8 * 8 + 2 * lc;
#pragma unroll
            for (int r = 0; r < 4; r++) {
                float v = sacc[t8][r] * 0.125f;
                if (maskT) {
                    int row = m0 + wrow + lr + ((r >= 2) ? 8 : 0);
                    int col = cbase + (r & 1);
                    if (col > row) v = -3.402823466e38f;
                }
                sacc[t8][r] = v;
            }
        }

        float mx0 = -3.402823466e38f, mx1 = -3.402823466e38f;
#pragma unroll
        for (int t8 = 0; t8 < 8; t8++) {
            mx0 = fmaxf(mx0, fmaxf(sacc[t8][0], sacc[t8][1]));
            mx1 = fmaxf(mx1, fmaxf(sacc[t8][2], sacc[t8][3]));
        }
        mx0 = fmaxf(mx0, __shfl_xor_sync(0xffffffffu, mx0, 1));
        mx0 = fmaxf(mx0, __shfl_xor_sync(0xffffffffu, mx0, 2));
        mx1 = fmaxf(mx1, __shfl_xor_sync(0xffffffffu, mx1, 1));
        mx1 = fmaxf(mx1, __shfl_xor_sync(0xffffffffu, mx1, 2));
        float nm0 = fmaxf(mrow0, mx0), nm1 = fmaxf(mrow1, mx1);
        float corr0 = __expf(mrow0 - nm0), corr1 = __expf(mrow1 - nm1);
        float rs0 = 0.f, rs1 = 0.f;
#pragma unroll
        for (int t8 = 0; t8 < 8; t8++) {
            float p0 = __expf(sacc[t8][0] - nm0);
            float p1 = __expf(sacc[t8][1] - nm0);
            float p2 = __expf(sacc[t8][2] - nm1);
            float p3 = __expf(sacc[t8][3] - nm1);
            rs0 += p0 + p1; rs1 += p2 + p3;
            int b0 = (wrow + lr) * ST + t8 * 8 + 2 * lc;
            Ps[b0]     = __float_as_uint(p0);
            Ps[b0 + 1] = __float_as_uint(p1);
            int b1 = (wrow + lr + 8) * ST + t8 * 8 + 2 * lc;
            Ps[b1]     = __float_as_uint(p2);
            Ps[b1 + 1] = __float_as_uint(p3);
        }
        rs0 += __shfl_xor_sync(0xffffffffu, rs0, 1);
        rs0 += __shfl_xor_sync(0xffffffffu, rs0, 2);
        rs1 += __shfl_xor_sync(0xffffffffu, rs1, 1);
        rs1 += __shfl_xor_sync(0xffffffffu, rs1, 2);
        lsum0 = lsum0 * corr0 + rs0;
        lsum1 = lsum1 * corr1 + rs1;
        mrow0 = nm0; mrow1 = nm1;
#pragma unroll
        for (int t8 = 0; t8 < 8; t8++) {
            o[t8][0] *= corr0; o[t8][1] *= corr0;
            o[t8][2] *= corr1; o[t8][3] *= corr1;
        }
        __syncwarp();

#pragma unroll
        for (int kk = 0; kk < 8; kk++) {
            const uint32_t* ap = &Ps[(wrow + lr) * ST + kk * 8 + lc];
            uint32_t a0 = ap[0], a1 = ap[8 * ST], a2 = ap[4], a3 = ap[8 * ST + 4];
#pragma unroll
            for (int t8 = 0; t8 < 8; t8++) {
                uint32_t b0 = Vs[(kk * 8 + lc) * ST + t8 * 8 + lr];
                uint32_t b1 = Vs[(kk * 8 + lc + 4) * ST + t8 * 8 + lr];
                mma_tf32(o[t8][0], o[t8][1], o[t8][2], o[t8][3],
                         a0, a1, a2, a3, b0, b1);
            }
        }
    }

    float invl0 = 1.f / lsum0, invl1 = 1.f / lsum1;
    int row0 = m0 + wrow + lr, row1 = row0 + 8;
#pragma unroll
    for (int t8 = 0; t8 < 8; t8++) {
        int col = t8 * 8 + 2 * lc;
        *(float2*)(g_ctx + ((size_t)eb * CAP + row0) * HD + col) =
            make_float2(o[t8][0] * invl0, o[t8][1] * invl0);
        *(float2*)(g_ctx + ((size_t)eb * CAP + row1) * HD + col) =
            make_float2(o[t8][2] * invl1, o[t8][3] * invl1);
    }
}

// ================= stage 6a: out = (ctx @ Wff + bff) * w -> dense g_out (TF32) =========
// grid (CAP/128=10, D/128=8, EB=32), 256 threads = 8 warps (4M x 2N), warp tile 32x64
__global__ void __launch_bounds__(256) outproj_kernel(const float* __restrict__ Wff,
                                                      const float* __restrict__ bff) {
    constexpr int AST = 72, BST = 136;
    extern __shared__ uint32_t dsm[];
    uint32_t* As = dsm;              // ctx [m=128][k=64]
    uint32_t* Bs = As + 128 * AST;   // Wff [k=64][n=128]
    int mt = blockIdx.x, nt = blockIdx.y, eb = blockIdx.z;
    int e = eb >> 1;
    int tid = threadIdx.x;
    int lane = tid & 31, w = tid >> 5;
    int lr = lane >> 2, lc = lane & 3;
    int wm = (w & 3) * 32, wn = (w >> 2) * 64;
    int m0 = mt * 128, n0 = nt * 128;

#pragma unroll
    for (int it = 0; it < 8; it++) {
        int idx = tid + it * 256;
        int row = idx >> 4, c4 = (idx & 15) << 2;
        float4 a4 = *(const float4*)(g_ctx + ((size_t)eb * CAP + m0 + row) * HD + c4);
        uint32_t* d = &As[row * AST + c4];
        d[0] = __float_as_uint(a4.x); d[1] = __float_as_uint(a4.y);
        d[2] = __float_as_uint(a4.z); d[3] = __float_as_uint(a4.w);
    }
#pragma unroll
    for (int it = 0; it < 8; it++) {
        int idx = tid + it * 256;
        int row = idx >> 5, c4 = (idx & 31) << 2;
        float4 b4 = *(const float4*)(Wff + ((size_t)e * HD + row) * D + n0 + c4);
        uint32_t* d = &Bs[row * BST + c4];
        d[0] = __float_as_uint(b4.x); d[1] = __float_as_uint(b4.y);
        d[2] = __float_as_uint(b4.z); d[3] = __float_as_uint(b4.w);
    }
    __syncthreads();

    float acc[2][8][4];
#pragma unroll
    for (int mi = 0; mi < 2; mi++)
#pragma unroll
        for (int t8 = 0; t8 < 8; t8++)
#pragma unroll
            for (int r = 0; r < 4; r++) acc[mi][t8][r] = 0.f;

#pragma unroll
    for (int kk = 0; kk < 8; kk++) {
        uint32_t a[2][4];
#pragma unroll
        for (int mi = 0; mi < 2; mi++) {
            const uint32_t* ap = &As[(wm + mi * 16 + lr) * AST + kk * 8 + lc];
            a[mi][0] = ap[0]; a[mi][1] = ap[8 * AST];
            a[mi][2] = ap[4]; a[mi][3] = ap[8 * AST + 4];
        }
#pragma unroll
        for (int t8 = 0; t8 < 8; t8++) {
            uint32_t b0 = Bs[(kk * 8 + lc) * BST + wn + t8 * 8 + lr];
            uint32_t b1 = Bs[(kk * 8 + lc + 4) * BST + wn + t8 * 8 + lr];
#pragma unroll
            for (int mi = 0; mi < 2; mi++)
                mma_tf32(acc[mi][t8][0], acc[mi][t8][1], acc[mi][t8][2], acc[mi][t8][3],
                         a[mi][0], a[mi][1], a[mi][2], a[mi][3], b0, b1);
        }
    }

#pragma unroll
    for (int mi = 0; mi < 2; mi++) {
        int row0 = m0 + wm + mi * 16 + lr;
        int row1 = row0 + 8;
        float wv0 = g_w[eb * CAP + row0];
        float wv1 = g_w[eb * CAP + row1];
#pragma unroll
        for (int t8 = 0; t8 < 8; t8++) {
            int col = n0 + wn + t8 * 8 + 2 * lc;
            float2 bf = *(const float2*)(bff + col);
            *(float2*)(g_out + ((size_t)eb * CAP + row0) * D + col) =
                make_float2((acc[mi][t8][0] + bf.x) * wv0, (acc[mi][t8][1] + bf.y) * wv0);
            *(float2*)(g_out + ((size_t)eb * CAP + row1) * D + col) =
                make_float2((acc[mi][t8][2] + bf.x) * wv1, (acc[mi][t8][3] + bf.y) * wv1);
        }
    }
}

// ================= stage 6b: gather-combine + residual + LayerNorm =================
__global__ void ln_kernel(const float* __restrict__ x,
                          const float* __restrict__ gamma,
                          const float* __restrict__ beta,
                          float* __restrict__ out) {
    int token = blockIdx.x;
    int b = token >> 11;  // S = 2048
    int tid = threadIdx.x;
    __shared__ int sh_base[E];
    __shared__ float red[8];
    if (tid < E) {
        int p = g_inv[tid * NTOK + token];
        sh_base[tid] = (p < 0) ? -1 : ((tid * B + b) * CAP + p);
    }
    __syncthreads();
    float4 c = make_float4(0.f, 0.f, 0.f, 0.f);
#pragma unroll
    for (int e = 0; e < E; e++) {
        int base = sh_base[e];
        if (base >= 0) {
            float4 t4 = *(const float4*)(g_out + (size_t)base * D + tid * 4);
            c.x += t4.x; c.y += t4.y; c.z += t4.z; c.w += t4.w;
        }
    }
    float4 x4 = *(const float4*)(x + (size_t)token * D + tid * 4);
    float h[4] = {x4.x + c.x, x4.y + c.y, x4.z + c.z, x4.w + c.w};
    float s = h[0] + h[1] + h[2] + h[3];
#pragma unroll
    for (int off = 16; off > 0; off >>= 1) s += __shfl_xor_sync(0xffffffffu, s, off);
    int warp = tid >> 5, lane = tid & 31;
    if (lane == 0) red[warp] = s;
    __syncthreads();
    float total = 0.f;
#pragma unroll
    for (int w = 0; w < 8; w++) total += red[w];
    __syncthreads();
    float mu = total * (1.0f / D);
    float ss = 0.f;
#pragma unroll
    for (int t = 0; t < 4; t++) {
        float dlt = h[t] - mu;
        ss += dlt * dlt;
    }
#pragma unroll
    for (int off = 16; off > 0; off >>= 1) ss += __shfl_xor_sync(0xffffffffu, ss, off);
    if (lane == 0) red[warp] = ss;
    __syncthreads();
    float vtot = 0.f;
#pragma unroll
    for (int w = 0; w < 8; w++) vtot += red[w];
    float var = vtot * (1.0f / D);
    float inv = rsqrtf(var + 1e-5f);
    float4 g4 = *(const float4*)(gamma + tid * 4);
    float4 be4 = *(const float4*)(beta + tid * 4);
    float4 o4;
    o4.x = (h[0] - mu) * inv * g4.x + be4.x;
    o4.y = (h[1] - mu) * inv * g4.y + be4.y;
    o4.z = (h[2] - mu) * inv * g4.z + be4.z;
    o4.w = (h[3] - mu) * inv * g4.w + be4.w;
    *(float4*)(out + (size_t)token * D + tid * 4) = o4;
}

// ================= launch =================
extern "C" void kernel_launch(void* const* d_in, const int* in_sizes, int n_in,
                              void* d_out, int out_size) {
    const float* x     = (const float*)d_in[0];
    const float* wg    = (const float*)d_in[1];
    const float* bg    = (const float*)d_in[2];
    const float* Wq    = (const float*)d_in[3];
    const float* Wkv   = (const float*)d_in[4];
    const float* Wff   = (const float*)d_in[5];
    const float* bff   = (const float*)d_in[6];
    const float* gamma = (const float*)d_in[7];
    const float* beta  = (const float*)d_in[8];
    float* out = (float*)d_out;

    (void)in_sizes; (void)n_in; (void)out_size;

    gate_kernel<<<NTOK, 256>>>(x, wg, bg);
    route_kernel<<<(S * E + 255) / 256, 256>>>();
    select_kernel<<<EB, 256>>>();

    int proj_smem = 3 * (64 * 20 + 16 * 200) * (int)sizeof(uint32_t);  // 53,760 B
    cudaFuncSetAttribute(proj_kernel, cudaFuncAttributeMaxDynamicSharedMemorySize, proj_smem);
    proj_kernel<<<dim3(CAP / 64, EB), 256, proj_smem>>>(x, Wq, Wkv);

    rope_kernel<<<(EB * CAP * 32 + 255) / 256, 256>>>();

    int attn_smem = 384 * 72 * (int)sizeof(uint32_t);   // 110,592 B
    cudaFuncSetAttribute(attn_kernel, cudaFuncAttributeMaxDynamicSharedMemorySize, attn_smem);
    attn_kernel<<<dim3(CAP / 128, EB), 256, attn_smem>>>();

    int op_smem = (128 * 72 + 64 * 136) * (int)sizeof(uint32_t);  // 71,680 B
    cudaFuncSetAttribute(outproj_kernel, cudaFuncAttributeMaxDynamicSharedMemorySize, op_smem);
    outproj_kernel<<<dim3(CAP / 128, D / 128, EB), 256, op_smem>>>(Wff, bff);

    ln_kernel<<<NTOK, 256>>>(x, gamma, beta, out);
}

// round 6
// speedup vs baseline: 2.5883x; 1.2321x over previous
#include <cuda_runtime.h>
#include <math.h>
#include <stdint.h>

// ---------------- problem constants ----------------
namespace {
constexpr int B = 2, S = 2048, D = 1024, E = 16, HD = 64, CAP = 1280, TOPK = 8;
constexpr float EPS = 1e-6f;
constexpr int EB = E * B;    // 32
constexpr int NTOK = B * S;  // 4096
}

// ---------------- scratch (device globals; no allocation allowed) ----------------
__device__ float g_route[NTOK * E];
__device__ unsigned char g_mask[EB * S];
__device__ int   g_seq[EB * CAP];
__device__ float g_w[EB * CAP];
__device__ int   g_inv[E * NTOK];
__device__ float g_q[EB * CAP * HD];
__device__ float g_k[EB * CAP * HD];
__device__ float g_v[EB * CAP * HD];
__device__ float g_ctx[EB * CAP * HD];
__device__ float g_out[(size_t)EB * CAP * D];

// ---------------- helpers ----------------
__device__ __forceinline__ void mma_tf32(float& c0, float& c1, float& c2, float& c3,
                                         uint32_t a0, uint32_t a1, uint32_t a2, uint32_t a3,
                                         uint32_t b0, uint32_t b1) {
    asm volatile(
        "mma.sync.aligned.m16n8k8.row.col.f32.tf32.tf32.f32 "
        "{%0,%1,%2,%3}, {%4,%5,%6,%7}, {%8,%9}, {%0,%1,%2,%3};\n"
        : "+f"(c0), "+f"(c1), "+f"(c2), "+f"(c3)
        : "r"(a0), "r"(a1), "r"(a2), "r"(a3), "r"(b0), "r"(b1));
}
__device__ __forceinline__ void cp_async16(uint32_t saddr, const void* g) {
    asm volatile("cp.async.ca.shared.global [%0], [%1], 16;" :: "r"(saddr), "l"(g));
}
__device__ __forceinline__ void cp_commit() { asm volatile("cp.async.commit_group;"); }
__device__ __forceinline__ void cp_wait0()  { asm volatile("cp.async.wait_group 0;"); }
__device__ __forceinline__ void cp_wait1()  { asm volatile("cp.async.wait_group 1;"); }

// ================= stage 1: gating =================
__global__ void gate_kernel(const float* __restrict__ x,
                            const float* __restrict__ wg,
                            const float* __restrict__ bg) {
    int token = blockIdx.x;
    const float* xr = x + (size_t)token * D;
    float acc[E];
#pragma unroll
    for (int e = 0; e < E; e++) acc[e] = 0.f;
    for (int d = threadIdx.x; d < D; d += 256) {
        float xv = xr[d];
        const float* w = wg + (size_t)d * E;
#pragma unroll
        for (int e = 0; e < E; e++) acc[e] += xv * w[e];
    }
#pragma unroll
    for (int off = 16; off > 0; off >>= 1) {
#pragma unroll
        for (int e = 0; e < E; e++)
            acc[e] += __shfl_xor_sync(0xffffffffu, acc[e], off);
    }
    __shared__ float red[8][E];
    int warp = threadIdx.x >> 5, lane = threadIdx.x & 31;
    if (lane == 0) {
#pragma unroll
        for (int e = 0; e < E; e++) red[warp][e] = acc[e];
    }
    __syncthreads();
    if (threadIdx.x == 0) {
        float g[E];
        float mx = -3.402823466e38f;
#pragma unroll
        for (int e = 0; e < E; e++) {
            float s = bg[e];
            for (int w = 0; w < 8; w++) s += red[w][e];
            g[e] = s;
            mx = fmaxf(mx, s);
        }
        float den = 0.f;
#pragma unroll
        for (int e = 0; e < E; e++) { g[e] = expf(g[e] - mx); den += g[e]; }
        float inv = 1.f / den;
#pragma unroll
        for (int e = 0; e < E; e++) g[e] *= inv;
#pragma unroll
        for (int e = 0; e < E; e++) {
            int r = 0;
#pragma unroll
            for (int j = 0; j < E; j++)
                r += (g[j] > g[e]) || (g[j] == g[e] && j < e);
            g_route[(size_t)token * E + e] = (r < TOPK) ? g[e] : 0.f;
        }
    }
}

// ================= stage 2: route normalize =================
__global__ void route_kernel() {
    int idx = blockIdx.x * blockDim.x + threadIdx.x;
    if (idx >= S * E) return;
    int s = idx / E, e = idx % E;
    float m0 = g_route[(size_t)s * E + e];
    float m1 = g_route[(size_t)(S + s) * E + e];
    float den = m0 + m1 + EPS;
    g_route[(size_t)s * E + e]       = m0 / den * 2.0f;
    g_route[(size_t)(S + s) * E + e] = m1 / den * 2.0f;
}

// ================= stage 3a: rank mask (full-chip parallel) =================
// grid (EB, 8), 256 threads; each thread ranks ONE row against all 2048
__global__ void mask_kernel() {
    int eb = blockIdx.x;
    int e = eb >> 1, b = eb & 1;
    __shared__ float sv[S];
    int tid = threadIdx.x;
    for (int s = tid; s < S; s += 256)
        sv[s] = g_route[(size_t)(b * S + s) * E + e];
    __syncthreads();
    int i = blockIdx.y * 256 + tid;
    float vi = sv[i];
    int c = 0;
#pragma unroll 4
    for (int j = 0; j < S; j++) {
        float vj = sv[j];
        c += (vj > vi) || (vj == vi && j < i);
    }
    g_mask[eb * S + i] = (c < CAP) ? 1 : 0;
}

// ================= stage 3b: compaction =================
__global__ void select_kernel() {
    int eb = blockIdx.x;
    int e = eb >> 1, b = eb & 1;
    __shared__ unsigned char sm[S];
    __shared__ int cnt[256];
    int t = threadIdx.x;
    for (int s = t; s < S; s += 256)
        sm[s] = g_mask[eb * S + s];
    __syncthreads();
    int local = 0;
#pragma unroll
    for (int k = 0; k < 8; k++) local += sm[t * 8 + k];
    cnt[t] = local;
    __syncthreads();
    if (t == 0) {
        int run = 0;
        for (int i = 0; i < 256; i++) { int c = cnt[i]; cnt[i] = run; run += c; }
    }
    __syncthreads();
    int pos = cnt[t];
#pragma unroll
    for (int k = 0; k < 8; k++) {
        int s = t * 8 + k;
        if (sm[s]) {
            g_seq[eb * CAP + pos] = s;
            g_w[eb * CAP + pos] = g_route[(size_t)(b * S + s) * E + e];
            g_inv[e * NTOK + b * S + s] = pos;
            pos++;
        } else {
            g_inv[e * NTOK + b * S + s] = -1;
        }
    }
}

// ================= stage 4a: fused Q/K/V projection, TF32 + cp.async, BK=32 =========
// grid (CAP/64=20, EB=32), 256 threads (8 warps: 2M x 4N), block tile 64x192
__global__ void __launch_bounds__(256) proj_kernel(const float* __restrict__ x,
                                                   const float* __restrict__ Wq,
                                                   const float* __restrict__ Wkv) {
    constexpr int AST = 36, BST = 200;
    constexpr int AW = 64 * AST;   // 2304 words per A stage
    constexpr int BW = 32 * BST;   // 6400 words per B stage
    extern __shared__ uint32_t dsm[];
    uint32_t* As = dsm;            // 2 stages [m=64][k=32]
    uint32_t* Bs = dsm + 2 * AW;   // 2 stages [k=32][n=192]
    int mt = blockIdx.x, eb = blockIdx.y;
    int e = eb >> 1, b = eb & 1;
    int tid = threadIdx.x;
    int lane = tid & 31, w = tid >> 5;
    int lr = lane >> 2, lc = lane & 3;
    int wm = (w & 1) * 32;
    int wn = (w >> 1) * 48;
    int m0 = mt * 64;

    // A: 64 rows x 32 k = 512 float4; thread owns rows r0, r0+32 at koff
    int r0 = tid >> 3;
    int koff = (tid & 7) << 2;
    int seq0 = g_seq[eb * CAP + m0 + r0];
    int seq1 = g_seq[eb * CAP + m0 + r0 + 32];
    const float* arow0 = x + (size_t)(b * S + seq0) * D + koff;
    const float* arow1 = x + (size_t)(b * S + seq1) * D + koff;
    uint32_t as0 = r0 * AST + koff;
    uint32_t as1 = (r0 + 32) * AST + koff;

    const float* wq  = Wq  + (size_t)e * D * HD;
    const float* wkv = Wkv + (size_t)e * D * (2 * HD);

    // B: 32 rows x 192 cols = 1536 float4; 6 per thread
    const float* bptr[6];
    int bstep[6];
    uint32_t bsoff[6];
#pragma unroll
    for (int it = 0; it < 6; it++) {
        int f = tid + it * 256;
        int bk = f / 48, bj = f % 48;
        if (bj < 16) { bptr[it] = wq  + (size_t)bk * HD       + bj * 4;        bstep[it] = HD; }
        else         { bptr[it] = wkv + (size_t)bk * (2 * HD) + (bj - 16) * 4; bstep[it] = 2 * HD; }
        bsoff[it] = bk * BST + bj * 4;
    }

    float acc[2][6][4];
#pragma unroll
    for (int i = 0; i < 2; i++)
#pragma unroll
        for (int j = 0; j < 6; j++)
#pragma unroll
            for (int r = 0; r < 4; r++) acc[i][j][r] = 0.f;

    // prologue: stage 0 (k=0)
    cp_async16((uint32_t)__cvta_generic_to_shared(As + as0), arow0);
    cp_async16((uint32_t)__cvta_generic_to_shared(As + as1), arow1);
#pragma unroll
    for (int it = 0; it < 6; it++)
        cp_async16((uint32_t)__cvta_generic_to_shared(Bs + bsoff[it]), bptr[it]);
    cp_commit();

    for (int kt = 0; kt < 32; kt++) {
        cp_wait0();
        __syncthreads();
        if (kt + 1 < 32) {
            int s = (kt + 1) & 1;
            int k0 = (kt + 1) * 32;
            cp_async16((uint32_t)__cvta_generic_to_shared(As + s * AW + as0), arow0 + k0);
            cp_async16((uint32_t)__cvta_generic_to_shared(As + s * AW + as1), arow1 + k0);
#pragma unroll
            for (int it = 0; it < 6; it++)
                cp_async16((uint32_t)__cvta_generic_to_shared(Bs + s * BW + bsoff[it]),
                           bptr[it] + (size_t)k0 * bstep[it]);
            cp_commit();
        }
        int cs = kt & 1;
        const uint32_t* Acur = As + cs * AW;
        const uint32_t* Bcur = Bs + cs * BW;
#pragma unroll
        for (int kb2 = 0; kb2 < 32; kb2 += 8) {
            uint32_t a[2][4], bb[6][2];
#pragma unroll
            for (int mb = 0; mb < 2; mb++) {
                const uint32_t* ap = &Acur[(wm + mb * 16 + lr) * AST + kb2 + lc];
                a[mb][0] = ap[0];
                a[mb][1] = ap[8 * AST];
                a[mb][2] = ap[4];
                a[mb][3] = ap[8 * AST + 4];
            }
#pragma unroll
            for (int nb = 0; nb < 6; nb++) {
                const uint32_t* bp = &Bcur[(kb2 + lc) * BST + wn + lr + nb * 8];
                bb[nb][0] = bp[0];
                bb[nb][1] = bp[4 * BST];
            }
#pragma unroll
            for (int mb = 0; mb < 2; mb++)
#pragma unroll
                for (int nb = 0; nb < 6; nb++)
                    mma_tf32(acc[mb][nb][0], acc[mb][nb][1], acc[mb][nb][2], acc[mb][nb][3],
                             a[mb][0], a[mb][1], a[mb][2], a[mb][3],
                             bb[nb][0], bb[nb][1]);
        }
    }

    // epilogue: cols 0-63 -> q, 64-127 -> k, 128-191 -> v
#pragma unroll
    for (int nb = 0; nb < 6; nb++) {
        int colg = wn + nb * 8 + 2 * lc;
        float* dst;
        int col;
        if (colg < 64)       { dst = g_q; col = colg; }
        else if (colg < 128) { dst = g_k; col = colg - 64; }
        else                 { dst = g_v; col = colg - 128; }
#pragma unroll
        for (int mb = 0; mb < 2; mb++) {
            int rowg = m0 + wm + mb * 16 + lr;
            size_t base0 = ((size_t)eb * CAP + rowg) * HD + col;
            size_t base1 = ((size_t)eb * CAP + rowg + 8) * HD + col;
            *(float2*)(dst + base0) = make_float2(acc[mb][nb][0], acc[mb][nb][1]);
            *(float2*)(dst + base1) = make_float2(acc[mb][nb][2], acc[mb][nb][3]);
        }
    }
}

// ================= stage 4b: RoPE on q and k =================
__global__ void rope_kernel() {
    int idx = blockIdx.x * blockDim.x + threadIdx.x;
    if (idx >= EB * CAP * 32) return;
    int h = idx & 31;
    int t = idx >> 5;
    int pos = g_seq[t];
    float invf = exp2f(-(float)h * 0.4152410118609203f);
    float ang = (float)pos * invf;
    float c, s;
    sincosf(ang, &s, &c);
    float* q = g_q + (size_t)t * HD;
    float* k = g_k + (size_t)t * HD;
    float q1 = q[h], q2 = q[h + 32];
    q[h]      = q1 * c - q2 * s;
    q[h + 32] = q2 * c + q1 * s;
    float k1 = k[h], k2 = k[h + 32];
    k[h]      = k1 * c - k2 * s;
    k[h + 32] = k2 * c + k1 * s;
}

// ================= stage 5: causal flash attention, TF32 + cp.async overlap =========
// grid (CAP/128=10, EB=32), 256 threads = 8 warps; warp w owns rows [16w,16w+16)
__global__ void __launch_bounds__(256, 2) attn_kernel() {
    constexpr int ST = 72;
    extern __shared__ uint32_t dsm[];
    uint32_t* Qs = dsm;                 // 128*ST
    uint32_t* Ks = Qs + 128 * ST;       // 64*ST
    uint32_t* Vs = Ks + 64 * ST;        // 64*ST
    uint32_t* Ps = Vs + 64 * ST;        // 128*ST
    int mt = blockIdx.x, eb = blockIdx.y;
    int m0 = mt * 128;
    const float* qptr = g_q + (size_t)eb * CAP * HD;
    const float* kptr = g_k + (size_t)eb * CAP * HD;
    const float* vptr = g_v + (size_t)eb * CAP * HD;
    int tid = threadIdx.x;
    int lane = tid & 31, w = tid >> 5;
    int lr = lane >> 2, lc = lane & 3;
    int wrow = 16 * w;

#pragma unroll
    for (int it = 0; it < 8; it++) {
        int idx = tid + it * 256;
        int row = idx >> 4, c4 = (idx & 15) << 2;
        float4 v4 = *(const float4*)(qptr + (size_t)(m0 + row) * HD + c4);
        uint32_t* d = &Qs[row * ST + c4];
        d[0] = __float_as_uint(v4.x); d[1] = __float_as_uint(v4.y);
        d[2] = __float_as_uint(v4.z); d[3] = __float_as_uint(v4.w);
    }

    float o[8][4];
#pragma unroll
    for (int t8 = 0; t8 < 8; t8++)
#pragma unroll
        for (int r = 0; r < 4; r++) o[t8][r] = 0.f;
    float mrow0 = -3.402823466e38f, mrow1 = -3.402823466e38f;
    float lsum0 = 0.f, lsum1 = 0.f;

    int ntiles = 2 * mt + 2;
    for (int nt = 0; nt < ntiles; nt++) {
        int n0 = nt * 64;
        __syncthreads();   // all warps done reading prev K/V (and Q visible, first iter)
        // issue K group then V group
#pragma unroll
        for (int it = 0; it < 4; it++) {
            int idx = tid + it * 256;
            int row = idx >> 4, c4 = (idx & 15) << 2;
            cp_async16((uint32_t)__cvta_generic_to_shared(Ks + row * ST + c4),
                       kptr + (size_t)(n0 + row) * HD + c4);
        }
        cp_commit();
#pragma unroll
        for (int it = 0; it < 4; it++) {
            int idx = tid + it * 256;
            int row = idx >> 4, c4 = (idx & 15) << 2;
            cp_async16((uint32_t)__cvta_generic_to_shared(Vs + row * ST + c4),
                       vptr + (size_t)(n0 + row) * HD + c4);
        }
        cp_commit();
        cp_wait1();        // K arrived (this thread)
        __syncthreads();   // K arrived (all threads); V still in flight

        float sacc[8][4];
#pragma unroll
        for (int t8 = 0; t8 < 8; t8++)
#pragma unroll
            for (int r = 0; r < 4; r++) sacc[t8][r] = 0.f;
#pragma unroll
        for (int kk = 0; kk < 8; kk++) {
            const uint32_t* ap = &Qs[(wrow + lr) * ST + kk * 8 + lc];
            uint32_t a0 = ap[0], a1 = ap[8 * ST], a2 = ap[4], a3 = ap[8 * ST + 4];
#pragma unroll
            for (int t8 = 0; t8 < 8; t8++) {
                const uint32_t* bp = &Ks[(t8 * 8 + lr) * ST + kk * 8 + lc];
                mma_tf32(sacc[t8][0], sacc[t8][1], sacc[t8][2], sacc[t8][3],
                         a0, a1, a2, a3, bp[0], bp[4]);
            }
        }

        bool maskT = (nt >= 2 * mt);
#pragma unroll
        for (int t8 = 0; t8 < 8; t8++) {
            int cbase = n0 + t8 * 8 + 2 * lc;
#pragma unroll
            for (int r = 0; r < 4; r++) {
                float v = sacc[t8][r] * 0.125f;
                if (maskT) {
                    int row = m0 + wrow + lr + ((r >= 2) ? 8 : 0);
                    int col = cbase + (r & 1);
                    if (col > row) v = -3.402823466e38f;
                }
                sacc[t8][r] = v;
            }
        }

        float mx0 = -3.402823466e38f, mx1 = -3.402823466e38f;
#pragma unroll
        for (int t8 = 0; t8 < 8; t8++) {
            mx0 = fmaxf(mx0, fmaxf(sacc[t8][0], sacc[t8][1]));
            mx1 = fmaxf(mx1, fmaxf(sacc[t8][2], sacc[t8][3]));
        }
        mx0 = fmaxf(mx0, __shfl_xor_sync(0xffffffffu, mx0, 1));
        mx0 = fmaxf(mx0, __shfl_xor_sync(0xffffffffu, mx0, 2));
        mx1 = fmaxf(mx1, __shfl_xor_sync(0xffffffffu, mx1, 1));
        mx1 = fmaxf(mx1, __shfl_xor_sync(0xffffffffu, mx1, 2));
        float nm0 = fmaxf(mrow0, mx0), nm1 = fmaxf(mrow1, mx1);
        float corr0 = __expf(mrow0 - nm0), corr1 = __expf(mrow1 - nm1);
        float rs0 = 0.f, rs1 = 0.f;
#pragma unroll
        for (int t8 = 0; t8 < 8; t8++) {
            float p0 = __expf(sacc[t8][0] - nm0);
            float p1 = __expf(sacc[t8][1] - nm0);
            float p2 = __expf(sacc[t8][2] - nm1);
            float p3 = __expf(sacc[t8][3] - nm1);
            rs0 += p0 + p1; rs1 += p2 + p3;
            int b0 = (wrow + lr) * ST + t8 * 8 + 2 * lc;
            Ps[b0]     = __float_as_uint(p0);
            Ps[b0 + 1] = __float_as_uint(p1);
            int b1 = (wrow + lr + 8) * ST + t8 * 8 + 2 * lc;
            Ps[b1]     = __float_as_uint(p2);
            Ps[b1 + 1] = __float_as_uint(p3);
        }
        rs0 += __shfl_xor_sync(0xffffffffu, rs0, 1);
        rs0 += __shfl_xor_sync(0xffffffffu, rs0, 2);
        rs1 += __shfl_xor_sync(0xffffffffu, rs1, 1);
        rs1 += __shfl_xor_sync(0xffffffffu, rs1, 2);
        lsum0 = lsum0 * corr0 + rs0;
        lsum1 = lsum1 * corr1 + rs1;
        mrow0 = nm0; mrow1 = nm1;
#pragma unroll
        for (int t8 = 0; t8 < 8; t8++) {
            o[t8][0] *= corr0; o[t8][1] *= corr0;
            o[t8][2] *= corr1; o[t8][3] *= corr1;
        }

        cp_wait0();        // V arrived (this thread)
        __syncthreads();   // V arrived (all threads); P visible (own warp anyway)

#pragma unroll
        for (int kk = 0; kk < 8; kk++) {
            const uint32_t* ap = &Ps[(wrow + lr) * ST + kk * 8 + lc];
            uint32_t a0 = ap[0], a1 = ap[8 * ST], a2 = ap[4], a3 = ap[8 * ST + 4];
#pragma unroll
            for (int t8 = 0; t8 < 8; t8++) {
                uint32_t b0 = Vs[(kk * 8 + lc) * ST + t8 * 8 + lr];
                uint32_t b1 = Vs[(kk * 8 + lc + 4) * ST + t8 * 8 + lr];
                mma_tf32(o[t8][0], o[t8][1], o[t8][2], o[t8][3],
                         a0, a1, a2, a3, b0, b1);
            }
        }
    }

    float invl0 = 1.f / lsum0, invl1 = 1.f / lsum1;
    int row0 = m0 + wrow + lr, row1 = row0 + 8;
#pragma unroll
    for (int t8 = 0; t8 < 8; t8++) {
        int col = t8 * 8 + 2 * lc;
        *(float2*)(g_ctx + ((size_t)eb * CAP + row0) * HD + col) =
            make_float2(o[t8][0] * invl0, o[t8][1] * invl0);
        *(float2*)(g_ctx + ((size_t)eb * CAP + row1) * HD + col) =
            make_float2(o[t8][2] * invl1, o[t8][3] * invl1);
    }
}

// ================= stage 6a: out = (ctx @ Wff + bff) * w -> dense g_out (TF32) =========
// grid (CAP/128=10, D/128=8, EB=32), 256 threads = 8 warps (4M x 2N)
__global__ void __launch_bounds__(256) outproj_kernel(const float* __restrict__ Wff,
                                                      const float* __restrict__ bff) {
    constexpr int AST = 72, BST = 136;
    extern __shared__ uint32_t dsm[];
    uint32_t* As = dsm;              // ctx [m=128][k=64]
    uint32_t* Bs = As + 128 * AST;   // Wff [k=64][n=128]
    int mt = blockIdx.x, nt = blockIdx.y, eb = blockIdx.z;
    int e = eb >> 1;
    int tid = threadIdx.x;
    int lane = tid & 31, w = tid >> 5;
    int lr = lane >> 2, lc = lane & 3;
    int wm = (w & 3) * 32, wn = (w >> 2) * 64;
    int m0 = mt * 128, n0 = nt * 128;

#pragma unroll
    for (int it = 0; it < 8; it++) {
        int idx = tid + it * 256;
        int row = idx >> 4, c4 = (idx & 15) << 2;
        cp_async16((uint32_t)__cvta_generic_to_shared(As + row * AST + c4),
                   g_ctx + ((size_t)eb * CAP + m0 + row) * HD + c4);
    }
#pragma unroll
    for (int it = 0; it < 8; it++) {
        int idx = tid + it * 256;
        int row = idx >> 5, c4 = (idx & 31) << 2;
        cp_async16((uint32_t)__cvta_generic_to_shared(Bs + row * BST + c4),
                   Wff + ((size_t)e * HD + row) * D + n0 + c4);
    }
    cp_commit();
    cp_wait0();
    __syncthreads();

    float acc[2][8][4];
#pragma unroll
    for (int mi = 0; mi < 2; mi++)
#pragma unroll
        for (int t8 = 0; t8 < 8; t8++)
#pragma unroll
            for (int r = 0; r < 4; r++) acc[mi][t8][r] = 0.f;

#pragma unroll
    for (int kk = 0; kk < 8; kk++) {
        uint32_t a[2][4];
#pragma unroll
        for (int mi = 0; mi < 2; mi++) {
            const uint32_t* ap = &As[(wm + mi * 16 + lr) * AST + kk * 8 + lc];
            a[mi][0] = ap[0]; a[mi][1] = ap[8 * AST];
            a[mi][2] = ap[4]; a[mi][3] = ap[8 * AST + 4];
        }
#pragma unroll
        for (int t8 = 0; t8 < 8; t8++) {
            uint32_t b0 = Bs[(kk * 8 + lc) * BST + wn + t8 * 8 + lr];
            uint32_t b1 = Bs[(kk * 8 + lc + 4) * BST + wn + t8 * 8 + lr];
#pragma unroll
            for (int mi = 0; mi < 2; mi++)
                mma_tf32(acc[mi][t8][0], acc[mi][t8][1], acc[mi][t8][2], acc[mi][t8][3],
                         a[mi][0], a[mi][1], a[mi][2], a[mi][3], b0, b1);
        }
    }

#pragma unroll
    for (int mi = 0; mi < 2; mi++) {
        int row0 = m0 + wm + mi * 16 + lr;
        int row1 = row0 + 8;
        float wv0 = g_w[eb * CAP + row0];
        float wv1 = g_w[eb * CAP + row1];
#pragma unroll
        for (int t8 = 0; t8 < 8; t8++) {
            int col = n0 + wn + t8 * 8 + 2 * lc;
            float2 bf = *(const float2*)(bff + col);
            *(float2*)(g_out + ((size_t)eb * CAP + row0) * D + col) =
                make_float2((acc[mi][t8][0] + bf.x) * wv0, (acc[mi][t8][1] + bf.y) * wv0);
            *(float2*)(g_out + ((size_t)eb * CAP + row1) * D + col) =
                make_float2((acc[mi][t8][2] + bf.x) * wv1, (acc[mi][t8][3] + bf.y) * wv1);
        }
    }
}

// ================= stage 6b: gather-combine + residual + LayerNorm =================
__global__ void ln_kernel(const float* __restrict__ x,
                          const float* __restrict__ gamma,
                          const float* __restrict__ beta,
                          float* __restrict__ out) {
    int token = blockIdx.x;
    int b = token >> 11;  // S = 2048
    int tid = threadIdx.x;
    __shared__ int sh_base[E];
    __shared__ float red[8];
    if (tid < E) {
        int p = g_inv[tid * NTOK + token];
        sh_base[tid] = (p < 0) ? -1 : ((tid * B + b) * CAP + p);
    }
    __syncthreads();
    float4 c = make_float4(0.f, 0.f, 0.f, 0.f);
#pragma unroll
    for (int e = 0; e < E; e++) {
        int base = sh_base[e];
        if (base >= 0) {
            float4 t4 = *(const float4*)(g_out + (size_t)base * D + tid * 4);
            c.x += t4.x; c.y += t4.y; c.z += t4.z; c.w += t4.w;
        }
    }
    float4 x4 = *(const float4*)(x + (size_t)token * D + tid * 4);
    float h[4] = {x4.x + c.x, x4.y + c.y, x4.z + c.z, x4.w + c.w};
    float s = h[0] + h[1] + h[2] + h[3];
#pragma unroll
    for (int off = 16; off > 0; off >>= 1) s += __shfl_xor_sync(0xffffffffu, s, off);
    int warp = tid >> 5, lane = tid & 31;
    if (lane == 0) red[warp] = s;
    __syncthreads();
    float total = 0.f;
#pragma unroll
    for (int w = 0; w < 8; w++) total += red[w];
    __syncthreads();
    float mu = total * (1.0f / D);
    float ss = 0.f;
#pragma unroll
    for (int t = 0; t < 4; t++) {
        float dlt = h[t] - mu;
        ss += dlt * dlt;
    }
#pragma unroll
    for (int off = 16; off > 0; off >>= 1) ss += __shfl_xor_sync(0xffffffffu, ss, off);
    if (lane == 0) red[warp] = ss;
    __syncthreads();
    float vtot = 0.f;
#pragma unroll
    for (int w = 0; w < 8; w++) vtot += red[w];
    float var = vtot * (1.0f / D);
    float inv = rsqrtf(var + 1e-5f);
    float4 g4 = *(const float4*)(gamma + tid * 4);
    float4 be4 = *(const float4*)(beta + tid * 4);
    float4 o4;
    o4.x = (h[0] - mu) * inv * g4.x + be4.x;
    o4.y = (h[1] - mu) * inv * g4.y + be4.y;
    o4.z = (h[2] - mu) * inv * g4.z + be4.z;
    o4.w = (h[3] - mu) * inv * g4.w + be4.w;
    *(float4*)(out + (size_t)token * D + tid * 4) = o4;
}

// ================= launch =================
extern "C" void kernel_launch(void* const* d_in, const int* in_sizes, int n_in,
                              void* d_out, int out_size) {
    const float* x     = (const float*)d_in[0];
    const float* wg    = (const float*)d_in[1];
    const float* bg    = (const float*)d_in[2];
    const float* Wq    = (const float*)d_in[3];
    const float* Wkv   = (const float*)d_in[4];
    const float* Wff   = (const float*)d_in[5];
    const float* bff   = (const float*)d_in[6];
    const float* gamma = (const float*)d_in[7];
    const float* beta  = (const float*)d_in[8];
    float* out = (float*)d_out;

    (void)in_sizes; (void)n_in; (void)out_size;

    gate_kernel<<<NTOK, 256>>>(x, wg, bg);
    route_kernel<<<(S * E + 255) / 256, 256>>>();
    mask_kernel<<<dim3(EB, 8), 256>>>();
    select_kernel<<<EB, 256>>>();

    int proj_smem = 2 * (64 * 36 + 32 * 200) * (int)sizeof(uint32_t);  // 69,632 B
    cudaFuncSetAttribute(proj_kernel, cudaFuncAttributeMaxDynamicSharedMemorySize, proj_smem);
    proj_kernel<<<dim3(CAP / 64, EB), 256, proj_smem>>>(x, Wq, Wkv);

    rope_kernel<<<(EB * CAP * 32 + 255) / 256, 256>>>();

    int attn_smem = 384 * 72 * (int)sizeof(uint32_t);   // 110,592 B
    cudaFuncSetAttribute(attn_kernel, cudaFuncAttributeMaxDynamicSharedMemorySize, attn_smem);
    attn_kernel<<<dim3(CAP / 128, EB), 256, attn_smem>>>();

    int op_smem = (128 * 72 + 64 * 136) * (int)sizeof(uint32_t);  // 71,680 B
    cudaFuncSetAttribute(outproj_kernel, cudaFuncAttributeMaxDynamicSharedMemorySize, op_smem);
    outproj_kernel<<<dim3(CAP / 128, D / 128, EB), 256, op_smem>>>(Wff, bff);

    ln_kernel<<<NTOK, 256>>>(x, gamma, beta, out);
}

// round 7
// speedup vs baseline: 2.6312x; 1.0166x over previous
#include <cuda_runtime.h>
#include <math.h>
#include <stdint.h>

// ---------------- problem constants ----------------
namespace {
constexpr int B = 2, S = 2048, D = 1024, E = 16, HD = 64, CAP = 1280, TOPK = 8;
constexpr float EPS = 1e-6f;
constexpr int EB = E * B;    // 32
constexpr int NTOK = B * S;  // 4096
}

// ---------------- scratch (device globals; no allocation allowed) ----------------
__device__ float g_route[NTOK * E];
__device__ unsigned char g_mask[EB * S];
__device__ int   g_seq[EB * CAP];
__device__ float g_w[EB * CAP];
__device__ int   g_inv[E * NTOK];
__device__ float g_q[EB * CAP * HD];
__device__ float g_k[EB * CAP * HD];
__device__ float g_v[EB * CAP * HD];
__device__ float g_ctx[EB * CAP * HD];
__device__ float g_opart[2 * EB * CAP * HD];   // unnormalized partial O per split
__device__ float g_pm[2 * EB * CAP];           // partial rowmax
__device__ float g_pl[2 * EB * CAP];           // partial rowsum
__device__ float g_out[(size_t)EB * CAP * D];

// ---------------- helpers ----------------
__device__ __forceinline__ void mma_tf32(float& c0, float& c1, float& c2, float& c3,
                                         uint32_t a0, uint32_t a1, uint32_t a2, uint32_t a3,
                                         uint32_t b0, uint32_t b1) {
    asm volatile(
        "mma.sync.aligned.m16n8k8.row.col.f32.tf32.tf32.f32 "
        "{%0,%1,%2,%3}, {%4,%5,%6,%7}, {%8,%9}, {%0,%1,%2,%3};\n"
        : "+f"(c0), "+f"(c1), "+f"(c2), "+f"(c3)
        : "r"(a0), "r"(a1), "r"(a2), "r"(a3), "r"(b0), "r"(b1));
}
__device__ __forceinline__ void cp_async16(uint32_t saddr, const void* g) {
    asm volatile("cp.async.ca.shared.global [%0], [%1], 16;" :: "r"(saddr), "l"(g));
}
__device__ __forceinline__ void cp_commit() { asm volatile("cp.async.commit_group;"); }
__device__ __forceinline__ void cp_wait0()  { asm volatile("cp.async.wait_group 0;"); }
__device__ __forceinline__ void cp_wait1()  { asm volatile("cp.async.wait_group 1;"); }

// ================= stage 1: gating =================
__global__ void gate_kernel(const float* __restrict__ x,
                            const float* __restrict__ wg,
                            const float* __restrict__ bg) {
    int token = blockIdx.x;
    const float* xr = x + (size_t)token * D;
    float acc[E];
#pragma unroll
    for (int e = 0; e < E; e++) acc[e] = 0.f;
    for (int d = threadIdx.x; d < D; d += 256) {
        float xv = xr[d];
        const float* w = wg + (size_t)d * E;
#pragma unroll
        for (int e = 0; e < E; e++) acc[e] += xv * w[e];
    }
#pragma unroll
    for (int off = 16; off > 0; off >>= 1) {
#pragma unroll
        for (int e = 0; e < E; e++)
            acc[e] += __shfl_xor_sync(0xffffffffu, acc[e], off);
    }
    __shared__ float red[8][E];
    int warp = threadIdx.x >> 5, lane = threadIdx.x & 31;
    if (lane == 0) {
#pragma unroll
        for (int e = 0; e < E; e++) red[warp][e] = acc[e];
    }
    __syncthreads();
    if (threadIdx.x == 0) {
        float g[E];
        float mx = -3.402823466e38f;
#pragma unroll
        for (int e = 0; e < E; e++) {
            float s = bg[e];
            for (int w = 0; w < 8; w++) s += red[w][e];
            g[e] = s;
            mx = fmaxf(mx, s);
        }
        float den = 0.f;
#pragma unroll
        for (int e = 0; e < E; e++) { g[e] = expf(g[e] - mx); den += g[e]; }
        float inv = 1.f / den;
#pragma unroll
        for (int e = 0; e < E; e++) g[e] *= inv;
#pragma unroll
        for (int e = 0; e < E; e++) {
            int r = 0;
#pragma unroll
            for (int j = 0; j < E; j++)
                r += (g[j] > g[e]) || (g[j] == g[e] && j < e);
            g_route[(size_t)token * E + e] = (r < TOPK) ? g[e] : 0.f;
        }
    }
}

// ================= stage 2: route normalize =================
__global__ void route_kernel() {
    int idx = blockIdx.x * blockDim.x + threadIdx.x;
    if (idx >= S * E) return;
    int s = idx / E, e = idx % E;
    float m0 = g_route[(size_t)s * E + e];
    float m1 = g_route[(size_t)(S + s) * E + e];
    float den = m0 + m1 + EPS;
    g_route[(size_t)s * E + e]       = m0 / den * 2.0f;
    g_route[(size_t)(S + s) * E + e] = m1 / den * 2.0f;
}

// ================= stage 3a: rank mask =================
__global__ void mask_kernel() {
    int eb = blockIdx.x;
    int e = eb >> 1, b = eb & 1;
    __shared__ float sv[S];
    int tid = threadIdx.x;
    for (int s = tid; s < S; s += 256)
        sv[s] = g_route[(size_t)(b * S + s) * E + e];
    __syncthreads();
    int i = blockIdx.y * 256 + tid;
    float vi = sv[i];
    int c = 0;
#pragma unroll 4
    for (int j = 0; j < S; j++) {
        float vj = sv[j];
        c += (vj > vi) || (vj == vi && j < i);
    }
    g_mask[eb * S + i] = (c < CAP) ? 1 : 0;
}

// ================= stage 3b: compaction =================
__global__ void select_kernel() {
    int eb = blockIdx.x;
    int e = eb >> 1, b = eb & 1;
    __shared__ unsigned char sm[S];
    __shared__ int cnt[256];
    int t = threadIdx.x;
    for (int s = t; s < S; s += 256)
        sm[s] = g_mask[eb * S + s];
    __syncthreads();
    int local = 0;
#pragma unroll
    for (int k = 0; k < 8; k++) local += sm[t * 8 + k];
    cnt[t] = local;
    __syncthreads();
    if (t == 0) {
        int run = 0;
        for (int i = 0; i < 256; i++) { int c = cnt[i]; cnt[i] = run; run += c; }
    }
    __syncthreads();
    int pos = cnt[t];
#pragma unroll
    for (int k = 0; k < 8; k++) {
        int s = t * 8 + k;
        if (sm[s]) {
            g_seq[eb * CAP + pos] = s;
            g_w[eb * CAP + pos] = g_route[(size_t)(b * S + s) * E + e];
            g_inv[e * NTOK + b * S + s] = pos;
            pos++;
        } else {
            g_inv[e * NTOK + b * S + s] = -1;
        }
    }
}

// ================= stage 4a: fused Q/K/V projection, TF32 + cp.async, BK=32 =========
__global__ void __launch_bounds__(256) proj_kernel(const float* __restrict__ x,
                                                   const float* __restrict__ Wq,
                                                   const float* __restrict__ Wkv) {
    constexpr int AST = 36, BST = 200;
    constexpr int AW = 64 * AST;
    constexpr int BW = 32 * BST;
    extern __shared__ uint32_t dsm[];
    uint32_t* As = dsm;
    uint32_t* Bs = dsm + 2 * AW;
    int mt = blockIdx.x, eb = blockIdx.y;
    int e = eb >> 1, b = eb & 1;
    int tid = threadIdx.x;
    int lane = tid & 31, w = tid >> 5;
    int lr = lane >> 2, lc = lane & 3;
    int wm = (w & 1) * 32;
    int wn = (w >> 1) * 48;
    int m0 = mt * 64;

    int r0 = tid >> 3;
    int koff = (tid & 7) << 2;
    int seq0 = g_seq[eb * CAP + m0 + r0];
    int seq1 = g_seq[eb * CAP + m0 + r0 + 32];
    const float* arow0 = x + (size_t)(b * S + seq0) * D + koff;
    const float* arow1 = x + (size_t)(b * S + seq1) * D + koff;
    uint32_t as0 = r0 * AST + koff;
    uint32_t as1 = (r0 + 32) * AST + koff;

    const float* wq  = Wq  + (size_t)e * D * HD;
    const float* wkv = Wkv + (size_t)e * D * (2 * HD);

    const float* bptr[6];
    int bstep[6];
    uint32_t bsoff[6];
#pragma unroll
    for (int it = 0; it < 6; it++) {
        int f = tid + it * 256;
        int bk = f / 48, bj = f % 48;
        if (bj < 16) { bptr[it] = wq  + (size_t)bk * HD       + bj * 4;        bstep[it] = HD; }
        else         { bptr[it] = wkv + (size_t)bk * (2 * HD) + (bj - 16) * 4; bstep[it] = 2 * HD; }
        bsoff[it] = bk * BST + bj * 4;
    }

    float acc[2][6][4];
#pragma unroll
    for (int i = 0; i < 2; i++)
#pragma unroll
        for (int j = 0; j < 6; j++)
#pragma unroll
            for (int r = 0; r < 4; r++) acc[i][j][r] = 0.f;

    cp_async16((uint32_t)__cvta_generic_to_shared(As + as0), arow0);
    cp_async16((uint32_t)__cvta_generic_to_shared(As + as1), arow1);
#pragma unroll
    for (int it = 0; it < 6; it++)
        cp_async16((uint32_t)__cvta_generic_to_shared(Bs + bsoff[it]), bptr[it]);
    cp_commit();

    for (int kt = 0; kt < 32; kt++) {
        cp_wait0();
        __syncthreads();
        if (kt + 1 < 32) {
            int s = (kt + 1) & 1;
            int k0 = (kt + 1) * 32;
            cp_async16((uint32_t)__cvta_generic_to_shared(As + s * AW + as0), arow0 + k0);
            cp_async16((uint32_t)__cvta_generic_to_shared(As + s * AW + as1), arow1 + k0);
#pragma unroll
            for (int it = 0; it < 6; it++)
                cp_async16((uint32_t)__cvta_generic_to_shared(Bs + s * BW + bsoff[it]),
                           bptr[it] + (size_t)k0 * bstep[it]);
            cp_commit();
        }
        int cs = kt & 1;
        const uint32_t* Acur = As + cs * AW;
        const uint32_t* Bcur = Bs + cs * BW;
#pragma unroll
        for (int kb2 = 0; kb2 < 32; kb2 += 8) {
            uint32_t a[2][4], bb[6][2];
#pragma unroll
            for (int mb = 0; mb < 2; mb++) {
                const uint32_t* ap = &Acur[(wm + mb * 16 + lr) * AST + kb2 + lc];
                a[mb][0] = ap[0];
                a[mb][1] = ap[8 * AST];
                a[mb][2] = ap[4];
                a[mb][3] = ap[8 * AST + 4];
            }
#pragma unroll
            for (int nb = 0; nb < 6; nb++) {
                const uint32_t* bp = &Bcur[(kb2 + lc) * BST + wn + lr + nb * 8];
                bb[nb][0] = bp[0];
                bb[nb][1] = bp[4 * BST];
            }
#pragma unroll
            for (int mb = 0; mb < 2; mb++)
#pragma unroll
                for (int nb = 0; nb < 6; nb++)
                    mma_tf32(acc[mb][nb][0], acc[mb][nb][1], acc[mb][nb][2], acc[mb][nb][3],
                             a[mb][0], a[mb][1], a[mb][2], a[mb][3],
                             bb[nb][0], bb[nb][1]);
        }
    }

#pragma unroll
    for (int nb = 0; nb < 6; nb++) {
        int colg = wn + nb * 8 + 2 * lc;
        float* dst;
        int col;
        if (colg < 64)       { dst = g_q; col = colg; }
        else if (colg < 128) { dst = g_k; col = colg - 64; }
        else                 { dst = g_v; col = colg - 128; }
#pragma unroll
        for (int mb = 0; mb < 2; mb++) {
            int rowg = m0 + wm + mb * 16 + lr;
            size_t base0 = ((size_t)eb * CAP + rowg) * HD + col;
            size_t base1 = ((size_t)eb * CAP + rowg + 8) * HD + col;
            *(float2*)(dst + base0) = make_float2(acc[mb][nb][0], acc[mb][nb][1]);
            *(float2*)(dst + base1) = make_float2(acc[mb][nb][2], acc[mb][nb][3]);
        }
    }
}

// ================= stage 4b: RoPE on q and k =================
__global__ void rope_kernel() {
    int idx = blockIdx.x * blockDim.x + threadIdx.x;
    if (idx >= EB * CAP * 32) return;
    int h = idx & 31;
    int t = idx >> 5;
    int pos = g_seq[t];
    float invf = exp2f(-(float)h * 0.4152410118609203f);
    float ang = (float)pos * invf;
    float c, s;
    sincosf(ang, &s, &c);
    float* q = g_q + (size_t)t * HD;
    float* k = g_k + (size_t)t * HD;
    float q1 = q[h], q2 = q[h + 32];
    q[h]      = q1 * c - q2 * s;
    q[h + 32] = q2 * c + q1 * s;
    float k1 = k[h], k2 = k[h + 32];
    k[h]      = k1 * c - k2 * s;
    k[h + 32] = k2 * c + k1 * s;
}

// ================= stage 5: split-KV causal flash attention, TF32 =================
// grid (10, EB, 2); block z = KV split; each block does mt+1 of the 2mt+2 tiles
__global__ void __launch_bounds__(256, 2) attn_kernel() {
    constexpr int ST = 72;
    extern __shared__ uint32_t dsm[];
    uint32_t* Qs = dsm;
    uint32_t* Ks = Qs + 128 * ST;
    uint32_t* Vs = Ks + 64 * ST;
    uint32_t* Ps = Vs + 64 * ST;
    int mt = 9 - blockIdx.x;          // longest blocks launch first
    int eb = blockIdx.y;
    int split = blockIdx.z;
    int m0 = mt * 128;
    const float* qptr = g_q + (size_t)eb * CAP * HD;
    const float* kptr = g_k + (size_t)eb * CAP * HD;
    const float* vptr = g_v + (size_t)eb * CAP * HD;
    int tid = threadIdx.x;
    int lane = tid & 31, w = tid >> 5;
    int lr = lane >> 2, lc = lane & 3;
    int wrow = 16 * w;

#pragma unroll
    for (int it = 0; it < 8; it++) {
        int idx = tid + it * 256;
        int row = idx >> 4, c4 = (idx & 15) << 2;
        float4 v4 = *(const float4*)(qptr + (size_t)(m0 + row) * HD + c4);
        uint32_t* d = &Qs[row * ST + c4];
        d[0] = __float_as_uint(v4.x); d[1] = __float_as_uint(v4.y);
        d[2] = __float_as_uint(v4.z); d[3] = __float_as_uint(v4.w);
    }

    float o[8][4];
#pragma unroll
    for (int t8 = 0; t8 < 8; t8++)
#pragma unroll
        for (int r = 0; r < 4; r++) o[t8][r] = 0.f;
    float mrow0 = -3.402823466e38f, mrow1 = -3.402823466e38f;
    float lsum0 = 0.f, lsum1 = 0.f;

    int half = mt + 1;
    int ntStart = split * half;
    int ntEnd = ntStart + half;
    for (int nt = ntStart; nt < ntEnd; nt++) {
        int n0 = nt * 64;
        __syncthreads();
#pragma unroll
        for (int it = 0; it < 4; it++) {
            int idx = tid + it * 256;
            int row = idx >> 4, c4 = (idx & 15) << 2;
            cp_async16((uint32_t)__cvta_generic_to_shared(Ks + row * ST + c4),
                       kptr + (size_t)(n0 + row) * HD + c4);
        }
        cp_commit();
#pragma unroll
        for (int it = 0; it < 4; it++) {
            int idx = tid + it * 256;
            int row = idx >> 4, c4 = (idx & 15) << 2;
            cp_async16((uint32_t)__cvta_generic_to_shared(Vs + row * ST + c4),
                       vptr + (size_t)(n0 + row) * HD + c4);
        }
        cp_commit();
        cp_wait1();
        __syncthreads();

        float sacc[8][4];
#pragma unroll
        for (int t8 = 0; t8 < 8; t8++)
#pragma unroll
            for (int r = 0; r < 4; r++) sacc[t8][r] = 0.f;
#pragma unroll
        for (int kk = 0; kk < 8; kk++) {
            const uint32_t* ap = &Qs[(wrow + lr) * ST + kk * 8 + lc];
            uint32_t a0 = ap[0], a1 = ap[8 * ST], a2 = ap[4], a3 = ap[8 * ST + 4];
#pragma unroll
            for (int t8 = 0; t8 < 8; t8++) {
                const uint32_t* bp = &Ks[(t8 * 8 + lr) * ST + kk * 8 + lc];
                mma_tf32(sacc[t8][0], sacc[t8][1], sacc[t8][2], sacc[t8][3],
                         a0, a1, a2, a3, bp[0], bp[4]);
            }
        }

        bool maskT = (nt >= 2 * mt);
#pragma unroll
        for (int t8 = 0; t8 < 8; t8++) {
            int cbase = n0 + t8 * 8 + 2 * lc;
#pragma unroll
            for (int r = 0; r < 4; r++) {
                float v = sacc[t8][r] * 0.125f;
                if (maskT) {
                    int row = m0 + wrow + lr + ((r >= 2) ? 8 : 0);
                    int col = cbase + (r & 1);
                    if (col > row) v = -3.402823466e38f;
                }
                sacc[t8][r] = v;
            }
        }

        float mx0 = -3.402823466e38f, mx1 = -3.402823466e38f;
#pragma unroll
        for (int t8 = 0; t8 < 8; t8++) {
            mx0 = fmaxf(mx0, fmaxf(sacc[t8][0], sacc[t8][1]));
            mx1 = fmaxf(mx1, fmaxf(sacc[t8][2], sacc[t8][3]));
        }
        mx0 = fmaxf(mx0, __shfl_xor_sync(0xffffffffu, mx0, 1));
        mx0 = fmaxf(mx0, __shfl_xor_sync(0xffffffffu, mx0, 2));
        mx1 = fmaxf(mx1, __shfl_xor_sync(0xffffffffu, mx1, 1));
        mx1 = fmaxf(mx1, __shfl_xor_sync(0xffffffffu, mx1, 2));
        float nm0 = fmaxf(mrow0, mx0), nm1 = fmaxf(mrow1, mx1);
        float corr0 = __expf(mrow0 - nm0), corr1 = __expf(mrow1 - nm1);
        float rs0 = 0.f, rs1 = 0.f;
#pragma unroll
        for (int t8 = 0; t8 < 8; t8++) {
            float p0 = __expf(sacc[t8][0] - nm0);
            float p1 = __expf(sacc[t8][1] - nm0);
            float p2 = __expf(sacc[t8][2] - nm1);
            float p3 = __expf(sacc[t8][3] - nm1);
            rs0 += p0 + p1; rs1 += p2 + p3;
            int b0 = (wrow + lr) * ST + t8 * 8 + 2 * lc;
            Ps[b0]     = __float_as_uint(p0);
            Ps[b0 + 1] = __float_as_uint(p1);
            int b1 = (wrow + lr + 8) * ST + t8 * 8 + 2 * lc;
            Ps[b1]     = __float_as_uint(p2);
            Ps[b1 + 1] = __float_as_uint(p3);
        }
        rs0 += __shfl_xor_sync(0xffffffffu, rs0, 1);
        rs0 += __shfl_xor_sync(0xffffffffu, rs0, 2);
        rs1 += __shfl_xor_sync(0xffffffffu, rs1, 1);
        rs1 += __shfl_xor_sync(0xffffffffu, rs1, 2);
        lsum0 = lsum0 * corr0 + rs0;
        lsum1 = lsum1 * corr1 + rs1;
        mrow0 = nm0; mrow1 = nm1;
#pragma unroll
        for (int t8 = 0; t8 < 8; t8++) {
            o[t8][0] *= corr0; o[t8][1] *= corr0;
            o[t8][2] *= corr1; o[t8][3] *= corr1;
        }

        cp_wait0();
        __syncthreads();

#pragma unroll
        for (int kk = 0; kk < 8; kk++) {
            const uint32_t* ap = &Ps[(wrow + lr) * ST + kk * 8 + lc];
            uint32_t a0 = ap[0], a1 = ap[8 * ST], a2 = ap[4], a3 = ap[8 * ST + 4];
#pragma unroll
            for (int t8 = 0; t8 < 8; t8++) {
                uint32_t b0 = Vs[(kk * 8 + lc) * ST + t8 * 8 + lr];
                uint32_t b1 = Vs[(kk * 8 + lc + 4) * ST + t8 * 8 + lr];
                mma_tf32(o[t8][0], o[t8][1], o[t8][2], o[t8][3],
                         a0, a1, a2, a3, b0, b1);
            }
        }
    }

    // write unnormalized partials + (m, l)
    int row0 = m0 + wrow + lr, row1 = row0 + 8;
    float* op = g_opart + (size_t)split * EB * CAP * HD;
#pragma unroll
    for (int t8 = 0; t8 < 8; t8++) {
        int col = t8 * 8 + 2 * lc;
        *(float2*)(op + ((size_t)eb * CAP + row0) * HD + col) = make_float2(o[t8][0], o[t8][1]);
        *(float2*)(op + ((size_t)eb * CAP + row1) * HD + col) = make_float2(o[t8][2], o[t8][3]);
    }
    if (lc == 0) {
        int base = split * EB * CAP + eb * CAP;
        g_pm[base + row0] = mrow0;
        g_pl[base + row0] = lsum0;
        g_pm[base + row1] = mrow1;
        g_pl[base + row1] = lsum1;
    }
}

// ================= stage 5b: combine splits =================
__global__ void combine_kernel() {
    int idx = blockIdx.x * blockDim.x + threadIdx.x;   // EB*CAP*16 threads
    if (idx >= EB * CAP * 16) return;
    int t = idx >> 4;
    int c4 = (idx & 15) << 2;
    float m0 = g_pm[t], m1 = g_pm[EB * CAP + t];
    float l0 = g_pl[t], l1 = g_pl[EB * CAP + t];
    float M = fmaxf(m0, m1);
    float s0 = __expf(m0 - M), s1 = __expf(m1 - M);
    float inv = 1.f / (l0 * s0 + l1 * s1);
    const float4 a = *(const float4*)(g_opart + (size_t)t * HD + c4);
    const float4 b = *(const float4*)(g_opart + (size_t)EB * CAP * HD + (size_t)t * HD + c4);
    float4 r;
    r.x = (a.x * s0 + b.x * s1) * inv;
    r.y = (a.y * s0 + b.y * s1) * inv;
    r.z = (a.z * s0 + b.z * s1) * inv;
    r.w = (a.w * s0 + b.w * s1) * inv;
    *(float4*)(g_ctx + (size_t)t * HD + c4) = r;
}

// ================= stage 6a: out = (ctx @ Wff + bff) * w -> dense g_out (TF32) =========
__global__ void __launch_bounds__(256) outproj_kernel(const float* __restrict__ Wff,
                                                      const float* __restrict__ bff) {
    constexpr int AST = 72, BST = 136;
    extern __shared__ uint32_t dsm[];
    uint32_t* As = dsm;
    uint32_t* Bs = As + 128 * AST;
    int mt = blockIdx.x, nt = blockIdx.y, eb = blockIdx.z;
    int e = eb >> 1;
    int tid = threadIdx.x;
    int lane = tid & 31, w = tid >> 5;
    int lr = lane >> 2, lc = lane & 3;
    int wm = (w & 3) * 32, wn = (w >> 2) * 64;
    int m0 = mt * 128, n0 = nt * 128;

#pragma unroll
    for (int it = 0; it < 8; it++) {
        int idx = tid + it * 256;
        int row = idx >> 4, c4 = (idx & 15) << 2;
        cp_async16((uint32_t)__cvta_generic_to_shared(As + row * AST + c4),
                   g_ctx + ((size_t)eb * CAP + m0 + row) * HD + c4);
    }
#pragma unroll
    for (int it = 0; it < 8; it++) {
        int idx = tid + it * 256;
        int row = idx >> 5, c4 = (idx & 31) << 2;
        cp_async16((uint32_t)__cvta_generic_to_shared(Bs + row * BST + c4),
                   Wff + ((size_t)e * HD + row) * D + n0 + c4);
    }
    cp_commit();
    cp_wait0();
    __syncthreads();

    float acc[2][8][4];
#pragma unroll
    for (int mi = 0; mi < 2; mi++)
#pragma unroll
        for (int t8 = 0; t8 < 8; t8++)
#pragma unroll
            for (int r = 0; r < 4; r++) acc[mi][t8][r] = 0.f;

#pragma unroll
    for (int kk = 0; kk < 8; kk++) {
        uint32_t a[2][4];
#pragma unroll
        for (int mi = 0; mi < 2; mi++) {
            const uint32_t* ap = &As[(wm + mi * 16 + lr) * AST + kk * 8 + lc];
            a[mi][0] = ap[0]; a[mi][1] = ap[8 * AST];
            a[mi][2] = ap[4]; a[mi][3] = ap[8 * AST + 4];
        }
#pragma unroll
        for (int t8 = 0; t8 < 8; t8++) {
            uint32_t b0 = Bs[(kk * 8 + lc) * BST + wn + t8 * 8 + lr];
            uint32_t b1 = Bs[(kk * 8 + lc + 4) * BST + wn + t8 * 8 + lr];
#pragma unroll
            for (int mi = 0; mi < 2; mi++)
                mma_tf32(acc[mi][t8][0], acc[mi][t8][1], acc[mi][t8][2], acc[mi][t8][3],
                         a[mi][0], a[mi][1], a[mi][2], a[mi][3], b0, b1);
        }
    }

#pragma unroll
    for (int mi = 0; mi < 2; mi++) {
        int row0 = m0 + wm + mi * 16 + lr;
        int row1 = row0 + 8;
        float wv0 = g_w[eb * CAP + row0];
        float wv1 = g_w[eb * CAP + row1];
#pragma unroll
        for (int t8 = 0; t8 < 8; t8++) {
            int col = n0 + wn + t8 * 8 + 2 * lc;
            float2 bf = *(const float2*)(bff + col);
            *(float2*)(g_out + ((size_t)eb * CAP + row0) * D + col) =
                make_float2((acc[mi][t8][0] + bf.x) * wv0, (acc[mi][t8][1] + bf.y) * wv0);
            *(float2*)(g_out + ((size_t)eb * CAP + row1) * D + col) =
                make_float2((acc[mi][t8][2] + bf.x) * wv1, (acc[mi][t8][3] + bf.y) * wv1);
        }
    }
}

// ================= stage 6b: gather-combine + residual + LayerNorm =================
__global__ void ln_kernel(const float* __restrict__ x,
                          const float* __restrict__ gamma,
                          const float* __restrict__ beta,
                          float* __restrict__ out) {
    int token = blockIdx.x;
    int b = token >> 11;
    int tid = threadIdx.x;
    __shared__ int sh_base[E];
    __shared__ float red[8];
    if (tid < E) {
        int p = g_inv[tid * NTOK + token];
        sh_base[tid] = (p < 0) ? -1 : ((tid * B + b) * CAP + p);
    }
    __syncthreads();
    float4 c = make_float4(0.f, 0.f, 0.f, 0.f);
#pragma unroll
    for (int e = 0; e < E; e++) {
        int base = sh_base[e];
        if (base >= 0) {
            float4 t4 = *(const float4*)(g_out + (size_t)base * D + tid * 4);
            c.x += t4.x; c.y += t4.y; c.z += t4.z; c.w += t4.w;
        }
    }
    float4 x4 = *(const float4*)(x + (size_t)token * D + tid * 4);
    float h[4] = {x4.x + c.x, x4.y + c.y, x4.z + c.z, x4.w + c.w};
    float s = h[0] + h[1] + h[2] + h[3];
#pragma unroll
    for (int off = 16; off > 0; off >>= 1) s += __shfl_xor_sync(0xffffffffu, s, off);
    int warp = tid >> 5, lane = tid & 31;
    if (lane == 0) red[warp] = s;
    __syncthreads();
    float total = 0.f;
#pragma unroll
    for (int w = 0; w < 8; w++) total += red[w];
    __syncthreads();
    float mu = total * (1.0f / D);
    float ss = 0.f;
#pragma unroll
    for (int t = 0; t < 4; t++) {
        float dlt = h[t] - mu;
        ss += dlt * dlt;
    }
#pragma unroll
    for (int off = 16; off > 0; off >>= 1) ss += __shfl_xor_sync(0xffffffffu, ss, off);
    if (lane == 0) red[warp] = ss;
    __syncthreads();
    float vtot = 0.f;
#pragma unroll
    for (int w = 0; w < 8; w++) vtot += red[w];
    float var = vtot * (1.0f / D);
    float inv = rsqrtf(var + 1e-5f);
    float4 g4 = *(const float4*)(gamma + tid * 4);
    float4 be4 = *(const float4*)(beta + tid * 4);
    float4 o4;
    o4.x = (h[0] - mu) * inv * g4.x + be4.x;
    o4.y = (h[1] - mu) * inv * g4.y + be4.y;
    o4.z = (h[2] - mu) * inv * g4.z + be4.z;
    o4.w = (h[3] - mu) * inv * g4.w + be4.w;
    *(float4*)(out + (size_t)token * D + tid * 4) = o4;
}

// ================= launch =================
extern "C" void kernel_launch(void* const* d_in, const int* in_sizes, int n_in,
                              void* d_out, int out_size) {
    const float* x     = (const float*)d_in[0];
    const float* wg    = (const float*)d_in[1];
    const float* bg    = (const float*)d_in[2];
    const float* Wq    = (const float*)d_in[3];
    const float* Wkv   = (const float*)d_in[4];
    const float* Wff   = (const float*)d_in[5];
    const float* bff   = (const float*)d_in[6];
    const float* gamma = (const float*)d_in[7];
    const float* beta  = (const float*)d_in[8];
    float* out = (float*)d_out;

    (void)in_sizes; (void)n_in; (void)out_size;

    gate_kernel<<<NTOK, 256>>>(x, wg, bg);
    route_kernel<<<(S * E + 255) / 256, 256>>>();
    mask_kernel<<<dim3(EB, 8), 256>>>();
    select_kernel<<<EB, 256>>>();

    int proj_smem = 2 * (64 * 36 + 32 * 200) * (int)sizeof(uint32_t);  // 69,632 B
    cudaFuncSetAttribute(proj_kernel, cudaFuncAttributeMaxDynamicSharedMemorySize, proj_smem);
    proj_kernel<<<dim3(CAP / 64, EB), 256, proj_smem>>>(x, Wq, Wkv);

    rope_kernel<<<(EB * CAP * 32 + 255) / 256, 256>>>();

    int attn_smem = 384 * 72 * (int)sizeof(uint32_t);   // 110,592 B
    cudaFuncSetAttribute(attn_kernel, cudaFuncAttributeMaxDynamicSharedMemorySize, attn_smem);
    attn_kernel<<<dim3(CAP / 128, EB, 2), 256, attn_smem>>>();

    combine_kernel<<<(EB * CAP * 16 + 255) / 256, 256>>>();

    int op_smem = (128 * 72 + 64 * 136) * (int)sizeof(uint32_t);  // 71,680 B
    cudaFuncSetAttribute(outproj_kernel, cudaFuncAttributeMaxDynamicSharedMemorySize, op_smem);
    outproj_kernel<<<dim3(CAP / 128, D / 128, EB), 256, op_smem>>>(Wff, bff);

    ln_kernel<<<NTOK, 256>>>(x, gamma, beta, out);
}

// round 8
// speedup vs baseline: 3.3832x; 1.2858x over previous
#include <cuda_runtime.h>
#include <cuda_bf16.h>
#include <math.h>
#include <stdint.h>

// ---------------- problem constants ----------------
namespace {
constexpr int B = 2, S = 2048, D = 1024, E = 16, HD = 64, CAP = 1280, TOPK = 8;
constexpr float EPS = 1e-6f;
constexpr int EB = E * B;    // 32
constexpr int NTOK = B * S;  // 4096
}

// ---------------- scratch (device globals; no allocation allowed) ----------------
__device__ float g_route[NTOK * E];
__device__ unsigned char g_mask[EB * S];
__device__ int   g_seq[EB * CAP];
__device__ float g_w[EB * CAP];
__device__ int   g_inv[E * NTOK];
__device__ float g_q[EB * CAP * HD];
__device__ float g_k[EB * CAP * HD];
__device__ float g_v[EB * CAP * HD];
__device__ float g_ctx[EB * CAP * HD];
__device__ float g_opart[2 * EB * CAP * HD];   // unnormalized partial O per split
__device__ float g_pm[2 * EB * CAP];           // partial rowmax
__device__ float g_pl[2 * EB * CAP];           // partial rowsum
__device__ __nv_bfloat16 g_out[(size_t)EB * CAP * D];  // per-expert weighted outputs (84MB)

// ---------------- helpers ----------------
__device__ __forceinline__ void mma_tf32(float& c0, float& c1, float& c2, float& c3,
                                         uint32_t a0, uint32_t a1, uint32_t a2, uint32_t a3,
                                         uint32_t b0, uint32_t b1) {
    asm volatile(
        "mma.sync.aligned.m16n8k8.row.col.f32.tf32.tf32.f32 "
        "{%0,%1,%2,%3}, {%4,%5,%6,%7}, {%8,%9}, {%0,%1,%2,%3};\n"
        : "+f"(c0), "+f"(c1), "+f"(c2), "+f"(c3)
        : "r"(a0), "r"(a1), "r"(a2), "r"(a3), "r"(b0), "r"(b1));
}
__device__ __forceinline__ void cp_async16(uint32_t saddr, const void* g) {
    asm volatile("cp.async.ca.shared.global [%0], [%1], 16;" :: "r"(saddr), "l"(g));
}
__device__ __forceinline__ void cp_commit() { asm volatile("cp.async.commit_group;"); }
__device__ __forceinline__ void cp_wait0()  { asm volatile("cp.async.wait_group 0;"); }
__device__ __forceinline__ void cp_wait1()  { asm volatile("cp.async.wait_group 1;"); }

// ================= stage 1: gating (warp-per-token) =================
// grid NTOK/8 = 512 blocks, 256 threads = 8 warps; lane l: expert l&15, half l>>4
__global__ void __launch_bounds__(256) gate_kernel(const float* __restrict__ x,
                                                   const float* __restrict__ wg,
                                                   const float* __restrict__ bg) {
    int warp = threadIdx.x >> 5;
    int lane = threadIdx.x & 31;
    int token = blockIdx.x * 8 + warp;
    int e = lane & 15, h = lane >> 4;
    const float* xr = x + (size_t)token * D + h * 512;
    const float* wr = wg + (size_t)(h * 512) * E + e;
    float acc = 0.f;
#pragma unroll 8
    for (int d = 0; d < 512; d++)
        acc += xr[d] * wr[(size_t)d * E];
    acc += __shfl_xor_sync(0xffffffffu, acc, 16);   // merge halves
    float g = acc + bg[e];
    float mx = g;
#pragma unroll
    for (int off = 8; off; off >>= 1)
        mx = fmaxf(mx, __shfl_xor_sync(0xffffffffu, mx, off));
    float ex = expf(g - mx);
    float sum = ex;
#pragma unroll
    for (int off = 8; off; off >>= 1)
        sum += __shfl_xor_sync(0xffffffffu, sum, off);
    float p = ex / sum;
    // rank with jax top_k tie semantics (lower index wins)
    int r = 0;
    int basel = lane & 16;
#pragma unroll
    for (int j = 0; j < 16; j++) {
        float pj = __shfl_sync(0xffffffffu, p, basel + j);
        r += (pj > p) || (pj == p && j < e);
    }
    if (lane < 16)
        g_route[(size_t)token * E + e] = (r < TOPK) ? p : 0.f;
}

// ================= stage 2: route normalize =================
__global__ void route_kernel() {
    int idx = blockIdx.x * blockDim.x + threadIdx.x;
    if (idx >= S * E) return;
    int s = idx / E, e = idx % E;
    float m0 = g_route[(size_t)s * E + e];
    float m1 = g_route[(size_t)(S + s) * E + e];
    float den = m0 + m1 + EPS;
    g_route[(size_t)s * E + e]       = m0 / den * 2.0f;
    g_route[(size_t)(S + s) * E + e] = m1 / den * 2.0f;
}

// ================= stage 3a: rank mask =================
__global__ void mask_kernel() {
    int eb = blockIdx.x;
    int e = eb >> 1, b = eb & 1;
    __shared__ float sv[S];
    int tid = threadIdx.x;
    for (int s = tid; s < S; s += 256)
        sv[s] = g_route[(size_t)(b * S + s) * E + e];
    __syncthreads();
    int i = blockIdx.y * 256 + tid;
    float vi = sv[i];
    int c = 0;
#pragma unroll 4
    for (int j = 0; j < S; j++) {
        float vj = sv[j];
        c += (vj > vi) || (vj == vi && j < i);
    }
    g_mask[eb * S + i] = (c < CAP) ? 1 : 0;
}

// ================= stage 3b: compaction =================
__global__ void select_kernel() {
    int eb = blockIdx.x;
    int e = eb >> 1, b = eb & 1;
    __shared__ unsigned char sm[S];
    __shared__ int cnt[256];
    int t = threadIdx.x;
    for (int s = t; s < S; s += 256)
        sm[s] = g_mask[eb * S + s];
    __syncthreads();
    int local = 0;
#pragma unroll
    for (int k = 0; k < 8; k++) local += sm[t * 8 + k];
    cnt[t] = local;
    __syncthreads();
    if (t == 0) {
        int run = 0;
        for (int i = 0; i < 256; i++) { int c = cnt[i]; cnt[i] = run; run += c; }
    }
    __syncthreads();
    int pos = cnt[t];
#pragma unroll
    for (int k = 0; k < 8; k++) {
        int s = t * 8 + k;
        if (sm[s]) {
            g_seq[eb * CAP + pos] = s;
            g_w[eb * CAP + pos] = g_route[(size_t)(b * S + s) * E + e];
            g_inv[e * NTOK + b * S + s] = pos;
            pos++;
        } else {
            g_inv[e * NTOK + b * S + s] = -1;
        }
    }
}

// ================= stage 4a: fused Q/K/V projection, TF32 + cp.async, BK=32 =========
__global__ void __launch_bounds__(256) proj_kernel(const float* __restrict__ x,
                                                   const float* __restrict__ Wq,
                                                   const float* __restrict__ Wkv) {
    constexpr int AST = 36, BST = 200;
    constexpr int AW = 64 * AST;
    constexpr int BW = 32 * BST;
    extern __shared__ uint32_t dsm[];
    uint32_t* As = dsm;
    uint32_t* Bs = dsm + 2 * AW;
    int mt = blockIdx.x, eb = blockIdx.y;
    int e = eb >> 1, b = eb & 1;
    int tid = threadIdx.x;
    int lane = tid & 31, w = tid >> 5;
    int lr = lane >> 2, lc = lane & 3;
    int wm = (w & 1) * 32;
    int wn = (w >> 1) * 48;
    int m0 = mt * 64;

    int r0 = tid >> 3;
    int koff = (tid & 7) << 2;
    int seq0 = g_seq[eb * CAP + m0 + r0];
    int seq1 = g_seq[eb * CAP + m0 + r0 + 32];
    const float* arow0 = x + (size_t)(b * S + seq0) * D + koff;
    const float* arow1 = x + (size_t)(b * S + seq1) * D + koff;
    uint32_t as0 = r0 * AST + koff;
    uint32_t as1 = (r0 + 32) * AST + koff;

    const float* wq  = Wq  + (size_t)e * D * HD;
    const float* wkv = Wkv + (size_t)e * D * (2 * HD);

    const float* bptr[6];
    int bstep[6];
    uint32_t bsoff[6];
#pragma unroll
    for (int it = 0; it < 6; it++) {
        int f = tid + it * 256;
        int bk = f / 48, bj = f % 48;
        if (bj < 16) { bptr[it] = wq  + (size_t)bk * HD       + bj * 4;        bstep[it] = HD; }
        else         { bptr[it] = wkv + (size_t)bk * (2 * HD) + (bj - 16) * 4; bstep[it] = 2 * HD; }
        bsoff[it] = bk * BST + bj * 4;
    }

    float acc[2][6][4];
#pragma unroll
    for (int i = 0; i < 2; i++)
#pragma unroll
        for (int j = 0; j < 6; j++)
#pragma unroll
            for (int r = 0; r < 4; r++) acc[i][j][r] = 0.f;

    cp_async16((uint32_t)__cvta_generic_to_shared(As + as0), arow0);
    cp_async16((uint32_t)__cvta_generic_to_shared(As + as1), arow1);
#pragma unroll
    for (int it = 0; it < 6; it++)
        cp_async16((uint32_t)__cvta_generic_to_shared(Bs + bsoff[it]), bptr[it]);
    cp_commit();

    for (int kt = 0; kt < 32; kt++) {
        cp_wait0();
        __syncthreads();
        if (kt + 1 < 32) {
            int s = (kt + 1) & 1;
            int k0 = (kt + 1) * 32;
            cp_async16((uint32_t)__cvta_generic_to_shared(As + s * AW + as0), arow0 + k0);
            cp_async16((uint32_t)__cvta_generic_to_shared(As + s * AW + as1), arow1 + k0);
#pragma unroll
            for (int it = 0; it < 6; it++)
                cp_async16((uint32_t)__cvta_generic_to_shared(Bs + s * BW + bsoff[it]),
                           bptr[it] + (size_t)k0 * bstep[it]);
            cp_commit();
        }
        int cs = kt & 1;
        const uint32_t* Acur = As + cs * AW;
        const uint32_t* Bcur = Bs + cs * BW;
#pragma unroll
        for (int kb2 = 0; kb2 < 32; kb2 += 8) {
            uint32_t a[2][4], bb[6][2];
#pragma unroll
            for (int mb = 0; mb < 2; mb++) {
                const uint32_t* ap = &Acur[(wm + mb * 16 + lr) * AST + kb2 + lc];
                a[mb][0] = ap[0];
                a[mb][1] = ap[8 * AST];
                a[mb][2] = ap[4];
                a[mb][3] = ap[8 * AST + 4];
            }
#pragma unroll
            for (int nb = 0; nb < 6; nb++) {
                const uint32_t* bp = &Bcur[(kb2 + lc) * BST + wn + lr + nb * 8];
                bb[nb][0] = bp[0];
                bb[nb][1] = bp[4 * BST];
            }
#pragma unroll
            for (int mb = 0; mb < 2; mb++)
#pragma unroll
                for (int nb = 0; nb < 6; nb++)
                    mma_tf32(acc[mb][nb][0], acc[mb][nb][1], acc[mb][nb][2], acc[mb][nb][3],
                             a[mb][0], a[mb][1], a[mb][2], a[mb][3],
                             bb[nb][0], bb[nb][1]);
        }
    }

#pragma unroll
    for (int nb = 0; nb < 6; nb++) {
        int colg = wn + nb * 8 + 2 * lc;
        float* dst;
        int col;
        if (colg < 64)       { dst = g_q; col = colg; }
        else if (colg < 128) { dst = g_k; col = colg - 64; }
        else                 { dst = g_v; col = colg - 128; }
#pragma unroll
        for (int mb = 0; mb < 2; mb++) {
            int rowg = m0 + wm + mb * 16 + lr;
            size_t base0 = ((size_t)eb * CAP + rowg) * HD + col;
            size_t base1 = ((size_t)eb * CAP + rowg + 8) * HD + col;
            *(float2*)(dst + base0) = make_float2(acc[mb][nb][0], acc[mb][nb][1]);
            *(float2*)(dst + base1) = make_float2(acc[mb][nb][2], acc[mb][nb][3]);
        }
    }
}

// ================= stage 4b: RoPE on q and k =================
__global__ void rope_kernel() {
    int idx = blockIdx.x * blockDim.x + threadIdx.x;
    if (idx >= EB * CAP * 32) return;
    int h = idx & 31;
    int t = idx >> 5;
    int pos = g_seq[t];
    float invf = exp2f(-(float)h * 0.4152410118609203f);
    float ang = (float)pos * invf;
    float c, s;
    sincosf(ang, &s, &c);
    float* q = g_q + (size_t)t * HD;
    float* k = g_k + (size_t)t * HD;
    float q1 = q[h], q2 = q[h + 32];
    q[h]      = q1 * c - q2 * s;
    q[h + 32] = q2 * c + q1 * s;
    float k1 = k[h], k2 = k[h + 32];
    k[h]      = k1 * c - k2 * s;
    k[h + 32] = k2 * c + k1 * s;
}

// ================= stage 5: split-KV causal flash attention, TF32 =================
__global__ void __launch_bounds__(256, 2) attn_kernel() {
    constexpr int ST = 72;
    extern __shared__ uint32_t dsm[];
    uint32_t* Qs = dsm;
    uint32_t* Ks = Qs + 128 * ST;
    uint32_t* Vs = Ks + 64 * ST;
    uint32_t* Ps = Vs + 64 * ST;
    int mt = 9 - blockIdx.x;
    int eb = blockIdx.y;
    int split = blockIdx.z;
    int m0 = mt * 128;
    const float* qptr = g_q + (size_t)eb * CAP * HD;
    const float* kptr = g_k + (size_t)eb * CAP * HD;
    const float* vptr = g_v + (size_t)eb * CAP * HD;
    int tid = threadIdx.x;
    int lane = tid & 31, w = tid >> 5;
    int lr = lane >> 2, lc = lane & 3;
    int wrow = 16 * w;

#pragma unroll
    for (int it = 0; it < 8; it++) {
        int idx = tid + it * 256;
        int row = idx >> 4, c4 = (idx & 15) << 2;
        float4 v4 = *(const float4*)(qptr + (size_t)(m0 + row) * HD + c4);
        uint32_t* d = &Qs[row * ST + c4];
        d[0] = __float_as_uint(v4.x); d[1] = __float_as_uint(v4.y);
        d[2] = __float_as_uint(v4.z); d[3] = __float_as_uint(v4.w);
    }

    float o[8][4];
#pragma unroll
    for (int t8 = 0; t8 < 8; t8++)
#pragma unroll
        for (int r = 0; r < 4; r++) o[t8][r] = 0.f;
    float mrow0 = -3.402823466e38f, mrow1 = -3.402823466e38f;
    float lsum0 = 0.f, lsum1 = 0.f;

    int half = mt + 1;
    int ntStart = split * half;
    int ntEnd = ntStart + half;
    for (int nt = ntStart; nt < ntEnd; nt++) {
        int n0 = nt * 64;
        __syncthreads();
#pragma unroll
        for (int it = 0; it < 4; it++) {
            int idx = tid + it * 256;
            int row = idx >> 4, c4 = (idx & 15) << 2;
            cp_async16((uint32_t)__cvta_generic_to_shared(Ks + row * ST + c4),
                       kptr + (size_t)(n0 + row) * HD + c4);
        }
        cp_commit();
#pragma unroll
        for (int it = 0; it < 4; it++) {
            int idx = tid + it * 256;
            int row = idx >> 4, c4 = (idx & 15) << 2;
            cp_async16((uint32_t)__cvta_generic_to_shared(Vs + row * ST + c4),
                       vptr + (size_t)(n0 + row) * HD + c4);
        }
        cp_commit();
        cp_wait1();
        __syncthreads();

        float sacc[8][4];
#pragma unroll
        for (int t8 = 0; t8 < 8; t8++)
#pragma unroll
            for (int r = 0; r < 4; r++) sacc[t8][r] = 0.f;
#pragma unroll
        for (int kk = 0; kk < 8; kk++) {
            const uint32_t* ap = &Qs[(wrow + lr) * ST + kk * 8 + lc];
            uint32_t a0 = ap[0], a1 = ap[8 * ST], a2 = ap[4], a3 = ap[8 * ST + 4];
#pragma unroll
            for (int t8 = 0; t8 < 8; t8++) {
                const uint32_t* bp = &Ks[(t8 * 8 + lr) * ST + kk * 8 + lc];
                mma_tf32(sacc[t8][0], sacc[t8][1], sacc[t8][2], sacc[t8][3],
                         a0, a1, a2, a3, bp[0], bp[4]);
            }
        }

        bool maskT = (nt >= 2 * mt);
#pragma unroll
        for (int t8 = 0; t8 < 8; t8++) {
            int cbase = n0 + t8 * 8 + 2 * lc;
#pragma unroll
            for (int r = 0; r < 4; r++) {
                float v = sacc[t8][r] * 0.125f;
                if (maskT) {
                    int row = m0 + wrow + lr + ((r >= 2) ? 8 : 0);
                    int col = cbase + (r & 1);
                    if (col > row) v = -3.402823466e38f;
                }
                sacc[t8][r] = v;
            }
        }

        float mx0 = -3.402823466e38f, mx1 = -3.402823466e38f;
#pragma unroll
        for (int t8 = 0; t8 < 8; t8++) {
            mx0 = fmaxf(mx0, fmaxf(sacc[t8][0], sacc[t8][1]));
            mx1 = fmaxf(mx1, fmaxf(sacc[t8][2], sacc[t8][3]));
        }
        mx0 = fmaxf(mx0, __shfl_xor_sync(0xffffffffu, mx0, 1));
        mx0 = fmaxf(mx0, __shfl_xor_sync(0xffffffffu, mx0, 2));
        mx1 = fmaxf(mx1, __shfl_xor_sync(0xffffffffu, mx1, 1));
        mx1 = fmaxf(mx1, __shfl_xor_sync(0xffffffffu, mx1, 2));
        float nm0 = fmaxf(mrow0, mx0), nm1 = fmaxf(mrow1, mx1);
        float corr0 = __expf(mrow0 - nm0), corr1 = __expf(mrow1 - nm1);
        float rs0 = 0.f, rs1 = 0.f;
#pragma unroll
        for (int t8 = 0; t8 < 8; t8++) {
            float p0 = __expf(sacc[t8][0] - nm0);
            float p1 = __expf(sacc[t8][1] - nm0);
            float p2 = __expf(sacc[t8][2] - nm1);
            float p3 = __expf(sacc[t8][3] - nm1);
            rs0 += p0 + p1; rs1 += p2 + p3;
            int b0 = (wrow + lr) * ST + t8 * 8 + 2 * lc;
            Ps[b0]     = __float_as_uint(p0);
            Ps[b0 + 1] = __float_as_uint(p1);
            int b1 = (wrow + lr + 8) * ST + t8 * 8 + 2 * lc;
            Ps[b1]     = __float_as_uint(p2);
            Ps[b1 + 1] = __float_as_uint(p3);
        }
        rs0 += __shfl_xor_sync(0xffffffffu, rs0, 1);
        rs0 += __shfl_xor_sync(0xffffffffu, rs0, 2);
        rs1 += __shfl_xor_sync(0xffffffffu, rs1, 1);
        rs1 += __shfl_xor_sync(0xffffffffu, rs1, 2);
        lsum0 = lsum0 * corr0 + rs0;
        lsum1 = lsum1 * corr1 + rs1;
        mrow0 = nm0; mrow1 = nm1;
#pragma unroll
        for (int t8 = 0; t8 < 8; t8++) {
            o[t8][0] *= corr0; o[t8][1] *= corr0;
            o[t8][2] *= corr1; o[t8][3] *= corr1;
        }

        cp_wait0();
        __syncthreads();

#pragma unroll
        for (int kk = 0; kk < 8; kk++) {
            const uint32_t* ap = &Ps[(wrow + lr) * ST + kk * 8 + lc];
            uint32_t a0 = ap[0], a1 = ap[8 * ST], a2 = ap[4], a3 = ap[8 * ST + 4];
#pragma unroll
            for (int t8 = 0; t8 < 8; t8++) {
                uint32_t b0 = Vs[(kk * 8 + lc) * ST + t8 * 8 + lr];
                uint32_t b1 = Vs[(kk * 8 + lc + 4) * ST + t8 * 8 + lr];
                mma_tf32(o[t8][0], o[t8][1], o[t8][2], o[t8][3],
                         a0, a1, a2, a3, b0, b1);
            }
        }
    }

    int row0 = m0 + wrow + lr, row1 = row0 + 8;
    float* op = g_opart + (size_t)split * EB * CAP * HD;
#pragma unroll
    for (int t8 = 0; t8 < 8; t8++) {
        int col = t8 * 8 + 2 * lc;
        *(float2*)(op + ((size_t)eb * CAP + row0) * HD + col) = make_float2(o[t8][0], o[t8][1]);
        *(float2*)(op + ((size_t)eb * CAP + row1) * HD + col) = make_float2(o[t8][2], o[t8][3]);
    }
    if (lc == 0) {
        int base = split * EB * CAP + eb * CAP;
        g_pm[base + row0] = mrow0;
        g_pl[base + row0] = lsum0;
        g_pm[base + row1] = mrow1;
        g_pl[base + row1] = lsum1;
    }
}

// ================= stage 5b: combine splits =================
__global__ void combine_kernel() {
    int idx = blockIdx.x * blockDim.x + threadIdx.x;
    if (idx >= EB * CAP * 16) return;
    int t = idx >> 4;
    int c4 = (idx & 15) << 2;
    float m0 = g_pm[t], m1 = g_pm[EB * CAP + t];
    float l0 = g_pl[t], l1 = g_pl[EB * CAP + t];
    float M = fmaxf(m0, m1);
    float s0 = __expf(m0 - M), s1 = __expf(m1 - M);
    float inv = 1.f / (l0 * s0 + l1 * s1);
    const float4 a = *(const float4*)(g_opart + (size_t)t * HD + c4);
    const float4 b = *(const float4*)(g_opart + (size_t)EB * CAP * HD + (size_t)t * HD + c4);
    float4 r;
    r.x = (a.x * s0 + b.x * s1) * inv;
    r.y = (a.y * s0 + b.y * s1) * inv;
    r.z = (a.z * s0 + b.z * s1) * inv;
    r.w = (a.w * s0 + b.w * s1) * inv;
    *(float4*)(g_ctx + (size_t)t * HD + c4) = r;
}

// ================= stage 6a: out = (ctx @ Wff + bff) * w -> bf16 g_out =========
__global__ void __launch_bounds__(256) outproj_kernel(const float* __restrict__ Wff,
                                                      const float* __restrict__ bff) {
    constexpr int AST = 72, BST = 136;
    extern __shared__ uint32_t dsm[];
    uint32_t* As = dsm;
    uint32_t* Bs = As + 128 * AST;
    int mt = blockIdx.x, nt = blockIdx.y, eb = blockIdx.z;
    int e = eb >> 1;
    int tid = threadIdx.x;
    int lane = tid & 31, w = tid >> 5;
    int lr = lane >> 2, lc = lane & 3;
    int wm = (w & 3) * 32, wn = (w >> 2) * 64;
    int m0 = mt * 128, n0 = nt * 128;

#pragma unroll
    for (int it = 0; it < 8; it++) {
        int idx = tid + it * 256;
        int row = idx >> 4, c4 = (idx & 15) << 2;
        cp_async16((uint32_t)__cvta_generic_to_shared(As + row * AST + c4),
                   g_ctx + ((size_t)eb * CAP + m0 + row) * HD + c4);
    }
#pragma unroll
    for (int it = 0; it < 8; it++) {
        int idx = tid + it * 256;
        int row = idx >> 5, c4 = (idx & 31) << 2;
        cp_async16((uint32_t)__cvta_generic_to_shared(Bs + row * BST + c4),
                   Wff + ((size_t)e * HD + row) * D + n0 + c4);
    }
    cp_commit();
    cp_wait0();
    __syncthreads();

    float acc[2][8][4];
#pragma unroll
    for (int mi = 0; mi < 2; mi++)
#pragma unroll
        for (int t8 = 0; t8 < 8; t8++)
#pragma unroll
            for (int r = 0; r < 4; r++) acc[mi][t8][r] = 0.f;

#pragma unroll
    for (int kk = 0; kk < 8; kk++) {
        uint32_t a[2][4];
#pragma unroll
        for (int mi = 0; mi < 2; mi++) {
            const uint32_t* ap = &As[(wm + mi * 16 + lr) * AST + kk * 8 + lc];
            a[mi][0] = ap[0]; a[mi][1] = ap[8 * AST];
            a[mi][2] = ap[4]; a[mi][3] = ap[8 * AST + 4];
        }
#pragma unroll
        for (int t8 = 0; t8 < 8; t8++) {
            uint32_t b0 = Bs[(kk * 8 + lc) * BST + wn + t8 * 8 + lr];
            uint32_t b1 = Bs[(kk * 8 + lc + 4) * BST + wn + t8 * 8 + lr];
#pragma unroll
            for (int mi = 0; mi < 2; mi++)
                mma_tf32(acc[mi][t8][0], acc[mi][t8][1], acc[mi][t8][2], acc[mi][t8][3],
                         a[mi][0], a[mi][1], a[mi][2], a[mi][3], b0, b1);
        }
    }

#pragma unroll
    for (int mi = 0; mi < 2; mi++) {
        int row0 = m0 + wm + mi * 16 + lr;
        int row1 = row0 + 8;
        float wv0 = g_w[eb * CAP + row0];
        float wv1 = g_w[eb * CAP + row1];
#pragma unroll
        for (int t8 = 0; t8 < 8; t8++) {
            int col = n0 + wn + t8 * 8 + 2 * lc;
            float2 bf = *(const float2*)(bff + col);
            if (wv0 != 0.f) {
                __nv_bfloat162 v;
                v.x = __float2bfloat16((acc[mi][t8][0] + bf.x) * wv0);
                v.y = __float2bfloat16((acc[mi][t8][1] + bf.y) * wv0);
                *(__nv_bfloat162*)(g_out + ((size_t)eb * CAP + row0) * D + col) = v;
            }
            if (wv1 != 0.f) {
                __nv_bfloat162 v;
                v.x = __float2bfloat16((acc[mi][t8][2] + bf.x) * wv1);
                v.y = __float2bfloat16((acc[mi][t8][3] + bf.y) * wv1);
                *(__nv_bfloat162*)(g_out + ((size_t)eb * CAP + row1) * D + col) = v;
            }
        }
    }
}

// ================= stage 6b: gather-combine + residual + LayerNorm =================
__global__ void ln_kernel(const float* __restrict__ x,
                          const float* __restrict__ gamma,
                          const float* __restrict__ beta,
                          float* __restrict__ out) {
    int token = blockIdx.x;
    int b = token >> 11;
    int tid = threadIdx.x;
    __shared__ int sh_base[E];
    __shared__ float red[8];
    if (tid < E) {
        int p = g_inv[tid * NTOK + token];
        int base = -1;
        if (p >= 0) {
            int idx = (tid * B + b) * CAP + p;
            if (g_w[idx] != 0.f) base = idx;
        }
        sh_base[tid] = base;
    }
    __syncthreads();
    float4 c = make_float4(0.f, 0.f, 0.f, 0.f);
#pragma unroll
    for (int e = 0; e < E; e++) {
        int base = sh_base[e];
        if (base >= 0) {
            uint2 u = *(const uint2*)(g_out + (size_t)base * D + tid * 4);
            __nv_bfloat162 p0 = *reinterpret_cast<__nv_bfloat162*>(&u.x);
            __nv_bfloat162 p1 = *reinterpret_cast<__nv_bfloat162*>(&u.y);
            c.x += __bfloat162float(p0.x); c.y += __bfloat162float(p0.y);
            c.z += __bfloat162float(p1.x); c.w += __bfloat162float(p1.y);
        }
    }
    float4 x4 = *(const float4*)(x + (size_t)token * D + tid * 4);
    float h[4] = {x4.x + c.x, x4.y + c.y, x4.z + c.z, x4.w + c.w};
    float s = h[0] + h[1] + h[2] + h[3];
#pragma unroll
    for (int off = 16; off > 0; off >>= 1) s += __shfl_xor_sync(0xffffffffu, s, off);
    int warp = tid >> 5, lane = tid & 31;
    if (lane == 0) red[warp] = s;
    __syncthreads();
    float total = 0.f;
#pragma unroll
    for (int w = 0; w < 8; w++) total += red[w];
    __syncthreads();
    float mu = total * (1.0f / D);
    float ss = 0.f;
#pragma unroll
    for (int t = 0; t < 4; t++) {
        float dlt = h[t] - mu;
        ss += dlt * dlt;
    }
#pragma unroll
    for (int off = 16; off > 0; off >>= 1) ss += __shfl_xor_sync(0xffffffffu, ss, off);
    if (lane == 0) red[warp] = ss;
    __syncthreads();
    float vtot = 0.f;
#pragma unroll
    for (int w = 0; w < 8; w++) vtot += red[w];
    float var = vtot * (1.0f / D);
    float inv = rsqrtf(var + 1e-5f);
    float4 g4 = *(const float4*)(gamma + tid * 4);
    float4 be4 = *(const float4*)(beta + tid * 4);
    float4 o4;
    o4.x = (h[0] - mu) * inv * g4.x + be4.x;
    o4.y = (h[1] - mu) * inv * g4.y + be4.y;
    o4.z = (h[2] - mu) * inv * g4.z + be4.z;
    o4.w = (h[3] - mu) * inv * g4.w + be4.w;
    *(float4*)(out + (size_t)token * D + tid * 4) = o4;
}

// ================= launch =================
extern "C" void kernel_launch(void* const* d_in, const int* in_sizes, int n_in,
                              void* d_out, int out_size) {
    const float* x     = (const float*)d_in[0];
    const float* wg    = (const float*)d_in[1];
    const float* bg    = (const float*)d_in[2];
    const float* Wq    = (const float*)d_in[3];
    const float* Wkv   = (const float*)d_in[4];
    const float* Wff   = (const float*)d_in[5];
    const float* bff   = (const float*)d_in[6];
    const float* gamma = (const float*)d_in[7];
    const float* beta  = (const float*)d_in[8];
    float* out = (float*)d_out;

    (void)in_sizes; (void)n_in; (void)out_size;

    gate_kernel<<<NTOK / 8, 256>>>(x, wg, bg);
    route_kernel<<<(S * E + 255) / 256, 256>>>();
    mask_kernel<<<dim3(EB, 8), 256>>>();
    select_kernel<<<EB, 256>>>();

    int proj_smem = 2 * (64 * 36 + 32 * 200) * (int)sizeof(uint32_t);  // 69,632 B
    cudaFuncSetAttribute(proj_kernel, cudaFuncAttributeMaxDynamicSharedMemorySize, proj_smem);
    proj_kernel<<<dim3(CAP / 64, EB), 256, proj_smem>>>(x, Wq, Wkv);

    rope_kernel<<<(EB * CAP * 32 + 255) / 256, 256>>>();

    int attn_smem = 384 * 72 * (int)sizeof(uint32_t);   // 110,592 B
    cudaFuncSetAttribute(attn_kernel, cudaFuncAttributeMaxDynamicSharedMemorySize, attn_smem);
    attn_kernel<<<dim3(CAP / 128, EB, 2), 256, attn_smem>>>();

    combine_kernel<<<(EB * CAP * 16 + 255) / 256, 256>>>();

    int op_smem = (128 * 72 + 64 * 136) * (int)sizeof(uint32_t);  // 71,680 B
    cudaFuncSetAttribute(outproj_kernel, cudaFuncAttributeMaxDynamicSharedMemorySize, op_smem);
    outproj_kernel<<<dim3(CAP / 128, D / 128, EB), 256, op_smem>>>(Wff, bff);

    ln_kernel<<<NTOK, 256>>>(x, gamma, beta, out);
}

// round 9
// speedup vs baseline: 3.8895x; 1.1497x over previous
#include <cuda_runtime.h>
#include <cuda_bf16.h>
#include <math.h>
#include <stdint.h>

// ---------------- problem constants ----------------
namespace {
constexpr int B = 2, S = 2048, D = 1024, E = 16, HD = 64, CAP = 1280, TOPK = 8;
constexpr float EPS = 1e-6f;
constexpr int EB = E * B;    // 32
constexpr int NTOK = B * S;  // 4096
}

// ---------------- scratch (device globals; no allocation allowed) ----------------
__device__ float g_route[NTOK * E];
__device__ unsigned char g_mask[EB * S];
__device__ int   g_seq[EB * CAP];
__device__ float g_w[EB * CAP];
__device__ int   g_inv[E * NTOK];
__device__ uint32_t g_qh[EB * CAP * 32];        // q bf16x2 pairs along HD
__device__ uint32_t g_kh[EB * CAP * 32];        // k bf16x2 pairs along HD
__device__ __nv_bfloat16 g_vt[(size_t)EB * HD * CAP];  // V transposed [eb][col][row]
__device__ float g_ctx[EB * CAP * HD];
__device__ float g_opart[2 * EB * CAP * HD];
__device__ float g_pm[2 * EB * CAP];
__device__ float g_pl[2 * EB * CAP];
__device__ __nv_bfloat16 g_out[(size_t)EB * CAP * D];

// ---------------- helpers ----------------
__device__ __forceinline__ void mma_tf32(float& c0, float& c1, float& c2, float& c3,
                                         uint32_t a0, uint32_t a1, uint32_t a2, uint32_t a3,
                                         uint32_t b0, uint32_t b1) {
    asm volatile(
        "mma.sync.aligned.m16n8k8.row.col.f32.tf32.tf32.f32 "
        "{%0,%1,%2,%3}, {%4,%5,%6,%7}, {%8,%9}, {%0,%1,%2,%3};\n"
        : "+f"(c0), "+f"(c1), "+f"(c2), "+f"(c3)
        : "r"(a0), "r"(a1), "r"(a2), "r"(a3), "r"(b0), "r"(b1));
}
__device__ __forceinline__ void mma_bf16(float& c0, float& c1, float& c2, float& c3,
                                         uint32_t a0, uint32_t a1, uint32_t a2, uint32_t a3,
                                         uint32_t b0, uint32_t b1) {
    asm volatile(
        "mma.sync.aligned.m16n8k16.row.col.f32.bf16.bf16.f32 "
        "{%0,%1,%2,%3}, {%4,%5,%6,%7}, {%8,%9}, {%0,%1,%2,%3};\n"
        : "+f"(c0), "+f"(c1), "+f"(c2), "+f"(c3)
        : "r"(a0), "r"(a1), "r"(a2), "r"(a3), "r"(b0), "r"(b1));
}
__device__ __forceinline__ uint32_t packbf(float a, float b) {
    __nv_bfloat162 t = __floats2bfloat162_rn(a, b);
    return *reinterpret_cast<uint32_t*>(&t);
}
__device__ __forceinline__ void cp_async16(uint32_t saddr, const void* g) {
    asm volatile("cp.async.ca.shared.global [%0], [%1], 16;" :: "r"(saddr), "l"(g));
}
__device__ __forceinline__ void cp_commit() { asm volatile("cp.async.commit_group;"); }
__device__ __forceinline__ void cp_wait0()  { asm volatile("cp.async.wait_group 0;"); }
__device__ __forceinline__ void cp_wait1()  { asm volatile("cp.async.wait_group 1;"); }

// ================= stage 1: gating (warp-per-token) =================
__global__ void __launch_bounds__(256) gate_kernel(const float* __restrict__ x,
                                                   const float* __restrict__ wg,
                                                   const float* __restrict__ bg) {
    int warp = threadIdx.x >> 5;
    int lane = threadIdx.x & 31;
    int token = blockIdx.x * 8 + warp;
    int e = lane & 15, h = lane >> 4;
    const float* xr = x + (size_t)token * D + h * 512;
    const float* wr = wg + (size_t)(h * 512) * E + e;
    float acc = 0.f;
#pragma unroll 8
    for (int d = 0; d < 512; d++)
        acc += xr[d] * wr[(size_t)d * E];
    acc += __shfl_xor_sync(0xffffffffu, acc, 16);
    float g = acc + bg[e];
    float mx = g;
#pragma unroll
    for (int off = 8; off; off >>= 1)
        mx = fmaxf(mx, __shfl_xor_sync(0xffffffffu, mx, off));
    float ex = expf(g - mx);
    float sum = ex;
#pragma unroll
    for (int off = 8; off; off >>= 1)
        sum += __shfl_xor_sync(0xffffffffu, sum, off);
    float p = ex / sum;
    int r = 0;
    int basel = lane & 16;
#pragma unroll
    for (int j = 0; j < 16; j++) {
        float pj = __shfl_sync(0xffffffffu, p, basel + j);
        r += (pj > p) || (pj == p && j < e);
    }
    if (lane < 16)
        g_route[(size_t)token * E + e] = (r < TOPK) ? p : 0.f;
}

// ================= stage 2: route normalize =================
__global__ void route_kernel() {
    int idx = blockIdx.x * blockDim.x + threadIdx.x;
    if (idx >= S * E) return;
    int s = idx / E, e = idx % E;
    float m0 = g_route[(size_t)s * E + e];
    float m1 = g_route[(size_t)(S + s) * E + e];
    float den = m0 + m1 + EPS;
    g_route[(size_t)s * E + e]       = m0 / den * 2.0f;
    g_route[(size_t)(S + s) * E + e] = m1 / den * 2.0f;
}

// ================= stage 3a: rank mask =================
__global__ void mask_kernel() {
    int eb = blockIdx.x;
    int e = eb >> 1, b = eb & 1;
    __shared__ float sv[S];
    int tid = threadIdx.x;
    for (int s = tid; s < S; s += 256)
        sv[s] = g_route[(size_t)(b * S + s) * E + e];
    __syncthreads();
    int i = blockIdx.y * 256 + tid;
    float vi = sv[i];
    int c = 0;
#pragma unroll 4
    for (int j = 0; j < S; j++) {
        float vj = sv[j];
        c += (vj > vi) || (vj == vi && j < i);
    }
    g_mask[eb * S + i] = (c < CAP) ? 1 : 0;
}

// ================= stage 3b: compaction =================
__global__ void select_kernel() {
    int eb = blockIdx.x;
    int e = eb >> 1, b = eb & 1;
    __shared__ unsigned char sm[S];
    __shared__ int cnt[256];
    int t = threadIdx.x;
    for (int s = t; s < S; s += 256)
        sm[s] = g_mask[eb * S + s];
    __syncthreads();
    int local = 0;
#pragma unroll
    for (int k = 0; k < 8; k++) local += sm[t * 8 + k];
    cnt[t] = local;
    __syncthreads();
    if (t == 0) {
        int run = 0;
        for (int i = 0; i < 256; i++) { int c = cnt[i]; cnt[i] = run; run += c; }
    }
    __syncthreads();
    int pos = cnt[t];
#pragma unroll
    for (int k = 0; k < 8; k++) {
        int s = t * 8 + k;
        if (sm[s]) {
            g_seq[eb * CAP + pos] = s;
            g_w[eb * CAP + pos] = g_route[(size_t)(b * S + s) * E + e];
            g_inv[e * NTOK + b * S + s] = pos;
            pos++;
        } else {
            g_inv[e * NTOK + b * S + s] = -1;
        }
    }
}

// ================= stage 4a: fused Q/K/V projection, TF32, bf16 outputs =========
__global__ void __launch_bounds__(256) proj_kernel(const float* __restrict__ x,
                                                   const float* __restrict__ Wq,
                                                   const float* __restrict__ Wkv) {
    constexpr int AST = 36, BST = 200;
    constexpr int AW = 64 * AST;
    constexpr int BW = 32 * BST;
    extern __shared__ uint32_t dsm[];
    uint32_t* As = dsm;
    uint32_t* Bs = dsm + 2 * AW;
    int mt = blockIdx.x, eb = blockIdx.y;
    int e = eb >> 1, b = eb & 1;
    int tid = threadIdx.x;
    int lane = tid & 31, w = tid >> 5;
    int lr = lane >> 2, lc = lane & 3;
    int wm = (w & 1) * 32;
    int wn = (w >> 1) * 48;
    int m0 = mt * 64;

    int r0 = tid >> 3;
    int koff = (tid & 7) << 2;
    int seq0 = g_seq[eb * CAP + m0 + r0];
    int seq1 = g_seq[eb * CAP + m0 + r0 + 32];
    const float* arow0 = x + (size_t)(b * S + seq0) * D + koff;
    const float* arow1 = x + (size_t)(b * S + seq1) * D + koff;
    uint32_t as0 = r0 * AST + koff;
    uint32_t as1 = (r0 + 32) * AST + koff;

    const float* wq  = Wq  + (size_t)e * D * HD;
    const float* wkv = Wkv + (size_t)e * D * (2 * HD);

    const float* bptr[6];
    int bstep[6];
    uint32_t bsoff[6];
#pragma unroll
    for (int it = 0; it < 6; it++) {
        int f = tid + it * 256;
        int bk = f / 48, bj = f % 48;
        if (bj < 16) { bptr[it] = wq  + (size_t)bk * HD       + bj * 4;        bstep[it] = HD; }
        else         { bptr[it] = wkv + (size_t)bk * (2 * HD) + (bj - 16) * 4; bstep[it] = 2 * HD; }
        bsoff[it] = bk * BST + bj * 4;
    }

    float acc[2][6][4];
#pragma unroll
    for (int i = 0; i < 2; i++)
#pragma unroll
        for (int j = 0; j < 6; j++)
#pragma unroll
            for (int r = 0; r < 4; r++) acc[i][j][r] = 0.f;

    cp_async16((uint32_t)__cvta_generic_to_shared(As + as0), arow0);
    cp_async16((uint32_t)__cvta_generic_to_shared(As + as1), arow1);
#pragma unroll
    for (int it = 0; it < 6; it++)
        cp_async16((uint32_t)__cvta_generic_to_shared(Bs + bsoff[it]), bptr[it]);
    cp_commit();

    for (int kt = 0; kt < 32; kt++) {
        cp_wait0();
        __syncthreads();
        if (kt + 1 < 32) {
            int s = (kt + 1) & 1;
            int k0 = (kt + 1) * 32;
            cp_async16((uint32_t)__cvta_generic_to_shared(As + s * AW + as0), arow0 + k0);
            cp_async16((uint32_t)__cvta_generic_to_shared(As + s * AW + as1), arow1 + k0);
#pragma unroll
            for (int it = 0; it < 6; it++)
                cp_async16((uint32_t)__cvta_generic_to_shared(Bs + s * BW + bsoff[it]),
                           bptr[it] + (size_t)k0 * bstep[it]);
            cp_commit();
        }
        int cs = kt & 1;
        const uint32_t* Acur = As + cs * AW;
        const uint32_t* Bcur = Bs + cs * BW;
#pragma unroll
        for (int kb2 = 0; kb2 < 32; kb2 += 8) {
            uint32_t a[2][4], bb[6][2];
#pragma unroll
            for (int mb = 0; mb < 2; mb++) {
                const uint32_t* ap = &Acur[(wm + mb * 16 + lr) * AST + kb2 + lc];
                a[mb][0] = ap[0];
                a[mb][1] = ap[8 * AST];
                a[mb][2] = ap[4];
                a[mb][3] = ap[8 * AST + 4];
            }
#pragma unroll
            for (int nb = 0; nb < 6; nb++) {
                const uint32_t* bp = &Bcur[(kb2 + lc) * BST + wn + lr + nb * 8];
                bb[nb][0] = bp[0];
                bb[nb][1] = bp[4 * BST];
            }
#pragma unroll
            for (int mb = 0; mb < 2; mb++)
#pragma unroll
                for (int nb = 0; nb < 6; nb++)
                    mma_tf32(acc[mb][nb][0], acc[mb][nb][1], acc[mb][nb][2], acc[mb][nb][3],
                             a[mb][0], a[mb][1], a[mb][2], a[mb][3],
                             bb[nb][0], bb[nb][1]);
        }
    }

    // epilogue: q/k packed bf16x2; v transposed bf16
#pragma unroll
    for (int nb = 0; nb < 6; nb++) {
        int colg = wn + nb * 8 + 2 * lc;
#pragma unroll
        for (int mb = 0; mb < 2; mb++) {
            int row0 = m0 + wm + mb * 16 + lr;
            int row1 = row0 + 8;
            if (colg < 64) {
                int pair = colg >> 1;
                g_qh[(eb * CAP + row0) * 32 + pair] = packbf(acc[mb][nb][0], acc[mb][nb][1]);
                g_qh[(eb * CAP + row1) * 32 + pair] = packbf(acc[mb][nb][2], acc[mb][nb][3]);
            } else if (colg < 128) {
                int pair = (colg - 64) >> 1;
                g_kh[(eb * CAP + row0) * 32 + pair] = packbf(acc[mb][nb][0], acc[mb][nb][1]);
                g_kh[(eb * CAP + row1) * 32 + pair] = packbf(acc[mb][nb][2], acc[mb][nb][3]);
            } else {
                int col = colg - 128;
                g_vt[(size_t)(eb * HD + col) * CAP + row0]     = __float2bfloat16(acc[mb][nb][0]);
                g_vt[(size_t)(eb * HD + col + 1) * CAP + row0] = __float2bfloat16(acc[mb][nb][1]);
                g_vt[(size_t)(eb * HD + col) * CAP + row1]     = __float2bfloat16(acc[mb][nb][2]);
                g_vt[(size_t)(eb * HD + col + 1) * CAP + row1] = __float2bfloat16(acc[mb][nb][3]);
            }
        }
    }
}

// ================= stage 4b: RoPE on packed bf16 q/k =================
__global__ void rope_kernel() {
    int idx = blockIdx.x * blockDim.x + threadIdx.x;
    if (idx >= EB * CAP * 16) return;
    int j = idx & 15;         // pair index 0..15 (cols 2j, 2j+1)
    int t = idx >> 4;
    int pos = g_seq[t];
    float invf0 = exp2f(-(float)(2 * j) * 0.4152410118609203f);
    float invf1 = exp2f(-(float)(2 * j + 1) * 0.4152410118609203f);
    float s0, c0, s1, c1;
    sincosf(pos * invf0, &s0, &c0);
    sincosf(pos * invf1, &s1, &c1);
    uint32_t* q = g_qh + (size_t)t * 32;
    uint32_t* k = g_kh + (size_t)t * 32;
    {
        float2 a = __bfloat1622float2(*(__nv_bfloat162*)&q[j]);
        float2 b = __bfloat1622float2(*(__nv_bfloat162*)&q[j + 16]);
        q[j]      = packbf(a.x * c0 - b.x * s0, a.y * c1 - b.y * s1);
        q[j + 16] = packbf(b.x * c0 + a.x * s0, b.y * c1 + a.y * s1);
    }
    {
        float2 a = __bfloat1622float2(*(__nv_bfloat162*)&k[j]);
        float2 b = __bfloat1622float2(*(__nv_bfloat162*)&k[j + 16]);
        k[j]      = packbf(a.x * c0 - b.x * s0, a.y * c1 - b.y * s1);
        k[j + 16] = packbf(b.x * c0 + a.x * s0, b.y * c1 + a.y * s1);
    }
}

// ================= stage 5: split-KV causal flash attention, BF16 mma =================
// grid (10, EB, 2); 256 threads = 8 warps; warp w owns rows [16w,16w+16)
__global__ void __launch_bounds__(256, 2) attn_kernel() {
    constexpr int ST = 36;    // uint32 (bf16x2 pair) stride
    extern __shared__ uint32_t dsm[];
    uint32_t* Qs  = dsm;               // 128*ST
    uint32_t* Ks  = Qs + 128 * ST;     // 64*ST
    uint32_t* Vts = Ks + 64 * ST;      // 64*ST  [col][row-pair]
    uint32_t* Ps  = Vts + 64 * ST;     // 128*ST
    int mt = 9 - blockIdx.x;
    int eb = blockIdx.y;
    int split = blockIdx.z;
    int m0 = mt * 128;
    const uint32_t* qptr = g_qh + (size_t)eb * CAP * 32;
    const uint32_t* kptr = g_kh + (size_t)eb * CAP * 32;
    const uint32_t* vtptr = (const uint32_t*)g_vt + (size_t)eb * HD * (CAP / 2);
    int tid = threadIdx.x;
    int lane = tid & 31, w = tid >> 5;
    int lr = lane >> 2, lc = lane & 3;
    int wrow = 16 * w;

    // Q tile 128 rows x 32 pairs via cp.async (4 chunks/thread)
#pragma unroll
    for (int it = 0; it < 4; it++) {
        int idx = tid + it * 256;
        int row = idx >> 3, c = idx & 7;
        cp_async16((uint32_t)__cvta_generic_to_shared(Qs + row * ST + c * 4),
                   qptr + (size_t)(m0 + row) * 32 + c * 4);
    }
    cp_commit();

    float o[8][4];
#pragma unroll
    for (int t8 = 0; t8 < 8; t8++)
#pragma unroll
        for (int r = 0; r < 4; r++) o[t8][r] = 0.f;
    float mrow0 = -3.402823466e38f, mrow1 = -3.402823466e38f;
    float lsum0 = 0.f, lsum1 = 0.f;

    int half = mt + 1;
    int ntStart = split * half;
    int ntEnd = ntStart + half;
    bool first = true;
    for (int nt = ntStart; nt < ntEnd; nt++) {
        int n0 = nt * 64;
        __syncthreads();
        // K tile: 64 rows x 32 pairs (2 chunks/thread)
#pragma unroll
        for (int it = 0; it < 2; it++) {
            int idx = tid + it * 256;
            int row = idx >> 3, c = idx & 7;
            cp_async16((uint32_t)__cvta_generic_to_shared(Ks + row * ST + c * 4),
                       kptr + (size_t)(n0 + row) * 32 + c * 4);
        }
        cp_commit();
        // Vt tile: 64 cols x 32 row-pairs (2 chunks/thread)
#pragma unroll
        for (int it = 0; it < 2; it++) {
            int idx = tid + it * 256;
            int col = idx >> 3, c = idx & 7;
            cp_async16((uint32_t)__cvta_generic_to_shared(Vts + col * ST + c * 4),
                       vtptr + (size_t)col * (CAP / 2) + (n0 >> 1) + c * 4);
        }
        cp_commit();
        cp_wait1();        // K (and Q on first iter) arrived for this thread
        __syncthreads();
        first = false;
        (void)first;

        // S = Q K^T : 4 k16 steps x 8 n8 tiles
        float sacc[8][4];
#pragma unroll
        for (int t8 = 0; t8 < 8; t8++)
#pragma unroll
            for (int r = 0; r < 4; r++) sacc[t8][r] = 0.f;
#pragma unroll
        for (int kk = 0; kk < 4; kk++) {
            const uint32_t* ap = &Qs[(wrow + lr) * ST + kk * 8 + lc];
            uint32_t a0 = ap[0], a1 = ap[8 * ST], a2 = ap[4], a3 = ap[8 * ST + 4];
#pragma unroll
            for (int t8 = 0; t8 < 8; t8++) {
                const uint32_t* bp = &Ks[(t8 * 8 + lr) * ST + kk * 8 + lc];
                mma_bf16(sacc[t8][0], sacc[t8][1], sacc[t8][2], sacc[t8][3],
                         a0, a1, a2, a3, bp[0], bp[4]);
            }
        }

        bool maskT = (nt >= 2 * mt);
#pragma unroll
        for (int t8 = 0; t8 < 8; t8++) {
            int cbase = n0 + t8 * 8 + 2 * lc;
#pragma unroll
            for (int r = 0; r < 4; r++) {
                float v = sacc[t8][r] * 0.125f;
                if (maskT) {
                    int row = m0 + wrow + lr + ((r >= 2) ? 8 : 0);
                    int col = cbase + (r & 1);
                    if (col > row) v = -3.402823466e38f;
                }
                sacc[t8][r] = v;
            }
        }

        float mx0 = -3.402823466e38f, mx1 = -3.402823466e38f;
#pragma unroll
        for (int t8 = 0; t8 < 8; t8++) {
            mx0 = fmaxf(mx0, fmaxf(sacc[t8][0], sacc[t8][1]));
            mx1 = fmaxf(mx1, fmaxf(sacc[t8][2], sacc[t8][3]));
        }
        mx0 = fmaxf(mx0, __shfl_xor_sync(0xffffffffu, mx0, 1));
        mx0 = fmaxf(mx0, __shfl_xor_sync(0xffffffffu, mx0, 2));
        mx1 = fmaxf(mx1, __shfl_xor_sync(0xffffffffu, mx1, 1));
        mx1 = fmaxf(mx1, __shfl_xor_sync(0xffffffffu, mx1, 2));
        float nm0 = fmaxf(mrow0, mx0), nm1 = fmaxf(mrow1, mx1);
        float corr0 = __expf(mrow0 - nm0), corr1 = __expf(mrow1 - nm1);
        float rs0 = 0.f, rs1 = 0.f;
#pragma unroll
        for (int t8 = 0; t8 < 8; t8++) {
            float p0 = __expf(sacc[t8][0] - nm0);
            float p1 = __expf(sacc[t8][1] - nm0);
            float p2 = __expf(sacc[t8][2] - nm1);
            float p3 = __expf(sacc[t8][3] - nm1);
            rs0 += p0 + p1; rs1 += p2 + p3;
            Ps[(wrow + lr) * ST + t8 * 4 + lc]     = packbf(p0, p1);
            Ps[(wrow + lr + 8) * ST + t8 * 4 + lc] = packbf(p2, p3);
        }
        rs0 += __shfl_xor_sync(0xffffffffu, rs0, 1);
        rs0 += __shfl_xor_sync(0xffffffffu, rs0, 2);
        rs1 += __shfl_xor_sync(0xffffffffu, rs1, 1);
        rs1 += __shfl_xor_sync(0xffffffffu, rs1, 2);
        lsum0 = lsum0 * corr0 + rs0;
        lsum1 = lsum1 * corr1 + rs1;
        mrow0 = nm0; mrow1 = nm1;
#pragma unroll
        for (int t8 = 0; t8 < 8; t8++) {
            o[t8][0] *= corr0; o[t8][1] *= corr0;
            o[t8][2] *= corr1; o[t8][3] *= corr1;
        }

        cp_wait0();        // Vt arrived
        __syncthreads();
        __syncwarp();

        // O += P V : A = P (k = kv rows), B = Vt
#pragma unroll
        for (int kk = 0; kk < 4; kk++) {
            const uint32_t* ap = &Ps[(wrow + lr) * ST + kk * 8 + lc];
            uint32_t a0 = ap[0], a1 = ap[8 * ST], a2 = ap[4], a3 = ap[8 * ST + 4];
#pragma unroll
            for (int t8 = 0; t8 < 8; t8++) {
                const uint32_t* bp = &Vts[(t8 * 8 + lr) * ST + kk * 8 + lc];
                mma_bf16(o[t8][0], o[t8][1], o[t8][2], o[t8][3],
                         a0, a1, a2, a3, bp[0], bp[4]);
            }
        }
    }

    int row0 = m0 + wrow + lr, row1 = row0 + 8;
    float* op = g_opart + (size_t)split * EB * CAP * HD;
#pragma unroll
    for (int t8 = 0; t8 < 8; t8++) {
        int col = t8 * 8 + 2 * lc;
        *(float2*)(op + ((size_t)eb * CAP + row0) * HD + col) = make_float2(o[t8][0], o[t8][1]);
        *(float2*)(op + ((size_t)eb * CAP + row1) * HD + col) = make_float2(o[t8][2], o[t8][3]);
    }
    if (lc == 0) {
        int base = split * EB * CAP + eb * CAP;
        g_pm[base + row0] = mrow0;
        g_pl[base + row0] = lsum0;
        g_pm[base + row1] = mrow1;
        g_pl[base + row1] = lsum1;
    }
}

// ================= stage 5b: combine splits =================
__global__ void combine_kernel() {
    int idx = blockIdx.x * blockDim.x + threadIdx.x;
    if (idx >= EB * CAP * 16) return;
    int t = idx >> 4;
    int c4 = (idx & 15) << 2;
    float m0 = g_pm[t], m1 = g_pm[EB * CAP + t];
    float l0 = g_pl[t], l1 = g_pl[EB * CAP + t];
    float M = fmaxf(m0, m1);
    float s0 = __expf(m0 - M), s1 = __expf(m1 - M);
    float inv = 1.f / (l0 * s0 + l1 * s1);
    const float4 a = *(const float4*)(g_opart + (size_t)t * HD + c4);
    const float4 b = *(const float4*)(g_opart + (size_t)EB * CAP * HD + (size_t)t * HD + c4);
    float4 r;
    r.x = (a.x * s0 + b.x * s1) * inv;
    r.y = (a.y * s0 + b.y * s1) * inv;
    r.z = (a.z * s0 + b.z * s1) * inv;
    r.w = (a.w * s0 + b.w * s1) * inv;
    *(float4*)(g_ctx + (size_t)t * HD + c4) = r;
}

// ================= stage 6a: out = (ctx @ Wff + bff) * w -> bf16 g_out =========
__global__ void __launch_bounds__(256) outproj_kernel(const float* __restrict__ Wff,
                                                      const float* __restrict__ bff) {
    constexpr int AST = 72, BST = 136;
    extern __shared__ uint32_t dsm[];
    uint32_t* As = dsm;
    uint32_t* Bs = As + 128 * AST;
    int mt = blockIdx.x, nt = blockIdx.y, eb = blockIdx.z;
    int e = eb >> 1;
    int tid = threadIdx.x;
    int lane = tid & 31, w = tid >> 5;
    int lr = lane >> 2, lc = lane & 3;
    int wm = (w & 3) * 32, wn = (w >> 2) * 64;
    int m0 = mt * 128, n0 = nt * 128;

#pragma unroll
    for (int it = 0; it < 8; it++) {
        int idx = tid + it * 256;
        int row = idx >> 4, c4 = (idx & 15) << 2;
        cp_async16((uint32_t)__cvta_generic_to_shared(As + row * AST + c4),
                   g_ctx + ((size_t)eb * CAP + m0 + row) * HD + c4);
    }
#pragma unroll
    for (int it = 0; it < 8; it++) {
        int idx = tid + it * 256;
        int row = idx >> 5, c4 = (idx & 31) << 2;
        cp_async16((uint32_t)__cvta_generic_to_shared(Bs + row * BST + c4),
                   Wff + ((size_t)e * HD + row) * D + n0 + c4);
    }
    cp_commit();
    cp_wait0();
    __syncthreads();

    float acc[2][8][4];
#pragma unroll
    for (int mi = 0; mi < 2; mi++)
#pragma unroll
        for (int t8 = 0; t8 < 8; t8++)
#pragma unroll
            for (int r = 0; r < 4; r++) acc[mi][t8][r] = 0.f;

#pragma unroll
    for (int kk = 0; kk < 8; kk++) {
        uint32_t a[2][4];
#pragma unroll
        for (int mi = 0; mi < 2; mi++) {
            const uint32_t* ap = &As[(wm + mi * 16 + lr) * AST + kk * 8 + lc];
            a[mi][0] = ap[0]; a[mi][1] = ap[8 * AST];
            a[mi][2] = ap[4]; a[mi][3] = ap[8 * AST + 4];
        }
#pragma unroll
        for (int t8 = 0; t8 < 8; t8++) {
            uint32_t b0 = Bs[(kk * 8 + lc) * BST + wn + t8 * 8 + lr];
            uint32_t b1 = Bs[(kk * 8 + lc + 4) * BST + wn + t8 * 8 + lr];
#pragma unroll
            for (int mi = 0; mi < 2; mi++)
                mma_tf32(acc[mi][t8][0], acc[mi][t8][1], acc[mi][t8][2], acc[mi][t8][3],
                         a[mi][0], a[mi][1], a[mi][2], a[mi][3], b0, b1);
        }
    }

#pragma unroll
    for (int mi = 0; mi < 2; mi++) {
        int row0 = m0 + wm + mi * 16 + lr;
        int row1 = row0 + 8;
        float wv0 = g_w[eb * CAP + row0];
        float wv1 = g_w[eb * CAP + row1];
#pragma unroll
        for (int t8 = 0; t8 < 8; t8++) {
            int col = n0 + wn + t8 * 8 + 2 * lc;
            float2 bf = *(const float2*)(bff + col);
            if (wv0 != 0.f) {
                __nv_bfloat162 v;
                v.x = __float2bfloat16((acc[mi][t8][0] + bf.x) * wv0);
                v.y = __float2bfloat16((acc[mi][t8][1] + bf.y) * wv0);
                *(__nv_bfloat162*)(g_out + ((size_t)eb * CAP + row0) * D + col) = v;
            }
            if (wv1 != 0.f) {
                __nv_bfloat162 v;
                v.x = __float2bfloat16((acc[mi][t8][2] + bf.x) * wv1);
                v.y = __float2bfloat16((acc[mi][t8][3] + bf.y) * wv1);
                *(__nv_bfloat162*)(g_out + ((size_t)eb * CAP + row1) * D + col) = v;
            }
        }
    }
}

// ================= stage 6b: gather-combine + residual + LayerNorm =================
__global__ void ln_kernel(const float* __restrict__ x,
                          const float* __restrict__ gamma,
                          const float* __restrict__ beta,
                          float* __restrict__ out) {
    int token = blockIdx.x;
    int b = token >> 11;
    int tid = threadIdx.x;
    __shared__ int sh_base[E];
    __shared__ float red[8];
    if (tid < E) {
        int p = g_inv[tid * NTOK + token];
        int base = -1;
        if (p >= 0) {
            int idx = (tid * B + b) * CAP + p;
            if (g_w[idx] != 0.f) base = idx;
        }
        sh_base[tid] = base;
    }
    __syncthreads();
    float4 c = make_float4(0.f, 0.f, 0.f, 0.f);
#pragma unroll
    for (int e = 0; e < E; e++) {
        int base = sh_base[e];
        if (base >= 0) {
            uint2 u = *(const uint2*)(g_out + (size_t)base * D + tid * 4);
            __nv_bfloat162 p0 = *reinterpret_cast<__nv_bfloat162*>(&u.x);
            __nv_bfloat162 p1 = *reinterpret_cast<__nv_bfloat162*>(&u.y);
            c.x += __bfloat162float(p0.x); c.y += __bfloat162float(p0.y);
            c.z += __bfloat162float(p1.x); c.w += __bfloat162float(p1.y);
        }
    }
    float4 x4 = *(const float4*)(x + (size_t)token * D + tid * 4);
    float h[4] = {x4.x + c.x, x4.y + c.y, x4.z + c.z, x4.w + c.w};
    float s = h[0] + h[1] + h[2] + h[3];
#pragma unroll
    for (int off = 16; off > 0; off >>= 1) s += __shfl_xor_sync(0xffffffffu, s, off);
    int warp = tid >> 5, lane = tid & 31;
    if (lane == 0) red[warp] = s;
    __syncthreads();
    float total = 0.f;
#pragma unroll
    for (int w = 0; w < 8; w++) total += red[w];
    __syncthreads();
    float mu = total * (1.0f / D);
    float ss = 0.f;
#pragma unroll
    for (int t = 0; t < 4; t++) {
        float dlt = h[t] - mu;
        ss += dlt * dlt;
    }
#pragma unroll
    for (int off = 16; off > 0; off >>= 1) ss += __shfl_xor_sync(0xffffffffu, ss, off);
    if (lane == 0) red[warp] = ss;
    __syncthreads();
    float vtot = 0.f;
#pragma unroll
    for (int w = 0; w < 8; w++) vtot += red[w];
    float var = vtot * (1.0f / D);
    float inv = rsqrtf(var + 1e-5f);
    float4 g4 = *(const float4*)(gamma + tid * 4);
    float4 be4 = *(const float4*)(beta + tid * 4);
    float4 o4;
    o4.x = (h[0] - mu) * inv * g4.x + be4.x;
    o4.y = (h[1] - mu) * inv * g4.y + be4.y;
    o4.z = (h[2] - mu) * inv * g4.z + be4.z;
    o4.w = (h[3] - mu) * inv * g4.w + be4.w;
    *(float4*)(out + (size_t)token * D + tid * 4) = o4;
}

// ================= launch =================
extern "C" void kernel_launch(void* const* d_in, const int* in_sizes, int n_in,
                              void* d_out, int out_size) {
    const float* x     = (const float*)d_in[0];
    const float* wg    = (const float*)d_in[1];
    const float* bg    = (const float*)d_in[2];
    const float* Wq    = (const float*)d_in[3];
    const float* Wkv   = (const float*)d_in[4];
    const float* Wff   = (const float*)d_in[5];
    const float* bff   = (const float*)d_in[6];
    const float* gamma = (const float*)d_in[7];
    const float* beta  = (const float*)d_in[8];
    float* out = (float*)d_out;

    (void)in_sizes; (void)n_in; (void)out_size;

    gate_kernel<<<NTOK / 8, 256>>>(x, wg, bg);
    route_kernel<<<(S * E + 255) / 256, 256>>>();
    mask_kernel<<<dim3(EB, 8), 256>>>();
    select_kernel<<<EB, 256>>>();

    int proj_smem = 2 * (64 * 36 + 32 * 200) * (int)sizeof(uint32_t);  // 69,632 B
    cudaFuncSetAttribute(proj_kernel, cudaFuncAttributeMaxDynamicSharedMemorySize, proj_smem);
    proj_kernel<<<dim3(CAP / 64, EB), 256, proj_smem>>>(x, Wq, Wkv);

    rope_kernel<<<(EB * CAP * 16 + 255) / 256, 256>>>();

    int attn_smem = 384 * 36 * (int)sizeof(uint32_t);   // 55,296 B
    cudaFuncSetAttribute(attn_kernel, cudaFuncAttributeMaxDynamicSharedMemorySize, attn_smem);
    attn_kernel<<<dim3(CAP / 128, EB, 2), 256, attn_smem>>>();

    combine_kernel<<<(EB * CAP * 16 + 255) / 256, 256>>>();

    int op_smem = (128 * 72 + 64 * 136) * (int)sizeof(uint32_t);  // 71,680 B
    cudaFuncSetAttribute(outproj_kernel, cudaFuncAttributeMaxDynamicSharedMemorySize, op_smem);
    outproj_kernel<<<dim3(CAP / 128, D / 128, EB), 256, op_smem>>>(Wff, bff);

    ln_kernel<<<NTOK, 256>>>(x, gamma, beta, out);
}

// round 10
// speedup vs baseline: 4.6665x; 1.1998x over previous
#include <cuda_runtime.h>
#include <cuda_bf16.h>
#include <math.h>
#include <stdint.h>

// ---------------- problem constants ----------------
namespace {
constexpr int B = 2, S = 2048, D = 1024, E = 16, HD = 64, CAP = 1280, TOPK = 8;
constexpr float EPS = 1e-6f;
constexpr int EB = E * B;    // 32
constexpr int NTOK = B * S;  // 4096
}

// ---------------- scratch (device globals; no allocation allowed) ----------------
__device__ float g_route[NTOK * E];
__device__ unsigned char g_mask[EB * S];
__device__ int   g_seq[EB * CAP];
__device__ float g_w[EB * CAP];
__device__ int   g_inv[E * NTOK];
__device__ uint32_t g_xh[NTOK * 512];                   // x packed bf16x2 along D
__device__ uint32_t g_wt[(size_t)E * 192 * 512];        // Wq|Wkv transposed: [e][n][kpair]
__device__ uint32_t g_wfft[(size_t)E * 1024 * 32];      // Wff transposed: [e][n][kpair]
__device__ uint32_t g_qh[EB * CAP * 32];                // q bf16x2 pairs along HD
__device__ uint32_t g_kh[EB * CAP * 32];                // k bf16x2 pairs along HD
__device__ __nv_bfloat16 g_vt[(size_t)EB * HD * CAP];   // V transposed [eb][col][row]
__device__ uint32_t g_ctxh[EB * CAP * 32];              // ctx packed bf16x2 along HD
__device__ float g_opart[2 * EB * CAP * HD];
__device__ float g_pm[2 * EB * CAP];
__device__ float g_pl[2 * EB * CAP];
__device__ __nv_bfloat16 g_out[(size_t)EB * CAP * D];

// ---------------- helpers ----------------
__device__ __forceinline__ void mma_bf16(float& c0, float& c1, float& c2, float& c3,
                                         uint32_t a0, uint32_t a1, uint32_t a2, uint32_t a3,
                                         uint32_t b0, uint32_t b1) {
    asm volatile(
        "mma.sync.aligned.m16n8k16.row.col.f32.bf16.bf16.f32 "
        "{%0,%1,%2,%3}, {%4,%5,%6,%7}, {%8,%9}, {%0,%1,%2,%3};\n"
        : "+f"(c0), "+f"(c1), "+f"(c2), "+f"(c3)
        : "r"(a0), "r"(a1), "r"(a2), "r"(a3), "r"(b0), "r"(b1));
}
__device__ __forceinline__ uint32_t packbf(float a, float b) {
    __nv_bfloat162 t = __floats2bfloat162_rn(a, b);
    return *reinterpret_cast<uint32_t*>(&t);
}
__device__ __forceinline__ void cp_async16(uint32_t saddr, const void* g) {
    asm volatile("cp.async.ca.shared.global [%0], [%1], 16;" :: "r"(saddr), "l"(g));
}
__device__ __forceinline__ void cp_commit() { asm volatile("cp.async.commit_group;"); }
__device__ __forceinline__ void cp_wait0()  { asm volatile("cp.async.wait_group 0;"); }
__device__ __forceinline__ void cp_wait1()  { asm volatile("cp.async.wait_group 1;"); }

// ================= prep: pack x to bf16 pairs =================
__global__ void xpack_kernel(const float* __restrict__ x) {
    int idx = blockIdx.x * 256 + threadIdx.x;     // NTOK*512
    float2 v = *(const float2*)(x + (size_t)idx * 2);
    g_xh[idx] = packbf(v.x, v.y);
}

// ================= prep: transpose-pack Wq|Wkv -> g_wt[e][n][kpair] =================
// grid (E, D/64, 192/64), 256 threads
__global__ void wt_kernel(const float* __restrict__ Wq, const float* __restrict__ Wkv) {
    __shared__ float sm[64][65];
    int e = blockIdx.x, k0 = blockIdx.y * 64, n0 = blockIdx.z * 64;
    const float* src;
    int stride;
    if (n0 < 64) { src = Wq + (size_t)e * D * HD + n0; stride = HD; }
    else         { src = Wkv + (size_t)e * D * 128 + (n0 - 64); stride = 128; }
    int tid = threadIdx.x;
#pragma unroll
    for (int i = 0; i < 16; i++) {
        int idx = tid + i * 256;
        int kk = idx >> 6, nn = idx & 63;
        sm[kk][nn] = src[(size_t)(k0 + kk) * stride + nn];
    }
    __syncthreads();
#pragma unroll
    for (int i = 0; i < 8; i++) {
        int idx = tid + i * 256;
        int n = idx >> 5, kp = idx & 31;
        g_wt[((size_t)(e * 192 + n0 + n)) * 512 + (k0 >> 1) + kp] =
            packbf(sm[2 * kp][n], sm[2 * kp + 1][n]);
    }
}

// ================= prep: transpose-pack Wff -> g_wfft[e][n][kpair] =================
// grid (E, D/64), 256 threads
__global__ void wff_kernel(const float* __restrict__ Wff) {
    __shared__ float sm[64][65];
    int e = blockIdx.x, n0 = blockIdx.y * 64;
    int tid = threadIdx.x;
#pragma unroll
    for (int i = 0; i < 16; i++) {
        int idx = tid + i * 256;
        int kk = idx >> 6, nn = idx & 63;
        sm[kk][nn] = Wff[(size_t)e * HD * D + (size_t)kk * D + n0 + nn];
    }
    __syncthreads();
#pragma unroll
    for (int i = 0; i < 8; i++) {
        int idx = tid + i * 256;
        int n = idx >> 5, kp = idx & 31;
        g_wfft[((size_t)(e * 1024 + n0 + n)) * 32 + kp] =
            packbf(sm[2 * kp][n], sm[2 * kp + 1][n]);
    }
}

// ================= stage 1: gating (warp-per-token) =================
__global__ void __launch_bounds__(256) gate_kernel(const float* __restrict__ x,
                                                   const float* __restrict__ wg,
                                                   const float* __restrict__ bg) {
    int warp = threadIdx.x >> 5;
    int lane = threadIdx.x & 31;
    int token = blockIdx.x * 8 + warp;
    int e = lane & 15, h = lane >> 4;
    const float* xr = x + (size_t)token * D + h * 512;
    const float* wr = wg + (size_t)(h * 512) * E + e;
    float acc = 0.f;
#pragma unroll 8
    for (int d = 0; d < 512; d++)
        acc += xr[d] * wr[(size_t)d * E];
    acc += __shfl_xor_sync(0xffffffffu, acc, 16);
    float g = acc + bg[e];
    float mx = g;
#pragma unroll
    for (int off = 8; off; off >>= 1)
        mx = fmaxf(mx, __shfl_xor_sync(0xffffffffu, mx, off));
    float ex = expf(g - mx);
    float sum = ex;
#pragma unroll
    for (int off = 8; off; off >>= 1)
        sum += __shfl_xor_sync(0xffffffffu, sum, off);
    float p = ex / sum;
    int r = 0;
    int basel = lane & 16;
#pragma unroll
    for (int j = 0; j < 16; j++) {
        float pj = __shfl_sync(0xffffffffu, p, basel + j);
        r += (pj > p) || (pj == p && j < e);
    }
    if (lane < 16)
        g_route[(size_t)token * E + e] = (r < TOPK) ? p : 0.f;
}

// ================= stage 2: route normalize =================
__global__ void route_kernel() {
    int idx = blockIdx.x * blockDim.x + threadIdx.x;
    if (idx >= S * E) return;
    int s = idx / E, e = idx % E;
    float m0 = g_route[(size_t)s * E + e];
    float m1 = g_route[(size_t)(S + s) * E + e];
    float den = m0 + m1 + EPS;
    g_route[(size_t)s * E + e]       = m0 / den * 2.0f;
    g_route[(size_t)(S + s) * E + e] = m1 / den * 2.0f;
}

// ================= stage 3a: rank mask =================
__global__ void mask_kernel() {
    int eb = blockIdx.x;
    int e = eb >> 1, b = eb & 1;
    __shared__ float sv[S];
    int tid = threadIdx.x;
    for (int s = tid; s < S; s += 256)
        sv[s] = g_route[(size_t)(b * S + s) * E + e];
    __syncthreads();
    int i = blockIdx.y * 256 + tid;
    float vi = sv[i];
    int c = 0;
#pragma unroll 4
    for (int j = 0; j < S; j++) {
        float vj = sv[j];
        c += (vj > vi) || (vj == vi && j < i);
    }
    g_mask[eb * S + i] = (c < CAP) ? 1 : 0;
}

// ================= stage 3b: compaction =================
__global__ void select_kernel() {
    int eb = blockIdx.x;
    int e = eb >> 1, b = eb & 1;
    __shared__ unsigned char sm[S];
    __shared__ int cnt[256];
    int t = threadIdx.x;
    for (int s = t; s < S; s += 256)
        sm[s] = g_mask[eb * S + s];
    __syncthreads();
    int local = 0;
#pragma unroll
    for (int k = 0; k < 8; k++) local += sm[t * 8 + k];
    cnt[t] = local;
    __syncthreads();
    if (t == 0) {
        int run = 0;
        for (int i = 0; i < 256; i++) { int c = cnt[i]; cnt[i] = run; run += c; }
    }
    __syncthreads();
    int pos = cnt[t];
#pragma unroll
    for (int k = 0; k < 8; k++) {
        int s = t * 8 + k;
        if (sm[s]) {
            g_seq[eb * CAP + pos] = s;
            g_w[eb * CAP + pos] = g_route[(size_t)(b * S + s) * E + e];
            g_inv[e * NTOK + b * S + s] = pos;
            pos++;
        } else {
            g_inv[e * NTOK + b * S + s] = -1;
        }
    }
}

// ================= stage 4a: fused Q/K/V projection, BF16 mma, BK=64 =========
// grid (CAP/64=20, EB=32), 256 threads (8 warps: 2M x 4N), block tile 64x192
__global__ void __launch_bounds__(256) proj_kernel() {
    constexpr int AST = 36, BST = 36;       // pair strides
    constexpr int AW = 64 * AST;            // 2304 words/stage
    constexpr int BW = 192 * BST;           // 6912 words/stage
    extern __shared__ uint32_t dsm[];
    uint32_t* As = dsm;            // [row][kpair] 64x32
    uint32_t* Bs = dsm + 2 * AW;   // [n][kpair] 192x32
    int mt = blockIdx.x, eb = blockIdx.y;
    int e = eb >> 1, b = eb & 1;
    int tid = threadIdx.x;
    int lane = tid & 31, w = tid >> 5;
    int lr = lane >> 2, lc = lane & 3;
    int wm = (w & 1) * 32;
    int wn = (w >> 1) * 48;
    int m0 = mt * 64;

    // A: 64 rows x 32 pairs = 512 chunks (2/thread): rows r0 and r0+32, chunk c
    int r0 = tid >> 3;
    int c = tid & 7;
    int seq0 = g_seq[eb * CAP + m0 + r0];
    int seq1 = g_seq[eb * CAP + m0 + r0 + 32];
    const uint32_t* arow0 = g_xh + (size_t)(b * S + seq0) * 512 + c * 4;
    const uint32_t* arow1 = g_xh + (size_t)(b * S + seq1) * 512 + c * 4;
    uint32_t as0 = r0 * AST + c * 4;
    uint32_t as1 = (r0 + 32) * AST + c * 4;

    // B: 192 n x 32 pairs = 1536 chunks (6/thread)
    const uint32_t* wtbase = g_wt + (size_t)e * 192 * 512;
    const uint32_t* bsrc[6];
    uint32_t bsoff[6];
#pragma unroll
    for (int it = 0; it < 6; it++) {
        int f = tid + it * 256;
        int n = f >> 3, cb = f & 7;
        bsrc[it] = wtbase + (size_t)n * 512 + cb * 4;
        bsoff[it] = n * BST + cb * 4;
    }

    float acc[2][6][4];
#pragma unroll
    for (int i = 0; i < 2; i++)
#pragma unroll
        for (int j = 0; j < 6; j++)
#pragma unroll
            for (int r = 0; r < 4; r++) acc[i][j][r] = 0.f;

    // prologue: stage 0 (kpair offset 0)
    cp_async16((uint32_t)__cvta_generic_to_shared(As + as0), arow0);
    cp_async16((uint32_t)__cvta_generic_to_shared(As + as1), arow1);
#pragma unroll
    for (int it = 0; it < 6; it++)
        cp_async16((uint32_t)__cvta_generic_to_shared(Bs + bsoff[it]), bsrc[it]);
    cp_commit();

    for (int kt = 0; kt < 16; kt++) {
        cp_wait0();
        __syncthreads();
        if (kt + 1 < 16) {
            int s = (kt + 1) & 1;
            int kp0 = (kt + 1) * 32;
            cp_async16((uint32_t)__cvta_generic_to_shared(As + s * AW + as0), arow0 + kp0);
            cp_async16((uint32_t)__cvta_generic_to_shared(As + s * AW + as1), arow1 + kp0);
#pragma unroll
            for (int it = 0; it < 6; it++)
                cp_async16((uint32_t)__cvta_generic_to_shared(Bs + s * BW + bsoff[it]),
                           bsrc[it] + kp0);
            cp_commit();
        }
        int cs = kt & 1;
        const uint32_t* Acur = As + cs * AW;
        const uint32_t* Bcur = Bs + cs * BW;
#pragma unroll
        for (int kk = 0; kk < 4; kk++) {
            uint32_t a[2][4], bb[6][2];
#pragma unroll
            for (int mb = 0; mb < 2; mb++) {
                const uint32_t* ap = &Acur[(wm + mb * 16 + lr) * AST + kk * 8 + lc];
                a[mb][0] = ap[0];
                a[mb][1] = ap[8 * AST];
                a[mb][2] = ap[4];
                a[mb][3] = ap[8 * AST + 4];
            }
#pragma unroll
            for (int nb = 0; nb < 6; nb++) {
                const uint32_t* bp = &Bcur[(wn + nb * 8 + lr) * BST + kk * 8 + lc];
                bb[nb][0] = bp[0];
                bb[nb][1] = bp[4];
            }
#pragma unroll
            for (int mb = 0; mb < 2; mb++)
#pragma unroll
                for (int nb = 0; nb < 6; nb++)
                    mma_bf16(acc[mb][nb][0], acc[mb][nb][1], acc[mb][nb][2], acc[mb][nb][3],
                             a[mb][0], a[mb][1], a[mb][2], a[mb][3],
                             bb[nb][0], bb[nb][1]);
        }
    }

    // epilogue: q/k packed bf16x2; v transposed bf16
#pragma unroll
    for (int nb = 0; nb < 6; nb++) {
        int colg = wn + nb * 8 + 2 * lc;
#pragma unroll
        for (int mb = 0; mb < 2; mb++) {
            int row0 = m0 + wm + mb * 16 + lr;
            int row1 = row0 + 8;
            if (colg < 64) {
                int pair = colg >> 1;
                g_qh[(eb * CAP + row0) * 32 + pair] = packbf(acc[mb][nb][0], acc[mb][nb][1]);
                g_qh[(eb * CAP + row1) * 32 + pair] = packbf(acc[mb][nb][2], acc[mb][nb][3]);
            } else if (colg < 128) {
                int pair = (colg - 64) >> 1;
                g_kh[(eb * CAP + row0) * 32 + pair] = packbf(acc[mb][nb][0], acc[mb][nb][1]);
                g_kh[(eb * CAP + row1) * 32 + pair] = packbf(acc[mb][nb][2], acc[mb][nb][3]);
            } else {
                int col = colg - 128;
                g_vt[(size_t)(eb * HD + col) * CAP + row0]     = __float2bfloat16(acc[mb][nb][0]);
                g_vt[(size_t)(eb * HD + col + 1) * CAP + row0] = __float2bfloat16(acc[mb][nb][1]);
                g_vt[(size_t)(eb * HD + col) * CAP + row1]     = __float2bfloat16(acc[mb][nb][2]);
                g_vt[(size_t)(eb * HD + col + 1) * CAP + row1] = __float2bfloat16(acc[mb][nb][3]);
            }
        }
    }
}

// ================= stage 4b: RoPE on packed bf16 q/k =================
__global__ void rope_kernel() {
    int idx = blockIdx.x * blockDim.x + threadIdx.x;
    if (idx >= EB * CAP * 16) return;
    int j = idx & 15;
    int t = idx >> 4;
    int pos = g_seq[t];
    float invf0 = exp2f(-(float)(2 * j) * 0.4152410118609203f);
    float invf1 = exp2f(-(float)(2 * j + 1) * 0.4152410118609203f);
    float s0, c0, s1, c1;
    sincosf(pos * invf0, &s0, &c0);
    sincosf(pos * invf1, &s1, &c1);
    uint32_t* q = g_qh + (size_t)t * 32;
    uint32_t* k = g_kh + (size_t)t * 32;
    {
        float2 a = __bfloat1622float2(*(__nv_bfloat162*)&q[j]);
        float2 b = __bfloat1622float2(*(__nv_bfloat162*)&q[j + 16]);
        q[j]      = packbf(a.x * c0 - b.x * s0, a.y * c1 - b.y * s1);
        q[j + 16] = packbf(b.x * c0 + a.x * s0, b.y * c1 + a.y * s1);
    }
    {
        float2 a = __bfloat1622float2(*(__nv_bfloat162*)&k[j]);
        float2 b = __bfloat1622float2(*(__nv_bfloat162*)&k[j + 16]);
        k[j]      = packbf(a.x * c0 - b.x * s0, a.y * c1 - b.y * s1);
        k[j + 16] = packbf(b.x * c0 + a.x * s0, b.y * c1 + a.y * s1);
    }
}

// ================= stage 5: split-KV causal flash attention, BF16 mma =================
__global__ void __launch_bounds__(256, 2) attn_kernel() {
    constexpr int ST = 36;
    extern __shared__ uint32_t dsm[];
    uint32_t* Qs  = dsm;
    uint32_t* Ks  = Qs + 128 * ST;
    uint32_t* Vts = Ks + 64 * ST;
    uint32_t* Ps  = Vts + 64 * ST;
    int mt = 9 - blockIdx.x;
    int eb = blockIdx.y;
    int split = blockIdx.z;
    int m0 = mt * 128;
    const uint32_t* qptr = g_qh + (size_t)eb * CAP * 32;
    const uint32_t* kptr = g_kh + (size_t)eb * CAP * 32;
    const uint32_t* vtptr = (const uint32_t*)g_vt + (size_t)eb * HD * (CAP / 2);
    int tid = threadIdx.x;
    int lane = tid & 31, w = tid >> 5;
    int lr = lane >> 2, lc = lane & 3;
    int wrow = 16 * w;

#pragma unroll
    for (int it = 0; it < 4; it++) {
        int idx = tid + it * 256;
        int row = idx >> 3, c = idx & 7;
        cp_async16((uint32_t)__cvta_generic_to_shared(Qs + row * ST + c * 4),
                   qptr + (size_t)(m0 + row) * 32 + c * 4);
    }
    cp_commit();

    float o[8][4];
#pragma unroll
    for (int t8 = 0; t8 < 8; t8++)
#pragma unroll
        for (int r = 0; r < 4; r++) o[t8][r] = 0.f;
    float mrow0 = -3.402823466e38f, mrow1 = -3.402823466e38f;
    float lsum0 = 0.f, lsum1 = 0.f;

    int half = mt + 1;
    int ntStart = split * half;
    int ntEnd = ntStart + half;
    for (int nt = ntStart; nt < ntEnd; nt++) {
        int n0 = nt * 64;
        __syncthreads();
#pragma unroll
        for (int it = 0; it < 2; it++) {
            int idx = tid + it * 256;
            int row = idx >> 3, c = idx & 7;
            cp_async16((uint32_t)__cvta_generic_to_shared(Ks + row * ST + c * 4),
                       kptr + (size_t)(n0 + row) * 32 + c * 4);
        }
        cp_commit();
#pragma unroll
        for (int it = 0; it < 2; it++) {
            int idx = tid + it * 256;
            int col = idx >> 3, c = idx & 7;
            cp_async16((uint32_t)__cvta_generic_to_shared(Vts + col * ST + c * 4),
                       vtptr + (size_t)col * (CAP / 2) + (n0 >> 1) + c * 4);
        }
        cp_commit();
        cp_wait1();
        __syncthreads();

        float sacc[8][4];
#pragma unroll
        for (int t8 = 0; t8 < 8; t8++)
#pragma unroll
            for (int r = 0; r < 4; r++) sacc[t8][r] = 0.f;
#pragma unroll
        for (int kk = 0; kk < 4; kk++) {
            const uint32_t* ap = &Qs[(wrow + lr) * ST + kk * 8 + lc];
            uint32_t a0 = ap[0], a1 = ap[8 * ST], a2 = ap[4], a3 = ap[8 * ST + 4];
#pragma unroll
            for (int t8 = 0; t8 < 8; t8++) {
                const uint32_t* bp = &Ks[(t8 * 8 + lr) * ST + kk * 8 + lc];
                mma_bf16(sacc[t8][0], sacc[t8][1], sacc[t8][2], sacc[t8][3],
                         a0, a1, a2, a3, bp[0], bp[4]);
            }
        }

        bool maskT = (nt >= 2 * mt);
#pragma unroll
        for (int t8 = 0; t8 < 8; t8++) {
            int cbase = n0 + t8 * 8 + 2 * lc;
#pragma unroll
            for (int r = 0; r < 4; r++) {
                float v = sacc[t8][r] * 0.125f;
                if (maskT) {
                    int row = m0 + wrow + lr + ((r >= 2) ? 8 : 0);
                    int col = cbase + (r & 1);
                    if (col > row) v = -3.402823466e38f;
                }
                sacc[t8][r] = v;
            }
        }

        float mx0 = -3.402823466e38f, mx1 = -3.402823466e38f;
#pragma unroll
        for (int t8 = 0; t8 < 8; t8++) {
            mx0 = fmaxf(mx0, fmaxf(sacc[t8][0], sacc[t8][1]));
            mx1 = fmaxf(mx1, fmaxf(sacc[t8][2], sacc[t8][3]));
        }
        mx0 = fmaxf(mx0, __shfl_xor_sync(0xffffffffu, mx0, 1));
        mx0 = fmaxf(mx0, __shfl_xor_sync(0xffffffffu, mx0, 2));
        mx1 = fmaxf(mx1, __shfl_xor_sync(0xffffffffu, mx1, 1));
        mx1 = fmaxf(mx1, __shfl_xor_sync(0xffffffffu, mx1, 2));
        float nm0 = fmaxf(mrow0, mx0), nm1 = fmaxf(mrow1, mx1);
        float corr0 = __expf(mrow0 - nm0), corr1 = __expf(mrow1 - nm1);
        float rs0 = 0.f, rs1 = 0.f;
#pragma unroll
        for (int t8 = 0; t8 < 8; t8++) {
            float p0 = __expf(sacc[t8][0] - nm0);
            float p1 = __expf(sacc[t8][1] - nm0);
            float p2 = __expf(sacc[t8][2] - nm1);
            float p3 = __expf(sacc[t8][3] - nm1);
            rs0 += p0 + p1; rs1 += p2 + p3;
            Ps[(wrow + lr) * ST + t8 * 4 + lc]     = packbf(p0, p1);
            Ps[(wrow + lr + 8) * ST + t8 * 4 + lc] = packbf(p2, p3);
        }
        rs0 += __shfl_xor_sync(0xffffffffu, rs0, 1);
        rs0 += __shfl_xor_sync(0xffffffffu, rs0, 2);
        rs1 += __shfl_xor_sync(0xffffffffu, rs1, 1);
        rs1 += __shfl_xor_sync(0xffffffffu, rs1, 2);
        lsum0 = lsum0 * corr0 + rs0;
        lsum1 = lsum1 * corr1 + rs1;
        mrow0 = nm0; mrow1 = nm1;
#pragma unroll
        for (int t8 = 0; t8 < 8; t8++) {
            o[t8][0] *= corr0; o[t8][1] *= corr0;
            o[t8][2] *= corr1; o[t8][3] *= corr1;
        }

        cp_wait0();
        __syncthreads();
        __syncwarp();

#pragma unroll
        for (int kk = 0; kk < 4; kk++) {
            const uint32_t* ap = &Ps[(wrow + lr) * ST + kk * 8 + lc];
            uint32_t a0 = ap[0], a1 = ap[8 * ST], a2 = ap[4], a3 = ap[8 * ST + 4];
#pragma unroll
            for (int t8 = 0; t8 < 8; t8++) {
                const uint32_t* bp = &Vts[(t8 * 8 + lr) * ST + kk * 8 + lc];
                mma_bf16(o[t8][0], o[t8][1], o[t8][2], o[t8][3],
                         a0, a1, a2, a3, bp[0], bp[4]);
            }
        }
    }

    int row0 = m0 + wrow + lr, row1 = row0 + 8;
    float* op = g_opart + (size_t)split * EB * CAP * HD;
#pragma unroll
    for (int t8 = 0; t8 < 8; t8++) {
        int col = t8 * 8 + 2 * lc;
        *(float2*)(op + ((size_t)eb * CAP + row0) * HD + col) = make_float2(o[t8][0], o[t8][1]);
        *(float2*)(op + ((size_t)eb * CAP + row1) * HD + col) = make_float2(o[t8][2], o[t8][3]);
    }
    if (lc == 0) {
        int base = split * EB * CAP + eb * CAP;
        g_pm[base + row0] = mrow0;
        g_pl[base + row0] = lsum0;
        g_pm[base + row1] = mrow1;
        g_pl[base + row1] = lsum1;
    }
}

// ================= stage 5b: combine splits -> packed bf16 ctx =================
__global__ void combine_kernel() {
    int idx = blockIdx.x * blockDim.x + threadIdx.x;
    if (idx >= EB * CAP * 16) return;
    int t = idx >> 4;
    int c4 = (idx & 15) << 2;
    float m0 = g_pm[t], m1 = g_pm[EB * CAP + t];
    float l0 = g_pl[t], l1 = g_pl[EB * CAP + t];
    float M = fmaxf(m0, m1);
    float s0 = __expf(m0 - M), s1 = __expf(m1 - M);
    float inv = 1.f / (l0 * s0 + l1 * s1);
    const float4 a = *(const float4*)(g_opart + (size_t)t * HD + c4);
    const float4 b = *(const float4*)(g_opart + (size_t)EB * CAP * HD + (size_t)t * HD + c4);
    uint2 o;
    o.x = packbf((a.x * s0 + b.x * s1) * inv, (a.y * s0 + b.y * s1) * inv);
    o.y = packbf((a.z * s0 + b.z * s1) * inv, (a.w * s0 + b.w * s1) * inv);
    *(uint2*)(g_ctxh + (size_t)t * 32 + (c4 >> 1)) = o;
}

// ================= stage 6a: out = (ctx @ Wff + bff) * w -> bf16 g_out (BF16 mma) =====
// grid (CAP/128=10, D/128=8, EB=32), 256 threads = 8 warps (4M x 2N)
__global__ void __launch_bounds__(256) outproj_kernel(const float* __restrict__ bff) {
    constexpr int AST = 36, BST = 36;
    extern __shared__ uint32_t dsm[];
    uint32_t* As = dsm;              // ctx [row][kpair] 128x32
    uint32_t* Bs = As + 128 * AST;   // Wfft [n][kpair] 128x32
    int mt = blockIdx.x, nt = blockIdx.y, eb = blockIdx.z;
    int e = eb >> 1;
    int tid = threadIdx.x;
    int lane = tid & 31, w = tid >> 5;
    int lr = lane >> 2, lc = lane & 3;
    int wm = (w & 3) * 32, wn = (w >> 2) * 64;
    int m0 = mt * 128, n0 = nt * 128;

#pragma unroll
    for (int it = 0; it < 4; it++) {
        int idx = tid + it * 256;
        int row = idx >> 3, c = idx & 7;
        cp_async16((uint32_t)__cvta_generic_to_shared(As + row * AST + c * 4),
                   g_ctxh + (size_t)(eb * CAP + m0 + row) * 32 + c * 4);
    }
#pragma unroll
    for (int it = 0; it < 4; it++) {
        int idx = tid + it * 256;
        int n = idx >> 3, c = idx & 7;
        cp_async16((uint32_t)__cvta_generic_to_shared(Bs + n * BST + c * 4),
                   g_wfft + (size_t)(e * 1024 + n0 + n) * 32 + c * 4);
    }
    cp_commit();
    cp_wait0();
    __syncthreads();

    float acc[2][8][4];
#pragma unroll
    for (int mi = 0; mi < 2; mi++)
#pragma unroll
        for (int t8 = 0; t8 < 8; t8++)
#pragma unroll
            for (int r = 0; r < 4; r++) acc[mi][t8][r] = 0.f;

#pragma unroll
    for (int kk = 0; kk < 4; kk++) {
        uint32_t a[2][4];
#pragma unroll
        for (int mi = 0; mi < 2; mi++) {
            const uint32_t* ap = &As[(wm + mi * 16 + lr) * AST + kk * 8 + lc];
            a[mi][0] = ap[0]; a[mi][1] = ap[8 * AST];
            a[mi][2] = ap[4]; a[mi][3] = ap[8 * AST + 4];
        }
#pragma unroll
        for (int t8 = 0; t8 < 8; t8++) {
            const uint32_t* bp = &Bs[(wn + t8 * 8 + lr) * BST + kk * 8 + lc];
#pragma unroll
            for (int mi = 0; mi < 2; mi++)
                mma_bf16(acc[mi][t8][0], acc[mi][t8][1], acc[mi][t8][2], acc[mi][t8][3],
                         a[mi][0], a[mi][1], a[mi][2], a[mi][3], bp[0], bp[4]);
        }
    }

#pragma unroll
    for (int mi = 0; mi < 2; mi++) {
        int row0 = m0 + wm + mi * 16 + lr;
        int row1 = row0 + 8;
        float wv0 = g_w[eb * CAP + row0];
        float wv1 = g_w[eb * CAP + row1];
#pragma unroll
        for (int t8 = 0; t8 < 8; t8++) {
            int col = n0 + wn + t8 * 8 + 2 * lc;
            float2 bf = *(const float2*)(bff + col);
            if (wv0 != 0.f) {
                __nv_bfloat162 v;
                v.x = __float2bfloat16((acc[mi][t8][0] + bf.x) * wv0);
                v.y = __float2bfloat16((acc[mi][t8][1] + bf.y) * wv0);
                *(__nv_bfloat162*)(g_out + ((size_t)eb * CAP + row0) * D + col) = v;
            }
            if (wv1 != 0.f) {
                __nv_bfloat162 v;
                v.x = __float2bfloat16((acc[mi][t8][2] + bf.x) * wv1);
                v.y = __float2bfloat16((acc[mi][t8][3] + bf.y) * wv1);
                *(__nv_bfloat162*)(g_out + ((size_t)eb * CAP + row1) * D + col) = v;
            }
        }
    }
}

// ================= stage 6b: gather-combine + residual + LayerNorm =================
__global__ void ln_kernel(const float* __restrict__ x,
                          const float* __restrict__ gamma,
                          const float* __restrict__ beta,
                          float* __restrict__ out) {
    int token = blockIdx.x;
    int b = token >> 11;
    int tid = threadIdx.x;
    __shared__ int sh_base[E];
    __shared__ float red[8];
    if (tid < E) {
        int p = g_inv[tid * NTOK + token];
        int base = -1;
        if (p >= 0) {
            int idx = (tid * B + b) * CAP + p;
            if (g_w[idx] != 0.f) base = idx;
        }
        sh_base[tid] = base;
    }
    __syncthreads();
    float4 c = make_float4(0.f, 0.f, 0.f, 0.f);
#pragma unroll
    for (int e = 0; e < E; e++) {
        int base = sh_base[e];
        if (base >= 0) {
            uint2 u = *(const uint2*)(g_out + (size_t)base * D + tid * 4);
            __nv_bfloat162 p0 = *reinterpret_cast<__nv_bfloat162*>(&u.x);
            __nv_bfloat162 p1 = *reinterpret_cast<__nv_bfloat162*>(&u.y);
            c.x += __bfloat162float(p0.x); c.y += __bfloat162float(p0.y);
            c.z += __bfloat162float(p1.x); c.w += __bfloat162float(p1.y);
        }
    }
    float4 x4 = *(const float4*)(x + (size_t)token * D + tid * 4);
    float h[4] = {x4.x + c.x, x4.y + c.y, x4.z + c.z, x4.w + c.w};
    float s = h[0] + h[1] + h[2] + h[3];
#pragma unroll
    for (int off = 16; off > 0; off >>= 1) s += __shfl_xor_sync(0xffffffffu, s, off);
    int warp = tid >> 5, lane = tid & 31;
    if (lane == 0) red[warp] = s;
    __syncthreads();
    float total = 0.f;
#pragma unroll
    for (int w = 0; w < 8; w++) total += red[w];
    __syncthreads();
    float mu = total * (1.0f / D);
    float ss = 0.f;
#pragma unroll
    for (int t = 0; t < 4; t++) {
        float dlt = h[t] - mu;
        ss += dlt * dlt;
    }
#pragma unroll
    for (int off = 16; off > 0; off >>= 1) ss += __shfl_xor_sync(0xffffffffu, ss, off);
    if (lane == 0) red[warp] = ss;
    __syncthreads();
    float vtot = 0.f;
#pragma unroll
    for (int w = 0; w < 8; w++) vtot += red[w];
    float var = vtot * (1.0f / D);
    float inv = rsqrtf(var + 1e-5f);
    float4 g4 = *(const float4*)(gamma + tid * 4);
    float4 be4 = *(const float4*)(beta + tid * 4);
    float4 o4;
    o4.x = (h[0] - mu) * inv * g4.x + be4.x;
    o4.y = (h[1] - mu) * inv * g4.y + be4.y;
    o4.z = (h[2] - mu) * inv * g4.z + be4.z;
    o4.w = (h[3] - mu) * inv * g4.w + be4.w;
    *(float4*)(out + (size_t)token * D + tid * 4) = o4;
}

// ================= launch =================
extern "C" void kernel_launch(void* const* d_in, const int* in_sizes, int n_in,
                              void* d_out, int out_size) {
    const float* x     = (const float*)d_in[0];
    const float* wg    = (const float*)d_in[1];
    const float* bg    = (const float*)d_in[2];
    const float* Wq    = (const float*)d_in[3];
    const float* Wkv   = (const float*)d_in[4];
    const float* Wff   = (const float*)d_in[5];
    const float* bff   = (const float*)d_in[6];
    const float* gamma = (const float*)d_in[7];
    const float* beta  = (const float*)d_in[8];
    float* out = (float*)d_out;

    (void)in_sizes; (void)n_in; (void)out_size;

    xpack_kernel<<<NTOK * 512 / 256, 256>>>(x);
    wt_kernel<<<dim3(E, D / 64, 3), 256>>>(Wq, Wkv);
    wff_kernel<<<dim3(E, D / 64), 256>>>(Wff);

    gate_kernel<<<NTOK / 8, 256>>>(x, wg, bg);
    route_kernel<<<(S * E + 255) / 256, 256>>>();
    mask_kernel<<<dim3(EB, 8), 256>>>();
    select_kernel<<<EB, 256>>>();

    int proj_smem = 2 * (64 * 36 + 192 * 36) * (int)sizeof(uint32_t);  // 73,728 B
    cudaFuncSetAttribute(proj_kernel, cudaFuncAttributeMaxDynamicSharedMemorySize, proj_smem);
    proj_kernel<<<dim3(CAP / 64, EB), 256, proj_smem>>>();

    rope_kernel<<<(EB * CAP * 16 + 255) / 256, 256>>>();

    int attn_smem = 384 * 36 * (int)sizeof(uint32_t);   // 55,296 B
    cudaFuncSetAttribute(attn_kernel, cudaFuncAttributeMaxDynamicSharedMemorySize, attn_smem);
    attn_kernel<<<dim3(CAP / 128, EB, 2), 256, attn_smem>>>();

    combine_kernel<<<(EB * CAP * 16 + 255) / 256, 256>>>();

    int op_smem = 2 * 128 * 36 * (int)sizeof(uint32_t);  // 36,864 B
    cudaFuncSetAttribute(outproj_kernel, cudaFuncAttributeMaxDynamicSharedMemorySize, op_smem);
    outproj_kernel<<<dim3(CAP / 128, D / 128, EB), 256, op_smem>>>(bff);

    ln_kernel<<<NTOK, 256>>>(x, gamma, beta, out);
}

// round 11
// speedup vs baseline: 4.9492x; 1.0606x over previous
#include <cuda_runtime.h>
#include <cuda_bf16.h>
#include <math.h>
#include <stdint.h>

// ---------------- problem constants ----------------
namespace {
constexpr int B = 2, S = 2048, D = 1024, E = 16, HD = 64, CAP = 1280, TOPK = 8;
constexpr float EPS = 1e-6f;
constexpr int EB = E * B;    // 32
constexpr int NTOK = B * S;  // 4096
}

// ---------------- scratch (device globals; no allocation allowed) ----------------
__device__ float g_route[NTOK * E];
__device__ float g_wgt[E * D];                          // gate weights transposed [e][d]
__device__ unsigned char g_mask[EB * S];
__device__ int   g_seq[EB * CAP];
__device__ float g_w[EB * CAP];
__device__ int   g_inv[E * NTOK];
__device__ uint32_t g_xh[NTOK * 512];                   // x packed bf16x2 along D
__device__ uint32_t g_wt[(size_t)E * 192 * 512];        // Wq|Wkv transposed: [e][n][kpair]
__device__ uint32_t g_wfft[(size_t)E * 1024 * 32];      // Wff transposed: [e][n][kpair]
__device__ uint32_t g_qh[EB * CAP * 32];                // q bf16x2 pairs along HD
__device__ uint32_t g_kh[EB * CAP * 32];                // k bf16x2 pairs along HD
__device__ __nv_bfloat16 g_vt[(size_t)EB * HD * CAP];   // V transposed [eb][col][row]
__device__ uint32_t g_ctxh[EB * CAP * 32];              // ctx packed bf16x2 along HD
__device__ float g_opart[2 * EB * CAP * HD];
__device__ float g_pm[2 * EB * CAP];
__device__ float g_pl[2 * EB * CAP];
__device__ __nv_bfloat16 g_out[(size_t)EB * CAP * D];

// ---------------- helpers ----------------
__device__ __forceinline__ void mma_bf16(float& c0, float& c1, float& c2, float& c3,
                                         uint32_t a0, uint32_t a1, uint32_t a2, uint32_t a3,
                                         uint32_t b0, uint32_t b1) {
    asm volatile(
        "mma.sync.aligned.m16n8k16.row.col.f32.bf16.bf16.f32 "
        "{%0,%1,%2,%3}, {%4,%5,%6,%7}, {%8,%9}, {%0,%1,%2,%3};\n"
        : "+f"(c0), "+f"(c1), "+f"(c2), "+f"(c3)
        : "r"(a0), "r"(a1), "r"(a2), "r"(a3), "r"(b0), "r"(b1));
}
__device__ __forceinline__ uint32_t packbf(float a, float b) {
    __nv_bfloat162 t = __floats2bfloat162_rn(a, b);
    return *reinterpret_cast<uint32_t*>(&t);
}
__device__ __forceinline__ void cp_async16(uint32_t saddr, const void* g) {
    asm volatile("cp.async.ca.shared.global [%0], [%1], 16;" :: "r"(saddr), "l"(g));
}
__device__ __forceinline__ void cp_commit() { asm volatile("cp.async.commit_group;"); }
__device__ __forceinline__ void cp_wait0()  { asm volatile("cp.async.wait_group 0;"); }
__device__ __forceinline__ void cp_wait1()  { asm volatile("cp.async.wait_group 1;"); }

// ================= prep: pack x to bf16 pairs =================
__global__ void xpack_kernel(const float* __restrict__ x) {
    int idx = blockIdx.x * 256 + threadIdx.x;     // NTOK*512
    float2 v = *(const float2*)(x + (size_t)idx * 2);
    g_xh[idx] = packbf(v.x, v.y);
}

// ================= prep: transpose gate weights =================
__global__ void wgt_kernel(const float* __restrict__ wg) {
    int idx = blockIdx.x * 256 + threadIdx.x;    // 0..16383
    int d = idx >> 4, e = idx & 15;
    g_wgt[e * D + d] = wg[idx];
}

// ================= prep: transpose-pack Wq|Wkv -> g_wt[e][n][kpair] =================
__global__ void wt_kernel(const float* __restrict__ Wq, const float* __restrict__ Wkv) {
    __shared__ float sm[64][65];
    int e = blockIdx.x, k0 = blockIdx.y * 64, n0 = blockIdx.z * 64;
    const float* src;
    int stride;
    if (n0 < 64) { src = Wq + (size_t)e * D * HD + n0; stride = HD; }
    else         { src = Wkv + (size_t)e * D * 128 + (n0 - 64); stride = 128; }
    int tid = threadIdx.x;
#pragma unroll
    for (int i = 0; i < 16; i++) {
        int idx = tid + i * 256;
        int kk = idx >> 6, nn = idx & 63;
        sm[kk][nn] = src[(size_t)(k0 + kk) * stride + nn];
    }
    __syncthreads();
#pragma unroll
    for (int i = 0; i < 8; i++) {
        int idx = tid + i * 256;
        int n = idx >> 5, kp = idx & 31;
        g_wt[((size_t)(e * 192 + n0 + n)) * 512 + (k0 >> 1) + kp] =
            packbf(sm[2 * kp][n], sm[2 * kp + 1][n]);
    }
}

// ================= prep: transpose-pack Wff -> g_wfft[e][n][kpair] =================
__global__ void wff_kernel(const float* __restrict__ Wff) {
    __shared__ float sm[64][65];
    int e = blockIdx.x, n0 = blockIdx.y * 64;
    int tid = threadIdx.x;
#pragma unroll
    for (int i = 0; i < 16; i++) {
        int idx = tid + i * 256;
        int kk = idx >> 6, nn = idx & 63;
        sm[kk][nn] = Wff[(size_t)e * HD * D + (size_t)kk * D + n0 + nn];
    }
    __syncthreads();
#pragma unroll
    for (int i = 0; i < 8; i++) {
        int idx = tid + i * 256;
        int n = idx >> 5, kp = idx & 31;
        g_wfft[((size_t)(e * 1024 + n0 + n)) * 32 + kp] =
            packbf(sm[2 * kp][n], sm[2 * kp + 1][n]);
    }
}

// ================= stage 1: gating (warp-per-token, lane-owns-d-slice) =================
__global__ void __launch_bounds__(256) gate_kernel(const float* __restrict__ x,
                                                   const float* __restrict__ bg) {
    int warp = threadIdx.x >> 5;
    int lane = threadIdx.x & 31;
    int token = blockIdx.x * 8 + warp;
    const float4* xr = (const float4*)(x + (size_t)token * D);
    float acc[E];
#pragma unroll
    for (int e = 0; e < E; e++) acc[e] = 0.f;
#pragma unroll
    for (int it = 0; it < 8; it++) {
        float4 xv = xr[lane + it * 32];
#pragma unroll
        for (int e = 0; e < E; e++) {
            float4 wv = *(const float4*)(g_wgt + e * D + (lane + it * 32) * 4);
            acc[e] += xv.x * wv.x + xv.y * wv.y + xv.z * wv.z + xv.w * wv.w;
        }
    }
#pragma unroll
    for (int off = 16; off; off >>= 1) {
#pragma unroll
        for (int e = 0; e < E; e++)
            acc[e] += __shfl_xor_sync(0xffffffffu, acc[e], off);
    }
    if (lane == 0) {
        float g[E];
        float mx = -3.402823466e38f;
#pragma unroll
        for (int e = 0; e < E; e++) {
            g[e] = acc[e] + bg[e];
            mx = fmaxf(mx, g[e]);
        }
        float den = 0.f;
#pragma unroll
        for (int e = 0; e < E; e++) { g[e] = expf(g[e] - mx); den += g[e]; }
        float inv = 1.f / den;
#pragma unroll
        for (int e = 0; e < E; e++) g[e] *= inv;
#pragma unroll
        for (int e = 0; e < E; e++) {
            int r = 0;
#pragma unroll
            for (int j = 0; j < E; j++)
                r += (g[j] > g[e]) || (g[j] == g[e] && j < e);
            g_route[(size_t)token * E + e] = (r < TOPK) ? g[e] : 0.f;
        }
    }
}

// ================= stage 2: route normalize =================
__global__ void route_kernel() {
    int idx = blockIdx.x * blockDim.x + threadIdx.x;
    if (idx >= S * E) return;
    int s = idx / E, e = idx % E;
    float m0 = g_route[(size_t)s * E + e];
    float m1 = g_route[(size_t)(S + s) * E + e];
    float den = m0 + m1 + EPS;
    g_route[(size_t)s * E + e]       = m0 / den * 2.0f;
    g_route[(size_t)(S + s) * E + e] = m1 / den * 2.0f;
}

// ================= stage 3a: rank mask (float4 inner loop) =================
__global__ void mask_kernel() {
    int eb = blockIdx.x;
    int e = eb >> 1, b = eb & 1;
    __shared__ float sv[S];
    int tid = threadIdx.x;
    for (int s = tid; s < S; s += 256)
        sv[s] = g_route[(size_t)(b * S + s) * E + e];
    __syncthreads();
    int i = blockIdx.y * 256 + tid;
    float vi = sv[i];
    int c = 0;
#pragma unroll 4
    for (int j4 = 0; j4 < S / 4; j4++) {
        float4 v = *(const float4*)(sv + j4 * 4);
        int j = j4 * 4;
        c += (v.x > vi) || (v.x == vi && (j + 0) < i);
        c += (v.y > vi) || (v.y == vi && (j + 1) < i);
        c += (v.z > vi) || (v.z == vi && (j + 2) < i);
        c += (v.w > vi) || (v.w == vi && (j + 3) < i);
    }
    g_mask[eb * S + i] = (c < CAP) ? 1 : 0;
}

// ================= stage 3b: compaction =================
__global__ void select_kernel() {
    int eb = blockIdx.x;
    int e = eb >> 1, b = eb & 1;
    __shared__ unsigned char sm[S];
    __shared__ int cnt[256];
    int t = threadIdx.x;
    for (int s = t; s < S; s += 256)
        sm[s] = g_mask[eb * S + s];
    __syncthreads();
    int local = 0;
#pragma unroll
    for (int k = 0; k < 8; k++) local += sm[t * 8 + k];
    cnt[t] = local;
    __syncthreads();
    if (t == 0) {
        int run = 0;
        for (int i = 0; i < 256; i++) { int c = cnt[i]; cnt[i] = run; run += c; }
    }
    __syncthreads();
    int pos = cnt[t];
#pragma unroll
    for (int k = 0; k < 8; k++) {
        int s = t * 8 + k;
        if (sm[s]) {
            g_seq[eb * CAP + pos] = s;
            g_w[eb * CAP + pos] = g_route[(size_t)(b * S + s) * E + e];
            g_inv[e * NTOK + b * S + s] = pos;
            pos++;
        } else {
            g_inv[e * NTOK + b * S + s] = -1;
        }
    }
}

// ================= stage 4a: fused Q/K/V projection, BF16 mma =========
__global__ void __launch_bounds__(256) proj_kernel() {
    constexpr int AST = 36, BST = 36;
    constexpr int AW = 64 * AST;
    constexpr int BW = 192 * BST;
    extern __shared__ uint32_t dsm[];
    uint32_t* As = dsm;
    uint32_t* Bs = dsm + 2 * AW;
    int mt = blockIdx.x, eb = blockIdx.y;
    int e = eb >> 1, b = eb & 1;
    int tid = threadIdx.x;
    int lane = tid & 31, w = tid >> 5;
    int lr = lane >> 2, lc = lane & 3;
    int wm = (w & 1) * 32;
    int wn = (w >> 1) * 48;
    int m0 = mt * 64;

    int r0 = tid >> 3;
    int c = tid & 7;
    int seq0 = g_seq[eb * CAP + m0 + r0];
    int seq1 = g_seq[eb * CAP + m0 + r0 + 32];
    const uint32_t* arow0 = g_xh + (size_t)(b * S + seq0) * 512 + c * 4;
    const uint32_t* arow1 = g_xh + (size_t)(b * S + seq1) * 512 + c * 4;
    uint32_t as0 = r0 * AST + c * 4;
    uint32_t as1 = (r0 + 32) * AST + c * 4;

    const uint32_t* wtbase = g_wt + (size_t)e * 192 * 512;
    const uint32_t* bsrc[6];
    uint32_t bsoff[6];
#pragma unroll
    for (int it = 0; it < 6; it++) {
        int f = tid + it * 256;
        int n = f >> 3, cb = f & 7;
        bsrc[it] = wtbase + (size_t)n * 512 + cb * 4;
        bsoff[it] = n * BST + cb * 4;
    }

    float acc[2][6][4];
#pragma unroll
    for (int i = 0; i < 2; i++)
#pragma unroll
        for (int j = 0; j < 6; j++)
#pragma unroll
            for (int r = 0; r < 4; r++) acc[i][j][r] = 0.f;

    cp_async16((uint32_t)__cvta_generic_to_shared(As + as0), arow0);
    cp_async16((uint32_t)__cvta_generic_to_shared(As + as1), arow1);
#pragma unroll
    for (int it = 0; it < 6; it++)
        cp_async16((uint32_t)__cvta_generic_to_shared(Bs + bsoff[it]), bsrc[it]);
    cp_commit();

    for (int kt = 0; kt < 16; kt++) {
        cp_wait0();
        __syncthreads();
        if (kt + 1 < 16) {
            int s = (kt + 1) & 1;
            int kp0 = (kt + 1) * 32;
            cp_async16((uint32_t)__cvta_generic_to_shared(As + s * AW + as0), arow0 + kp0);
            cp_async16((uint32_t)__cvta_generic_to_shared(As + s * AW + as1), arow1 + kp0);
#pragma unroll
            for (int it = 0; it < 6; it++)
                cp_async16((uint32_t)__cvta_generic_to_shared(Bs + s * BW + bsoff[it]),
                           bsrc[it] + kp0);
            cp_commit();
        }
        int cs = kt & 1;
        const uint32_t* Acur = As + cs * AW;
        const uint32_t* Bcur = Bs + cs * BW;
#pragma unroll
        for (int kk = 0; kk < 4; kk++) {
            uint32_t a[2][4], bb[6][2];
#pragma unroll
            for (int mb = 0; mb < 2; mb++) {
                const uint32_t* ap = &Acur[(wm + mb * 16 + lr) * AST + kk * 8 + lc];
                a[mb][0] = ap[0];
                a[mb][1] = ap[8 * AST];
                a[mb][2] = ap[4];
                a[mb][3] = ap[8 * AST + 4];
            }
#pragma unroll
            for (int nb = 0; nb < 6; nb++) {
                const uint32_t* bp = &Bcur[(wn + nb * 8 + lr) * BST + kk * 8 + lc];
                bb[nb][0] = bp[0];
                bb[nb][1] = bp[4];
            }
#pragma unroll
            for (int mb = 0; mb < 2; mb++)
#pragma unroll
                for (int nb = 0; nb < 6; nb++)
                    mma_bf16(acc[mb][nb][0], acc[mb][nb][1], acc[mb][nb][2], acc[mb][nb][3],
                             a[mb][0], a[mb][1], a[mb][2], a[mb][3],
                             bb[nb][0], bb[nb][1]);
        }
    }

#pragma unroll
    for (int nb = 0; nb < 6; nb++) {
        int colg = wn + nb * 8 + 2 * lc;
#pragma unroll
        for (int mb = 0; mb < 2; mb++) {
            int row0 = m0 + wm + mb * 16 + lr;
            int row1 = row0 + 8;
            if (colg < 64) {
                int pair = colg >> 1;
                g_qh[(eb * CAP + row0) * 32 + pair] = packbf(acc[mb][nb][0], acc[mb][nb][1]);
                g_qh[(eb * CAP + row1) * 32 + pair] = packbf(acc[mb][nb][2], acc[mb][nb][3]);
            } else if (colg < 128) {
                int pair = (colg - 64) >> 1;
                g_kh[(eb * CAP + row0) * 32 + pair] = packbf(acc[mb][nb][0], acc[mb][nb][1]);
                g_kh[(eb * CAP + row1) * 32 + pair] = packbf(acc[mb][nb][2], acc[mb][nb][3]);
            } else {
                int col = colg - 128;
                g_vt[(size_t)(eb * HD + col) * CAP + row0]     = __float2bfloat16(acc[mb][nb][0]);
                g_vt[(size_t)(eb * HD + col + 1) * CAP + row0] = __float2bfloat16(acc[mb][nb][1]);
                g_vt[(size_t)(eb * HD + col) * CAP + row1]     = __float2bfloat16(acc[mb][nb][2]);
                g_vt[(size_t)(eb * HD + col + 1) * CAP + row1] = __float2bfloat16(acc[mb][nb][3]);
            }
        }
    }
}

// ================= stage 4b: RoPE on packed bf16 q/k =================
__global__ void rope_kernel() {
    int idx = blockIdx.x * blockDim.x + threadIdx.x;
    if (idx >= EB * CAP * 16) return;
    int j = idx & 15;
    int t = idx >> 4;
    int pos = g_seq[t];
    float invf0 = exp2f(-(float)(2 * j) * 0.4152410118609203f);
    float invf1 = exp2f(-(float)(2 * j + 1) * 0.4152410118609203f);
    float s0, c0, s1, c1;
    sincosf(pos * invf0, &s0, &c0);
    sincosf(pos * invf1, &s1, &c1);
    uint32_t* q = g_qh + (size_t)t * 32;
    uint32_t* k = g_kh + (size_t)t * 32;
    {
        float2 a = __bfloat1622float2(*(__nv_bfloat162*)&q[j]);
        float2 b = __bfloat1622float2(*(__nv_bfloat162*)&q[j + 16]);
        q[j]      = packbf(a.x * c0 - b.x * s0, a.y * c1 - b.y * s1);
        q[j + 16] = packbf(b.x * c0 + a.x * s0, b.y * c1 + a.y * s1);
    }
    {
        float2 a = __bfloat1622float2(*(__nv_bfloat162*)&k[j]);
        float2 b = __bfloat1622float2(*(__nv_bfloat162*)&k[j + 16]);
        k[j]      = packbf(a.x * c0 - b.x * s0, a.y * c1 - b.y * s1);
        k[j + 16] = packbf(b.x * c0 + a.x * s0, b.y * c1 + a.y * s1);
    }
}

// ================= stage 5: split-KV causal flash attention, BF16 mma =================
__global__ void __launch_bounds__(256, 2) attn_kernel() {
    constexpr int ST = 36;
    extern __shared__ uint32_t dsm[];
    uint32_t* Qs  = dsm;
    uint32_t* Ks  = Qs + 128 * ST;
    uint32_t* Vts = Ks + 64 * ST;
    uint32_t* Ps  = Vts + 64 * ST;
    int mt = 9 - blockIdx.x;
    int eb = blockIdx.y;
    int split = blockIdx.z;
    int m0 = mt * 128;
    const uint32_t* qptr = g_qh + (size_t)eb * CAP * 32;
    const uint32_t* kptr = g_kh + (size_t)eb * CAP * 32;
    const uint32_t* vtptr = (const uint32_t*)g_vt + (size_t)eb * HD * (CAP / 2);
    int tid = threadIdx.x;
    int lane = tid & 31, w = tid >> 5;
    int lr = lane >> 2, lc = lane & 3;
    int wrow = 16 * w;

#pragma unroll
    for (int it = 0; it < 4; it++) {
        int idx = tid + it * 256;
        int row = idx >> 3, c = idx & 7;
        cp_async16((uint32_t)__cvta_generic_to_shared(Qs + row * ST + c * 4),
                   qptr + (size_t)(m0 + row) * 32 + c * 4);
    }
    cp_commit();

    float o[8][4];
#pragma unroll
    for (int t8 = 0; t8 < 8; t8++)
#pragma unroll
        for (int r = 0; r < 4; r++) o[t8][r] = 0.f;
    float mrow0 = -3.402823466e38f, mrow1 = -3.402823466e38f;
    float lsum0 = 0.f, lsum1 = 0.f;

    int half = mt + 1;
    int ntStart = split * half;
    int ntEnd = ntStart + half;
    for (int nt = ntStart; nt < ntEnd; nt++) {
        int n0 = nt * 64;
        __syncthreads();
#pragma unroll
        for (int it = 0; it < 2; it++) {
            int idx = tid + it * 256;
            int row = idx >> 3, c = idx & 7;
            cp_async16((uint32_t)__cvta_generic_to_shared(Ks + row * ST + c * 4),
                       kptr + (size_t)(n0 + row) * 32 + c * 4);
        }
        cp_commit();
#pragma unroll
        for (int it = 0; it < 2; it++) {
            int idx = tid + it * 256;
            int col = idx >> 3, c = idx & 7;
            cp_async16((uint32_t)__cvta_generic_to_shared(Vts + col * ST + c * 4),
                       vtptr + (size_t)col * (CAP / 2) + (n0 >> 1) + c * 4);
        }
        cp_commit();
        cp_wait1();
        __syncthreads();

        float sacc[8][4];
#pragma unroll
        for (int t8 = 0; t8 < 8; t8++)
#pragma unroll
            for (int r = 0; r < 4; r++) sacc[t8][r] = 0.f;
#pragma unroll
        for (int kk = 0; kk < 4; kk++) {
            const uint32_t* ap = &Qs[(wrow + lr) * ST + kk * 8 + lc];
            uint32_t a0 = ap[0], a1 = ap[8 * ST], a2 = ap[4], a3 = ap[8 * ST + 4];
#pragma unroll
            for (int t8 = 0; t8 < 8; t8++) {
                const uint32_t* bp = &Ks[(t8 * 8 + lr) * ST + kk * 8 + lc];
                mma_bf16(sacc[t8][0], sacc[t8][1], sacc[t8][2], sacc[t8][3],
                         a0, a1, a2, a3, bp[0], bp[4]);
            }
        }

        bool maskT = (nt >= 2 * mt);
#pragma unroll
        for (int t8 = 0; t8 < 8; t8++) {
            int cbase = n0 + t8 * 8 + 2 * lc;
#pragma unroll
            for (int r = 0; r < 4; r++) {
                float v = sacc[t8][r] * 0.125f;
                if (maskT) {
                    int row = m0 + wrow + lr + ((r >= 2) ? 8 : 0);
                    int col = cbase + (r & 1);
                    if (col > row) v = -3.402823466e38f;
                }
                sacc[t8][r] = v;
            }
        }

        float mx0 = -3.402823466e38f, mx1 = -3.402823466e38f;
#pragma unroll
        for (int t8 = 0; t8 < 8; t8++) {
            mx0 = fmaxf(mx0, fmaxf(sacc[t8][0], sacc[t8][1]));
            mx1 = fmaxf(mx1, fmaxf(sacc[t8][2], sacc[t8][3]));
        }
        mx0 = fmaxf(mx0, __shfl_xor_sync(0xffffffffu, mx0, 1));
        mx0 = fmaxf(mx0, __shfl_xor_sync(0xffffffffu, mx0, 2));
        mx1 = fmaxf(mx1, __shfl_xor_sync(0xffffffffu, mx1, 1));
        mx1 = fmaxf(mx1, __shfl_xor_sync(0xffffffffu, mx1, 2));
        float nm0 = fmaxf(mrow0, mx0), nm1 = fmaxf(mrow1, mx1);
        float corr0 = __expf(mrow0 - nm0), corr1 = __expf(mrow1 - nm1);
        float rs0 = 0.f, rs1 = 0.f;
#pragma unroll
        for (int t8 = 0; t8 < 8; t8++) {
            float p0 = __expf(sacc[t8][0] - nm0);
            float p1 = __expf(sacc[t8][1] - nm0);
            float p2 = __expf(sacc[t8][2] - nm1);
            float p3 = __expf(sacc[t8][3] - nm1);
            rs0 += p0 + p1; rs1 += p2 + p3;
            Ps[(wrow + lr) * ST + t8 * 4 + lc]     = packbf(p0, p1);
            Ps[(wrow + lr + 8) * ST + t8 * 4 + lc] = packbf(p2, p3);
        }
        rs0 += __shfl_xor_sync(0xffffffffu, rs0, 1);
        rs0 += __shfl_xor_sync(0xffffffffu, rs0, 2);
        rs1 += __shfl_xor_sync(0xffffffffu, rs1, 1);
        rs1 += __shfl_xor_sync(0xffffffffu, rs1, 2);
        lsum0 = lsum0 * corr0 + rs0;
        lsum1 = lsum1 * corr1 + rs1;
        mrow0 = nm0; mrow1 = nm1;
#pragma unroll
        for (int t8 = 0; t8 < 8; t8++) {
            o[t8][0] *= corr0; o[t8][1] *= corr0;
            o[t8][2] *= corr1; o[t8][3] *= corr1;
        }

        cp_wait0();
        __syncthreads();
        __syncwarp();

#pragma unroll
        for (int kk = 0; kk < 4; kk++) {
            const uint32_t* ap = &Ps[(wrow + lr) * ST + kk * 8 + lc];
            uint32_t a0 = ap[0], a1 = ap[8 * ST], a2 = ap[4], a3 = ap[8 * ST + 4];
#pragma unroll
            for (int t8 = 0; t8 < 8; t8++) {
                const uint32_t* bp = &Vts[(t8 * 8 + lr) * ST + kk * 8 + lc];
                mma_bf16(o[t8][0], o[t8][1], o[t8][2], o[t8][3],
                         a0, a1, a2, a3, bp[0], bp[4]);
            }
        }
    }

    int row0 = m0 + wrow + lr, row1 = row0 + 8;
    float* op = g_opart + (size_t)split * EB * CAP * HD;
#pragma unroll
    for (int t8 = 0; t8 < 8; t8++) {
        int col = t8 * 8 + 2 * lc;
        *(float2*)(op + ((size_t)eb * CAP + row0) * HD + col) = make_float2(o[t8][0], o[t8][1]);
        *(float2*)(op + ((size_t)eb * CAP + row1) * HD + col) = make_float2(o[t8][2], o[t8][3]);
    }
    if (lc == 0) {
        int base = split * EB * CAP + eb * CAP;
        g_pm[base + row0] = mrow0;
        g_pl[base + row0] = lsum0;
        g_pm[base + row1] = mrow1;
        g_pl[base + row1] = lsum1;
    }
}

// ================= stage 5b: combine splits -> packed bf16 ctx =================
__global__ void combine_kernel() {
    int idx = blockIdx.x * blockDim.x + threadIdx.x;
    if (idx >= EB * CAP * 16) return;
    int t = idx >> 4;
    int c4 = (idx & 15) << 2;
    float m0 = g_pm[t], m1 = g_pm[EB * CAP + t];
    float l0 = g_pl[t], l1 = g_pl[EB * CAP + t];
    float M = fmaxf(m0, m1);
    float s0 = __expf(m0 - M), s1 = __expf(m1 - M);
    float inv = 1.f / (l0 * s0 + l1 * s1);
    const float4 a = *(const float4*)(g_opart + (size_t)t * HD + c4);
    const float4 b = *(const float4*)(g_opart + (size_t)EB * CAP * HD + (size_t)t * HD + c4);
    uint2 o;
    o.x = packbf((a.x * s0 + b.x * s1) * inv, (a.y * s0 + b.y * s1) * inv);
    o.y = packbf((a.z * s0 + b.z * s1) * inv, (a.w * s0 + b.w * s1) * inv);
    *(uint2*)(g_ctxh + (size_t)t * 32 + (c4 >> 1)) = o;
}

// ================= stage 6a: out = (ctx @ Wff + bff) * w -> bf16 g_out (BF16 mma) =====
__global__ void __launch_bounds__(256) outproj_kernel(const float* __restrict__ bff) {
    constexpr int AST = 36, BST = 36;
    extern __shared__ uint32_t dsm[];
    uint32_t* As = dsm;
    uint32_t* Bs = As + 128 * AST;
    int mt = blockIdx.x, nt = blockIdx.y, eb = blockIdx.z;
    int e = eb >> 1;
    int tid = threadIdx.x;
    int lane = tid & 31, w = tid >> 5;
    int lr = lane >> 2, lc = lane & 3;
    int wm = (w & 3) * 32, wn = (w >> 2) * 64;
    int m0 = mt * 128, n0 = nt * 128;

#pragma unroll
    for (int it = 0; it < 4; it++) {
        int idx = tid + it * 256;
        int row = idx >> 3, c = idx & 7;
        cp_async16((uint32_t)__cvta_generic_to_shared(As + row * AST + c * 4),
                   g_ctxh + (size_t)(eb * CAP + m0 + row) * 32 + c * 4);
    }
#pragma unroll
    for (int it = 0; it < 4; it++) {
        int idx = tid + it * 256;
        int n = idx >> 3, c = idx & 7;
        cp_async16((uint32_t)__cvta_generic_to_shared(Bs + n * BST + c * 4),
                   g_wfft + (size_t)(e * 1024 + n0 + n) * 32 + c * 4);
    }
    cp_commit();
    cp_wait0();
    __syncthreads();

    float acc[2][8][4];
#pragma unroll
    for (int mi = 0; mi < 2; mi++)
#pragma unroll
        for (int t8 = 0; t8 < 8; t8++)
#pragma unroll
            for (int r = 0; r < 4; r++) acc[mi][t8][r] = 0.f;

#pragma unroll
    for (int kk = 0; kk < 4; kk++) {
        uint32_t a[2][4];
#pragma unroll
        for (int mi = 0; mi < 2; mi++) {
            const uint32_t* ap = &As[(wm + mi * 16 + lr) * AST + kk * 8 + lc];
            a[mi][0] = ap[0]; a[mi][1] = ap[8 * AST];
            a[mi][2] = ap[4]; a[mi][3] = ap[8 * AST + 4];
        }
#pragma unroll
        for (int t8 = 0; t8 < 8; t8++) {
            const uint32_t* bp = &Bs[(wn + t8 * 8 + lr) * BST + kk * 8 + lc];
#pragma unroll
            for (int mi = 0; mi < 2; mi++)
                mma_bf16(acc[mi][t8][0], acc[mi][t8][1], acc[mi][t8][2], acc[mi][t8][3],
                         a[mi][0], a[mi][1], a[mi][2], a[mi][3], bp[0], bp[4]);
        }
    }

#pragma unroll
    for (int mi = 0; mi < 2; mi++) {
        int row0 = m0 + wm + mi * 16 + lr;
        int row1 = row0 + 8;
        float wv0 = g_w[eb * CAP + row0];
        float wv1 = g_w[eb * CAP + row1];
#pragma unroll
        for (int t8 = 0; t8 < 8; t8++) {
            int col = n0 + wn + t8 * 8 + 2 * lc;
            float2 bf = *(const float2*)(bff + col);
            if (wv0 != 0.f) {
                __nv_bfloat162 v;
                v.x = __float2bfloat16((acc[mi][t8][0] + bf.x) * wv0);
                v.y = __float2bfloat16((acc[mi][t8][1] + bf.y) * wv0);
                *(__nv_bfloat162*)(g_out + ((size_t)eb * CAP + row0) * D + col) = v;
            }
            if (wv1 != 0.f) {
                __nv_bfloat162 v;
                v.x = __float2bfloat16((acc[mi][t8][2] + bf.x) * wv1);
                v.y = __float2bfloat16((acc[mi][t8][3] + bf.y) * wv1);
                *(__nv_bfloat162*)(g_out + ((size_t)eb * CAP + row1) * D + col) = v;
            }
        }
    }
}

// ================= stage 6b: gather-combine + residual + LayerNorm =================
__global__ void ln_kernel(const float* __restrict__ x,
                          const float* __restrict__ gamma,
                          const float* __restrict__ beta,
                          float* __restrict__ out) {
    int token = blockIdx.x;
    int b = token >> 11;
    int tid = threadIdx.x;
    __shared__ int sh_base[E];
    __shared__ float red[8];
    if (tid < E) {
        int p = g_inv[tid * NTOK + token];
        int base = -1;
        if (p >= 0) {
            int idx = (tid * B + b) * CAP + p;
            if (g_w[idx] != 0.f) base = idx;
        }
        sh_base[tid] = base;
    }
    __syncthreads();
    float4 c = make_float4(0.f, 0.f, 0.f, 0.f);
#pragma unroll
    for (int e = 0; e < E; e++) {
        int base = sh_base[e];
        if (base >= 0) {
            uint2 u = *(const uint2*)(g_out + (size_t)base * D + tid * 4);
            __nv_bfloat162 p0 = *reinterpret_cast<__nv_bfloat162*>(&u.x);
            __nv_bfloat162 p1 = *reinterpret_cast<__nv_bfloat162*>(&u.y);
            c.x += __bfloat162float(p0.x); c.y += __bfloat162float(p0.y);
            c.z += __bfloat162float(p1.x); c.w += __bfloat162float(p1.y);
        }
    }
    float4 x4 = *(const float4*)(x + (size_t)token * D + tid * 4);
    float h[4] = {x4.x + c.x, x4.y + c.y, x4.z + c.z, x4.w + c.w};
    float s = h[0] + h[1] + h[2] + h[3];
#pragma unroll
    for (int off = 16; off > 0; off >>= 1) s += __shfl_xor_sync(0xffffffffu, s, off);
    int warp = tid >> 5, lane = tid & 31;
    if (lane == 0) red[warp] = s;
    __syncthreads();
    float total = 0.f;
#pragma unroll
    for (int w = 0; w < 8; w++) total += red[w];
    __syncthreads();
    float mu = total * (1.0f / D);
    float ss = 0.f;
#pragma unroll
    for (int t = 0; t < 4; t++) {
        float dlt = h[t] - mu;
        ss += dlt * dlt;
    }
#pragma unroll
    for (int off = 16; off > 0; off >>= 1) ss += __shfl_xor_sync(0xffffffffu, ss, off);
    if (lane == 0) red[warp] = ss;
    __syncthreads();
    float vtot = 0.f;
#pragma unroll
    for (int w = 0; w < 8; w++) vtot += red[w];
    float var = vtot * (1.0f / D);
    float inv = rsqrtf(var + 1e-5f);
    float4 g4 = *(const float4*)(gamma + tid * 4);
    float4 be4 = *(const float4*)(beta + tid * 4);
    float4 o4;
    o4.x = (h[0] - mu) * inv * g4.x + be4.x;
    o4.y = (h[1] - mu) * inv * g4.y + be4.y;
    o4.z = (h[2] - mu) * inv * g4.z + be4.z;
    o4.w = (h[3] - mu) * inv * g4.w + be4.w;
    *(float4*)(out + (size_t)token * D + tid * 4) = o4;
}

// ================= launch =================
extern "C" void kernel_launch(void* const* d_in, const int* in_sizes, int n_in,
                              void* d_out, int out_size) {
    const float* x     = (const float*)d_in[0];
    const float* wg    = (const float*)d_in[1];
    const float* bg    = (const float*)d_in[2];
    const float* Wq    = (const float*)d_in[3];
    const float* Wkv   = (const float*)d_in[4];
    const float* Wff   = (const float*)d_in[5];
    const float* bff   = (const float*)d_in[6];
    const float* gamma = (const float*)d_in[7];
    const float* beta  = (const float*)d_in[8];
    float* out = (float*)d_out;

    (void)in_sizes; (void)n_in; (void)out_size;

    wgt_kernel<<<E * D / 256, 256>>>(wg);
    xpack_kernel<<<NTOK * 512 / 256, 256>>>(x);
    wt_kernel<<<dim3(E, D / 64, 3), 256>>>(Wq, Wkv);
    wff_kernel<<<dim3(E, D / 64), 256>>>(Wff);

    gate_kernel<<<NTOK / 8, 256>>>(x, bg);
    route_kernel<<<(S * E + 255) / 256, 256>>>();
    mask_kernel<<<dim3(EB, 8), 256>>>();
    select_kernel<<<EB, 256>>>();

    int proj_smem = 2 * (64 * 36 + 192 * 36) * (int)sizeof(uint32_t);  // 73,728 B
    cudaFuncSetAttribute(proj_kernel, cudaFuncAttributeMaxDynamicSharedMemorySize, proj_smem);
    proj_kernel<<<dim3(CAP / 64, EB), 256, proj_smem>>>();

    rope_kernel<<<(EB * CAP * 16 + 255) / 256, 256>>>();

    int attn_smem = 384 * 36 * (int)sizeof(uint32_t);   // 55,296 B
    cudaFuncSetAttribute(attn_kernel, cudaFuncAttributeMaxDynamicSharedMemorySize, attn_smem);
    attn_kernel<<<dim3(CAP / 128, EB, 2), 256, attn_smem>>>();

    combine_kernel<<<(EB * CAP * 16 + 255) / 256, 256>>>();

    int op_smem = 2 * 128 * 36 * (int)sizeof(uint32_t);  // 36,864 B
    cudaFuncSetAttribute(outproj_kernel, cudaFuncAttributeMaxDynamicSharedMemorySize, op_smem);
    outproj_kernel<<<dim3(CAP / 128, D / 128, EB), 256, op_smem>>>(bff);

    ln_kernel<<<NTOK, 256>>>(x, gamma, beta, out);
}

// round 12
// speedup vs baseline: 5.0361x; 1.0176x over previous
#include <cuda_runtime.h>
#include <cuda_bf16.h>
#include <math.h>
#include <stdint.h>

// ---------------- problem constants ----------------
namespace {
constexpr int B = 2, S = 2048, D = 1024, E = 16, HD = 64, CAP = 1280, TOPK = 8;
constexpr float EPS = 1e-6f;
constexpr int EB = E * B;    // 32
constexpr int NTOK = B * S;  // 4096
}

// ---------------- scratch (device globals; no allocation allowed) ----------------
__device__ float g_route[NTOK * E];
__device__ float g_routeT[EB * S];                      // transposed route for select
__device__ float g_wgt[E * D];                          // gate weights transposed [e][d]
__device__ unsigned char g_mask[EB * S];
__device__ int   g_seq[EB * CAP];
__device__ float g_w[EB * CAP];
__device__ int   g_inv[E * NTOK];
__device__ uint32_t g_xh[NTOK * 512];                   // x packed bf16x2 along D
__device__ uint32_t g_wt[(size_t)E * 192 * 512];        // Wq|Wkv transposed: [e][n][kpair]
__device__ uint32_t g_wfft[(size_t)E * 1024 * 32];      // Wff transposed: [e][n][kpair]
__device__ uint32_t g_qh[EB * CAP * 32];                // q bf16x2 pairs along HD
__device__ uint32_t g_kh[EB * CAP * 32];                // k bf16x2 pairs along HD
__device__ __nv_bfloat16 g_vt[(size_t)EB * HD * CAP];   // V transposed [eb][col][row]
__device__ uint32_t g_ctxh[EB * CAP * 32];              // ctx packed bf16x2 along HD
__device__ float g_opart[2 * EB * CAP * HD];
__device__ float g_pm[2 * EB * CAP];
__device__ float g_pl[2 * EB * CAP];
__device__ __nv_bfloat16 g_out[(size_t)EB * CAP * D];

// ---------------- helpers ----------------
__device__ __forceinline__ void mma_bf16(float& c0, float& c1, float& c2, float& c3,
                                         uint32_t a0, uint32_t a1, uint32_t a2, uint32_t a3,
                                         uint32_t b0, uint32_t b1) {
    asm volatile(
        "mma.sync.aligned.m16n8k16.row.col.f32.bf16.bf16.f32 "
        "{%0,%1,%2,%3}, {%4,%5,%6,%7}, {%8,%9}, {%0,%1,%2,%3};\n"
        : "+f"(c0), "+f"(c1), "+f"(c2), "+f"(c3)
        : "r"(a0), "r"(a1), "r"(a2), "r"(a3), "r"(b0), "r"(b1));
}
__device__ __forceinline__ uint32_t packbf(float a, float b) {
    __nv_bfloat162 t = __floats2bfloat162_rn(a, b);
    return *reinterpret_cast<uint32_t*>(&t);
}
__device__ __forceinline__ void cp_async16(uint32_t saddr, const void* g) {
    asm volatile("cp.async.ca.shared.global [%0], [%1], 16;" :: "r"(saddr), "l"(g));
}
__device__ __forceinline__ void cp_commit() { asm volatile("cp.async.commit_group;"); }
__device__ __forceinline__ void cp_wait0()  { asm volatile("cp.async.wait_group 0;"); }
__device__ __forceinline__ void cp_wait1()  { asm volatile("cp.async.wait_group 1;"); }

// ================= prep: pack x to bf16 pairs =================
__global__ void xpack_kernel(const float* __restrict__ x) {
    int idx = blockIdx.x * 256 + threadIdx.x;     // NTOK*512
    float2 v = *(const float2*)(x + (size_t)idx * 2);
    g_xh[idx] = packbf(v.x, v.y);
}

// ================= prep: transpose gate weights =================
__global__ void wgt_kernel(const float* __restrict__ wg) {
    int idx = blockIdx.x * 256 + threadIdx.x;    // 0..16383
    int d = idx >> 4, e = idx & 15;
    g_wgt[e * D + d] = wg[idx];
}

// ================= prep: transpose-pack Wq|Wkv -> g_wt[e][n][kpair] =================
__global__ void wt_kernel(const float* __restrict__ Wq, const float* __restrict__ Wkv) {
    __shared__ float sm[64][65];
    int e = blockIdx.x, k0 = blockIdx.y * 64, n0 = blockIdx.z * 64;
    const float* src;
    int stride;
    if (n0 < 64) { src = Wq + (size_t)e * D * HD + n0; stride = HD; }
    else         { src = Wkv + (size_t)e * D * 128 + (n0 - 64); stride = 128; }
    int tid = threadIdx.x;
#pragma unroll
    for (int i = 0; i < 16; i++) {
        int idx = tid + i * 256;
        int kk = idx >> 6, nn = idx & 63;
        sm[kk][nn] = src[(size_t)(k0 + kk) * stride + nn];
    }
    __syncthreads();
#pragma unroll
    for (int i = 0; i < 8; i++) {
        int idx = tid + i * 256;
        int n = idx >> 5, kp = idx & 31;
        g_wt[((size_t)(e * 192 + n0 + n)) * 512 + (k0 >> 1) + kp] =
            packbf(sm[2 * kp][n], sm[2 * kp + 1][n]);
    }
}

// ================= prep: transpose-pack Wff -> g_wfft[e][n][kpair] =================
__global__ void wff_kernel(const float* __restrict__ Wff) {
    __shared__ float sm[64][65];
    int e = blockIdx.x, n0 = blockIdx.y * 64;
    int tid = threadIdx.x;
#pragma unroll
    for (int i = 0; i < 16; i++) {
        int idx = tid + i * 256;
        int kk = idx >> 6, nn = idx & 63;
        sm[kk][nn] = Wff[(size_t)e * HD * D + (size_t)kk * D + n0 + nn];
    }
    __syncthreads();
#pragma unroll
    for (int i = 0; i < 8; i++) {
        int idx = tid + i * 256;
        int n = idx >> 5, kp = idx & 31;
        g_wfft[((size_t)(e * 1024 + n0 + n)) * 32 + kp] =
            packbf(sm[2 * kp][n], sm[2 * kp + 1][n]);
    }
}

// ================= stage 1: gating (warp-per-token, lane-owns-d-slice) =================
__global__ void __launch_bounds__(256) gate_kernel(const float* __restrict__ x,
                                                   const float* __restrict__ bg) {
    int warp = threadIdx.x >> 5;
    int lane = threadIdx.x & 31;
    int token = blockIdx.x * 8 + warp;
    const float4* xr = (const float4*)(x + (size_t)token * D);
    float acc[E];
#pragma unroll
    for (int e = 0; e < E; e++) acc[e] = 0.f;
#pragma unroll
    for (int it = 0; it < 8; it++) {
        float4 xv = xr[lane + it * 32];
#pragma unroll
        for (int e = 0; e < E; e++) {
            float4 wv = *(const float4*)(g_wgt + e * D + (lane + it * 32) * 4);
            acc[e] += xv.x * wv.x + xv.y * wv.y + xv.z * wv.z + xv.w * wv.w;
        }
    }
#pragma unroll
    for (int off = 16; off; off >>= 1) {
#pragma unroll
        for (int e = 0; e < E; e++)
            acc[e] += __shfl_xor_sync(0xffffffffu, acc[e], off);
    }
    if (lane == 0) {
        float g[E];
        float mx = -3.402823466e38f;
#pragma unroll
        for (int e = 0; e < E; e++) {
            g[e] = acc[e] + bg[e];
            mx = fmaxf(mx, g[e]);
        }
        float den = 0.f;
#pragma unroll
        for (int e = 0; e < E; e++) { g[e] = expf(g[e] - mx); den += g[e]; }
        float inv = 1.f / den;
#pragma unroll
        for (int e = 0; e < E; e++) g[e] *= inv;
#pragma unroll
        for (int e = 0; e < E; e++) {
            int r = 0;
#pragma unroll
            for (int j = 0; j < E; j++)
                r += (g[j] > g[e]) || (g[j] == g[e] && j < e);
            g_route[(size_t)token * E + e] = (r < TOPK) ? g[e] : 0.f;
        }
    }
}

// ================= stage 2: route normalize =================
__global__ void route_kernel() {
    int idx = blockIdx.x * blockDim.x + threadIdx.x;
    if (idx >= S * E) return;
    int s = idx / E, e = idx % E;
    float m0 = g_route[(size_t)s * E + e];
    float m1 = g_route[(size_t)(S + s) * E + e];
    float den = m0 + m1 + EPS;
    g_route[(size_t)s * E + e]       = m0 / den * 2.0f;
    g_route[(size_t)(S + s) * E + e] = m1 / den * 2.0f;
}

// ================= stage 3a: rank mask + route transpose =================
__global__ void mask_kernel() {
    int eb = blockIdx.x;
    int e = eb >> 1, b = eb & 1;
    __shared__ float sv[S];
    int tid = threadIdx.x;
    for (int s = tid; s < S; s += 256)
        sv[s] = g_route[(size_t)(b * S + s) * E + e];
    __syncthreads();
    if (blockIdx.y == 0) {
        for (int s = tid; s < S; s += 256)
            g_routeT[eb * S + s] = sv[s];
    }
    int i = blockIdx.y * 256 + tid;
    float vi = sv[i];
    int c = 0;
#pragma unroll 4
    for (int j4 = 0; j4 < S / 4; j4++) {
        float4 v = *(const float4*)(sv + j4 * 4);
        int j = j4 * 4;
        c += (v.x > vi) || (v.x == vi && (j + 0) < i);
        c += (v.y > vi) || (v.y == vi && (j + 1) < i);
        c += (v.z > vi) || (v.z == vi && (j + 2) < i);
        c += (v.w > vi) || (v.w == vi && (j + 3) < i);
    }
    g_mask[eb * S + i] = (c < CAP) ? 1 : 0;
}

// ================= stage 3b: compaction (parallel scan) =================
__global__ void select_kernel() {
    int eb = blockIdx.x;
    int e = eb >> 1, b = eb & 1;
    __shared__ unsigned char sm[S];
    __shared__ float sv[S];
    __shared__ int wsum[8];
    int t = threadIdx.x;
    for (int s = t; s < S; s += 256) {
        sm[s] = g_mask[eb * S + s];
        sv[s] = g_routeT[eb * S + s];
    }
    __syncthreads();
    int local = 0;
#pragma unroll
    for (int k = 0; k < 8; k++) local += sm[t * 8 + k];
    int lane = t & 31, warp = t >> 5;
    int scan = local;
#pragma unroll
    for (int off = 1; off < 32; off <<= 1) {
        int v = __shfl_up_sync(0xffffffffu, scan, off);
        if (lane >= off) scan += v;
    }
    if (lane == 31) wsum[warp] = scan;
    __syncthreads();
    int base = 0;
#pragma unroll
    for (int wi = 0; wi < 8; wi++)
        if (wi < warp) base += wsum[wi];
    int pos = base + scan - local;   // exclusive prefix
#pragma unroll
    for (int k = 0; k < 8; k++) {
        int s = t * 8 + k;
        if (sm[s]) {
            g_seq[eb * CAP + pos] = s;
            g_w[eb * CAP + pos] = sv[s];
            g_inv[e * NTOK + b * S + s] = pos;
            pos++;
        } else {
            g_inv[e * NTOK + b * S + s] = -1;
        }
    }
}

// ================= stage 4a: fused Q/K/V projection, BF16 mma =========
__global__ void __launch_bounds__(256) proj_kernel() {
    constexpr int AST = 36, BST = 36;
    constexpr int AW = 64 * AST;
    constexpr int BW = 192 * BST;
    extern __shared__ uint32_t dsm[];
    uint32_t* As = dsm;
    uint32_t* Bs = dsm + 2 * AW;
    int mt = blockIdx.x, eb = blockIdx.y;
    int e = eb >> 1, b = eb & 1;
    int tid = threadIdx.x;
    int lane = tid & 31, w = tid >> 5;
    int lr = lane >> 2, lc = lane & 3;
    int wm = (w & 1) * 32;
    int wn = (w >> 1) * 48;
    int m0 = mt * 64;

    int r0 = tid >> 3;
    int c = tid & 7;
    int seq0 = g_seq[eb * CAP + m0 + r0];
    int seq1 = g_seq[eb * CAP + m0 + r0 + 32];
    const uint32_t* arow0 = g_xh + (size_t)(b * S + seq0) * 512 + c * 4;
    const uint32_t* arow1 = g_xh + (size_t)(b * S + seq1) * 512 + c * 4;
    uint32_t as0 = r0 * AST + c * 4;
    uint32_t as1 = (r0 + 32) * AST + c * 4;

    const uint32_t* wtbase = g_wt + (size_t)e * 192 * 512;
    const uint32_t* bsrc[6];
    uint32_t bsoff[6];
#pragma unroll
    for (int it = 0; it < 6; it++) {
        int f = tid + it * 256;
        int n = f >> 3, cb = f & 7;
        bsrc[it] = wtbase + (size_t)n * 512 + cb * 4;
        bsoff[it] = n * BST + cb * 4;
    }

    float acc[2][6][4];
#pragma unroll
    for (int i = 0; i < 2; i++)
#pragma unroll
        for (int j = 0; j < 6; j++)
#pragma unroll
            for (int r = 0; r < 4; r++) acc[i][j][r] = 0.f;

    cp_async16((uint32_t)__cvta_generic_to_shared(As + as0), arow0);
    cp_async16((uint32_t)__cvta_generic_to_shared(As + as1), arow1);
#pragma unroll
    for (int it = 0; it < 6; it++)
        cp_async16((uint32_t)__cvta_generic_to_shared(Bs + bsoff[it]), bsrc[it]);
    cp_commit();

    for (int kt = 0; kt < 16; kt++) {
        cp_wait0();
        __syncthreads();
        if (kt + 1 < 16) {
            int s = (kt + 1) & 1;
            int kp0 = (kt + 1) * 32;
            cp_async16((uint32_t)__cvta_generic_to_shared(As + s * AW + as0), arow0 + kp0);
            cp_async16((uint32_t)__cvta_generic_to_shared(As + s * AW + as1), arow1 + kp0);
#pragma unroll
            for (int it = 0; it < 6; it++)
                cp_async16((uint32_t)__cvta_generic_to_shared(Bs + s * BW + bsoff[it]),
                           bsrc[it] + kp0);
            cp_commit();
        }
        int cs = kt & 1;
        const uint32_t* Acur = As + cs * AW;
        const uint32_t* Bcur = Bs + cs * BW;
#pragma unroll
        for (int kk = 0; kk < 4; kk++) {
            uint32_t a[2][4], bb[6][2];
#pragma unroll
            for (int mb = 0; mb < 2; mb++) {
                const uint32_t* ap = &Acur[(wm + mb * 16 + lr) * AST + kk * 8 + lc];
                a[mb][0] = ap[0];
                a[mb][1] = ap[8 * AST];
                a[mb][2] = ap[4];
                a[mb][3] = ap[8 * AST + 4];
            }
#pragma unroll
            for (int nb = 0; nb < 6; nb++) {
                const uint32_t* bp = &Bcur[(wn + nb * 8 + lr) * BST + kk * 8 + lc];
                bb[nb][0] = bp[0];
                bb[nb][1] = bp[4];
            }
#pragma unroll
            for (int mb = 0; mb < 2; mb++)
#pragma unroll
                for (int nb = 0; nb < 6; nb++)
                    mma_bf16(acc[mb][nb][0], acc[mb][nb][1], acc[mb][nb][2], acc[mb][nb][3],
                             a[mb][0], a[mb][1], a[mb][2], a[mb][3],
                             bb[nb][0], bb[nb][1]);
        }
    }

#pragma unroll
    for (int nb = 0; nb < 6; nb++) {
        int colg = wn + nb * 8 + 2 * lc;
#pragma unroll
        for (int mb = 0; mb < 2; mb++) {
            int row0 = m0 + wm + mb * 16 + lr;
            int row1 = row0 + 8;
            if (colg < 64) {
                int pair = colg >> 1;
                g_qh[(eb * CAP + row0) * 32 + pair] = packbf(acc[mb][nb][0], acc[mb][nb][1]);
                g_qh[(eb * CAP + row1) * 32 + pair] = packbf(acc[mb][nb][2], acc[mb][nb][3]);
            } else if (colg < 128) {
                int pair = (colg - 64) >> 1;
                g_kh[(eb * CAP + row0) * 32 + pair] = packbf(acc[mb][nb][0], acc[mb][nb][1]);
                g_kh[(eb * CAP + row1) * 32 + pair] = packbf(acc[mb][nb][2], acc[mb][nb][3]);
            } else {
                int col = colg - 128;
                g_vt[(size_t)(eb * HD + col) * CAP + row0]     = __float2bfloat16(acc[mb][nb][0]);
                g_vt[(size_t)(eb * HD + col + 1) * CAP + row0] = __float2bfloat16(acc[mb][nb][1]);
                g_vt[(size_t)(eb * HD + col) * CAP + row1]     = __float2bfloat16(acc[mb][nb][2]);
                g_vt[(size_t)(eb * HD + col + 1) * CAP + row1] = __float2bfloat16(acc[mb][nb][3]);
            }
        }
    }
}

// ================= stage 4b: RoPE on packed bf16 q/k =================
__global__ void rope_kernel() {
    int idx = blockIdx.x * blockDim.x + threadIdx.x;
    if (idx >= EB * CAP * 16) return;
    int j = idx & 15;
    int t = idx >> 4;
    int pos = g_seq[t];
    float invf0 = exp2f(-(float)(2 * j) * 0.4152410118609203f);
    float invf1 = exp2f(-(float)(2 * j + 1) * 0.4152410118609203f);
    float s0, c0, s1, c1;
    sincosf(pos * invf0, &s0, &c0);
    sincosf(pos * invf1, &s1, &c1);
    uint32_t* q = g_qh + (size_t)t * 32;
    uint32_t* k = g_kh + (size_t)t * 32;
    {
        float2 a = __bfloat1622float2(*(__nv_bfloat162*)&q[j]);
        float2 b = __bfloat1622float2(*(__nv_bfloat162*)&q[j + 16]);
        q[j]      = packbf(a.x * c0 - b.x * s0, a.y * c1 - b.y * s1);
        q[j + 16] = packbf(b.x * c0 + a.x * s0, b.y * c1 + a.y * s1);
    }
    {
        float2 a = __bfloat1622float2(*(__nv_bfloat162*)&k[j]);
        float2 b = __bfloat1622float2(*(__nv_bfloat162*)&k[j + 16]);
        k[j]      = packbf(a.x * c0 - b.x * s0, a.y * c1 - b.y * s1);
        k[j + 16] = packbf(b.x * c0 + a.x * s0, b.y * c1 + a.y * s1);
    }
}

// ================= stage 5: split-KV causal flash attention, BF16 mma, double-buffered K/V ====
__global__ void __launch_bounds__(256, 2) attn_kernel() {
    constexpr int ST = 36;
    extern __shared__ uint32_t dsm[];
    uint32_t* Qs   = dsm;                       // 128*ST
    uint32_t* KsB  = dsm + 128 * ST;            // 2 x 64*ST
    uint32_t* VtsB = dsm + 256 * ST;            // 2 x 64*ST
    uint32_t* Ps   = dsm + 384 * ST;            // 128*ST
    int mt = 9 - blockIdx.x;
    int eb = blockIdx.y;
    int split = blockIdx.z;
    int m0 = mt * 128;
    const uint32_t* qptr = g_qh + (size_t)eb * CAP * 32;
    const uint32_t* kptr = g_kh + (size_t)eb * CAP * 32;
    const uint32_t* vtptr = (const uint32_t*)g_vt + (size_t)eb * HD * (CAP / 2);
    int tid = threadIdx.x;
    int lane = tid & 31, w = tid >> 5;
    int lr = lane >> 2, lc = lane & 3;
    int wrow = 16 * w;

    int half = mt + 1;
    int ntStart = split * half;
    int ntEnd = ntStart + half;

    // Q tile loads (join tile-0's cp group)
#pragma unroll
    for (int it = 0; it < 4; it++) {
        int idx = tid + it * 256;
        int row = idx >> 3, c = idx & 7;
        cp_async16((uint32_t)__cvta_generic_to_shared(Qs + row * ST + c * 4),
                   qptr + (size_t)(m0 + row) * 32 + c * 4);
    }
    // issue tile ntStart (K + V in one group, committed together with Q)
    {
        int buf = ntStart & 1;
        int n0 = ntStart * 64;
        uint32_t* Kd = KsB + buf * 64 * ST;
        uint32_t* Vd = VtsB + buf * 64 * ST;
#pragma unroll
        for (int it = 0; it < 2; it++) {
            int idx = tid + it * 256;
            int row = idx >> 3, c = idx & 7;
            cp_async16((uint32_t)__cvta_generic_to_shared(Kd + row * ST + c * 4),
                       kptr + (size_t)(n0 + row) * 32 + c * 4);
            cp_async16((uint32_t)__cvta_generic_to_shared(Vd + row * ST + c * 4),
                       vtptr + (size_t)row * (CAP / 2) + (n0 >> 1) + c * 4);
        }
        cp_commit();
    }

    float o[8][4];
#pragma unroll
    for (int t8 = 0; t8 < 8; t8++)
#pragma unroll
        for (int r = 0; r < 4; r++) o[t8][r] = 0.f;
    float mrow0 = -3.402823466e38f, mrow1 = -3.402823466e38f;
    float lsum0 = 0.f, lsum1 = 0.f;

    for (int nt = ntStart; nt < ntEnd; nt++) {
        __syncthreads();   // all warps done reading buffer (nt+1)&1 (tile nt-1)
        if (nt + 1 < ntEnd) {
            int buf = (nt + 1) & 1;
            int n0n = (nt + 1) * 64;
            uint32_t* Kd = KsB + buf * 64 * ST;
            uint32_t* Vd = VtsB + buf * 64 * ST;
#pragma unroll
            for (int it = 0; it < 2; it++) {
                int idx = tid + it * 256;
                int row = idx >> 3, c = idx & 7;
                cp_async16((uint32_t)__cvta_generic_to_shared(Kd + row * ST + c * 4),
                           kptr + (size_t)(n0n + row) * 32 + c * 4);
                cp_async16((uint32_t)__cvta_generic_to_shared(Vd + row * ST + c * 4),
                           vtptr + (size_t)row * (CAP / 2) + (n0n >> 1) + c * 4);
            }
            cp_commit();
            cp_wait1();    // current tile (and Q on first iter) complete
        } else {
            cp_wait0();
        }
        __syncthreads();

        int n0 = nt * 64;
        const uint32_t* Ks  = KsB + (nt & 1) * 64 * ST;
        const uint32_t* Vts = VtsB + (nt & 1) * 64 * ST;

        float sacc[8][4];
#pragma unroll
        for (int t8 = 0; t8 < 8; t8++)
#pragma unroll
            for (int r = 0; r < 4; r++) sacc[t8][r] = 0.f;
#pragma unroll
        for (int kk = 0; kk < 4; kk++) {
            const uint32_t* ap = &Qs[(wrow + lr) * ST + kk * 8 + lc];
            uint32_t a0 = ap[0], a1 = ap[8 * ST], a2 = ap[4], a3 = ap[8 * ST + 4];
#pragma unroll
            for (int t8 = 0; t8 < 8; t8++) {
                const uint32_t* bp = &Ks[(t8 * 8 + lr) * ST + kk * 8 + lc];
                mma_bf16(sacc[t8][0], sacc[t8][1], sacc[t8][2], sacc[t8][3],
                         a0, a1, a2, a3, bp[0], bp[4]);
            }
        }

        bool maskT = (nt >= 2 * mt);
#pragma unroll
        for (int t8 = 0; t8 < 8; t8++) {
            int cbase = n0 + t8 * 8 + 2 * lc;
#pragma unroll
            for (int r = 0; r < 4; r++) {
                float v = sacc[t8][r] * 0.125f;
                if (maskT) {
                    int row = m0 + wrow + lr + ((r >= 2) ? 8 : 0);
                    int col = cbase + (r & 1);
                    if (col > row) v = -3.402823466e38f;
                }
                sacc[t8][r] = v;
            }
        }

        float mx0 = -3.402823466e38f, mx1 = -3.402823466e38f;
#pragma unroll
        for (int t8 = 0; t8 < 8; t8++) {
            mx0 = fmaxf(mx0, fmaxf(sacc[t8][0], sacc[t8][1]));
            mx1 = fmaxf(mx1, fmaxf(sacc[t8][2], sacc[t8][3]));
        }
        mx0 = fmaxf(mx0, __shfl_xor_sync(0xffffffffu, mx0, 1));
        mx0 = fmaxf(mx0, __shfl_xor_sync(0xffffffffu, mx0, 2));
        mx1 = fmaxf(mx1, __shfl_xor_sync(0xffffffffu, mx1, 1));
        mx1 = fmaxf(mx1, __shfl_xor_sync(0xffffffffu, mx1, 2));
        float nm0 = fmaxf(mrow0, mx0), nm1 = fmaxf(mrow1, mx1);
        float corr0 = __expf(mrow0 - nm0), corr1 = __expf(mrow1 - nm1);
        float rs0 = 0.f, rs1 = 0.f;
#pragma unroll
        for (int t8 = 0; t8 < 8; t8++) {
            float p0 = __expf(sacc[t8][0] - nm0);
            float p1 = __expf(sacc[t8][1] - nm0);
            float p2 = __expf(sacc[t8][2] - nm1);
            float p3 = __expf(sacc[t8][3] - nm1);
            rs0 += p0 + p1; rs1 += p2 + p3;
            Ps[(wrow + lr) * ST + t8 * 4 + lc]     = packbf(p0, p1);
            Ps[(wrow + lr + 8) * ST + t8 * 4 + lc] = packbf(p2, p3);
        }
        rs0 += __shfl_xor_sync(0xffffffffu, rs0, 1);
        rs0 += __shfl_xor_sync(0xffffffffu, rs0, 2);
        rs1 += __shfl_xor_sync(0xffffffffu, rs1, 1);
        rs1 += __shfl_xor_sync(0xffffffffu, rs1, 2);
        lsum0 = lsum0 * corr0 + rs0;
        lsum1 = lsum1 * corr1 + rs1;
        mrow0 = nm0; mrow1 = nm1;
#pragma unroll
        for (int t8 = 0; t8 < 8; t8++) {
            o[t8][0] *= corr0; o[t8][1] *= corr0;
            o[t8][2] *= corr1; o[t8][3] *= corr1;
        }
        __syncwarp();

#pragma unroll
        for (int kk = 0; kk < 4; kk++) {
            const uint32_t* ap = &Ps[(wrow + lr) * ST + kk * 8 + lc];
            uint32_t a0 = ap[0], a1 = ap[8 * ST], a2 = ap[4], a3 = ap[8 * ST + 4];
#pragma unroll
            for (int t8 = 0; t8 < 8; t8++) {
                const uint32_t* bp = &Vts[(t8 * 8 + lr) * ST + kk * 8 + lc];
                mma_bf16(o[t8][0], o[t8][1], o[t8][2], o[t8][3],
                         a0, a1, a2, a3, bp[0], bp[4]);
            }
        }
    }

    int row0 = m0 + wrow + lr, row1 = row0 + 8;
    float* op = g_opart + (size_t)split * EB * CAP * HD;
#pragma unroll
    for (int t8 = 0; t8 < 8; t8++) {
        int col = t8 * 8 + 2 * lc;
        *(float2*)(op + ((size_t)eb * CAP + row0) * HD + col) = make_float2(o[t8][0], o[t8][1]);
        *(float2*)(op + ((size_t)eb * CAP + row1) * HD + col) = make_float2(o[t8][2], o[t8][3]);
    }
    if (lc == 0) {
        int base = split * EB * CAP + eb * CAP;
        g_pm[base + row0] = mrow0;
        g_pl[base + row0] = lsum0;
        g_pm[base + row1] = mrow1;
        g_pl[base + row1] = lsum1;
    }
}

// ================= stage 5b: combine splits -> packed bf16 ctx =================
__global__ void combine_kernel() {
    int idx = blockIdx.x * blockDim.x + threadIdx.x;
    if (idx >= EB * CAP * 16) return;
    int t = idx >> 4;
    int c4 = (idx & 15) << 2;
    float m0 = g_pm[t], m1 = g_pm[EB * CAP + t];
    float l0 = g_pl[t], l1 = g_pl[EB * CAP + t];
    float M = fmaxf(m0, m1);
    float s0 = __expf(m0 - M), s1 = __expf(m1 - M);
    float inv = 1.f / (l0 * s0 + l1 * s1);
    const float4 a = *(const float4*)(g_opart + (size_t)t * HD + c4);
    const float4 b = *(const float4*)(g_opart + (size_t)EB * CAP * HD + (size_t)t * HD + c4);
    uint2 o;
    o.x = packbf((a.x * s0 + b.x * s1) * inv, (a.y * s0 + b.y * s1) * inv);
    o.y = packbf((a.z * s0 + b.z * s1) * inv, (a.w * s0 + b.w * s1) * inv);
    *(uint2*)(g_ctxh + (size_t)t * 32 + (c4 >> 1)) = o;
}

// ================= stage 6a: out = (ctx @ Wff + bff) * w -> bf16 g_out (BF16 mma) =====
__global__ void __launch_bounds__(256) outproj_kernel(const float* __restrict__ bff) {
    constexpr int AST = 36, BST = 36;
    extern __shared__ uint32_t dsm[];
    uint32_t* As = dsm;
    uint32_t* Bs = As + 128 * AST;
    int mt = blockIdx.x, nt = blockIdx.y, eb = blockIdx.z;
    int e = eb >> 1;
    int tid = threadIdx.x;
    int lane = tid & 31, w = tid >> 5;
    int lr = lane >> 2, lc = lane & 3;
    int wm = (w & 3) * 32, wn = (w >> 2) * 64;
    int m0 = mt * 128, n0 = nt * 128;

#pragma unroll
    for (int it = 0; it < 4; it++) {
        int idx = tid + it * 256;
        int row = idx >> 3, c = idx & 7;
        cp_async16((uint32_t)__cvta_generic_to_shared(As + row * AST + c * 4),
                   g_ctxh + (size_t)(eb * CAP + m0 + row) * 32 + c * 4);
    }
#pragma unroll
    for (int it = 0; it < 4; it++) {
        int idx = tid + it * 256;
        int n = idx >> 3, c = idx & 7;
        cp_async16((uint32_t)__cvta_generic_to_shared(Bs + n * BST + c * 4),
                   g_wfft + (size_t)(e * 1024 + n0 + n) * 32 + c * 4);
    }
    cp_commit();
    cp_wait0();
    __syncthreads();

    float acc[2][8][4];
#pragma unroll
    for (int mi = 0; mi < 2; mi++)
#pragma unroll
        for (int t8 = 0; t8 < 8; t8++)
#pragma unroll
            for (int r = 0; r < 4; r++) acc[mi][t8][r] = 0.f;

#pragma unroll
    for (int kk = 0; kk < 4; kk++) {
        uint32_t a[2][4];
#pragma unroll
        for (int mi = 0; mi < 2; mi++) {
            const uint32_t* ap = &As[(wm + mi * 16 + lr) * AST + kk * 8 + lc];
            a[mi][0] = ap[0]; a[mi][1] = ap[8 * AST];
            a[mi][2] = ap[4]; a[mi][3] = ap[8 * AST + 4];
        }
#pragma unroll
        for (int t8 = 0; t8 < 8; t8++) {
            const uint32_t* bp = &Bs[(wn + t8 * 8 + lr) * BST + kk * 8 + lc];
#pragma unroll
            for (int mi = 0; mi < 2; mi++)
                mma_bf16(acc[mi][t8][0], acc[mi][t8][1], acc[mi][t8][2], acc[mi][t8][3],
                         a[mi][0], a[mi][1], a[mi][2], a[mi][3], bp[0], bp[4]);
        }
    }

#pragma unroll
    for (int mi = 0; mi < 2; mi++) {
        int row0 = m0 + wm + mi * 16 + lr;
        int row1 = row0 + 8;
        float wv0 = g_w[eb * CAP + row0];
        float wv1 = g_w[eb * CAP + row1];
#pragma unroll
        for (int t8 = 0; t8 < 8; t8++) {
            int col = n0 + wn + t8 * 8 + 2 * lc;
            float2 bf = *(const float2*)(bff + col);
            if (wv0 != 0.f) {
                __nv_bfloat162 v;
                v.x = __float2bfloat16((acc[mi][t8][0] + bf.x) * wv0);
                v.y = __float2bfloat16((acc[mi][t8][1] + bf.y) * wv0);
                *(__nv_bfloat162*)(g_out + ((size_t)eb * CAP + row0) * D + col) = v;
            }
            if (wv1 != 0.f) {
                __nv_bfloat162 v;
                v.x = __float2bfloat16((acc[mi][t8][2] + bf.x) * wv1);
                v.y = __float2bfloat16((acc[mi][t8][3] + bf.y) * wv1);
                *(__nv_bfloat162*)(g_out + ((size_t)eb * CAP + row1) * D + col) = v;
            }
        }
    }
}

// ================= stage 6b: gather-combine + residual + LayerNorm =================
__global__ void ln_kernel(const float* __restrict__ x,
                          const float* __restrict__ gamma,
                          const float* __restrict__ beta,
                          float* __restrict__ out) {
    int token = blockIdx.x;
    int b = token >> 11;
    int tid = threadIdx.x;
    __shared__ int sh_base[E];
    __shared__ float red[8];
    if (tid < E) {
        int p = g_inv[tid * NTOK + token];
        int base = -1;
        if (p >= 0) {
            int idx = (tid * B + b) * CAP + p;
            if (g_w[idx] != 0.f) base = idx;
        }
        sh_base[tid] = base;
    }
    __syncthreads();
    float4 c = make_float4(0.f, 0.f, 0.f, 0.f);
#pragma unroll
    for (int e = 0; e < E; e++) {
        int base = sh_base[e];
        if (base >= 0) {
            uint2 u = *(const uint2*)(g_out + (size_t)base * D + tid * 4);
            __nv_bfloat162 p0 = *reinterpret_cast<__nv_bfloat162*>(&u.x);
            __nv_bfloat162 p1 = *reinterpret_cast<__nv_bfloat162*>(&u.y);
            c.x += __bfloat162float(p0.x); c.y += __bfloat162float(p0.y);
            c.z += __bfloat162float(p1.x); c.w += __bfloat162float(p1.y);
        }
    }
    float4 x4 = *(const float4*)(x + (size_t)token * D + tid * 4);
    float h[4] = {x4.x + c.x, x4.y + c.y, x4.z + c.z, x4.w + c.w};
    float s = h[0] + h[1] + h[2] + h[3];
#pragma unroll
    for (int off = 16; off > 0; off >>= 1) s += __shfl_xor_sync(0xffffffffu, s, off);
    int warp = tid >> 5, lane = tid & 31;
    if (lane == 0) red[warp] = s;
    __syncthreads();
    float total = 0.f;
#pragma unroll
    for (int w = 0; w < 8; w++) total += red[w];
    __syncthreads();
    float mu = total * (1.0f / D);
    float ss = 0.f;
#pragma unroll
    for (int t = 0; t < 4; t++) {
        float dlt = h[t] - mu;
        ss += dlt * dlt;
    }
#pragma unroll
    for (int off = 16; off > 0; off >>= 1) ss += __shfl_xor_sync(0xffffffffu, ss, off);
    if (lane == 0) red[warp] = ss;
    __syncthreads();
    float vtot = 0.f;
#pragma unroll
    for (int w = 0; w < 8; w++) vtot += red[w];
    float var = vtot * (1.0f / D);
    float inv = rsqrtf(var + 1e-5f);
    float4 g4 = *(const float4*)(gamma + tid * 4);
    float4 be4 = *(const float4*)(beta + tid * 4);
    float4 o4;
    o4.x = (h[0] - mu) * inv * g4.x + be4.x;
    o4.y = (h[1] - mu) * inv * g4.y + be4.y;
    o4.z = (h[2] - mu) * inv * g4.z + be4.z;
    o4.w = (h[3] - mu) * inv * g4.w + be4.w;
    *(float4*)(out + (size_t)token * D + tid * 4) = o4;
}

// ================= launch =================
extern "C" void kernel_launch(void* const* d_in, const int* in_sizes, int n_in,
                              void* d_out, int out_size) {
    const float* x     = (const float*)d_in[0];
    const float* wg    = (const float*)d_in[1];
    const float* bg    = (const float*)d_in[2];
    const float* Wq    = (const float*)d_in[3];
    const float* Wkv   = (const float*)d_in[4];
    const float* Wff   = (const float*)d_in[5];
    const float* bff   = (const float*)d_in[6];
    const float* gamma = (const float*)d_in[7];
    const float* beta  = (const float*)d_in[8];
    float* out = (float*)d_out;

    (void)in_sizes; (void)n_in; (void)out_size;

    wgt_kernel<<<E * D / 256, 256>>>(wg);
    xpack_kernel<<<NTOK * 512 / 256, 256>>>(x);
    wt_kernel<<<dim3(E, D / 64, 3), 256>>>(Wq, Wkv);
    wff_kernel<<<dim3(E, D / 64), 256>>>(Wff);

    gate_kernel<<<NTOK / 8, 256>>>(x, bg);
    route_kernel<<<(S * E + 255) / 256, 256>>>();
    mask_kernel<<<dim3(EB, 8), 256>>>();
    select_kernel<<<EB, 256>>>();

    int proj_smem = 2 * (64 * 36 + 192 * 36) * (int)sizeof(uint32_t);  // 73,728 B
    cudaFuncSetAttribute(proj_kernel, cudaFuncAttributeMaxDynamicSharedMemorySize, proj_smem);
    proj_kernel<<<dim3(CAP / 64, EB), 256, proj_smem>>>();

    rope_kernel<<<(EB * CAP * 16 + 255) / 256, 256>>>();

    int attn_smem = 512 * 36 * (int)sizeof(uint32_t);   // 73,728 B
    cudaFuncSetAttribute(attn_kernel, cudaFuncAttributeMaxDynamicSharedMemorySize, attn_smem);
    attn_kernel<<<dim3(CAP / 128, EB, 2), 256, attn_smem>>>();

    combine_kernel<<<(EB * CAP * 16 + 255) / 256, 256>>>();

    int op_smem = 2 * 128 * 36 * (int)sizeof(uint32_t);  // 36,864 B
    cudaFuncSetAttribute(outproj_kernel, cudaFuncAttributeMaxDynamicSharedMemorySize, op_smem);
    outproj_kernel<<<dim3(CAP / 128, D / 128, EB), 256, op_smem>>>(bff);

    ln_kernel<<<NTOK, 256>>>(x, gamma, beta, out);
}

// round 13
// speedup vs baseline: 5.1875x; 1.0301x over previous
#include <cuda_runtime.h>
#include <cuda_bf16.h>
#include <math.h>
#include <stdint.h>

// ---------------- problem constants ----------------
namespace {
constexpr int B = 2, S = 2048, D = 1024, E = 16, HD = 64, CAP = 1280, TOPK = 8;
constexpr float EPS = 1e-6f;
constexpr int EB = E * B;    // 32
constexpr int NTOK = B * S;  // 4096
}

// ---------------- scratch (device globals; no allocation allowed) ----------------
__device__ float g_route[NTOK * E];                     // raw masked-gate values mg
__device__ float g_routeT[EB * S];                      // normalized route, transposed
__device__ float g_wgt[E * D];                          // gate weights transposed [e][d]
__device__ unsigned char g_mask[EB * S];
__device__ int   g_seq[EB * CAP];
__device__ float g_w[EB * CAP];
__device__ int   g_inv[E * NTOK];
__device__ uint32_t g_xh[NTOK * 512];                   // x packed bf16x2 along D
__device__ uint32_t g_wt[(size_t)E * 192 * 512];        // Wq|Wkv transposed: [e][n][kpair]
__device__ uint32_t g_wfft[(size_t)E * 1024 * 32];      // Wff transposed: [e][n][kpair]
__device__ uint32_t g_qh[EB * CAP * 32];                // q bf16x2 pairs along HD
__device__ uint32_t g_kh[EB * CAP * 32];                // k bf16x2 pairs along HD
__device__ __nv_bfloat16 g_vt[(size_t)EB * HD * CAP];   // V transposed [eb][col][row]
__device__ uint32_t g_ctxh[EB * CAP * 32];              // ctx packed bf16x2 along HD
__device__ float g_opart[2 * EB * CAP * HD];
__device__ float g_pm[2 * EB * CAP];
__device__ float g_pl[2 * EB * CAP];
__device__ __nv_bfloat16 g_out[(size_t)EB * CAP * D];

// ---------------- helpers ----------------
__device__ __forceinline__ void mma_bf16(float& c0, float& c1, float& c2, float& c3,
                                         uint32_t a0, uint32_t a1, uint32_t a2, uint32_t a3,
                                         uint32_t b0, uint32_t b1) {
    asm volatile(
        "mma.sync.aligned.m16n8k16.row.col.f32.bf16.bf16.f32 "
        "{%0,%1,%2,%3}, {%4,%5,%6,%7}, {%8,%9}, {%0,%1,%2,%3};\n"
        : "+f"(c0), "+f"(c1), "+f"(c2), "+f"(c3)
        : "r"(a0), "r"(a1), "r"(a2), "r"(a3), "r"(b0), "r"(b1));
}
__device__ __forceinline__ uint32_t packbf(float a, float b) {
    __nv_bfloat162 t = __floats2bfloat162_rn(a, b);
    return *reinterpret_cast<uint32_t*>(&t);
}
__device__ __forceinline__ void cp_async16(uint32_t saddr, const void* g) {
    asm volatile("cp.async.ca.shared.global [%0], [%1], 16;" :: "r"(saddr), "l"(g));
}
__device__ __forceinline__ void cp_commit() { asm volatile("cp.async.commit_group;"); }
__device__ __forceinline__ void cp_wait0()  { asm volatile("cp.async.wait_group 0;"); }
__device__ __forceinline__ void cp_wait1()  { asm volatile("cp.async.wait_group 1;"); }

// ================= prep: transpose gate weights (must precede fat kernel) =========
__global__ void wgt_kernel(const float* __restrict__ wg) {
    int idx = blockIdx.x * 256 + threadIdx.x;    // 0..16383
    int d = idx >> 4, e = idx & 15;
    g_wgt[e * D + d] = wg[idx];
}

// ================= fat front-end kernel: gate | xpack | wt | wff =================
// blocks [0,512): gate; [512,2560): xpack; [2560,3328): wt; [3328,3584): wff
__global__ void __launch_bounds__(256) fat_kernel(const float* __restrict__ x,
                                                  const float* __restrict__ bg,
                                                  const float* __restrict__ Wq,
                                                  const float* __restrict__ Wkv,
                                                  const float* __restrict__ Wff) {
    __shared__ float sm[64][65];
    int bx = blockIdx.x;
    int tid = threadIdx.x;

    if (bx < 512) {
        // ---- gate: warp-per-token ----
        int warp = tid >> 5;
        int lane = tid & 31;
        int token = bx * 8 + warp;
        const float4* xr = (const float4*)(x + (size_t)token * D);
        float acc[E];
#pragma unroll
        for (int e = 0; e < E; e++) acc[e] = 0.f;
#pragma unroll
        for (int it = 0; it < 8; it++) {
            float4 xv = xr[lane + it * 32];
#pragma unroll
            for (int e = 0; e < E; e++) {
                float4 wv = *(const float4*)(g_wgt + e * D + (lane + it * 32) * 4);
                acc[e] += xv.x * wv.x + xv.y * wv.y + xv.z * wv.z + xv.w * wv.w;
            }
        }
#pragma unroll
        for (int off = 16; off; off >>= 1) {
#pragma unroll
            for (int e = 0; e < E; e++)
                acc[e] += __shfl_xor_sync(0xffffffffu, acc[e], off);
        }
        if (lane == 0) {
            float g[E];
            float mx = -3.402823466e38f;
#pragma unroll
            for (int e = 0; e < E; e++) {
                g[e] = acc[e] + bg[e];
                mx = fmaxf(mx, g[e]);
            }
            float den = 0.f;
#pragma unroll
            for (int e = 0; e < E; e++) { g[e] = expf(g[e] - mx); den += g[e]; }
            float inv = 1.f / den;
#pragma unroll
            for (int e = 0; e < E; e++) g[e] *= inv;
#pragma unroll
            for (int e = 0; e < E; e++) {
                int r = 0;
#pragma unroll
                for (int j = 0; j < E; j++)
                    r += (g[j] > g[e]) || (g[j] == g[e] && j < e);
                g_route[(size_t)token * E + e] = (r < TOPK) ? g[e] : 0.f;
            }
        }
    } else if (bx < 2560) {
        // ---- xpack: 4 bf16x2 pairs per thread ----
        int idx = (bx - 512) * 256 + tid;      // 0 .. NTOK*512/4 - 1
        const float4* src = (const float4*)x + (size_t)idx * 2;
        float4 v0 = src[0];
        float4 v1 = src[1];
        uint4 o;
        o.x = packbf(v0.x, v0.y);
        o.y = packbf(v0.z, v0.w);
        o.z = packbf(v1.x, v1.y);
        o.w = packbf(v1.z, v1.w);
        *((uint4*)g_xh + idx) = o;
    } else if (bx < 3328) {
        // ---- wt: transpose-pack Wq|Wkv ----
        int i = bx - 2560;                      // 0..767
        int e = i / 48;
        int rem = i % 48;
        int k0 = (rem / 3) * 64;
        int nz = rem % 3;
        int n0 = nz * 64;
        const float* src;
        int stride;
        if (nz == 0) { src = Wq + (size_t)e * D * HD; stride = HD; }
        else         { src = Wkv + (size_t)e * D * 128 + (n0 - 64); stride = 128; }
#pragma unroll
        for (int it = 0; it < 16; it++) {
            int idx = tid + it * 256;
            int kk = idx >> 6, nn = idx & 63;
            sm[kk][nn] = src[(size_t)(k0 + kk) * stride + nn];
        }
        __syncthreads();
#pragma unroll
        for (int it = 0; it < 8; it++) {
            int idx = tid + it * 256;
            int n = idx >> 5, kp = idx & 31;
            g_wt[((size_t)(e * 192 + n0 + n)) * 512 + (k0 >> 1) + kp] =
                packbf(sm[2 * kp][n], sm[2 * kp + 1][n]);
        }
    } else {
        // ---- wff: transpose-pack Wff ----
        int i = bx - 3328;                      // 0..255
        int e = i >> 4;
        int n0 = (i & 15) * 64;
#pragma unroll
        for (int it = 0; it < 16; it++) {
            int idx = tid + it * 256;
            int kk = idx >> 6, nn = idx & 63;
            sm[kk][nn] = Wff[(size_t)e * HD * D + (size_t)kk * D + n0 + nn];
        }
        __syncthreads();
#pragma unroll
        for (int it = 0; it < 8; it++) {
            int idx = tid + it * 256;
            int n = idx >> 5, kp = idx & 31;
            g_wfft[((size_t)(e * 1024 + n0 + n)) * 32 + kp] =
                packbf(sm[2 * kp][n], sm[2 * kp + 1][n]);
        }
    }
}

// ================= stage 3a: normalize + rank mask + route transpose =================
__global__ void mask_kernel() {
    int eb = blockIdx.x;
    int e = eb >> 1, b = eb & 1;
    __shared__ float sv[S];
    int tid = threadIdx.x;
    for (int s = tid; s < S; s += 256) {
        float m0 = g_route[(size_t)s * E + e];
        float m1 = g_route[(size_t)(S + s) * E + e];
        float den = m0 + m1 + EPS;
        sv[s] = (b ? m1 : m0) / den * 2.0f;
    }
    __syncthreads();
    if (blockIdx.y == 0) {
        for (int s = tid; s < S; s += 256)
            g_routeT[eb * S + s] = sv[s];
    }
    int i = blockIdx.y * 256 + tid;
    float vi = sv[i];
    int c = 0;
#pragma unroll 4
    for (int j4 = 0; j4 < S / 4; j4++) {
        float4 v = *(const float4*)(sv + j4 * 4);
        int j = j4 * 4;
        c += (v.x > vi) || (v.x == vi && (j + 0) < i);
        c += (v.y > vi) || (v.y == vi && (j + 1) < i);
        c += (v.z > vi) || (v.z == vi && (j + 2) < i);
        c += (v.w > vi) || (v.w == vi && (j + 3) < i);
    }
    g_mask[eb * S + i] = (c < CAP) ? 1 : 0;
}

// ================= stage 3b: compaction (parallel scan) =================
__global__ void select_kernel() {
    int eb = blockIdx.x;
    int e = eb >> 1, b = eb & 1;
    __shared__ unsigned char sm[S];
    __shared__ float sv[S];
    __shared__ int wsum[8];
    int t = threadIdx.x;
    for (int s = t; s < S; s += 256) {
        sm[s] = g_mask[eb * S + s];
        sv[s] = g_routeT[eb * S + s];
    }
    __syncthreads();
    int local = 0;
#pragma unroll
    for (int k = 0; k < 8; k++) local += sm[t * 8 + k];
    int lane = t & 31, warp = t >> 5;
    int scan = local;
#pragma unroll
    for (int off = 1; off < 32; off <<= 1) {
        int v = __shfl_up_sync(0xffffffffu, scan, off);
        if (lane >= off) scan += v;
    }
    if (lane == 31) wsum[warp] = scan;
    __syncthreads();
    int base = 0;
#pragma unroll
    for (int wi = 0; wi < 8; wi++)
        if (wi < warp) base += wsum[wi];
    int pos = base + scan - local;   // exclusive prefix
#pragma unroll
    for (int k = 0; k < 8; k++) {
        int s = t * 8 + k;
        if (sm[s]) {
            g_seq[eb * CAP + pos] = s;
            g_w[eb * CAP + pos] = sv[s];
            g_inv[e * NTOK + b * S + s] = pos;
            pos++;
        } else {
            g_inv[e * NTOK + b * S + s] = -1;
        }
    }
}

// ================= stage 4a: fused Q/K/V projection, BF16 mma =========
__global__ void __launch_bounds__(256) proj_kernel() {
    constexpr int AST = 36, BST = 36;
    constexpr int AW = 64 * AST;
    constexpr int BW = 192 * BST;
    extern __shared__ uint32_t dsm[];
    uint32_t* As = dsm;
    uint32_t* Bs = dsm + 2 * AW;
    int mt = blockIdx.x, eb = blockIdx.y;
    int e = eb >> 1, b = eb & 1;
    int tid = threadIdx.x;
    int lane = tid & 31, w = tid >> 5;
    int lr = lane >> 2, lc = lane & 3;
    int wm = (w & 1) * 32;
    int wn = (w >> 1) * 48;
    int m0 = mt * 64;

    int r0 = tid >> 3;
    int c = tid & 7;
    int seq0 = g_seq[eb * CAP + m0 + r0];
    int seq1 = g_seq[eb * CAP + m0 + r0 + 32];
    const uint32_t* arow0 = g_xh + (size_t)(b * S + seq0) * 512 + c * 4;
    const uint32_t* arow1 = g_xh + (size_t)(b * S + seq1) * 512 + c * 4;
    uint32_t as0 = r0 * AST + c * 4;
    uint32_t as1 = (r0 + 32) * AST + c * 4;

    const uint32_t* wtbase = g_wt + (size_t)e * 192 * 512;
    const uint32_t* bsrc[6];
    uint32_t bsoff[6];
#pragma unroll
    for (int it = 0; it < 6; it++) {
        int f = tid + it * 256;
        int n = f >> 3, cb = f & 7;
        bsrc[it] = wtbase + (size_t)n * 512 + cb * 4;
        bsoff[it] = n * BST + cb * 4;
    }

    float acc[2][6][4];
#pragma unroll
    for (int i = 0; i < 2; i++)
#pragma unroll
        for (int j = 0; j < 6; j++)
#pragma unroll
            for (int r = 0; r < 4; r++) acc[i][j][r] = 0.f;

    cp_async16((uint32_t)__cvta_generic_to_shared(As + as0), arow0);
    cp_async16((uint32_t)__cvta_generic_to_shared(As + as1), arow1);
#pragma unroll
    for (int it = 0; it < 6; it++)
        cp_async16((uint32_t)__cvta_generic_to_shared(Bs + bsoff[it]), bsrc[it]);
    cp_commit();

    for (int kt = 0; kt < 16; kt++) {
        cp_wait0();
        __syncthreads();
        if (kt + 1 < 16) {
            int s = (kt + 1) & 1;
            int kp0 = (kt + 1) * 32;
            cp_async16((uint32_t)__cvta_generic_to_shared(As + s * AW + as0), arow0 + kp0);
            cp_async16((uint32_t)__cvta_generic_to_shared(As + s * AW + as1), arow1 + kp0);
#pragma unroll
            for (int it = 0; it < 6; it++)
                cp_async16((uint32_t)__cvta_generic_to_shared(Bs + s * BW + bsoff[it]),
                           bsrc[it] + kp0);
            cp_commit();
        }
        int cs = kt & 1;
        const uint32_t* Acur = As + cs * AW;
        const uint32_t* Bcur = Bs + cs * BW;
#pragma unroll
        for (int kk = 0; kk < 4; kk++) {
            uint32_t a[2][4], bb[6][2];
#pragma unroll
            for (int mb = 0; mb < 2; mb++) {
                const uint32_t* ap = &Acur[(wm + mb * 16 + lr) * AST + kk * 8 + lc];
                a[mb][0] = ap[0];
                a[mb][1] = ap[8 * AST];
                a[mb][2] = ap[4];
                a[mb][3] = ap[8 * AST + 4];
            }
#pragma unroll
            for (int nb = 0; nb < 6; nb++) {
                const uint32_t* bp = &Bcur[(wn + nb * 8 + lr) * BST + kk * 8 + lc];
                bb[nb][0] = bp[0];
                bb[nb][1] = bp[4];
            }
#pragma unroll
            for (int mb = 0; mb < 2; mb++)
#pragma unroll
                for (int nb = 0; nb < 6; nb++)
                    mma_bf16(acc[mb][nb][0], acc[mb][nb][1], acc[mb][nb][2], acc[mb][nb][3],
                             a[mb][0], a[mb][1], a[mb][2], a[mb][3],
                             bb[nb][0], bb[nb][1]);
        }
    }

#pragma unroll
    for (int nb = 0; nb < 6; nb++) {
        int colg = wn + nb * 8 + 2 * lc;
#pragma unroll
        for (int mb = 0; mb < 2; mb++) {
            int row0 = m0 + wm + mb * 16 + lr;
            int row1 = row0 + 8;
            if (colg < 64) {
                int pair = colg >> 1;
                g_qh[(eb * CAP + row0) * 32 + pair] = packbf(acc[mb][nb][0], acc[mb][nb][1]);
                g_qh[(eb * CAP + row1) * 32 + pair] = packbf(acc[mb][nb][2], acc[mb][nb][3]);
            } else if (colg < 128) {
                int pair = (colg - 64) >> 1;
                g_kh[(eb * CAP + row0) * 32 + pair] = packbf(acc[mb][nb][0], acc[mb][nb][1]);
                g_kh[(eb * CAP + row1) * 32 + pair] = packbf(acc[mb][nb][2], acc[mb][nb][3]);
            } else {
                int col = colg - 128;
                g_vt[(size_t)(eb * HD + col) * CAP + row0]     = __float2bfloat16(acc[mb][nb][0]);
                g_vt[(size_t)(eb * HD + col + 1) * CAP + row0] = __float2bfloat16(acc[mb][nb][1]);
                g_vt[(size_t)(eb * HD + col) * CAP + row1]     = __float2bfloat16(acc[mb][nb][2]);
                g_vt[(size_t)(eb * HD + col + 1) * CAP + row1] = __float2bfloat16(acc[mb][nb][3]);
            }
        }
    }
}

// ================= stage 4b: RoPE on packed bf16 q/k =================
__global__ void rope_kernel() {
    int idx = blockIdx.x * blockDim.x + threadIdx.x;
    if (idx >= EB * CAP * 16) return;
    int j = idx & 15;
    int t = idx >> 4;
    int pos = g_seq[t];
    float invf0 = exp2f(-(float)(2 * j) * 0.4152410118609203f);
    float invf1 = exp2f(-(float)(2 * j + 1) * 0.4152410118609203f);
    float s0, c0, s1, c1;
    sincosf(pos * invf0, &s0, &c0);
    sincosf(pos * invf1, &s1, &c1);
    uint32_t* q = g_qh + (size_t)t * 32;
    uint32_t* k = g_kh + (size_t)t * 32;
    {
        float2 a = __bfloat1622float2(*(__nv_bfloat162*)&q[j]);
        float2 b = __bfloat1622float2(*(__nv_bfloat162*)&q[j + 16]);
        q[j]      = packbf(a.x * c0 - b.x * s0, a.y * c1 - b.y * s1);
        q[j + 16] = packbf(b.x * c0 + a.x * s0, b.y * c1 + a.y * s1);
    }
    {
        float2 a = __bfloat1622float2(*(__nv_bfloat162*)&k[j]);
        float2 b = __bfloat1622float2(*(__nv_bfloat162*)&k[j + 16]);
        k[j]      = packbf(a.x * c0 - b.x * s0, a.y * c1 - b.y * s1);
        k[j + 16] = packbf(b.x * c0 + a.x * s0, b.y * c1 + a.y * s1);
    }
}

// ================= stage 5: split-KV causal flash attention, BF16 mma, double-buffered ====
__global__ void __launch_bounds__(256, 2) attn_kernel() {
    constexpr int ST = 36;
    extern __shared__ uint32_t dsm[];
    uint32_t* Qs   = dsm;                       // 128*ST
    uint32_t* KsB  = dsm + 128 * ST;            // 2 x 64*ST
    uint32_t* VtsB = dsm + 256 * ST;            // 2 x 64*ST
    uint32_t* Ps   = dsm + 384 * ST;            // 128*ST
    int mt = 9 - blockIdx.x;
    int eb = blockIdx.y;
    int split = blockIdx.z;
    int m0 = mt * 128;
    const uint32_t* qptr = g_qh + (size_t)eb * CAP * 32;
    const uint32_t* kptr = g_kh + (size_t)eb * CAP * 32;
    const uint32_t* vtptr = (const uint32_t*)g_vt + (size_t)eb * HD * (CAP / 2);
    int tid = threadIdx.x;
    int lane = tid & 31, w = tid >> 5;
    int lr = lane >> 2, lc = lane & 3;
    int wrow = 16 * w;

    int half = mt + 1;
    int ntStart = split * half;
    int ntEnd = ntStart + half;

#pragma unroll
    for (int it = 0; it < 4; it++) {
        int idx = tid + it * 256;
        int row = idx >> 3, c = idx & 7;
        cp_async16((uint32_t)__cvta_generic_to_shared(Qs + row * ST + c * 4),
                   qptr + (size_t)(m0 + row) * 32 + c * 4);
    }
    {
        int buf = ntStart & 1;
        int n0 = ntStart * 64;
        uint32_t* Kd = KsB + buf * 64 * ST;
        uint32_t* Vd = VtsB + buf * 64 * ST;
#pragma unroll
        for (int it = 0; it < 2; it++) {
            int idx = tid + it * 256;
            int row = idx >> 3, c = idx & 7;
            cp_async16((uint32_t)__cvta_generic_to_shared(Kd + row * ST + c * 4),
                       kptr + (size_t)(n0 + row) * 32 + c * 4);
            cp_async16((uint32_t)__cvta_generic_to_shared(Vd + row * ST + c * 4),
                       vtptr + (size_t)row * (CAP / 2) + (n0 >> 1) + c * 4);
        }
        cp_commit();
    }

    float o[8][4];
#pragma unroll
    for (int t8 = 0; t8 < 8; t8++)
#pragma unroll
        for (int r = 0; r < 4; r++) o[t8][r] = 0.f;
    float mrow0 = -3.402823466e38f, mrow1 = -3.402823466e38f;
    float lsum0 = 0.f, lsum1 = 0.f;

    for (int nt = ntStart; nt < ntEnd; nt++) {
        __syncthreads();
        if (nt + 1 < ntEnd) {
            int buf = (nt + 1) & 1;
            int n0n = (nt + 1) * 64;
            uint32_t* Kd = KsB + buf * 64 * ST;
            uint32_t* Vd = VtsB + buf * 64 * ST;
#pragma unroll
            for (int it = 0; it < 2; it++) {
                int idx = tid + it * 256;
                int row = idx >> 3, c = idx & 7;
                cp_async16((uint32_t)__cvta_generic_to_shared(Kd + row * ST + c * 4),
                           kptr + (size_t)(n0n + row) * 32 + c * 4);
                cp_async16((uint32_t)__cvta_generic_to_shared(Vd + row * ST + c * 4),
                           vtptr + (size_t)row * (CAP / 2) + (n0n >> 1) + c * 4);
            }
            cp_commit();
            cp_wait1();
        } else {
            cp_wait0();
        }
        __syncthreads();

        int n0 = nt * 64;
        const uint32_t* Ks  = KsB + (nt & 1) * 64 * ST;
        const uint32_t* Vts = VtsB + (nt & 1) * 64 * ST;

        float sacc[8][4];
#pragma unroll
        for (int t8 = 0; t8 < 8; t8++)
#pragma unroll
            for (int r = 0; r < 4; r++) sacc[t8][r] = 0.f;
#pragma unroll
        for (int kk = 0; kk < 4; kk++) {
            const uint32_t* ap = &Qs[(wrow + lr) * ST + kk * 8 + lc];
            uint32_t a0 = ap[0], a1 = ap[8 * ST], a2 = ap[4], a3 = ap[8 * ST + 4];
#pragma unroll
            for (int t8 = 0; t8 < 8; t8++) {
                const uint32_t* bp = &Ks[(t8 * 8 + lr) * ST + kk * 8 + lc];
                mma_bf16(sacc[t8][0], sacc[t8][1], sacc[t8][2], sacc[t8][3],
                         a0, a1, a2, a3, bp[0], bp[4]);
            }
        }

        bool maskT = (nt >= 2 * mt);
#pragma unroll
        for (int t8 = 0; t8 < 8; t8++) {
            int cbase = n0 + t8 * 8 + 2 * lc;
#pragma unroll
            for (int r = 0; r < 4; r++) {
                float v = sacc[t8][r] * 0.125f;
                if (maskT) {
                    int row = m0 + wrow + lr + ((r >= 2) ? 8 : 0);
                    int col = cbase + (r & 1);
                    if (col > row) v = -3.402823466e38f;
                }
                sacc[t8][r] = v;
            }
        }

        float mx0 = -3.402823466e38f, mx1 = -3.402823466e38f;
#pragma unroll
        for (int t8 = 0; t8 < 8; t8++) {
            mx0 = fmaxf(mx0, fmaxf(sacc[t8][0], sacc[t8][1]));
            mx1 = fmaxf(mx1, fmaxf(sacc[t8][2], sacc[t8][3]));
        }
        mx0 = fmaxf(mx0, __shfl_xor_sync(0xffffffffu, mx0, 1));
        mx0 = fmaxf(mx0, __shfl_xor_sync(0xffffffffu, mx0, 2));
        mx1 = fmaxf(mx1, __shfl_xor_sync(0xffffffffu, mx1, 1));
        mx1 = fmaxf(mx1, __shfl_xor_sync(0xffffffffu, mx1, 2));
        float nm0 = fmaxf(mrow0, mx0), nm1 = fmaxf(mrow1, mx1);
        float corr0 = __expf(mrow0 - nm0), corr1 = __expf(mrow1 - nm1);
        float rs0 = 0.f, rs1 = 0.f;
#pragma unroll
        for (int t8 = 0; t8 < 8; t8++) {
            float p0 = __expf(sacc[t8][0] - nm0);
            float p1 = __expf(sacc[t8][1] - nm0);
            float p2 = __expf(sacc[t8][2] - nm1);
            float p3 = __expf(sacc[t8][3] - nm1);
            rs0 += p0 + p1; rs1 += p2 + p3;
            Ps[(wrow + lr) * ST + t8 * 4 + lc]     = packbf(p0, p1);
            Ps[(wrow + lr + 8) * ST + t8 * 4 + lc] = packbf(p2, p3);
        }
        rs0 += __shfl_xor_sync(0xffffffffu, rs0, 1);
        rs0 += __shfl_xor_sync(0xffffffffu, rs0, 2);
        rs1 += __shfl_xor_sync(0xffffffffu, rs1, 1);
        rs1 += __shfl_xor_sync(0xffffffffu, rs1, 2);
        lsum0 = lsum0 * corr0 + rs0;
        lsum1 = lsum1 * corr1 + rs1;
        mrow0 = nm0; mrow1 = nm1;
#pragma unroll
        for (int t8 = 0; t8 < 8; t8++) {
            o[t8][0] *= corr0; o[t8][1] *= corr0;
            o[t8][2] *= corr1; o[t8][3] *= corr1;
        }
        __syncwarp();

#pragma unroll
        for (int kk = 0; kk < 4; kk++) {
            const uint32_t* ap = &Ps[(wrow + lr) * ST + kk * 8 + lc];
            uint32_t a0 = ap[0], a1 = ap[8 * ST], a2 = ap[4], a3 = ap[8 * ST + 4];
#pragma unroll
            for (int t8 = 0; t8 < 8; t8++) {
                const uint32_t* bp = &Vts[(t8 * 8 + lr) * ST + kk * 8 + lc];
                mma_bf16(o[t8][0], o[t8][1], o[t8][2], o[t8][3],
                         a0, a1, a2, a3, bp[0], bp[4]);
            }
        }
    }

    int row0 = m0 + wrow + lr, row1 = row0 + 8;
    float* op = g_opart + (size_t)split * EB * CAP * HD;
#pragma unroll
    for (int t8 = 0; t8 < 8; t8++) {
        int col = t8 * 8 + 2 * lc;
        *(float2*)(op + ((size_t)eb * CAP + row0) * HD + col) = make_float2(o[t8][0], o[t8][1]);
        *(float2*)(op + ((size_t)eb * CAP + row1) * HD + col) = make_float2(o[t8][2], o[t8][3]);
    }
    if (lc == 0) {
        int base = split * EB * CAP + eb * CAP;
        g_pm[base + row0] = mrow0;
        g_pl[base + row0] = lsum0;
        g_pm[base + row1] = mrow1;
        g_pl[base + row1] = lsum1;
    }
}

// ================= stage 5b: combine splits -> packed bf16 ctx =================
__global__ void combine_kernel() {
    int idx = blockIdx.x * blockDim.x + threadIdx.x;
    if (idx >= EB * CAP * 16) return;
    int t = idx >> 4;
    int c4 = (idx & 15) << 2;
    float m0 = g_pm[t], m1 = g_pm[EB * CAP + t];
    float l0 = g_pl[t], l1 = g_pl[EB * CAP + t];
    float M = fmaxf(m0, m1);
    float s0 = __expf(m0 - M), s1 = __expf(m1 - M);
    float inv = 1.f / (l0 * s0 + l1 * s1);
    const float4 a = *(const float4*)(g_opart + (size_t)t * HD + c4);
    const float4 b = *(const float4*)(g_opart + (size_t)EB * CAP * HD + (size_t)t * HD + c4);
    uint2 o;
    o.x = packbf((a.x * s0 + b.x * s1) * inv, (a.y * s0 + b.y * s1) * inv);
    o.y = packbf((a.z * s0 + b.z * s1) * inv, (a.w * s0 + b.w * s1) * inv);
    *(uint2*)(g_ctxh + (size_t)t * 32 + (c4 >> 1)) = o;
}

// ================= stage 6a: out = (ctx @ Wff + bff) * w -> bf16 g_out (BF16 mma) =====
__global__ void __launch_bounds__(256) outproj_kernel(const float* __restrict__ bff) {
    constexpr int AST = 36, BST = 36;
    extern __shared__ uint32_t dsm[];
    uint32_t* As = dsm;
    uint32_t* Bs = As + 128 * AST;
    int mt = blockIdx.x, nt = blockIdx.y, eb = blockIdx.z;
    int e = eb >> 1;
    int tid = threadIdx.x;
    int lane = tid & 31, w = tid >> 5;
    int lr = lane >> 2, lc = lane & 3;
    int wm = (w & 3) * 32, wn = (w >> 2) * 64;
    int m0 = mt * 128, n0 = nt * 128;

#pragma unroll
    for (int it = 0; it < 4; it++) {
        int idx = tid + it * 256;
        int row = idx >> 3, c = idx & 7;
        cp_async16((uint32_t)__cvta_generic_to_shared(As + row * AST + c * 4),
                   g_ctxh + (size_t)(eb * CAP + m0 + row) * 32 + c * 4);
    }
#pragma unroll
    for (int it = 0; it < 4; it++) {
        int idx = tid + it * 256;
        int n = idx >> 3, c = idx & 7;
        cp_async16((uint32_t)__cvta_generic_to_shared(Bs + n * BST + c * 4),
                   g_wfft + (size_t)(e * 1024 + n0 + n) * 32 + c * 4);
    }
    cp_commit();
    cp_wait0();
    __syncthreads();

    float acc[2][8][4];
#pragma unroll
    for (int mi = 0; mi < 2; mi++)
#pragma unroll
        for (int t8 = 0; t8 < 8; t8++)
#pragma unroll
            for (int r = 0; r < 4; r++) acc[mi][t8][r] = 0.f;

#pragma unroll
    for (int kk = 0; kk < 4; kk++) {
        uint32_t a[2][4];
#pragma unroll
        for (int mi = 0; mi < 2; mi++) {
            const uint32_t* ap = &As[(wm + mi * 16 + lr) * AST + kk * 8 + lc];
            a[mi][0] = ap[0]; a[mi][1] = ap[8 * AST];
            a[mi][2] = ap[4]; a[mi][3] = ap[8 * AST + 4];
        }
#pragma unroll
        for (int t8 = 0; t8 < 8; t8++) {
            const uint32_t* bp = &Bs[(wn + t8 * 8 + lr) * BST + kk * 8 + lc];
#pragma unroll
            for (int mi = 0; mi < 2; mi++)
                mma_bf16(acc[mi][t8][0], acc[mi][t8][1], acc[mi][t8][2], acc[mi][t8][3],
                         a[mi][0], a[mi][1], a[mi][2], a[mi][3], bp[0], bp[4]);
        }
    }

#pragma unroll
    for (int mi = 0; mi < 2; mi++) {
        int row0 = m0 + wm + mi * 16 + lr;
        int row1 = row0 + 8;
        float wv0 = g_w[eb * CAP + row0];
        float wv1 = g_w[eb * CAP + row1];
#pragma unroll
        for (int t8 = 0; t8 < 8; t8++) {
            int col = n0 + wn + t8 * 8 + 2 * lc;
            float2 bf = *(const float2*)(bff + col);
            if (wv0 != 0.f) {
                __nv_bfloat162 v;
                v.x = __float2bfloat16((acc[mi][t8][0] + bf.x) * wv0);
                v.y = __float2bfloat16((acc[mi][t8][1] + bf.y) * wv0);
                *(__nv_bfloat162*)(g_out + ((size_t)eb * CAP + row0) * D + col) = v;
            }
            if (wv1 != 0.f) {
                __nv_bfloat162 v;
                v.x = __float2bfloat16((acc[mi][t8][2] + bf.x) * wv1);
                v.y = __float2bfloat16((acc[mi][t8][3] + bf.y) * wv1);
                *(__nv_bfloat162*)(g_out + ((size_t)eb * CAP + row1) * D + col) = v;
            }
        }
    }
}

// ================= stage 6b: gather-combine + residual + LayerNorm =================
__global__ void ln_kernel(const float* __restrict__ x,
                          const float* __restrict__ gamma,
                          const float* __restrict__ beta,
                          float* __restrict__ out) {
    int token = blockIdx.x;
    int b = token >> 11;
    int tid = threadIdx.x;
    __shared__ int sh_base[E];
    __shared__ float red[8];
    if (tid < E) {
        int p = g_inv[tid * NTOK + token];
        int base = -1;
        if (p >= 0) {
            int idx = (tid * B + b) * CAP + p;
            if (g_w[idx] != 0.f) base = idx;
        }
        sh_base[tid] = base;
    }
    __syncthreads();
    float4 c = make_float4(0.f, 0.f, 0.f, 0.f);
#pragma unroll
    for (int e = 0; e < E; e++) {
        int base = sh_base[e];
        if (base >= 0) {
            uint2 u = *(const uint2*)(g_out + (size_t)base * D + tid * 4);
            __nv_bfloat162 p0 = *reinterpret_cast<__nv_bfloat162*>(&u.x);
            __nv_bfloat162 p1 = *reinterpret_cast<__nv_bfloat162*>(&u.y);
            c.x += __bfloat162float(p0.x); c.y += __bfloat162float(p0.y);
            c.z += __bfloat162float(p1.x); c.w += __bfloat162float(p1.y);
        }
    }
    float4 x4 = *(const float4*)(x + (size_t)token * D + tid * 4);
    float h[4] = {x4.x + c.x, x4.y + c.y, x4.z + c.z, x4.w + c.w};
    float s = h[0] + h[1] + h[2] + h[3];
#pragma unroll
    for (int off = 16; off > 0; off >>= 1) s += __shfl_xor_sync(0xffffffffu, s, off);
    int warp = tid >> 5, lane = tid & 31;
    if (lane == 0) red[warp] = s;
    __syncthreads();
    float total = 0.f;
#pragma unroll
    for (int w = 0; w < 8; w++) total += red[w];
    __syncthreads();
    float mu = total * (1.0f / D);
    float ss = 0.f;
#pragma unroll
    for (int t = 0; t < 4; t++) {
        float dlt = h[t] - mu;
        ss += dlt * dlt;
    }
#pragma unroll
    for (int off = 16; off > 0; off >>= 1) ss += __shfl_xor_sync(0xffffffffu, ss, off);
    if (lane == 0) red[warp] = ss;
    __syncthreads();
    float vtot = 0.f;
#pragma unroll
    for (int w = 0; w < 8; w++) vtot += red[w];
    float var = vtot * (1.0f / D);
    float inv = rsqrtf(var + 1e-5f);
    float4 g4 = *(const float4*)(gamma + tid * 4);
    float4 be4 = *(const float4*)(beta + tid * 4);
    float4 o4;
    o4.x = (h[0] - mu) * inv * g4.x + be4.x;
    o4.y = (h[1] - mu) * inv * g4.y + be4.y;
    o4.z = (h[2] - mu) * inv * g4.z + be4.z;
    o4.w = (h[3] - mu) * inv * g4.w + be4.w;
    *(float4*)(out + (size_t)token * D + tid * 4) = o4;
}

// ================= launch =================
extern "C" void kernel_launch(void* const* d_in, const int* in_sizes, int n_in,
                              void* d_out, int out_size) {
    const float* x     = (const float*)d_in[0];
    const float* wg    = (const float*)d_in[1];
    const float* bg    = (const float*)d_in[2];
    const float* Wq    = (const float*)d_in[3];
    const float* Wkv   = (const float*)d_in[4];
    const float* Wff   = (const float*)d_in[5];
    const float* bff   = (const float*)d_in[6];
    const float* gamma = (const float*)d_in[7];
    const float* beta  = (const float*)d_in[8];
    float* out = (float*)d_out;

    (void)in_sizes; (void)n_in; (void)out_size;

    wgt_kernel<<<E * D / 256, 256>>>(wg);
    fat_kernel<<<3584, 256>>>(x, bg, Wq, Wkv, Wff);

    mask_kernel<<<dim3(EB, 8), 256>>>();
    select_kernel<<<EB, 256>>>();

    int proj_smem = 2 * (64 * 36 + 192 * 36) * (int)sizeof(uint32_t);  // 73,728 B
    cudaFuncSetAttribute(proj_kernel, cudaFuncAttributeMaxDynamicSharedMemorySize, proj_smem);
    proj_kernel<<<dim3(CAP / 64, EB), 256, proj_smem>>>();

    rope_kernel<<<(EB * CAP * 16 + 255) / 256, 256>>>();

    int attn_smem = 512 * 36 * (int)sizeof(uint32_t);   // 73,728 B
    cudaFuncSetAttribute(attn_kernel, cudaFuncAttributeMaxDynamicSharedMemorySize, attn_smem);
    attn_kernel<<<dim3(CAP / 128, EB, 2), 256, attn_smem>>>();

    combine_kernel<<<(EB * CAP * 16 + 255) / 256, 256>>>();

    int op_smem = 2 * 128 * 36 * (int)sizeof(uint32_t);  // 36,864 B
    cudaFuncSetAttribute(outproj_kernel, cudaFuncAttributeMaxDynamicSharedMemorySize, op_smem);
    outproj_kernel<<<dim3(CAP / 128, D / 128, EB), 256, op_smem>>>(bff);

    ln_kernel<<<NTOK, 256>>>(x, gamma, beta, out);
}

// round 14
// speedup vs baseline: 5.2253x; 1.0073x over previous
#include <cuda_runtime.h>
#include <cuda_bf16.h>
#include <math.h>
#include <stdint.h>

// ---------------- problem constants ----------------
namespace {
constexpr int B = 2, S = 2048, D = 1024, E = 16, HD = 64, CAP = 1280, TOPK = 8;
constexpr float EPS = 1e-6f;
constexpr int EB = E * B;    // 32
constexpr int NTOK = B * S;  // 4096
constexpr int MAXPOS = 2048;
}

// ---------------- scratch (device globals; no allocation allowed) ----------------
__device__ float g_route[NTOK * E];                     // raw masked-gate values mg
__device__ float g_routeT[EB * S];                      // normalized route, transposed
__device__ float g_wgt[E * D];                          // gate weights transposed [e][d]
__device__ unsigned char g_mask[EB * S];
__device__ int   g_cnt[EB * 8];                         // selected count per 256-row chunk
__device__ float2 g_rope[MAXPOS * 32];                  // (cos,sin) per [pos][h]
__device__ int   g_seq[EB * CAP];
__device__ float g_w[EB * CAP];
__device__ int   g_inv[E * NTOK];
__device__ uint32_t g_xh[NTOK * 512];                   // x packed bf16x2 along D
__device__ uint32_t g_wt[(size_t)E * 192 * 512];        // Wq|Wkv transposed: [e][n][kpair]
__device__ uint32_t g_wfft[(size_t)E * 1024 * 32];      // Wff transposed: [e][n][kpair]
__device__ uint32_t g_qh[EB * CAP * 32];                // q bf16x2 pairs along HD
__device__ uint32_t g_kh[EB * CAP * 32];                // k bf16x2 pairs along HD
__device__ __nv_bfloat16 g_vt[(size_t)EB * HD * CAP];   // V transposed [eb][col][row]
__device__ uint32_t g_ctxh[EB * CAP * 32];              // ctx packed bf16x2 along HD
__device__ float g_opart[2 * EB * CAP * HD];
__device__ float g_pm[2 * EB * CAP];
__device__ float g_pl[2 * EB * CAP];
__device__ __nv_bfloat16 g_out[(size_t)EB * CAP * D];

// ---------------- helpers ----------------
__device__ __forceinline__ void mma_bf16(float& c0, float& c1, float& c2, float& c3,
                                         uint32_t a0, uint32_t a1, uint32_t a2, uint32_t a3,
                                         uint32_t b0, uint32_t b1) {
    asm volatile(
        "mma.sync.aligned.m16n8k16.row.col.f32.bf16.bf16.f32 "
        "{%0,%1,%2,%3}, {%4,%5,%6,%7}, {%8,%9}, {%0,%1,%2,%3};\n"
        : "+f"(c0), "+f"(c1), "+f"(c2), "+f"(c3)
        : "r"(a0), "r"(a1), "r"(a2), "r"(a3), "r"(b0), "r"(b1));
}
__device__ __forceinline__ uint32_t packbf(float a, float b) {
    __nv_bfloat162 t = __floats2bfloat162_rn(a, b);
    return *reinterpret_cast<uint32_t*>(&t);
}
__device__ __forceinline__ void cp_async16(uint32_t saddr, const void* g) {
    asm volatile("cp.async.ca.shared.global [%0], [%1], 16;" :: "r"(saddr), "l"(g));
}
__device__ __forceinline__ void cp_commit() { asm volatile("cp.async.commit_group;"); }
__device__ __forceinline__ void cp_wait0()  { asm volatile("cp.async.wait_group 0;"); }
__device__ __forceinline__ void cp_wait1()  { asm volatile("cp.async.wait_group 1;"); }

// ================= prep: transpose gate weights (must precede fat kernel) =========
__global__ void wgt_kernel(const float* __restrict__ wg) {
    int idx = blockIdx.x * 256 + threadIdx.x;    // 0..16383
    int d = idx >> 4, e = idx & 15;
    g_wgt[e * D + d] = wg[idx];
}

// ================= fat front-end: gate | xpack | wt | wff | rope-table =================
// blocks [0,512): gate; [512,2560): xpack; [2560,3328): wt; [3328,3584): wff; [3584,3840): rope table
__global__ void __launch_bounds__(256) fat_kernel(const float* __restrict__ x,
                                                  const float* __restrict__ bg,
                                                  const float* __restrict__ Wq,
                                                  const float* __restrict__ Wkv,
                                                  const float* __restrict__ Wff) {
    __shared__ float sm[64][65];
    int bx = blockIdx.x;
    int tid = threadIdx.x;

    if (bx < 512) {
        // ---- gate: warp-per-token ----
        int warp = tid >> 5;
        int lane = tid & 31;
        int token = bx * 8 + warp;
        const float4* xr = (const float4*)(x + (size_t)token * D);
        float acc[E];
#pragma unroll
        for (int e = 0; e < E; e++) acc[e] = 0.f;
#pragma unroll
        for (int it = 0; it < 8; it++) {
            float4 xv = xr[lane + it * 32];
#pragma unroll
            for (int e = 0; e < E; e++) {
                float4 wv = *(const float4*)(g_wgt + e * D + (lane + it * 32) * 4);
                acc[e] += xv.x * wv.x + xv.y * wv.y + xv.z * wv.z + xv.w * wv.w;
            }
        }
#pragma unroll
        for (int off = 16; off; off >>= 1) {
#pragma unroll
            for (int e = 0; e < E; e++)
                acc[e] += __shfl_xor_sync(0xffffffffu, acc[e], off);
        }
        if (lane == 0) {
            float g[E];
            float mx = -3.402823466e38f;
#pragma unroll
            for (int e = 0; e < E; e++) {
                g[e] = acc[e] + bg[e];
                mx = fmaxf(mx, g[e]);
            }
            float den = 0.f;
#pragma unroll
            for (int e = 0; e < E; e++) { g[e] = expf(g[e] - mx); den += g[e]; }
            float inv = 1.f / den;
#pragma unroll
            for (int e = 0; e < E; e++) g[e] *= inv;
#pragma unroll
            for (int e = 0; e < E; e++) {
                int r = 0;
#pragma unroll
                for (int j = 0; j < E; j++)
                    r += (g[j] > g[e]) || (g[j] == g[e] && j < e);
                g_route[(size_t)token * E + e] = (r < TOPK) ? g[e] : 0.f;
            }
        }
    } else if (bx < 2560) {
        // ---- xpack: 4 bf16x2 pairs per thread ----
        int idx = (bx - 512) * 256 + tid;
        const float4* src = (const float4*)x + (size_t)idx * 2;
        float4 v0 = src[0];
        float4 v1 = src[1];
        uint4 o;
        o.x = packbf(v0.x, v0.y);
        o.y = packbf(v0.z, v0.w);
        o.z = packbf(v1.x, v1.y);
        o.w = packbf(v1.z, v1.w);
        *((uint4*)g_xh + idx) = o;
    } else if (bx < 3328) {
        // ---- wt: transpose-pack Wq|Wkv ----
        int i = bx - 2560;
        int e = i / 48;
        int rem = i % 48;
        int k0 = (rem / 3) * 64;
        int nz = rem % 3;
        int n0 = nz * 64;
        const float* src;
        int stride;
        if (nz == 0) { src = Wq + (size_t)e * D * HD; stride = HD; }
        else         { src = Wkv + (size_t)e * D * 128 + (n0 - 64); stride = 128; }
#pragma unroll
        for (int it = 0; it < 16; it++) {
            int idx = tid + it * 256;
            int kk = idx >> 6, nn = idx & 63;
            sm[kk][nn] = src[(size_t)(k0 + kk) * stride + nn];
        }
        __syncthreads();
#pragma unroll
        for (int it = 0; it < 8; it++) {
            int idx = tid + it * 256;
            int n = idx >> 5, kp = idx & 31;
            g_wt[((size_t)(e * 192 + n0 + n)) * 512 + (k0 >> 1) + kp] =
                packbf(sm[2 * kp][n], sm[2 * kp + 1][n]);
        }
    } else if (bx < 3584) {
        // ---- wff: transpose-pack Wff ----
        int i = bx - 3328;
        int e = i >> 4;
        int n0 = (i & 15) * 64;
#pragma unroll
        for (int it = 0; it < 16; it++) {
            int idx = tid + it * 256;
            int kk = idx >> 6, nn = idx & 63;
            sm[kk][nn] = Wff[(size_t)e * HD * D + (size_t)kk * D + n0 + nn];
        }
        __syncthreads();
#pragma unroll
        for (int it = 0; it < 8; it++) {
            int idx = tid + it * 256;
            int n = idx >> 5, kp = idx & 31;
            g_wfft[((size_t)(e * 1024 + n0 + n)) * 32 + kp] =
                packbf(sm[2 * kp][n], sm[2 * kp + 1][n]);
        }
    } else {
        // ---- rope table: (cos,sin)[pos][h] ----
        int idx = (bx - 3584) * 256 + tid;      // 0..65535
        int pos = idx >> 5, h = idx & 31;
        float invf = exp2f(-(float)h * 0.4152410118609203f);
        float sv, cv;
        sincosf((float)pos * invf, &sv, &cv);
        g_rope[idx] = make_float2(cv, sv);
    }
}

// ================= stage 3a: normalize + rank mask + counts + g_inv init =================
__global__ void mask_kernel() {
    int eb = blockIdx.x;
    int e = eb >> 1, b = eb & 1;
    __shared__ float sv[S];
    int tid = threadIdx.x;
    for (int s = tid; s < S; s += 256) {
        float m0 = g_route[(size_t)s * E + e];
        float m1 = g_route[(size_t)(S + s) * E + e];
        float den = m0 + m1 + EPS;
        sv[s] = (b ? m1 : m0) / den * 2.0f;
    }
    __syncthreads();
    if (blockIdx.y == 0) {
        for (int s = tid; s < S; s += 256)
            g_routeT[eb * S + s] = sv[s];
    }
    int i = blockIdx.y * 256 + tid;
    float vi = sv[i];
    int c = 0;
#pragma unroll 4
    for (int j4 = 0; j4 < S / 4; j4++) {
        float4 v = *(const float4*)(sv + j4 * 4);
        int j = j4 * 4;
        c += (v.x > vi) || (v.x == vi && (j + 0) < i);
        c += (v.y > vi) || (v.y == vi && (j + 1) < i);
        c += (v.z > vi) || (v.z == vi && (j + 2) < i);
        c += (v.w > vi) || (v.w == vi && (j + 3) < i);
    }
    int sel = (c < CAP) ? 1 : 0;
    g_mask[eb * S + i] = (unsigned char)sel;
    g_inv[e * NTOK + b * S + i] = -1;
    int total = __syncthreads_count(sel);
    if (tid == 0) g_cnt[eb * 8 + blockIdx.y] = total;
}

// ================= stage 3b: compaction, one row per thread, grid (EB,8) =================
__global__ void select_kernel() {
    int eb = blockIdx.x, y = blockIdx.y;
    int e = eb >> 1, b = eb & 1;
    __shared__ int wsum[8];
    int t = threadIdx.x;
    int base = 0;
#pragma unroll
    for (int yy = 0; yy < 8; yy++)
        if (yy < y) base += g_cnt[eb * 8 + yy];
    int i = y * 256 + t;
    int sel = g_mask[eb * S + i];
    int lane = t & 31, warp = t >> 5;
    int scan = sel;
#pragma unroll
    for (int off = 1; off < 32; off <<= 1) {
        int v = __shfl_up_sync(0xffffffffu, scan, off);
        if (lane >= off) scan += v;
    }
    if (lane == 31) wsum[warp] = scan;
    __syncthreads();
#pragma unroll
    for (int wi = 0; wi < 8; wi++)
        if (wi < warp) base += wsum[wi];
    if (sel) {
        int pos = base + scan - sel;   // exclusive prefix
        g_seq[eb * CAP + pos] = i;
        g_w[eb * CAP + pos] = g_routeT[eb * S + i];
        g_inv[e * NTOK + b * S + i] = pos;
    }
}

// ================= stage 4a: fused Q/K/V projection, BF16 mma =========
__global__ void __launch_bounds__(256) proj_kernel() {
    constexpr int AST = 36, BST = 36;
    constexpr int AW = 64 * AST;
    constexpr int BW = 192 * BST;
    extern __shared__ uint32_t dsm[];
    uint32_t* As = dsm;
    uint32_t* Bs = dsm + 2 * AW;
    int mt = blockIdx.x, eb = blockIdx.y;
    int e = eb >> 1, b = eb & 1;
    int tid = threadIdx.x;
    int lane = tid & 31, w = tid >> 5;
    int lr = lane >> 2, lc = lane & 3;
    int wm = (w & 1) * 32;
    int wn = (w >> 1) * 48;
    int m0 = mt * 64;

    int r0 = tid >> 3;
    int c = tid & 7;
    int seq0 = g_seq[eb * CAP + m0 + r0];
    int seq1 = g_seq[eb * CAP + m0 + r0 + 32];
    const uint32_t* arow0 = g_xh + (size_t)(b * S + seq0) * 512 + c * 4;
    const uint32_t* arow1 = g_xh + (size_t)(b * S + seq1) * 512 + c * 4;
    uint32_t as0 = r0 * AST + c * 4;
    uint32_t as1 = (r0 + 32) * AST + c * 4;

    const uint32_t* wtbase = g_wt + (size_t)e * 192 * 512;
    const uint32_t* bsrc[6];
    uint32_t bsoff[6];
#pragma unroll
    for (int it = 0; it < 6; it++) {
        int f = tid + it * 256;
        int n = f >> 3, cb = f & 7;
        bsrc[it] = wtbase + (size_t)n * 512 + cb * 4;
        bsoff[it] = n * BST + cb * 4;
    }

    float acc[2][6][4];
#pragma unroll
    for (int i = 0; i < 2; i++)
#pragma unroll
        for (int j = 0; j < 6; j++)
#pragma unroll
            for (int r = 0; r < 4; r++) acc[i][j][r] = 0.f;

    cp_async16((uint32_t)__cvta_generic_to_shared(As + as0), arow0);
    cp_async16((uint32_t)__cvta_generic_to_shared(As + as1), arow1);
#pragma unroll
    for (int it = 0; it < 6; it++)
        cp_async16((uint32_t)__cvta_generic_to_shared(Bs + bsoff[it]), bsrc[it]);
    cp_commit();

    for (int kt = 0; kt < 16; kt++) {
        cp_wait0();
        __syncthreads();
        if (kt + 1 < 16) {
            int s = (kt + 1) & 1;
            int kp0 = (kt + 1) * 32;
            cp_async16((uint32_t)__cvta_generic_to_shared(As + s * AW + as0), arow0 + kp0);
            cp_async16((uint32_t)__cvta_generic_to_shared(As + s * AW + as1), arow1 + kp0);
#pragma unroll
            for (int it = 0; it < 6; it++)
                cp_async16((uint32_t)__cvta_generic_to_shared(Bs + s * BW + bsoff[it]),
                           bsrc[it] + kp0);
            cp_commit();
        }
        int cs = kt & 1;
        const uint32_t* Acur = As + cs * AW;
        const uint32_t* Bcur = Bs + cs * BW;
#pragma unroll
        for (int kk = 0; kk < 4; kk++) {
            uint32_t a[2][4], bb[6][2];
#pragma unroll
            for (int mb = 0; mb < 2; mb++) {
                const uint32_t* ap = &Acur[(wm + mb * 16 + lr) * AST + kk * 8 + lc];
                a[mb][0] = ap[0];
                a[mb][1] = ap[8 * AST];
                a[mb][2] = ap[4];
                a[mb][3] = ap[8 * AST + 4];
            }
#pragma unroll
            for (int nb = 0; nb < 6; nb++) {
                const uint32_t* bp = &Bcur[(wn + nb * 8 + lr) * BST + kk * 8 + lc];
                bb[nb][0] = bp[0];
                bb[nb][1] = bp[4];
            }
#pragma unroll
            for (int mb = 0; mb < 2; mb++)
#pragma unroll
                for (int nb = 0; nb < 6; nb++)
                    mma_bf16(acc[mb][nb][0], acc[mb][nb][1], acc[mb][nb][2], acc[mb][nb][3],
                             a[mb][0], a[mb][1], a[mb][2], a[mb][3],
                             bb[nb][0], bb[nb][1]);
        }
    }

#pragma unroll
    for (int nb = 0; nb < 6; nb++) {
        int colg = wn + nb * 8 + 2 * lc;
#pragma unroll
        for (int mb = 0; mb < 2; mb++) {
            int row0 = m0 + wm + mb * 16 + lr;
            int row1 = row0 + 8;
            if (colg < 64) {
                int pair = colg >> 1;
                g_qh[(eb * CAP + row0) * 32 + pair] = packbf(acc[mb][nb][0], acc[mb][nb][1]);
                g_qh[(eb * CAP + row1) * 32 + pair] = packbf(acc[mb][nb][2], acc[mb][nb][3]);
            } else if (colg < 128) {
                int pair = (colg - 64) >> 1;
                g_kh[(eb * CAP + row0) * 32 + pair] = packbf(acc[mb][nb][0], acc[mb][nb][1]);
                g_kh[(eb * CAP + row1) * 32 + pair] = packbf(acc[mb][nb][2], acc[mb][nb][3]);
            } else {
                int col = colg - 128;
                g_vt[(size_t)(eb * HD + col) * CAP + row0]     = __float2bfloat16(acc[mb][nb][0]);
                g_vt[(size_t)(eb * HD + col + 1) * CAP + row0] = __float2bfloat16(acc[mb][nb][1]);
                g_vt[(size_t)(eb * HD + col) * CAP + row1]     = __float2bfloat16(acc[mb][nb][2]);
                g_vt[(size_t)(eb * HD + col + 1) * CAP + row1] = __float2bfloat16(acc[mb][nb][3]);
            }
        }
    }
}

// ================= stage 4b: RoPE via table =================
__global__ void rope_kernel() {
    int idx = blockIdx.x * blockDim.x + threadIdx.x;
    if (idx >= EB * CAP * 16) return;
    int j = idx & 15;
    int t = idx >> 4;
    int pos = g_seq[t];
    float2 cs0 = g_rope[pos * 32 + 2 * j];
    float2 cs1 = g_rope[pos * 32 + 2 * j + 1];
    float c0 = cs0.x, s0 = cs0.y;
    float c1 = cs1.x, s1 = cs1.y;
    uint32_t* q = g_qh + (size_t)t * 32;
    uint32_t* k = g_kh + (size_t)t * 32;
    {
        float2 a = __bfloat1622float2(*(__nv_bfloat162*)&q[j]);
        float2 b = __bfloat1622float2(*(__nv_bfloat162*)&q[j + 16]);
        q[j]      = packbf(a.x * c0 - b.x * s0, a.y * c1 - b.y * s1);
        q[j + 16] = packbf(b.x * c0 + a.x * s0, b.y * c1 + a.y * s1);
    }
    {
        float2 a = __bfloat1622float2(*(__nv_bfloat162*)&k[j]);
        float2 b = __bfloat1622float2(*(__nv_bfloat162*)&k[j + 16]);
        k[j]      = packbf(a.x * c0 - b.x * s0, a.y * c1 - b.y * s1);
        k[j + 16] = packbf(b.x * c0 + a.x * s0, b.y * c1 + a.y * s1);
    }
}

// ================= stage 5: split-KV causal flash attention, BF16 mma, double-buffered ====
__global__ void __launch_bounds__(256, 2) attn_kernel() {
    constexpr int ST = 36;
    extern __shared__ uint32_t dsm[];
    uint32_t* Qs   = dsm;                       // 128*ST
    uint32_t* KsB  = dsm + 128 * ST;            // 2 x 64*ST
    uint32_t* VtsB = dsm + 256 * ST;            // 2 x 64*ST
    uint32_t* Ps   = dsm + 384 * ST;            // 128*ST
    int mt = 9 - blockIdx.x;
    int eb = blockIdx.y;
    int split = blockIdx.z;
    int m0 = mt * 128;
    const uint32_t* qptr = g_qh + (size_t)eb * CAP * 32;
    const uint32_t* kptr = g_kh + (size_t)eb * CAP * 32;
    const uint32_t* vtptr = (const uint32_t*)g_vt + (size_t)eb * HD * (CAP / 2);
    int tid = threadIdx.x;
    int lane = tid & 31, w = tid >> 5;
    int lr = lane >> 2, lc = lane & 3;
    int wrow = 16 * w;

    int half = mt + 1;
    int ntStart = split * half;
    int ntEnd = ntStart + half;

#pragma unroll
    for (int it = 0; it < 4; it++) {
        int idx = tid + it * 256;
        int row = idx >> 3, c = idx & 7;
        cp_async16((uint32_t)__cvta_generic_to_shared(Qs + row * ST + c * 4),
                   qptr + (size_t)(m0 + row) * 32 + c * 4);
    }
    {
        int buf = ntStart & 1;
        int n0 = ntStart * 64;
        uint32_t* Kd = KsB + buf * 64 * ST;
        uint32_t* Vd = VtsB + buf * 64 * ST;
#pragma unroll
        for (int it = 0; it < 2; it++) {
            int idx = tid + it * 256;
            int row = idx >> 3, c = idx & 7;
            cp_async16((uint32_t)__cvta_generic_to_shared(Kd + row * ST + c * 4),
                       kptr + (size_t)(n0 + row) * 32 + c * 4);
            cp_async16((uint32_t)__cvta_generic_to_shared(Vd + row * ST + c * 4),
                       vtptr + (size_t)row * (CAP / 2) + (n0 >> 1) + c * 4);
        }
        cp_commit();
    }

    float o[8][4];
#pragma unroll
    for (int t8 = 0; t8 < 8; t8++)
#pragma unroll
        for (int r = 0; r < 4; r++) o[t8][r] = 0.f;
    float mrow0 = -3.402823466e38f, mrow1 = -3.402823466e38f;
    float lsum0 = 0.f, lsum1 = 0.f;

    for (int nt = ntStart; nt < ntEnd; nt++) {
        __syncthreads();
        if (nt + 1 < ntEnd) {
            int buf = (nt + 1) & 1;
            int n0n = (nt + 1) * 64;
            uint32_t* Kd = KsB + buf * 64 * ST;
            uint32_t* Vd = VtsB + buf * 64 * ST;
#pragma unroll
            for (int it = 0; it < 2; it++) {
                int idx = tid + it * 256;
                int row = idx >> 3, c = idx & 7;
                cp_async16((uint32_t)__cvta_generic_to_shared(Kd + row * ST + c * 4),
                           kptr + (size_t)(n0n + row) * 32 + c * 4);
                cp_async16((uint32_t)__cvta_generic_to_shared(Vd + row * ST + c * 4),
                           vtptr + (size_t)row * (CAP / 2) + (n0n >> 1) + c * 4);
            }
            cp_commit();
            cp_wait1();
        } else {
            cp_wait0();
        }
        __syncthreads();

        int n0 = nt * 64;
        const uint32_t* Ks  = KsB + (nt & 1) * 64 * ST;
        const uint32_t* Vts = VtsB + (nt & 1) * 64 * ST;

        float sacc[8][4];
#pragma unroll
        for (int t8 = 0; t8 < 8; t8++)
#pragma unroll
            for (int r = 0; r < 4; r++) sacc[t8][r] = 0.f;
#pragma unroll
        for (int kk = 0; kk < 4; kk++) {
            const uint32_t* ap = &Qs[(wrow + lr) * ST + kk * 8 + lc];
            uint32_t a0 = ap[0], a1 = ap[8 * ST], a2 = ap[4], a3 = ap[8 * ST + 4];
#pragma unroll
            for (int t8 = 0; t8 < 8; t8++) {
                const uint32_t* bp = &Ks[(t8 * 8 + lr) * ST + kk * 8 + lc];
                mma_bf16(sacc[t8][0], sacc[t8][1], sacc[t8][2], sacc[t8][3],
                         a0, a1, a2, a3, bp[0], bp[4]);
            }
        }

        bool maskT = (nt >= 2 * mt);
#pragma unroll
        for (int t8 = 0; t8 < 8; t8++) {
            int cbase = n0 + t8 * 8 + 2 * lc;
#pragma unroll
            for (int r = 0; r < 4; r++) {
                float v = sacc[t8][r] * 0.125f;
                if (maskT) {
                    int row = m0 + wrow + lr + ((r >= 2) ? 8 : 0);
                    int col = cbase + (r & 1);
                    if (col > row) v = -3.402823466e38f;
                }
                sacc[t8][r] = v;
            }
        }

        float mx0 = -3.402823466e38f, mx1 = -3.402823466e38f;
#pragma unroll
        for (int t8 = 0; t8 < 8; t8++) {
            mx0 = fmaxf(mx0, fmaxf(sacc[t8][0], sacc[t8][1]));
            mx1 = fmaxf(mx1, fmaxf(sacc[t8][2], sacc[t8][3]));
        }
        mx0 = fmaxf(mx0, __shfl_xor_sync(0xffffffffu, mx0, 1));
        mx0 = fmaxf(mx0, __shfl_xor_sync(0xffffffffu, mx0, 2));
        mx1 = fmaxf(mx1, __shfl_xor_sync(0xffffffffu, mx1, 1));
        mx1 = fmaxf(mx1, __shfl_xor_sync(0xffffffffu, mx1, 2));
        float nm0 = fmaxf(mrow0, mx0), nm1 = fmaxf(mrow1, mx1);
        float corr0 = __expf(mrow0 - nm0), corr1 = __expf(mrow1 - nm1);
        float rs0 = 0.f, rs1 = 0.f;
#pragma unroll
        for (int t8 = 0; t8 < 8; t8++) {
            float p0 = __expf(sacc[t8][0] - nm0);
            float p1 = __expf(sacc[t8][1] - nm0);
            float p2 = __expf(sacc[t8][2] - nm1);
            float p3 = __expf(sacc[t8][3] - nm1);
            rs0 += p0 + p1; rs1 += p2 + p3;
            Ps[(wrow + lr) * ST + t8 * 4 + lc]     = packbf(p0, p1);
            Ps[(wrow + lr + 8) * ST + t8 * 4 + lc] = packbf(p2, p3);
        }
        rs0 += __shfl_xor_sync(0xffffffffu, rs0, 1);
        rs0 += __shfl_xor_sync(0xffffffffu, rs0, 2);
        rs1 += __shfl_xor_sync(0xffffffffu, rs1, 1);
        rs1 += __shfl_xor_sync(0xffffffffu, rs1, 2);
        lsum0 = lsum0 * corr0 + rs0;
        lsum1 = lsum1 * corr1 + rs1;
        mrow0 = nm0; mrow1 = nm1;
#pragma unroll
        for (int t8 = 0; t8 < 8; t8++) {
            o[t8][0] *= corr0; o[t8][1] *= corr0;
            o[t8][2] *= corr1; o[t8][3] *= corr1;
        }
        __syncwarp();

#pragma unroll
        for (int kk = 0; kk < 4; kk++) {
            const uint32_t* ap = &Ps[(wrow + lr) * ST + kk * 8 + lc];
            uint32_t a0 = ap[0], a1 = ap[8 * ST], a2 = ap[4], a3 = ap[8 * ST + 4];
#pragma unroll
            for (int t8 = 0; t8 < 8; t8++) {
                const uint32_t* bp = &Vts[(t8 * 8 + lr) * ST + kk * 8 + lc];
                mma_bf16(o[t8][0], o[t8][1], o[t8][2], o[t8][3],
                         a0, a1, a2, a3, bp[0], bp[4]);
            }
        }
    }

    int row0 = m0 + wrow + lr, row1 = row0 + 8;
    float* op = g_opart + (size_t)split * EB * CAP * HD;
#pragma unroll
    for (int t8 = 0; t8 < 8; t8++) {
        int col = t8 * 8 + 2 * lc;
        *(float2*)(op + ((size_t)eb * CAP + row0) * HD + col) = make_float2(o[t8][0], o[t8][1]);
        *(float2*)(op + ((size_t)eb * CAP + row1) * HD + col) = make_float2(o[t8][2], o[t8][3]);
    }
    if (lc == 0) {
        int base = split * EB * CAP + eb * CAP;
        g_pm[base + row0] = mrow0;
        g_pl[base + row0] = lsum0;
        g_pm[base + row1] = mrow1;
        g_pl[base + row1] = lsum1;
    }
}

// ================= stage 5b: combine splits -> packed bf16 ctx =================
__global__ void combine_kernel() {
    int idx = blockIdx.x * blockDim.x + threadIdx.x;
    if (idx >= EB * CAP * 16) return;
    int t = idx >> 4;
    int c4 = (idx & 15) << 2;
    float m0 = g_pm[t], m1 = g_pm[EB * CAP + t];
    float l0 = g_pl[t], l1 = g_pl[EB * CAP + t];
    float M = fmaxf(m0, m1);
    float s0 = __expf(m0 - M), s1 = __expf(m1 - M);
    float inv = 1.f / (l0 * s0 + l1 * s1);
    const float4 a = *(const float4*)(g_opart + (size_t)t * HD + c4);
    const float4 b = *(const float4*)(g_opart + (size_t)EB * CAP * HD + (size_t)t * HD + c4);
    uint2 o;
    o.x = packbf((a.x * s0 + b.x * s1) * inv, (a.y * s0 + b.y * s1) * inv);
    o.y = packbf((a.z * s0 + b.z * s1) * inv, (a.w * s0 + b.w * s1) * inv);
    *(uint2*)(g_ctxh + (size_t)t * 32 + (c4 >> 1)) = o;
}

// ================= stage 6a: out = (ctx @ Wff + bff) * w -> bf16 g_out (BF16 mma) =====
__global__ void __launch_bounds__(256) outproj_kernel(const float* __restrict__ bff) {
    constexpr int AST = 36, BST = 36;
    extern __shared__ uint32_t dsm[];
    uint32_t* As = dsm;
    uint32_t* Bs = As + 128 * AST;
    int mt = blockIdx.x, nt = blockIdx.y, eb = blockIdx.z;
    int e = eb >> 1;
    int tid = threadIdx.x;
    int lane = tid & 31, w = tid >> 5;
    int lr = lane >> 2, lc = lane & 3;
    int wm = (w & 3) * 32, wn = (w >> 2) * 64;
    int m0 = mt * 128, n0 = nt * 128;

#pragma unroll
    for (int it = 0; it < 4; it++) {
        int idx = tid + it * 256;
        int row = idx >> 3, c = idx & 7;
        cp_async16((uint32_t)__cvta_generic_to_shared(As + row * AST + c * 4),
                   g_ctxh + (size_t)(eb * CAP + m0 + row) * 32 + c * 4);
    }
#pragma unroll
    for (int it = 0; it < 4; it++) {
        int idx = tid + it * 256;
        int n = idx >> 3, c = idx & 7;
        cp_async16((uint32_t)__cvta_generic_to_shared(Bs + n * BST + c * 4),
                   g_wfft + (size_t)(e * 1024 + n0 + n) * 32 + c * 4);
    }
    cp_commit();
    cp_wait0();
    __syncthreads();

    float acc[2][8][4];
#pragma unroll
    for (int mi = 0; mi < 2; mi++)
#pragma unroll
        for (int t8 = 0; t8 < 8; t8++)
#pragma unroll
            for (int r = 0; r < 4; r++) acc[mi][t8][r] = 0.f;

#pragma unroll
    for (int kk = 0; kk < 4; kk++) {
        uint32_t a[2][4];
#pragma unroll
        for (int mi = 0; mi < 2; mi++) {
            const uint32_t* ap = &As[(wm + mi * 16 + lr) * AST + kk * 8 + lc];
            a[mi][0] = ap[0]; a[mi][1] = ap[8 * AST];
            a[mi][2] = ap[4]; a[mi][3] = ap[8 * AST + 4];
        }
#pragma unroll
        for (int t8 = 0; t8 < 8; t8++) {
            const uint32_t* bp = &Bs[(wn + t8 * 8 + lr) * BST + kk * 8 + lc];
#pragma unroll
            for (int mi = 0; mi < 2; mi++)
                mma_bf16(acc[mi][t8][0], acc[mi][t8][1], acc[mi][t8][2], acc[mi][t8][3],
                         a[mi][0], a[mi][1], a[mi][2], a[mi][3], bp[0], bp[4]);
        }
    }

#pragma unroll
    for (int mi = 0; mi < 2; mi++) {
        int row0 = m0 + wm + mi * 16 + lr;
        int row1 = row0 + 8;
        float wv0 = g_w[eb * CAP + row0];
        float wv1 = g_w[eb * CAP + row1];
#pragma unroll
        for (int t8 = 0; t8 < 8; t8++) {
            int col = n0 + wn + t8 * 8 + 2 * lc;
            float2 bf = *(const float2*)(bff + col);
            if (wv0 != 0.f) {
                __nv_bfloat162 v;
                v.x = __float2bfloat16((acc[mi][t8][0] + bf.x) * wv0);
                v.y = __float2bfloat16((acc[mi][t8][1] + bf.y) * wv0);
                *(__nv_bfloat162*)(g_out + ((size_t)eb * CAP + row0) * D + col) = v;
            }
            if (wv1 != 0.f) {
                __nv_bfloat162 v;
                v.x = __float2bfloat16((acc[mi][t8][2] + bf.x) * wv1);
                v.y = __float2bfloat16((acc[mi][t8][3] + bf.y) * wv1);
                *(__nv_bfloat162*)(g_out + ((size_t)eb * CAP + row1) * D + col) = v;
            }
        }
    }
}

// ================= stage 6b: gather-combine + residual + LayerNorm =================
__global__ void ln_kernel(const float* __restrict__ x,
                          const float* __restrict__ gamma,
                          const float* __restrict__ beta,
                          float* __restrict__ out) {
    int token = blockIdx.x;
    int b = token >> 11;
    int tid = threadIdx.x;
    __shared__ int sh_base[E];
    __shared__ float red[8];
    if (tid < E) {
        int p = g_inv[tid * NTOK + token];
        int base = -1;
        if (p >= 0) {
            int idx = (tid * B + b) * CAP + p;
            if (g_w[idx] != 0.f) base = idx;
        }
        sh_base[tid] = base;
    }
    __syncthreads();
    float4 c = make_float4(0.f, 0.f, 0.f, 0.f);
#pragma unroll
    for (int e = 0; e < E; e++) {
        int base = sh_base[e];
        if (base >= 0) {
            uint2 u = *(const uint2*)(g_out + (size_t)base * D + tid * 4);
            __nv_bfloat162 p0 = *reinterpret_cast<__nv_bfloat162*>(&u.x);
            __nv_bfloat162 p1 = *reinterpret_cast<__nv_bfloat162*>(&u.y);
            c.x += __bfloat162float(p0.x); c.y += __bfloat162float(p0.y);
            c.z += __bfloat162float(p1.x); c.w += __bfloat162float(p1.y);
        }
    }
    float4 x4 = *(const float4*)(x + (size_t)token * D + tid * 4);
    float h[4] = {x4.x + c.x, x4.y + c.y, x4.z + c.z, x4.w + c.w};
    float s = h[0] + h[1] + h[2] + h[3];
#pragma unroll
    for (int off = 16; off > 0; off >>= 1) s += __shfl_xor_sync(0xffffffffu, s, off);
    int warp = tid >> 5, lane = tid & 31;
    if (lane == 0) red[warp] = s;
    __syncthreads();
    float total = 0.f;
#pragma unroll
    for (int w = 0; w < 8; w++) total += red[w];
    __syncthreads();
    float mu = total * (1.0f / D);
    float ss = 0.f;
#pragma unroll
    for (int t = 0; t < 4; t++) {
        float dlt = h[t] - mu;
        ss += dlt * dlt;
    }
#pragma unroll
    for (int off = 16; off > 0; off >>= 1) ss += __shfl_xor_sync(0xffffffffu, ss, off);
    if (lane == 0) red[warp] = ss;
    __syncthreads();
    float vtot = 0.f;
#pragma unroll
    for (int w = 0; w < 8; w++) vtot += red[w];
    float var = vtot * (1.0f / D);
    float inv = rsqrtf(var + 1e-5f);
    float4 g4 = *(const float4*)(gamma + tid * 4);
    float4 be4 = *(const float4*)(beta + tid * 4);
    float4 o4;
    o4.x = (h[0] - mu) * inv * g4.x + be4.x;
    o4.y = (h[1] - mu) * inv * g4.y + be4.y;
    o4.z = (h[2] - mu) * inv * g4.z + be4.z;
    o4.w = (h[3] - mu) * inv * g4.w + be4.w;
    *(float4*)(out + (size_t)token * D + tid * 4) = o4;
}

// ================= launch =================
extern "C" void kernel_launch(void* const* d_in, const int* in_sizes, int n_in,
                              void* d_out, int out_size) {
    const float* x     = (const float*)d_in[0];
    const float* wg    = (const float*)d_in[1];
    const float* bg    = (const float*)d_in[2];
    const float* Wq    = (const float*)d_in[3];
    const float* Wkv   = (const float*)d_in[4];
    const float* Wff   = (const float*)d_in[5];
    const float* bff   = (const float*)d_in[6];
    const float* gamma = (const float*)d_in[7];
    const float* beta  = (const float*)d_in[8];
    float* out = (float*)d_out;

    (void)in_sizes; (void)n_in; (void)out_size;

    wgt_kernel<<<E * D / 256, 256>>>(wg);
    fat_kernel<<<3840, 256>>>(x, bg, Wq, Wkv, Wff);

    mask_kernel<<<dim3(EB, 8), 256>>>();
    select_kernel<<<dim3(EB, 8), 256>>>();

    int proj_smem = 2 * (64 * 36 + 192 * 36) * (int)sizeof(uint32_t);  // 73,728 B
    cudaFuncSetAttribute(proj_kernel, cudaFuncAttributeMaxDynamicSharedMemorySize, proj_smem);
    proj_kernel<<<dim3(CAP / 64, EB), 256, proj_smem>>>();

    rope_kernel<<<(EB * CAP * 16 + 255) / 256, 256>>>();

    int attn_smem = 512 * 36 * (int)sizeof(uint32_t);   // 73,728 B
    cudaFuncSetAttribute(attn_kernel, cudaFuncAttributeMaxDynamicSharedMemorySize, attn_smem);
    attn_kernel<<<dim3(CAP / 128, EB, 2), 256, attn_smem>>>();

    combine_kernel<<<(EB * CAP * 16 + 255) / 256, 256>>>();

    int op_smem = 2 * 128 * 36 * (int)sizeof(uint32_t);  // 36,864 B
    cudaFuncSetAttribute(outproj_kernel, cudaFuncAttributeMaxDynamicSharedMemorySize, op_smem);
    outproj_kernel<<<dim3(CAP / 128, D / 128, EB), 256, op_smem>>>(bff);

    ln_kernel<<<NTOK, 256>>>(x, gamma, beta, out);
}

// round 15
// speedup vs baseline: 5.3243x; 1.0190x over previous
#include <cuda_runtime.h>
#include <cuda_bf16.h>
#include <math.h>
#include <stdint.h>

// ---------------- problem constants ----------------
namespace {
constexpr int B = 2, S = 2048, D = 1024, E = 16, HD = 64, CAP = 1280, TOPK = 8;
constexpr float EPS = 1e-6f;
constexpr int EB = E * B;    // 32
constexpr int NTOK = B * S;  // 4096
constexpr int MAXPOS = 2048;
}

// ---------------- scratch (device globals; no allocation allowed) ----------------
__device__ float g_route[NTOK * E];                     // raw masked-gate values mg
__device__ float g_routeT[EB * S];                      // normalized route, transposed
__device__ float g_wgt[E * D];                          // gate weights transposed [e][d]
__device__ unsigned char g_mask[EB * S];
__device__ int   g_cnt[EB * 8];                         // selected count per 256-row chunk
__device__ float2 g_rope[MAXPOS * 32];                  // (cos,sin) per [pos][h]
__device__ int   g_seq[EB * CAP];
__device__ float g_w[EB * CAP];
__device__ int   g_inv[E * NTOK];
__device__ uint32_t g_xh[NTOK * 512];                   // x packed bf16x2 along D
__device__ uint32_t g_wt[(size_t)E * 192 * 512];        // Wq|Wkv transposed: [e][n][kpair]
__device__ uint32_t g_wfft[(size_t)E * 1024 * 32];      // Wff transposed: [e][n][kpair]
__device__ uint32_t g_qh[EB * CAP * 32];                // q bf16x2 pairs along HD
__device__ uint32_t g_kh[EB * CAP * 32];                // k bf16x2 pairs along HD
__device__ __nv_bfloat16 g_vt[(size_t)EB * HD * CAP];   // V transposed [eb][col][row]
__device__ uint32_t g_ctxh[EB * CAP * 32];              // ctx packed bf16x2 along HD
__device__ float g_opart[2 * EB * CAP * HD];
__device__ float g_pm[2 * EB * CAP];
__device__ float g_pl[2 * EB * CAP];
__device__ __nv_bfloat16 g_out[(size_t)EB * CAP * D];

// ---------------- helpers ----------------
__device__ __forceinline__ void mma_bf16(float& c0, float& c1, float& c2, float& c3,
                                         uint32_t a0, uint32_t a1, uint32_t a2, uint32_t a3,
                                         uint32_t b0, uint32_t b1) {
    asm volatile(
        "mma.sync.aligned.m16n8k16.row.col.f32.bf16.bf16.f32 "
        "{%0,%1,%2,%3}, {%4,%5,%6,%7}, {%8,%9}, {%0,%1,%2,%3};\n"
        : "+f"(c0), "+f"(c1), "+f"(c2), "+f"(c3)
        : "r"(a0), "r"(a1), "r"(a2), "r"(a3), "r"(b0), "r"(b1));
}
__device__ __forceinline__ uint32_t packbf(float a, float b) {
    __nv_bfloat162 t = __floats2bfloat162_rn(a, b);
    return *reinterpret_cast<uint32_t*>(&t);
}
__device__ __forceinline__ void cp_async16(uint32_t saddr, const void* g) {
    asm volatile("cp.async.ca.shared.global [%0], [%1], 16;" :: "r"(saddr), "l"(g));
}
__device__ __forceinline__ void cp_commit() { asm volatile("cp.async.commit_group;"); }
__device__ __forceinline__ void cp_wait0()  { asm volatile("cp.async.wait_group 0;"); }
__device__ __forceinline__ void cp_wait1()  { asm volatile("cp.async.wait_group 1;"); }

// ================= prep: transpose gate weights (must precede fat kernel) =========
__global__ void wgt_kernel(const float* __restrict__ wg) {
    int idx = blockIdx.x * 256 + threadIdx.x;    // 0..16383
    int d = idx >> 4, e = idx & 15;
    g_wgt[e * D + d] = wg[idx];
}

// ================= fat front-end: gate | xpack | wt | wff | rope-table =================
__global__ void __launch_bounds__(256) fat_kernel(const float* __restrict__ x,
                                                  const float* __restrict__ bg,
                                                  const float* __restrict__ Wq,
                                                  const float* __restrict__ Wkv,
                                                  const float* __restrict__ Wff) {
    __shared__ float sm[64][65];
    int bx = blockIdx.x;
    int tid = threadIdx.x;

    if (bx < 512) {
        // ---- gate: warp-per-token ----
        int warp = tid >> 5;
        int lane = tid & 31;
        int token = bx * 8 + warp;
        const float4* xr = (const float4*)(x + (size_t)token * D);
        float acc[E];
#pragma unroll
        for (int e = 0; e < E; e++) acc[e] = 0.f;
#pragma unroll
        for (int it = 0; it < 8; it++) {
            float4 xv = xr[lane + it * 32];
#pragma unroll
            for (int e = 0; e < E; e++) {
                float4 wv = *(const float4*)(g_wgt + e * D + (lane + it * 32) * 4);
                acc[e] += xv.x * wv.x + xv.y * wv.y + xv.z * wv.z + xv.w * wv.w;
            }
        }
#pragma unroll
        for (int off = 16; off; off >>= 1) {
#pragma unroll
            for (int e = 0; e < E; e++)
                acc[e] += __shfl_xor_sync(0xffffffffu, acc[e], off);
        }
        if (lane == 0) {
            float g[E];
            float mx = -3.402823466e38f;
#pragma unroll
            for (int e = 0; e < E; e++) {
                g[e] = acc[e] + bg[e];
                mx = fmaxf(mx, g[e]);
            }
            float den = 0.f;
#pragma unroll
            for (int e = 0; e < E; e++) { g[e] = expf(g[e] - mx); den += g[e]; }
            float inv = 1.f / den;
#pragma unroll
            for (int e = 0; e < E; e++) g[e] *= inv;
#pragma unroll
            for (int e = 0; e < E; e++) {
                int r = 0;
#pragma unroll
                for (int j = 0; j < E; j++)
                    r += (g[j] > g[e]) || (g[j] == g[e] && j < e);
                g_route[(size_t)token * E + e] = (r < TOPK) ? g[e] : 0.f;
            }
        }
    } else if (bx < 2560) {
        // ---- xpack ----
        int idx = (bx - 512) * 256 + tid;
        const float4* src = (const float4*)x + (size_t)idx * 2;
        float4 v0 = src[0];
        float4 v1 = src[1];
        uint4 o;
        o.x = packbf(v0.x, v0.y);
        o.y = packbf(v0.z, v0.w);
        o.z = packbf(v1.x, v1.y);
        o.w = packbf(v1.z, v1.w);
        *((uint4*)g_xh + idx) = o;
    } else if (bx < 3328) {
        // ---- wt ----
        int i = bx - 2560;
        int e = i / 48;
        int rem = i % 48;
        int k0 = (rem / 3) * 64;
        int nz = rem % 3;
        int n0 = nz * 64;
        const float* src;
        int stride;
        if (nz == 0) { src = Wq + (size_t)e * D * HD; stride = HD; }
        else         { src = Wkv + (size_t)e * D * 128 + (n0 - 64); stride = 128; }
#pragma unroll
        for (int it = 0; it < 16; it++) {
            int idx = tid + it * 256;
            int kk = idx >> 6, nn = idx & 63;
            sm[kk][nn] = src[(size_t)(k0 + kk) * stride + nn];
        }
        __syncthreads();
#pragma unroll
        for (int it = 0; it < 8; it++) {
            int idx = tid + it * 256;
            int n = idx >> 5, kp = idx & 31;
            g_wt[((size_t)(e * 192 + n0 + n)) * 512 + (k0 >> 1) + kp] =
                packbf(sm[2 * kp][n], sm[2 * kp + 1][n]);
        }
    } else if (bx < 3584) {
        // ---- wff ----
        int i = bx - 3328;
        int e = i >> 4;
        int n0 = (i & 15) * 64;
#pragma unroll
        for (int it = 0; it < 16; it++) {
            int idx = tid + it * 256;
            int kk = idx >> 6, nn = idx & 63;
            sm[kk][nn] = Wff[(size_t)e * HD * D + (size_t)kk * D + n0 + nn];
        }
        __syncthreads();
#pragma unroll
        for (int it = 0; it < 8; it++) {
            int idx = tid + it * 256;
            int n = idx >> 5, kp = idx & 31;
            g_wfft[((size_t)(e * 1024 + n0 + n)) * 32 + kp] =
                packbf(sm[2 * kp][n], sm[2 * kp + 1][n]);
        }
    } else {
        // ---- rope table ----
        int idx = (bx - 3584) * 256 + tid;
        int pos = idx >> 5, h = idx & 31;
        float invf = exp2f(-(float)h * 0.4152410118609203f);
        float sv, cv;
        sincosf((float)pos * invf, &sv, &cv);
        g_rope[idx] = make_float2(cv, sv);
    }
}

// ================= stage 3a: normalize + rank mask + counts + g_inv init =================
__global__ void mask_kernel() {
    int eb = blockIdx.x;
    int e = eb >> 1, b = eb & 1;
    __shared__ float sv[S];
    int tid = threadIdx.x;
    for (int s = tid; s < S; s += 256) {
        float m0 = g_route[(size_t)s * E + e];
        float m1 = g_route[(size_t)(S + s) * E + e];
        float den = m0 + m1 + EPS;
        sv[s] = (b ? m1 : m0) / den * 2.0f;
    }
    __syncthreads();
    if (blockIdx.y == 0) {
        for (int s = tid; s < S; s += 256)
            g_routeT[eb * S + s] = sv[s];
    }
    int i = blockIdx.y * 256 + tid;
    float vi = sv[i];
    int c = 0;
#pragma unroll 4
    for (int j4 = 0; j4 < S / 4; j4++) {
        float4 v = *(const float4*)(sv + j4 * 4);
        int j = j4 * 4;
        c += (v.x > vi) || (v.x == vi && (j + 0) < i);
        c += (v.y > vi) || (v.y == vi && (j + 1) < i);
        c += (v.z > vi) || (v.z == vi && (j + 2) < i);
        c += (v.w > vi) || (v.w == vi && (j + 3) < i);
    }
    int sel = (c < CAP) ? 1 : 0;
    g_mask[eb * S + i] = (unsigned char)sel;
    g_inv[e * NTOK + b * S + i] = -1;
    int total = __syncthreads_count(sel);
    if (tid == 0) g_cnt[eb * 8 + blockIdx.y] = total;
}

// ================= stage 3b: compaction, one row per thread, grid (EB,8) =================
__global__ void select_kernel() {
    int eb = blockIdx.x, y = blockIdx.y;
    int e = eb >> 1, b = eb & 1;
    __shared__ int wsum[8];
    int t = threadIdx.x;
    int base = 0;
#pragma unroll
    for (int yy = 0; yy < 8; yy++)
        if (yy < y) base += g_cnt[eb * 8 + yy];
    int i = y * 256 + t;
    int sel = g_mask[eb * S + i];
    int lane = t & 31, warp = t >> 5;
    int scan = sel;
#pragma unroll
    for (int off = 1; off < 32; off <<= 1) {
        int v = __shfl_up_sync(0xffffffffu, scan, off);
        if (lane >= off) scan += v;
    }
    if (lane == 31) wsum[warp] = scan;
    __syncthreads();
#pragma unroll
    for (int wi = 0; wi < 8; wi++)
        if (wi < warp) base += wsum[wi];
    if (sel) {
        int pos = base + scan - sel;
        g_seq[eb * CAP + pos] = i;
        g_w[eb * CAP + pos] = g_routeT[eb * S + i];
        g_inv[e * NTOK + b * S + i] = pos;
    }
}

// ================= stage 4a: fused Q/K/V projection, BF16 mma =========
__global__ void __launch_bounds__(256) proj_kernel() {
    constexpr int AST = 36, BST = 36;
    constexpr int AW = 64 * AST;
    constexpr int BW = 192 * BST;
    extern __shared__ uint32_t dsm[];
    uint32_t* As = dsm;
    uint32_t* Bs = dsm + 2 * AW;
    int mt = blockIdx.x, eb = blockIdx.y;
    int e = eb >> 1, b = eb & 1;
    int tid = threadIdx.x;
    int lane = tid & 31, w = tid >> 5;
    int lr = lane >> 2, lc = lane & 3;
    int wm = (w & 1) * 32;
    int wn = (w >> 1) * 48;
    int m0 = mt * 64;

    int r0 = tid >> 3;
    int c = tid & 7;
    int seq0 = g_seq[eb * CAP + m0 + r0];
    int seq1 = g_seq[eb * CAP + m0 + r0 + 32];
    const uint32_t* arow0 = g_xh + (size_t)(b * S + seq0) * 512 + c * 4;
    const uint32_t* arow1 = g_xh + (size_t)(b * S + seq1) * 512 + c * 4;
    uint32_t as0 = r0 * AST + c * 4;
    uint32_t as1 = (r0 + 32) * AST + c * 4;

    const uint32_t* wtbase = g_wt + (size_t)e * 192 * 512;
    const uint32_t* bsrc[6];
    uint32_t bsoff[6];
#pragma unroll
    for (int it = 0; it < 6; it++) {
        int f = tid + it * 256;
        int n = f >> 3, cb = f & 7;
        bsrc[it] = wtbase + (size_t)n * 512 + cb * 4;
        bsoff[it] = n * BST + cb * 4;
    }

    float acc[2][6][4];
#pragma unroll
    for (int i = 0; i < 2; i++)
#pragma unroll
        for (int j = 0; j < 6; j++)
#pragma unroll
            for (int r = 0; r < 4; r++) acc[i][j][r] = 0.f;

    cp_async16((uint32_t)__cvta_generic_to_shared(As + as0), arow0);
    cp_async16((uint32_t)__cvta_generic_to_shared(As + as1), arow1);
#pragma unroll
    for (int it = 0; it < 6; it++)
        cp_async16((uint32_t)__cvta_generic_to_shared(Bs + bsoff[it]), bsrc[it]);
    cp_commit();

    for (int kt = 0; kt < 16; kt++) {
        cp_wait0();
        __syncthreads();
        if (kt + 1 < 16) {
            int s = (kt + 1) & 1;
            int kp0 = (kt + 1) * 32;
            cp_async16((uint32_t)__cvta_generic_to_shared(As + s * AW + as0), arow0 + kp0);
            cp_async16((uint32_t)__cvta_generic_to_shared(As + s * AW + as1), arow1 + kp0);
#pragma unroll
            for (int it = 0; it < 6; it++)
                cp_async16((uint32_t)__cvta_generic_to_shared(Bs + s * BW + bsoff[it]),
                           bsrc[it] + kp0);
            cp_commit();
        }
        int cs = kt & 1;
        const uint32_t* Acur = As + cs * AW;
        const uint32_t* Bcur = Bs + cs * BW;
#pragma unroll
        for (int kk = 0; kk < 4; kk++) {
            uint32_t a[2][4], bb[6][2];
#pragma unroll
            for (int mb = 0; mb < 2; mb++) {
                const uint32_t* ap = &Acur[(wm + mb * 16 + lr) * AST + kk * 8 + lc];
                a[mb][0] = ap[0];
                a[mb][1] = ap[8 * AST];
                a[mb][2] = ap[4];
                a[mb][3] = ap[8 * AST + 4];
            }
#pragma unroll
            for (int nb = 0; nb < 6; nb++) {
                const uint32_t* bp = &Bcur[(wn + nb * 8 + lr) * BST + kk * 8 + lc];
                bb[nb][0] = bp[0];
                bb[nb][1] = bp[4];
            }
#pragma unroll
            for (int mb = 0; mb < 2; mb++)
#pragma unroll
                for (int nb = 0; nb < 6; nb++)
                    mma_bf16(acc[mb][nb][0], acc[mb][nb][1], acc[mb][nb][2], acc[mb][nb][3],
                             a[mb][0], a[mb][1], a[mb][2], a[mb][3],
                             bb[nb][0], bb[nb][1]);
        }
    }

#pragma unroll
    for (int nb = 0; nb < 6; nb++) {
        int colg = wn + nb * 8 + 2 * lc;
#pragma unroll
        for (int mb = 0; mb < 2; mb++) {
            int row0 = m0 + wm + mb * 16 + lr;
            int row1 = row0 + 8;
            if (colg < 64) {
                int pair = colg >> 1;
                g_qh[(eb * CAP + row0) * 32 + pair] = packbf(acc[mb][nb][0], acc[mb][nb][1]);
                g_qh[(eb * CAP + row1) * 32 + pair] = packbf(acc[mb][nb][2], acc[mb][nb][3]);
            } else if (colg < 128) {
                int pair = (colg - 64) >> 1;
                g_kh[(eb * CAP + row0) * 32 + pair] = packbf(acc[mb][nb][0], acc[mb][nb][1]);
                g_kh[(eb * CAP + row1) * 32 + pair] = packbf(acc[mb][nb][2], acc[mb][nb][3]);
            } else {
                int col = colg - 128;
                g_vt[(size_t)(eb * HD + col) * CAP + row0]     = __float2bfloat16(acc[mb][nb][0]);
                g_vt[(size_t)(eb * HD + col + 1) * CAP + row0] = __float2bfloat16(acc[mb][nb][1]);
                g_vt[(size_t)(eb * HD + col) * CAP + row1]     = __float2bfloat16(acc[mb][nb][2]);
                g_vt[(size_t)(eb * HD + col + 1) * CAP + row1] = __float2bfloat16(acc[mb][nb][3]);
            }
        }
    }
}

// ================= stage 4b: RoPE via table =================
__global__ void rope_kernel() {
    int idx = blockIdx.x * blockDim.x + threadIdx.x;
    if (idx >= EB * CAP * 16) return;
    int j = idx & 15;
    int t = idx >> 4;
    int pos = g_seq[t];
    float2 cs0 = g_rope[pos * 32 + 2 * j];
    float2 cs1 = g_rope[pos * 32 + 2 * j + 1];
    float c0 = cs0.x, s0 = cs0.y;
    float c1 = cs1.x, s1 = cs1.y;
    uint32_t* q = g_qh + (size_t)t * 32;
    uint32_t* k = g_kh + (size_t)t * 32;
    {
        float2 a = __bfloat1622float2(*(__nv_bfloat162*)&q[j]);
        float2 b = __bfloat1622float2(*(__nv_bfloat162*)&q[j + 16]);
        q[j]      = packbf(a.x * c0 - b.x * s0, a.y * c1 - b.y * s1);
        q[j + 16] = packbf(b.x * c0 + a.x * s0, b.y * c1 + a.y * s1);
    }
    {
        float2 a = __bfloat1622float2(*(__nv_bfloat162*)&k[j]);
        float2 b = __bfloat1622float2(*(__nv_bfloat162*)&k[j + 16]);
        k[j]      = packbf(a.x * c0 - b.x * s0, a.y * c1 - b.y * s1);
        k[j + 16] = packbf(b.x * c0 + a.x * s0, b.y * c1 + a.y * s1);
    }
}

// ================= stage 5: split-KV flash attention, BF16 mma, register-resident P ====
__global__ void __launch_bounds__(256, 2) attn_kernel() {
    constexpr int ST = 36;
    extern __shared__ uint32_t dsm[];
    uint32_t* Qs   = dsm;                       // 128*ST
    uint32_t* KsB  = dsm + 128 * ST;            // 2 x 64*ST
    uint32_t* VtsB = dsm + 256 * ST;            // 2 x 64*ST
    int mt = 9 - blockIdx.x;
    int eb = blockIdx.y;
    int split = blockIdx.z;
    int m0 = mt * 128;
    const uint32_t* qptr = g_qh + (size_t)eb * CAP * 32;
    const uint32_t* kptr = g_kh + (size_t)eb * CAP * 32;
    const uint32_t* vtptr = (const uint32_t*)g_vt + (size_t)eb * HD * (CAP / 2);
    int tid = threadIdx.x;
    int lane = tid & 31, w = tid >> 5;
    int lr = lane >> 2, lc = lane & 3;
    int wrow = 16 * w;

    int half = mt + 1;
    int ntStart = split * half;
    int ntEnd = ntStart + half;

#pragma unroll
    for (int it = 0; it < 4; it++) {
        int idx = tid + it * 256;
        int row = idx >> 3, c = idx & 7;
        cp_async16((uint32_t)__cvta_generic_to_shared(Qs + row * ST + c * 4),
                   qptr + (size_t)(m0 + row) * 32 + c * 4);
    }
    {
        int buf = ntStart & 1;
        int n0 = ntStart * 64;
        uint32_t* Kd = KsB + buf * 64 * ST;
        uint32_t* Vd = VtsB + buf * 64 * ST;
#pragma unroll
        for (int it = 0; it < 2; it++) {
            int idx = tid + it * 256;
            int row = idx >> 3, c = idx & 7;
            cp_async16((uint32_t)__cvta_generic_to_shared(Kd + row * ST + c * 4),
                       kptr + (size_t)(n0 + row) * 32 + c * 4);
            cp_async16((uint32_t)__cvta_generic_to_shared(Vd + row * ST + c * 4),
                       vtptr + (size_t)row * (CAP / 2) + (n0 >> 1) + c * 4);
        }
        cp_commit();
    }

    float o[8][4];
#pragma unroll
    for (int t8 = 0; t8 < 8; t8++)
#pragma unroll
        for (int r = 0; r < 4; r++) o[t8][r] = 0.f;
    float mrow0 = -3.402823466e38f, mrow1 = -3.402823466e38f;
    float lsum0 = 0.f, lsum1 = 0.f;

    for (int nt = ntStart; nt < ntEnd; nt++) {
        __syncthreads();
        if (nt + 1 < ntEnd) {
            int buf = (nt + 1) & 1;
            int n0n = (nt + 1) * 64;
            uint32_t* Kd = KsB + buf * 64 * ST;
            uint32_t* Vd = VtsB + buf * 64 * ST;
#pragma unroll
            for (int it = 0; it < 2; it++) {
                int idx = tid + it * 256;
                int row = idx >> 3, c = idx & 7;
                cp_async16((uint32_t)__cvta_generic_to_shared(Kd + row * ST + c * 4),
                           kptr + (size_t)(n0n + row) * 32 + c * 4);
                cp_async16((uint32_t)__cvta_generic_to_shared(Vd + row * ST + c * 4),
                           vtptr + (size_t)row * (CAP / 2) + (n0n >> 1) + c * 4);
            }
            cp_commit();
            cp_wait1();
        } else {
            cp_wait0();
        }
        __syncthreads();

        int n0 = nt * 64;
        const uint32_t* Ks  = KsB + (nt & 1) * 64 * ST;
        const uint32_t* Vts = VtsB + (nt & 1) * 64 * ST;

        float sacc[8][4];
#pragma unroll
        for (int t8 = 0; t8 < 8; t8++)
#pragma unroll
            for (int r = 0; r < 4; r++) sacc[t8][r] = 0.f;
#pragma unroll
        for (int kk = 0; kk < 4; kk++) {
            const uint32_t* ap = &Qs[(wrow + lr) * ST + kk * 8 + lc];
            uint32_t a0 = ap[0], a1 = ap[8 * ST], a2 = ap[4], a3 = ap[8 * ST + 4];
#pragma unroll
            for (int t8 = 0; t8 < 8; t8++) {
                const uint32_t* bp = &Ks[(t8 * 8 + lr) * ST + kk * 8 + lc];
                mma_bf16(sacc[t8][0], sacc[t8][1], sacc[t8][2], sacc[t8][3],
                         a0, a1, a2, a3, bp[0], bp[4]);
            }
        }

        bool maskT = (nt >= 2 * mt);
#pragma unroll
        for (int t8 = 0; t8 < 8; t8++) {
            int cbase = n0 + t8 * 8 + 2 * lc;
#pragma unroll
            for (int r = 0; r < 4; r++) {
                float v = sacc[t8][r] * 0.125f;
                if (maskT) {
                    int row = m0 + wrow + lr + ((r >= 2) ? 8 : 0);
                    int col = cbase + (r & 1);
                    if (col > row) v = -3.402823466e38f;
                }
                sacc[t8][r] = v;
            }
        }

        float mx0 = -3.402823466e38f, mx1 = -3.402823466e38f;
#pragma unroll
        for (int t8 = 0; t8 < 8; t8++) {
            mx0 = fmaxf(mx0, fmaxf(sacc[t8][0], sacc[t8][1]));
            mx1 = fmaxf(mx1, fmaxf(sacc[t8][2], sacc[t8][3]));
        }
        mx0 = fmaxf(mx0, __shfl_xor_sync(0xffffffffu, mx0, 1));
        mx0 = fmaxf(mx0, __shfl_xor_sync(0xffffffffu, mx0, 2));
        mx1 = fmaxf(mx1, __shfl_xor_sync(0xffffffffu, mx1, 1));
        mx1 = fmaxf(mx1, __shfl_xor_sync(0xffffffffu, mx1, 2));
        float nm0 = fmaxf(mrow0, mx0), nm1 = fmaxf(mrow1, mx1);
        float corr0 = __expf(mrow0 - nm0), corr1 = __expf(mrow1 - nm1);
        float rs0 = 0.f, rs1 = 0.f;
        uint32_t pp0[8], pp1[8];   // register-resident P: pp0 = rows lr, pp1 = rows lr+8
#pragma unroll
        for (int t8 = 0; t8 < 8; t8++) {
            float p0 = __expf(sacc[t8][0] - nm0);
            float p1 = __expf(sacc[t8][1] - nm0);
            float p2 = __expf(sacc[t8][2] - nm1);
            float p3 = __expf(sacc[t8][3] - nm1);
            rs0 += p0 + p1; rs1 += p2 + p3;
            pp0[t8] = packbf(p0, p1);
            pp1[t8] = packbf(p2, p3);
        }
        rs0 += __shfl_xor_sync(0xffffffffu, rs0, 1);
        rs0 += __shfl_xor_sync(0xffffffffu, rs0, 2);
        rs1 += __shfl_xor_sync(0xffffffffu, rs1, 1);
        rs1 += __shfl_xor_sync(0xffffffffu, rs1, 2);
        lsum0 = lsum0 * corr0 + rs0;
        lsum1 = lsum1 * corr1 + rs1;
        mrow0 = nm0; mrow1 = nm1;
#pragma unroll
        for (int t8 = 0; t8 < 8; t8++) {
            o[t8][0] *= corr0; o[t8][1] *= corr0;
            o[t8][2] *= corr1; o[t8][3] *= corr1;
        }

        // O += P V : A-fragments come straight from registers
#pragma unroll
        for (int kk = 0; kk < 4; kk++) {
            uint32_t a0 = pp0[2 * kk];
            uint32_t a1 = pp1[2 * kk];
            uint32_t a2 = pp0[2 * kk + 1];
            uint32_t a3 = pp1[2 * kk + 1];
#pragma unroll
            for (int t8 = 0; t8 < 8; t8++) {
                const uint32_t* bp = &Vts[(t8 * 8 + lr) * ST + kk * 8 + lc];
                mma_bf16(o[t8][0], o[t8][1], o[t8][2], o[t8][3],
                         a0, a1, a2, a3, bp[0], bp[4]);
            }
        }
    }

    int row0 = m0 + wrow + lr, row1 = row0 + 8;
    float* op = g_opart + (size_t)split * EB * CAP * HD;
#pragma unroll
    for (int t8 = 0; t8 < 8; t8++) {
        int col = t8 * 8 + 2 * lc;
        *(float2*)(op + ((size_t)eb * CAP + row0) * HD + col) = make_float2(o[t8][0], o[t8][1]);
        *(float2*)(op + ((size_t)eb * CAP + row1) * HD + col) = make_float2(o[t8][2], o[t8][3]);
    }
    if (lc == 0) {
        int base = split * EB * CAP + eb * CAP;
        g_pm[base + row0] = mrow0;
        g_pl[base + row0] = lsum0;
        g_pm[base + row1] = mrow1;
        g_pl[base + row1] = lsum1;
    }
}

// ================= stage 5b: combine splits -> packed bf16 ctx =================
__global__ void combine_kernel() {
    int idx = blockIdx.x * blockDim.x + threadIdx.x;
    if (idx >= EB * CAP * 16) return;
    int t = idx >> 4;
    int c4 = (idx & 15) << 2;
    float m0 = g_pm[t], m1 = g_pm[EB * CAP + t];
    float l0 = g_pl[t], l1 = g_pl[EB * CAP + t];
    float M = fmaxf(m0, m1);
    float s0 = __expf(m0 - M), s1 = __expf(m1 - M);
    float inv = 1.f / (l0 * s0 + l1 * s1);
    const float4 a = *(const float4*)(g_opart + (size_t)t * HD + c4);
    const float4 b = *(const float4*)(g_opart + (size_t)EB * CAP * HD + (size_t)t * HD + c4);
    uint2 o;
    o.x = packbf((a.x * s0 + b.x * s1) * inv, (a.y * s0 + b.y * s1) * inv);
    o.y = packbf((a.z * s0 + b.z * s1) * inv, (a.w * s0 + b.w * s1) * inv);
    *(uint2*)(g_ctxh + (size_t)t * 32 + (c4 >> 1)) = o;
}

// ================= stage 6a: out = (ctx @ Wff + bff) * w -> bf16 g_out (BF16 mma) =====
__global__ void __launch_bounds__(256) outproj_kernel(const float* __restrict__ bff) {
    constexpr int AST = 36, BST = 36;
    extern __shared__ uint32_t dsm[];
    uint32_t* As = dsm;
    uint32_t* Bs = As + 128 * AST;
    int mt = blockIdx.x, nt = blockIdx.y, eb = blockIdx.z;
    int e = eb >> 1;
    int tid = threadIdx.x;
    int lane = tid & 31, w = tid >> 5;
    int lr = lane >> 2, lc = lane & 3;
    int wm = (w & 3) * 32, wn = (w >> 2) * 64;
    int m0 = mt * 128, n0 = nt * 128;

#pragma unroll
    for (int it = 0; it < 4; it++) {
        int idx = tid + it * 256;
        int row = idx >> 3, c = idx & 7;
        cp_async16((uint32_t)__cvta_generic_to_shared(As + row * AST + c * 4),
                   g_ctxh + (size_t)(eb * CAP + m0 + row) * 32 + c * 4);
    }
#pragma unroll
    for (int it = 0; it < 4; it++) {
        int idx = tid + it * 256;
        int n = idx >> 3, c = idx & 7;
        cp_async16((uint32_t)__cvta_generic_to_shared(Bs + n * BST + c * 4),
                   g_wfft + (size_t)(e * 1024 + n0 + n) * 32 + c * 4);
    }
    cp_commit();
    cp_wait0();
    __syncthreads();

    float acc[2][8][4];
#pragma unroll
    for (int mi = 0; mi < 2; mi++)
#pragma unroll
        for (int t8 = 0; t8 < 8; t8++)
#pragma unroll
            for (int r = 0; r < 4; r++) acc[mi][t8][r] = 0.f;

#pragma unroll
    for (int kk = 0; kk < 4; kk++) {
        uint32_t a[2][4];
#pragma unroll
        for (int mi = 0; mi < 2; mi++) {
            const uint32_t* ap = &As[(wm + mi * 16 + lr) * AST + kk * 8 + lc];
            a[mi][0] = ap[0]; a[mi][1] = ap[8 * AST];
            a[mi][2] = ap[4]; a[mi][3] = ap[8 * AST + 4];
        }
#pragma unroll
        for (int t8 = 0; t8 < 8; t8++) {
            const uint32_t* bp = &Bs[(wn + t8 * 8 + lr) * BST + kk * 8 + lc];
#pragma unroll
            for (int mi = 0; mi < 2; mi++)
                mma_bf16(acc[mi][t8][0], acc[mi][t8][1], acc[mi][t8][2], acc[mi][t8][3],
                         a[mi][0], a[mi][1], a[mi][2], a[mi][3], bp[0], bp[4]);
        }
    }

#pragma unroll
    for (int mi = 0; mi < 2; mi++) {
        int row0 = m0 + wm + mi * 16 + lr;
        int row1 = row0 + 8;
        float wv0 = g_w[eb * CAP + row0];
        float wv1 = g_w[eb * CAP + row1];
#pragma unroll
        for (int t8 = 0; t8 < 8; t8++) {
            int col = n0 + wn + t8 * 8 + 2 * lc;
            float2 bf = *(const float2*)(bff + col);
            if (wv0 != 0.f) {
                __nv_bfloat162 v;
                v.x = __float2bfloat16((acc[mi][t8][0] + bf.x) * wv0);
                v.y = __float2bfloat16((acc[mi][t8][1] + bf.y) * wv0);
                *(__nv_bfloat162*)(g_out + ((size_t)eb * CAP + row0) * D + col) = v;
            }
            if (wv1 != 0.f) {
                __nv_bfloat162 v;
                v.x = __float2bfloat16((acc[mi][t8][2] + bf.x) * wv1);
                v.y = __float2bfloat16((acc[mi][t8][3] + bf.y) * wv1);
                *(__nv_bfloat162*)(g_out + ((size_t)eb * CAP + row1) * D + col) = v;
            }
        }
    }
}

// ================= stage 6b: gather-combine + residual + LayerNorm =================
__global__ void ln_kernel(const float* __restrict__ x,
                          const float* __restrict__ gamma,
                          const float* __restrict__ beta,
                          float* __restrict__ out) {
    int token = blockIdx.x;
    int b = token >> 11;
    int tid = threadIdx.x;
    __shared__ int sh_base[E];
    __shared__ float red[8];
    if (tid < E) {
        int p = g_inv[tid * NTOK + token];
        int base = -1;
        if (p >= 0) {
            int idx = (tid * B + b) * CAP + p;
            if (g_w[idx] != 0.f) base = idx;
        }
        sh_base[tid] = base;
    }
    __syncthreads();
    float4 c = make_float4(0.f, 0.f, 0.f, 0.f);
#pragma unroll
    for (int e = 0; e < E; e++) {
        int base = sh_base[e];
        if (base >= 0) {
            uint2 u = *(const uint2*)(g_out + (size_t)base * D + tid * 4);
            __nv_bfloat162 p0 = *reinterpret_cast<__nv_bfloat162*>(&u.x);
            __nv_bfloat162 p1 = *reinterpret_cast<__nv_bfloat162*>(&u.y);
            c.x += __bfloat162float(p0.x); c.y += __bfloat162float(p0.y);
            c.z += __bfloat162float(p1.x); c.w += __bfloat162float(p1.y);
        }
    }
    float4 x4 = *(const float4*)(x + (size_t)token * D + tid * 4);
    float h[4] = {x4.x + c.x, x4.y + c.y, x4.z + c.z, x4.w + c.w};
    float s = h[0] + h[1] + h[2] + h[3];
#pragma unroll
    for (int off = 16; off > 0; off >>= 1) s += __shfl_xor_sync(0xffffffffu, s, off);
    int warp = tid >> 5, lane = tid & 31;
    if (lane == 0) red[warp] = s;
    __syncthreads();
    float total = 0.f;
#pragma unroll
    for (int w = 0; w < 8; w++) total += red[w];
    __syncthreads();
    float mu = total * (1.0f / D);
    float ss = 0.f;
#pragma unroll
    for (int t = 0; t < 4; t++) {
        float dlt = h[t] - mu;
        ss += dlt * dlt;
    }
#pragma unroll
    for (int off = 16; off > 0; off >>= 1) ss += __shfl_xor_sync(0xffffffffu, ss, off);
    if (lane == 0) red[warp] = ss;
    __syncthreads();
    float vtot = 0.f;
#pragma unroll
    for (int w = 0; w < 8; w++) vtot += red[w];
    float var = vtot * (1.0f / D);
    float inv = rsqrtf(var + 1e-5f);
    float4 g4 = *(const float4*)(gamma + tid * 4);
    float4 be4 = *(const float4*)(beta + tid * 4);
    float4 o4;
    o4.x = (h[0] - mu) * inv * g4.x + be4.x;
    o4.y = (h[1] - mu) * inv * g4.y + be4.y;
    o4.z = (h[2] - mu) * inv * g4.z + be4.z;
    o4.w = (h[3] - mu) * inv * g4.w + be4.w;
    *(float4*)(out + (size_t)token * D + tid * 4) = o4;
}

// ================= launch =================
extern "C" void kernel_launch(void* const* d_in, const int* in_sizes, int n_in,
                              void* d_out, int out_size) {
    const float* x     = (const float*)d_in[0];
    const float* wg    = (const float*)d_in[1];
    const float* bg    = (const float*)d_in[2];
    const float* Wq    = (const float*)d_in[3];
    const float* Wkv   = (const float*)d_in[4];
    const float* Wff   = (const float*)d_in[5];
    const float* bff   = (const float*)d_in[6];
    const float* gamma = (const float*)d_in[7];
    const float* beta  = (const float*)d_in[8];
    float* out = (float*)d_out;

    (void)in_sizes; (void)n_in; (void)out_size;

    wgt_kernel<<<E * D / 256, 256>>>(wg);
    fat_kernel<<<3840, 256>>>(x, bg, Wq, Wkv, Wff);

    mask_kernel<<<dim3(EB, 8), 256>>>();
    select_kernel<<<dim3(EB, 8), 256>>>();

    int proj_smem = 2 * (64 * 36 + 192 * 36) * (int)sizeof(uint32_t);  // 73,728 B
    cudaFuncSetAttribute(proj_kernel, cudaFuncAttributeMaxDynamicSharedMemorySize, proj_smem);
    proj_kernel<<<dim3(CAP / 64, EB), 256, proj_smem>>>();

    rope_kernel<<<(EB * CAP * 16 + 255) / 256, 256>>>();

    int attn_smem = 384 * 36 * (int)sizeof(uint32_t);   // 55,296 B
    cudaFuncSetAttribute(attn_kernel, cudaFuncAttributeMaxDynamicSharedMemorySize, attn_smem);
    attn_kernel<<<dim3(CAP / 128, EB, 2), 256, attn_smem>>>();

    combine_kernel<<<(EB * CAP * 16 + 255) / 256, 256>>>();

    int op_smem = 2 * 128 * 36 * (int)sizeof(uint32_t);  // 36,864 B
    cudaFuncSetAttribute(outproj_kernel, cudaFuncAttributeMaxDynamicSharedMemorySize, op_smem);
    outproj_kernel<<<dim3(CAP / 128, D / 128, EB), 256, op_smem>>>(bff);

    ln_kernel<<<NTOK, 256>>>(x, gamma, beta, out);
}